// round 1
// baseline (speedup 1.0000x reference)
#include <cuda_runtime.h>
#include <math.h>

// Problem dims (fixed by the reference)
#define Tn 8192
#define Dn 1024
#define Hn 16
#define HDn 64
#define Fn 4096
#define En 8
#define Bn 4
#define Sn 2048

// ---------------- scratch (static device allocations; no cudaMalloc allowed) ---------
__device__ float g_q[Tn * Dn];
__device__ float g_k[Tn * Dn];
__device__ float g_v[Tn * Dn];
__device__ float g_ctx[Tn * Dn];
__device__ float g_ao[Tn * Dn];
__device__ float g_x1[Tn * Dn];
__device__ float g_xs[Tn * Dn];
__device__ float g_xsort[Tn * Dn];
__device__ float g_moe[Tn * Dn];
__device__ float g_h1[(size_t)Tn * Fn];
__device__ int g_route[Tn];
__device__ int g_dest[Tn];
__device__ int g_off[En + 1];

// =====================================================================================
// Generic SGEMM:  C[m, n] = A[m, :] . W[n, :]  + bias[n]   (NT layout, both row-major)
// 128x128 block tile, 8x8 per-thread microtile, K staged in 16-deep smem slabs.
// USE_OFF=1: expert-batched variant; rows [off[e], off[e+1]) of the global row space,
// with per-expert weight/bias strides. Inactive blocks exit immediately.
// =====================================================================================
template <int RELU, int USE_OFF>
__global__ void __launch_bounds__(256, 2) sgemm_nt(
    const float* __restrict__ A, const float* __restrict__ W,
    const float* __restrict__ bias, float* __restrict__ C,
    int N, int K, int Mfull, const int* __restrict__ off, size_t wstride) {
  int e = blockIdx.z;
  int m_start, m_end;
  if (USE_OFF) {
    m_start = off[e];
    m_end = off[e + 1];
  } else {
    m_start = 0;
    m_end = Mfull;
  }
  int m0 = m_start + (int)blockIdx.y * 128;
  if (m0 >= m_end) return;

  const float* Wp = W + (size_t)e * wstride;
  const float* bp = bias + (size_t)e * N;
  int n0 = blockIdx.x * 128;

  __shared__ float As[16][128];
  __shared__ float Bs[16][128];

  int tid = threadIdx.x;
  int tx = tid & 15, ty = tid >> 4;

  float acc[8][8];
#pragma unroll
  for (int i = 0; i < 8; i++)
#pragma unroll
    for (int j = 0; j < 8; j++) acc[i][j] = 0.f;

  int lr = tid >> 2;        // 0..63
  int lk = (tid & 3) * 4;   // 0,4,8,12

  for (int k0 = 0; k0 < K; k0 += 16) {
#pragma unroll
    for (int l = 0; l < 2; l++) {
      int r = lr + l * 64;
      int grow = m0 + r;
      float4 av = make_float4(0.f, 0.f, 0.f, 0.f);
      if (grow < m_end) av = *(const float4*)(A + (size_t)grow * K + k0 + lk);
      As[lk + 0][r] = av.x;
      As[lk + 1][r] = av.y;
      As[lk + 2][r] = av.z;
      As[lk + 3][r] = av.w;
      float4 bv = *(const float4*)(Wp + (size_t)(n0 + r) * K + k0 + lk);
      Bs[lk + 0][r] = bv.x;
      Bs[lk + 1][r] = bv.y;
      Bs[lk + 2][r] = bv.z;
      Bs[lk + 3][r] = bv.w;
    }
    __syncthreads();
#pragma unroll
    for (int kk = 0; kk < 16; kk++) {
      float a[8], b[8];
      *(float4*)&a[0] = *(const float4*)&As[kk][ty * 8];
      *(float4*)&a[4] = *(const float4*)&As[kk][ty * 8 + 4];
      *(float4*)&b[0] = *(const float4*)&Bs[kk][tx * 8];
      *(float4*)&b[4] = *(const float4*)&Bs[kk][tx * 8 + 4];
#pragma unroll
      for (int i = 0; i < 8; i++)
#pragma unroll
        for (int j = 0; j < 8; j++) acc[i][j] += a[i] * b[j];
    }
    __syncthreads();
  }

  float bb[8];
#pragma unroll
  for (int j = 0; j < 8; j++) bb[j] = bp[n0 + tx * 8 + j];

#pragma unroll
  for (int i = 0; i < 8; i++) {
    int grow = m0 + ty * 8 + i;
    if (grow < m_end) {
      float outv[8];
#pragma unroll
      for (int j = 0; j < 8; j++) {
        float v = acc[i][j] + bb[j];
        if (RELU) v = fmaxf(v, 0.f);
        outv[j] = v;
      }
      float* cp = C + (size_t)grow * N + n0 + tx * 8;
      *(float4*)cp = *(float4*)&outv[0];
      *(float4*)(cp + 4) = *(float4*)&outv[4];
    }
  }
}

// =====================================================================================
// Flash attention: per (b,h), 64-query tiles against 64-key tiles, online softmax.
// 256 threads, each owns a 4x4 microtile of the 64x64 score / output tiles.
// Qs/Ks stored d-major, Vs row-major, P stored transposed — all float4 LDS.
// =====================================================================================
__global__ void __launch_bounds__(256) flash_attn(
    const float* __restrict__ Q, const float* __restrict__ K,
    const float* __restrict__ V, const int* __restrict__ mask,
    float* __restrict__ O) {
  extern __shared__ float sm[];
  float* Qs = sm;                 // [64][68]  Qs[d][r]
  float* Ks = sm + 64 * 68;       // [64][68]  Ks[d][c]
  float* Vs = sm + 2 * 64 * 68;   // [64][68]  Vs[kk][d]
  float* Ps = sm + 3 * 64 * 68;   // [64][68]  Ps[kk][r]
  __shared__ int msk[64];

  int bh = blockIdx.y;
  int b = bh >> 4, h = bh & 15;
  int q0 = blockIdx.x * 64;
  int tid = threadIdx.x;
  int tx = tid & 15, ty = tid >> 4;
  int r0 = ty * 4, c0 = tx * 4;

  // stage Q tile, transposed to d-major
#pragma unroll
  for (int l = 0; l < 4; l++) {
    int p = tid + l * 256;
    int r = p >> 4, dc = (p & 15) * 4;
    float4 qv = *(const float4*)(Q + (size_t)(b * Sn + q0 + r) * Dn + h * HDn + dc);
    Qs[(dc + 0) * 68 + r] = qv.x;
    Qs[(dc + 1) * 68 + r] = qv.y;
    Qs[(dc + 2) * 68 + r] = qv.z;
    Qs[(dc + 3) * 68 + r] = qv.w;
  }

  float m[4], lsum[4], o[4][4];
#pragma unroll
  for (int i = 0; i < 4; i++) {
    m[i] = -1e30f;
    lsum[i] = 0.f;
#pragma unroll
    for (int j = 0; j < 4; j++) o[i][j] = 0.f;
  }

  for (int t0 = 0; t0 < Sn; t0 += 64) {
    __syncthreads();  // prev PV readers done (and Qs staged on first iter)
#pragma unroll
    for (int l = 0; l < 4; l++) {
      int p = tid + l * 256;
      int r = p >> 4, dc = (p & 15) * 4;
      size_t base = (size_t)(b * Sn + t0 + r) * Dn + h * HDn + dc;
      float4 kv = *(const float4*)(K + base);
      Ks[(dc + 0) * 68 + r] = kv.x;
      Ks[(dc + 1) * 68 + r] = kv.y;
      Ks[(dc + 2) * 68 + r] = kv.z;
      Ks[(dc + 3) * 68 + r] = kv.w;
      float4 vv = *(const float4*)(V + base);
      *(float4*)(Vs + r * 68 + dc) = vv;
    }
    if (tid < 64) msk[tid] = mask[b * Sn + t0 + tid];
    __syncthreads();

    float s[4][4];
#pragma unroll
    for (int i = 0; i < 4; i++)
#pragma unroll
      for (int j = 0; j < 4; j++) s[i][j] = 0.f;

#pragma unroll 16
    for (int d = 0; d < 64; d++) {
      float qa[4], kb[4];
      *(float4*)qa = *(const float4*)(Qs + d * 68 + r0);
      *(float4*)kb = *(const float4*)(Ks + d * 68 + c0);
#pragma unroll
      for (int i = 0; i < 4; i++)
#pragma unroll
        for (int j = 0; j < 4; j++) s[i][j] += qa[i] * kb[j];
    }

#pragma unroll
    for (int j = 0; j < 4; j++) {
      bool masked = (msk[c0 + j] == 0);
#pragma unroll
      for (int i = 0; i < 4; i++) s[i][j] = masked ? -1e10f : s[i][j] * 0.125f;
    }

#pragma unroll
    for (int i = 0; i < 4; i++) {
      float mx = fmaxf(fmaxf(s[i][0], s[i][1]), fmaxf(s[i][2], s[i][3]));
      mx = fmaxf(mx, __shfl_xor_sync(0xffffffffu, mx, 1));
      mx = fmaxf(mx, __shfl_xor_sync(0xffffffffu, mx, 2));
      mx = fmaxf(mx, __shfl_xor_sync(0xffffffffu, mx, 4));
      mx = fmaxf(mx, __shfl_xor_sync(0xffffffffu, mx, 8));
      float mnew = fmaxf(m[i], mx);
      float scale = __expf(m[i] - mnew);
      m[i] = mnew;
      float rs = 0.f;
#pragma unroll
      for (int j = 0; j < 4; j++) {
        float p = __expf(s[i][j] - mnew);
        s[i][j] = p;
        rs += p;
      }
      rs += __shfl_xor_sync(0xffffffffu, rs, 1);
      rs += __shfl_xor_sync(0xffffffffu, rs, 2);
      rs += __shfl_xor_sync(0xffffffffu, rs, 4);
      rs += __shfl_xor_sync(0xffffffffu, rs, 8);
      lsum[i] = lsum[i] * scale + rs;
#pragma unroll
      for (int j = 0; j < 4; j++) {
        o[i][j] *= scale;
        Ps[(c0 + j) * 68 + r0 + i] = s[i][j];
      }
    }
    __syncthreads();

#pragma unroll 16
    for (int kk = 0; kk < 64; kk++) {
      float pa[4], vb[4];
      *(float4*)pa = *(const float4*)(Ps + kk * 68 + r0);
      *(float4*)vb = *(const float4*)(Vs + kk * 68 + c0);
#pragma unroll
      for (int i = 0; i < 4; i++)
#pragma unroll
        for (int j = 0; j < 4; j++) o[i][j] += pa[i] * vb[j];
    }
  }

#pragma unroll
  for (int i = 0; i < 4; i++) {
    float inv = 1.f / lsum[i];
    float outv[4];
#pragma unroll
    for (int j = 0; j < 4; j++) outv[j] = o[i][j] * inv;
    *(float4*)(O + (size_t)(b * Sn + q0 + r0 + i) * Dn + h * HDn + c0) = *(float4*)outv;
  }
}

// =====================================================================================
// out = LayerNorm(A + B) * g + be    — one block per token, 256 threads x float4
// =====================================================================================
__global__ void __launch_bounds__(256) add_ln(
    const float* __restrict__ A, const float* __restrict__ Bv,
    const float* __restrict__ g, const float* __restrict__ be,
    float* __restrict__ out) {
  int t = blockIdx.x;
  int tid = threadIdx.x;
  float4 a = *(const float4*)(A + (size_t)t * Dn + tid * 4);
  float4 b = *(const float4*)(Bv + (size_t)t * Dn + tid * 4);
  float4 x = make_float4(a.x + b.x, a.y + b.y, a.z + b.z, a.w + b.w);
  float sumv = x.x + x.y + x.z + x.w;
  float sq = x.x * x.x + x.y * x.y + x.z * x.z + x.w * x.w;
#pragma unroll
  for (int off = 16; off; off >>= 1) {
    sumv += __shfl_xor_sync(0xffffffffu, sumv, off);
    sq += __shfl_xor_sync(0xffffffffu, sq, off);
  }
  __shared__ float ws[8], wq[8];
  __shared__ float s_mean, s_rstd;
  int wid = tid >> 5, lane = tid & 31;
  if (lane == 0) {
    ws[wid] = sumv;
    wq[wid] = sq;
  }
  __syncthreads();
  if (tid == 0) {
    float s = 0.f, q = 0.f;
#pragma unroll
    for (int i = 0; i < 8; i++) {
      s += ws[i];
      q += wq[i];
    }
    float mean = s * (1.f / Dn);
    float var = q * (1.f / Dn) - mean * mean;
    s_mean = mean;
    s_rstd = rsqrtf(var + 1e-5f);
  }
  __syncthreads();
  float mean = s_mean, rstd = s_rstd;
  float4 gg = *(const float4*)(g + tid * 4);
  float4 bb = *(const float4*)(be + tid * 4);
  float4 y;
  y.x = (x.x - mean) * rstd * gg.x + bb.x;
  y.y = (x.y - mean) * rstd * gg.y + bb.y;
  y.z = (x.z - mean) * rstd * gg.z + bb.z;
  y.w = (x.w - mean) * rstd * gg.w + bb.w;
  *(float4*)(out + (size_t)t * Dn + tid * 4) = y;
}

// =====================================================================================
// Router: logits = x1 @ switch_w^T + switch_b; top-1 softmax prob; xs = x1 * pmax
// One block (128 threads) per token; switch_w staged in smem.
// =====================================================================================
__global__ void __launch_bounds__(128) router_kernel(
    const float* __restrict__ x1, const float* __restrict__ sw,
    const float* __restrict__ sb, float* __restrict__ xs,
    int* __restrict__ route) {
  __shared__ float ssw[En * Dn];
  int t = blockIdx.x;
  int tid = threadIdx.x;
  for (int i = tid; i < En * Dn / 4; i += 128)
    ((float4*)ssw)[i] = ((const float4*)sw)[i];
  __syncthreads();

  float acc[En];
#pragma unroll
  for (int e = 0; e < En; e++) acc[e] = 0.f;
  float xv[8];
#pragma unroll
  for (int l = 0; l < 2; l++) {
    int d = (tid + l * 128) * 4;
    float4 x = *(const float4*)(x1 + (size_t)t * Dn + d);
    xv[l * 4 + 0] = x.x;
    xv[l * 4 + 1] = x.y;
    xv[l * 4 + 2] = x.z;
    xv[l * 4 + 3] = x.w;
#pragma unroll
    for (int e = 0; e < En; e++) {
      const float* swp = ssw + e * Dn + d;
      acc[e] += x.x * swp[0] + x.y * swp[1] + x.z * swp[2] + x.w * swp[3];
    }
  }
#pragma unroll
  for (int e = 0; e < En; e++)
#pragma unroll
    for (int off = 16; off; off >>= 1) acc[e] += __shfl_xor_sync(0xffffffffu, acc[e], off);

  __shared__ float wsum[4][En];
  __shared__ float s_p;
  int wid = tid >> 5, lane = tid & 31;
  if (lane == 0)
#pragma unroll
    for (int e = 0; e < En; e++) wsum[wid][e] = acc[e];
  __syncthreads();
  if (tid == 0) {
    float lg[En];
#pragma unroll
    for (int e = 0; e < En; e++)
      lg[e] = wsum[0][e] + wsum[1][e] + wsum[2][e] + wsum[3][e] + sb[e];
    int am = 0;
    float mx = lg[0];
#pragma unroll
    for (int e = 1; e < En; e++)
      if (lg[e] > mx) {  // strict > == jnp.argmax first-max tie-break
        mx = lg[e];
        am = e;
      }
    float sum = 0.f;
#pragma unroll
    for (int e = 0; e < En; e++) sum += __expf(lg[e] - mx);
    s_p = 1.f / sum;  // pmax = exp(0)/sum
    route[t] = am;
  }
  __syncthreads();
  float p = s_p;
#pragma unroll
  for (int l = 0; l < 2; l++) {
    int d = (tid + l * 128) * 4;
    float4 y = make_float4(xv[l * 4] * p, xv[l * 4 + 1] * p, xv[l * 4 + 2] * p,
                           xv[l * 4 + 3] * p);
    *(float4*)(xs + (size_t)t * Dn + d) = y;
  }
}

// =====================================================================================
// Deterministic stable counting sort by expert id.
// Single block, 256 threads x 32 tokens. Produces dest[t] (token's stable rank when
// sorted by expert) and off[0..E] (expert segment offsets).
// =====================================================================================
__global__ void __launch_bounds__(256) sort_routes(
    const int* __restrict__ route, int* __restrict__ dest, int* __restrict__ off) {
  __shared__ int hist[256][En];
  __shared__ int tot[En];
  __shared__ int eoff[En + 1];
  int tid = threadIdx.x;
  int h[En];
#pragma unroll
  for (int e = 0; e < En; e++) h[e] = 0;
  int base = tid * 32;
  for (int i = 0; i < 32; i++) h[route[base + i]]++;
#pragma unroll
  for (int e = 0; e < En; e++) hist[tid][e] = h[e];
  __syncthreads();
  if (tid < En) {
    int e = tid;
    int run = 0;
    for (int i = 0; i < 256; i++) {
      int v = hist[i][e];
      hist[i][e] = run;  // exclusive prefix within expert
      run += v;
    }
    tot[e] = run;
  }
  __syncthreads();
  if (tid == 0) {
    int r = 0;
    for (int e = 0; e < En; e++) {
      eoff[e] = r;
      off[e] = r;
      r += tot[e];
    }
    eoff[En] = r;
    off[En] = r;
  }
  __syncthreads();
  int run[En];
#pragma unroll
  for (int e = 0; e < En; e++) run[e] = eoff[e] + hist[tid][e];
  for (int i = 0; i < 32; i++) {
    int e = route[base + i];
    dest[base + i] = run[e]++;
  }
}

// xsort[dest[t], :] = xs[t, :]
__global__ void __launch_bounds__(256) gather_rows(
    const float* __restrict__ xs, const int* __restrict__ dest,
    float* __restrict__ xsort) {
  int t = blockIdx.x;
  int c = threadIdx.x;
  int dt = dest[t];
  ((float4*)xsort)[(size_t)dt * (Dn / 4) + c] =
      ((const float4*)xs)[(size_t)t * (Dn / 4) + c];
}

// =====================================================================================
extern "C" void kernel_launch(void* const* d_in, const int* in_sizes, int n_in,
                              void* d_out, int out_size) {
  const float* x = (const float*)d_in[0];
  const float* wq = (const float*)d_in[1];
  const float* bq = (const float*)d_in[2];
  const float* wk = (const float*)d_in[3];
  const float* bk = (const float*)d_in[4];
  const float* wv = (const float*)d_in[5];
  const float* bv = (const float*)d_in[6];
  const float* wo = (const float*)d_in[7];
  const float* bo = (const float*)d_in[8];
  const float* ln1g = (const float*)d_in[9];
  const float* ln1b = (const float*)d_in[10];
  const float* ln2g = (const float*)d_in[11];
  const float* ln2b = (const float*)d_in[12];
  const float* sw = (const float*)d_in[13];
  const float* sb = (const float*)d_in[14];
  const float* ew1 = (const float*)d_in[15];
  const float* eb1 = (const float*)d_in[16];
  const float* ew2 = (const float*)d_in[17];
  const float* eb2 = (const float*)d_in[18];
  const int* mask = (const int*)d_in[19];
  float* out = (float*)d_out;

  float *q, *k, *v, *ctx, *ao, *x1, *xs, *xsort, *moe, *h1;
  int *route, *dest, *off;
  cudaGetSymbolAddress((void**)&q, g_q);
  cudaGetSymbolAddress((void**)&k, g_k);
  cudaGetSymbolAddress((void**)&v, g_v);
  cudaGetSymbolAddress((void**)&ctx, g_ctx);
  cudaGetSymbolAddress((void**)&ao, g_ao);
  cudaGetSymbolAddress((void**)&x1, g_x1);
  cudaGetSymbolAddress((void**)&xs, g_xs);
  cudaGetSymbolAddress((void**)&xsort, g_xsort);
  cudaGetSymbolAddress((void**)&moe, g_moe);
  cudaGetSymbolAddress((void**)&h1, g_h1);
  cudaGetSymbolAddress((void**)&route, g_route);
  cudaGetSymbolAddress((void**)&dest, g_dest);
  cudaGetSymbolAddress((void**)&off, g_off);

  const int FLASH_SMEM = 4 * 64 * 68 * 4;  // 69632 B
  cudaFuncSetAttribute(flash_attn, cudaFuncAttributeMaxDynamicSharedMemorySize,
                       FLASH_SMEM);

  dim3 blk(256);

  // --- attention block ---
  sgemm_nt<0, 0><<<dim3(Dn / 128, Tn / 128, 1), blk>>>(x, wq, bq, q, Dn, Dn, Tn, nullptr, 0);
  sgemm_nt<0, 0><<<dim3(Dn / 128, Tn / 128, 1), blk>>>(x, wk, bk, k, Dn, Dn, Tn, nullptr, 0);
  sgemm_nt<0, 0><<<dim3(Dn / 128, Tn / 128, 1), blk>>>(x, wv, bv, v, Dn, Dn, Tn, nullptr, 0);
  flash_attn<<<dim3(Sn / 64, Bn * Hn), blk, FLASH_SMEM>>>(q, k, v, mask, ctx);
  sgemm_nt<0, 0><<<dim3(Dn / 128, Tn / 128, 1), blk>>>(ctx, wo, bo, ao, Dn, Dn, Tn, nullptr, 0);
  add_ln<<<Tn, 256>>>(x, ao, ln1g, ln1b, x1);

  // --- MoE block ---
  router_kernel<<<Tn, 128>>>(x1, sw, sb, xs, route);
  sort_routes<<<1, 256>>>(route, dest, off);
  gather_rows<<<Tn, 256>>>(xs, dest, xsort);
  sgemm_nt<1, 1><<<dim3(Fn / 128, Tn / 128, En), blk>>>(xsort, ew1, eb1, h1, Fn, Dn, 0, off,
                                                        (size_t)Fn * Dn);
  sgemm_nt<0, 1><<<dim3(Dn / 128, Tn / 128, En), blk>>>(h1, ew2, eb2, moe, Dn, Fn, 0, off,
                                                        (size_t)Dn * Fn);
  add_ln<<<Tn, 256>>>(x1, moe, ln2g, ln2b, out);
}

// round 2
// speedup vs baseline: 1.8910x; 1.8910x over previous
#include <cuda_runtime.h>
#include <math.h>

// Problem dims (fixed by the reference)
#define Tn 8192
#define Dn 1024
#define Hn 16
#define HDn 64
#define Fn 4096
#define En 8
#define Bn 4
#define Sn 2048

// ---------------- scratch (static device allocations; no cudaMalloc allowed) ---------
__device__ float g_q[Tn * Dn];
__device__ float g_k[Tn * Dn];
__device__ float g_v[Tn * Dn];
__device__ float g_ctx[Tn * Dn];
__device__ float g_ao[Tn * Dn];
__device__ float g_x1[Tn * Dn];
__device__ float g_xs[Tn * Dn];
__device__ float g_xsort[Tn * Dn];
__device__ float g_moe[Tn * Dn];
__device__ float g_h1[(size_t)Tn * Fn];
__device__ int g_route[Tn];
__device__ int g_dest[Tn];
__device__ int g_off[En + 1];

// =====================================================================================
// TF32 tensor-core GEMM:  C[m,n] = A[m,:] . W[n,:] + bias[n]   (NT, both row-major)
// 128x128 block tile, BK=32 K-slabs, 8 warps each computing 32x64 via m16n8k8 tf32 mma.
// Smem: A and B row-major with stride 36 -> bank index 4*g+t is conflict-free for both
// the STS.128 staging and the LDS.32 fragment reads.
// USE_OFF=1: expert-batched rows [off[e], off[e+1]) with per-expert weight/bias stride.
// =====================================================================================
#define BK 32
#define LDA 36  // 32 + 4 pad

__device__ __forceinline__ unsigned f2tf(float x) {
  unsigned r;
  asm("cvt.rna.tf32.f32 %0, %1;" : "=r"(r) : "f"(x));
  return r;
}

__device__ __forceinline__ void mma_tf32(float* c, const unsigned* a, const unsigned* b) {
  asm volatile(
      "mma.sync.aligned.m16n8k8.row.col.f32.tf32.tf32.f32 "
      "{%0,%1,%2,%3},{%4,%5,%6,%7},{%8,%9},{%0,%1,%2,%3};"
      : "+f"(c[0]), "+f"(c[1]), "+f"(c[2]), "+f"(c[3])
      : "r"(a[0]), "r"(a[1]), "r"(a[2]), "r"(a[3]), "r"(b[0]), "r"(b[1]));
}

template <int RELU, int USE_OFF>
__global__ void __launch_bounds__(256) tgemm(
    const float* __restrict__ A, const float* __restrict__ W,
    const float* __restrict__ bias, float* __restrict__ C,
    int N, int K, int Mfull, const int* __restrict__ off, size_t wstride) {
  int e = blockIdx.z;
  int m_start, m_end;
  if (USE_OFF) {
    m_start = off[e];
    m_end = off[e + 1];
  } else {
    m_start = 0;
    m_end = Mfull;
  }
  int m0 = m_start + (int)blockIdx.y * 128;
  if (m0 >= m_end) return;

  const float* Wp = W + (size_t)e * wstride;
  const float* bp = bias + (size_t)e * N;
  int n0 = blockIdx.x * 128;

  __shared__ unsigned As[128 * LDA];
  __shared__ unsigned Bs[128 * LDA];

  int tid = threadIdx.x;
  int lane = tid & 31, wid = tid >> 5;
  int wm = (wid >> 1) * 32;  // warp m offset in tile (4 warps along m)
  int wn = (wid & 1) * 64;   // warp n offset in tile (2 warps along n)
  int g = lane >> 2, t = lane & 3;

  float acc[2][8][4];
#pragma unroll
  for (int i = 0; i < 2; i++)
#pragma unroll
    for (int j = 0; j < 8; j++)
#pragma unroll
      for (int l = 0; l < 4; l++) acc[i][j][l] = 0.f;

  // staging assignment: 4 float4 per thread per matrix per slab
  int srow[4], skq[4];
#pragma unroll
  for (int i = 0; i < 4; i++) {
    int idx = tid + i * 256;
    srow[i] = idx >> 3;
    skq[i] = (idx & 7) << 2;
  }

  float4 pa[4], pb[4];
  // prefetch slab 0
#pragma unroll
  for (int i = 0; i < 4; i++) {
    int grow = m0 + srow[i];
    pa[i] = make_float4(0.f, 0.f, 0.f, 0.f);
    if (grow < m_end) pa[i] = *(const float4*)(A + (size_t)grow * K + skq[i]);
    pb[i] = *(const float4*)(Wp + (size_t)(n0 + srow[i]) * K + skq[i]);
  }

  for (int k0 = 0; k0 < K; k0 += BK) {
    // store staged slab to smem (tf32-rounded)
#pragma unroll
    for (int i = 0; i < 4; i++) {
      unsigned* ap = As + srow[i] * LDA + skq[i];
      ap[0] = f2tf(pa[i].x); ap[1] = f2tf(pa[i].y);
      ap[2] = f2tf(pa[i].z); ap[3] = f2tf(pa[i].w);
      unsigned* bpp = Bs + srow[i] * LDA + skq[i];
      bpp[0] = f2tf(pb[i].x); bpp[1] = f2tf(pb[i].y);
      bpp[2] = f2tf(pb[i].z); bpp[3] = f2tf(pb[i].w);
    }
    __syncthreads();

    // prefetch next slab while computing
    int kn = k0 + BK;
    if (kn < K) {
#pragma unroll
      for (int i = 0; i < 4; i++) {
        int grow = m0 + srow[i];
        pa[i] = make_float4(0.f, 0.f, 0.f, 0.f);
        if (grow < m_end) pa[i] = *(const float4*)(A + (size_t)grow * K + kn + skq[i]);
        pb[i] = *(const float4*)(Wp + (size_t)(n0 + srow[i]) * K + kn + skq[i]);
      }
    }

#pragma unroll
    for (int kk = 0; kk < BK; kk += 8) {
      unsigned af[2][4];
#pragma unroll
      for (int mf = 0; mf < 2; mf++) {
        const unsigned* a0 = As + (wm + mf * 16 + g) * LDA + kk + t;
        const unsigned* a1 = As + (wm + mf * 16 + g + 8) * LDA + kk + t;
        af[mf][0] = a0[0];
        af[mf][1] = a1[0];
        af[mf][2] = a0[4];
        af[mf][3] = a1[4];
      }
#pragma unroll
      for (int nf = 0; nf < 8; nf++) {
        unsigned bf[2];
        const unsigned* b0 = Bs + (wn + nf * 8 + g) * LDA + kk + t;
        bf[0] = b0[0];
        bf[1] = b0[4];
        mma_tf32(acc[0][nf], af[0], bf);
        mma_tf32(acc[1][nf], af[1], bf);
      }
    }
    __syncthreads();
  }

  // epilogue: c0/c1 at (row g, cols 2t,2t+1); c2/c3 at row g+8
#pragma unroll
  for (int nf = 0; nf < 8; nf++) {
    int col = n0 + wn + nf * 8 + 2 * t;
    float2 bb = *(const float2*)(bp + col);
#pragma unroll
    for (int mf = 0; mf < 2; mf++) {
      int row0 = m0 + wm + mf * 16 + g;
      float v0 = acc[mf][nf][0] + bb.x;
      float v1 = acc[mf][nf][1] + bb.y;
      float v2 = acc[mf][nf][2] + bb.x;
      float v3 = acc[mf][nf][3] + bb.y;
      if (RELU) {
        v0 = fmaxf(v0, 0.f); v1 = fmaxf(v1, 0.f);
        v2 = fmaxf(v2, 0.f); v3 = fmaxf(v3, 0.f);
      }
      if (row0 < m_end)
        *(float2*)(C + (size_t)row0 * N + col) = make_float2(v0, v1);
      if (row0 + 8 < m_end)
        *(float2*)(C + (size_t)(row0 + 8) * N + col) = make_float2(v2, v3);
    }
  }
}

// =====================================================================================
// Flash attention: per (b,h), 64-query tiles against 64-key tiles, online softmax.
// 256 threads, each owns a 4x4 microtile of the 64x64 score / output tiles. fp32.
// =====================================================================================
__global__ void __launch_bounds__(256) flash_attn(
    const float* __restrict__ Q, const float* __restrict__ K,
    const float* __restrict__ V, const int* __restrict__ mask,
    float* __restrict__ O) {
  extern __shared__ float sm[];
  float* Qs = sm;                 // [64][68]  Qs[d][r]
  float* Ks = sm + 64 * 68;       // [64][68]  Ks[d][c]
  float* Vs = sm + 2 * 64 * 68;   // [64][68]  Vs[kk][d]
  float* Ps = sm + 3 * 64 * 68;   // [64][68]  Ps[kk][r]
  __shared__ int msk[64];

  int bh = blockIdx.y;
  int b = bh >> 4, h = bh & 15;
  int q0 = blockIdx.x * 64;
  int tid = threadIdx.x;
  int tx = tid & 15, ty = tid >> 4;
  int r0 = ty * 4, c0 = tx * 4;

#pragma unroll
  for (int l = 0; l < 4; l++) {
    int p = tid + l * 256;
    int r = p >> 4, dc = (p & 15) * 4;
    float4 qv = *(const float4*)(Q + (size_t)(b * Sn + q0 + r) * Dn + h * HDn + dc);
    Qs[(dc + 0) * 68 + r] = qv.x;
    Qs[(dc + 1) * 68 + r] = qv.y;
    Qs[(dc + 2) * 68 + r] = qv.z;
    Qs[(dc + 3) * 68 + r] = qv.w;
  }

  float m[4], lsum[4], o[4][4];
#pragma unroll
  for (int i = 0; i < 4; i++) {
    m[i] = -1e30f;
    lsum[i] = 0.f;
#pragma unroll
    for (int j = 0; j < 4; j++) o[i][j] = 0.f;
  }

  for (int t0 = 0; t0 < Sn; t0 += 64) {
    __syncthreads();
#pragma unroll
    for (int l = 0; l < 4; l++) {
      int p = tid + l * 256;
      int r = p >> 4, dc = (p & 15) * 4;
      size_t base = (size_t)(b * Sn + t0 + r) * Dn + h * HDn + dc;
      float4 kv = *(const float4*)(K + base);
      Ks[(dc + 0) * 68 + r] = kv.x;
      Ks[(dc + 1) * 68 + r] = kv.y;
      Ks[(dc + 2) * 68 + r] = kv.z;
      Ks[(dc + 3) * 68 + r] = kv.w;
      float4 vv = *(const float4*)(V + base);
      *(float4*)(Vs + r * 68 + dc) = vv;
    }
    if (tid < 64) msk[tid] = mask[b * Sn + t0 + tid];
    __syncthreads();

    float s[4][4];
#pragma unroll
    for (int i = 0; i < 4; i++)
#pragma unroll
      for (int j = 0; j < 4; j++) s[i][j] = 0.f;

#pragma unroll 16
    for (int d = 0; d < 64; d++) {
      float qa[4], kb[4];
      *(float4*)qa = *(const float4*)(Qs + d * 68 + r0);
      *(float4*)kb = *(const float4*)(Ks + d * 68 + c0);
#pragma unroll
      for (int i = 0; i < 4; i++)
#pragma unroll
        for (int j = 0; j < 4; j++) s[i][j] += qa[i] * kb[j];
    }

#pragma unroll
    for (int j = 0; j < 4; j++) {
      bool masked = (msk[c0 + j] == 0);
#pragma unroll
      for (int i = 0; i < 4; i++) s[i][j] = masked ? -1e10f : s[i][j] * 0.125f;
    }

#pragma unroll
    for (int i = 0; i < 4; i++) {
      float mx = fmaxf(fmaxf(s[i][0], s[i][1]), fmaxf(s[i][2], s[i][3]));
      mx = fmaxf(mx, __shfl_xor_sync(0xffffffffu, mx, 1));
      mx = fmaxf(mx, __shfl_xor_sync(0xffffffffu, mx, 2));
      mx = fmaxf(mx, __shfl_xor_sync(0xffffffffu, mx, 4));
      mx = fmaxf(mx, __shfl_xor_sync(0xffffffffu, mx, 8));
      float mnew = fmaxf(m[i], mx);
      float scale = __expf(m[i] - mnew);
      m[i] = mnew;
      float rs = 0.f;
#pragma unroll
      for (int j = 0; j < 4; j++) {
        float p = __expf(s[i][j] - mnew);
        s[i][j] = p;
        rs += p;
      }
      rs += __shfl_xor_sync(0xffffffffu, rs, 1);
      rs += __shfl_xor_sync(0xffffffffu, rs, 2);
      rs += __shfl_xor_sync(0xffffffffu, rs, 4);
      rs += __shfl_xor_sync(0xffffffffu, rs, 8);
      lsum[i] = lsum[i] * scale + rs;
#pragma unroll
      for (int j = 0; j < 4; j++) {
        o[i][j] *= scale;
        Ps[(c0 + j) * 68 + r0 + i] = s[i][j];
      }
    }
    __syncthreads();

#pragma unroll 16
    for (int kk = 0; kk < 64; kk++) {
      float pa[4], vb[4];
      *(float4*)pa = *(const float4*)(Ps + kk * 68 + r0);
      *(float4*)vb = *(const float4*)(Vs + kk * 68 + c0);
#pragma unroll
      for (int i = 0; i < 4; i++)
#pragma unroll
        for (int j = 0; j < 4; j++) o[i][j] += pa[i] * vb[j];
    }
  }

#pragma unroll
  for (int i = 0; i < 4; i++) {
    float inv = 1.f / lsum[i];
    float outv[4];
#pragma unroll
    for (int j = 0; j < 4; j++) outv[j] = o[i][j] * inv;
    *(float4*)(O + (size_t)(b * Sn + q0 + r0 + i) * Dn + h * HDn + c0) = *(float4*)outv;
  }
}

// =====================================================================================
// out = LayerNorm(A + B) * g + be    — one block per token, 256 threads x float4
// =====================================================================================
__global__ void __launch_bounds__(256) add_ln(
    const float* __restrict__ A, const float* __restrict__ Bv,
    const float* __restrict__ g, const float* __restrict__ be,
    float* __restrict__ out) {
  int t = blockIdx.x;
  int tid = threadIdx.x;
  float4 a = *(const float4*)(A + (size_t)t * Dn + tid * 4);
  float4 b = *(const float4*)(Bv + (size_t)t * Dn + tid * 4);
  float4 x = make_float4(a.x + b.x, a.y + b.y, a.z + b.z, a.w + b.w);
  float sumv = x.x + x.y + x.z + x.w;
  float sq = x.x * x.x + x.y * x.y + x.z * x.z + x.w * x.w;
#pragma unroll
  for (int off = 16; off; off >>= 1) {
    sumv += __shfl_xor_sync(0xffffffffu, sumv, off);
    sq += __shfl_xor_sync(0xffffffffu, sq, off);
  }
  __shared__ float ws[8], wq[8];
  __shared__ float s_mean, s_rstd;
  int wid = tid >> 5, lane = tid & 31;
  if (lane == 0) {
    ws[wid] = sumv;
    wq[wid] = sq;
  }
  __syncthreads();
  if (tid == 0) {
    float s = 0.f, q = 0.f;
#pragma unroll
    for (int i = 0; i < 8; i++) {
      s += ws[i];
      q += wq[i];
    }
    float mean = s * (1.f / Dn);
    float var = q * (1.f / Dn) - mean * mean;
    s_mean = mean;
    s_rstd = rsqrtf(var + 1e-5f);
  }
  __syncthreads();
  float mean = s_mean, rstd = s_rstd;
  float4 gg = *(const float4*)(g + tid * 4);
  float4 bb = *(const float4*)(be + tid * 4);
  float4 y;
  y.x = (x.x - mean) * rstd * gg.x + bb.x;
  y.y = (x.y - mean) * rstd * gg.y + bb.y;
  y.z = (x.z - mean) * rstd * gg.z + bb.z;
  y.w = (x.w - mean) * rstd * gg.w + bb.w;
  *(float4*)(out + (size_t)t * Dn + tid * 4) = y;
}

// =====================================================================================
// Router: logits = x1 @ switch_w^T + switch_b; top-1 softmax prob; xs = x1 * pmax
// =====================================================================================
__global__ void __launch_bounds__(128) router_kernel(
    const float* __restrict__ x1, const float* __restrict__ sw,
    const float* __restrict__ sb, float* __restrict__ xs,
    int* __restrict__ route) {
  __shared__ float ssw[En * Dn];
  int t = blockIdx.x;
  int tid = threadIdx.x;
  for (int i = tid; i < En * Dn / 4; i += 128)
    ((float4*)ssw)[i] = ((const float4*)sw)[i];
  __syncthreads();

  float acc[En];
#pragma unroll
  for (int e = 0; e < En; e++) acc[e] = 0.f;
  float xv[8];
#pragma unroll
  for (int l = 0; l < 2; l++) {
    int d = (tid + l * 128) * 4;
    float4 x = *(const float4*)(x1 + (size_t)t * Dn + d);
    xv[l * 4 + 0] = x.x;
    xv[l * 4 + 1] = x.y;
    xv[l * 4 + 2] = x.z;
    xv[l * 4 + 3] = x.w;
#pragma unroll
    for (int e = 0; e < En; e++) {
      const float* swp = ssw + e * Dn + d;
      acc[e] += x.x * swp[0] + x.y * swp[1] + x.z * swp[2] + x.w * swp[3];
    }
  }
#pragma unroll
  for (int e = 0; e < En; e++)
#pragma unroll
    for (int off = 16; off; off >>= 1) acc[e] += __shfl_xor_sync(0xffffffffu, acc[e], off);

  __shared__ float wsum[4][En];
  __shared__ float s_p;
  int wid = tid >> 5, lane = tid & 31;
  if (lane == 0)
#pragma unroll
    for (int e = 0; e < En; e++) wsum[wid][e] = acc[e];
  __syncthreads();
  if (tid == 0) {
    float lg[En];
#pragma unroll
    for (int e = 0; e < En; e++)
      lg[e] = wsum[0][e] + wsum[1][e] + wsum[2][e] + wsum[3][e] + sb[e];
    int am = 0;
    float mx = lg[0];
#pragma unroll
    for (int e = 1; e < En; e++)
      if (lg[e] > mx) {
        mx = lg[e];
        am = e;
      }
    float sum = 0.f;
#pragma unroll
    for (int e = 0; e < En; e++) sum += __expf(lg[e] - mx);
    s_p = 1.f / sum;
    route[t] = am;
  }
  __syncthreads();
  float p = s_p;
#pragma unroll
  for (int l = 0; l < 2; l++) {
    int d = (tid + l * 128) * 4;
    float4 y = make_float4(xv[l * 4] * p, xv[l * 4 + 1] * p, xv[l * 4 + 2] * p,
                           xv[l * 4 + 3] * p);
    *(float4*)(xs + (size_t)t * Dn + d) = y;
  }
}

// =====================================================================================
// Deterministic stable counting sort by expert id (single block).
// =====================================================================================
__global__ void __launch_bounds__(256) sort_routes(
    const int* __restrict__ route, int* __restrict__ dest, int* __restrict__ off) {
  __shared__ int hist[256][En];
  __shared__ int tot[En];
  __shared__ int eoff[En + 1];
  int tid = threadIdx.x;
  int h[En];
#pragma unroll
  for (int e = 0; e < En; e++) h[e] = 0;
  int base = tid * 32;
  for (int i = 0; i < 32; i++) h[route[base + i]]++;
#pragma unroll
  for (int e = 0; e < En; e++) hist[tid][e] = h[e];
  __syncthreads();
  if (tid < En) {
    int e = tid;
    int run = 0;
    for (int i = 0; i < 256; i++) {
      int v = hist[i][e];
      hist[i][e] = run;
      run += v;
    }
    tot[e] = run;
  }
  __syncthreads();
  if (tid == 0) {
    int r = 0;
    for (int e = 0; e < En; e++) {
      eoff[e] = r;
      off[e] = r;
      r += tot[e];
    }
    eoff[En] = r;
    off[En] = r;
  }
  __syncthreads();
  int run[En];
#pragma unroll
  for (int e = 0; e < En; e++) run[e] = eoff[e] + hist[tid][e];
  for (int i = 0; i < 32; i++) {
    int e = route[base + i];
    dest[base + i] = run[e]++;
  }
}

// xsort[dest[t], :] = xs[t, :]
__global__ void __launch_bounds__(256) gather_rows(
    const float* __restrict__ xs, const int* __restrict__ dest,
    float* __restrict__ xsort) {
  int t = blockIdx.x;
  int c = threadIdx.x;
  int dt = dest[t];
  ((float4*)xsort)[(size_t)dt * (Dn / 4) + c] =
      ((const float4*)xs)[(size_t)t * (Dn / 4) + c];
}

// =====================================================================================
extern "C" void kernel_launch(void* const* d_in, const int* in_sizes, int n_in,
                              void* d_out, int out_size) {
  const float* x = (const float*)d_in[0];
  const float* wq = (const float*)d_in[1];
  const float* bq = (const float*)d_in[2];
  const float* wk = (const float*)d_in[3];
  const float* bk = (const float*)d_in[4];
  const float* wv = (const float*)d_in[5];
  const float* bv = (const float*)d_in[6];
  const float* wo = (const float*)d_in[7];
  const float* bo = (const float*)d_in[8];
  const float* ln1g = (const float*)d_in[9];
  const float* ln1b = (const float*)d_in[10];
  const float* ln2g = (const float*)d_in[11];
  const float* ln2b = (const float*)d_in[12];
  const float* sw = (const float*)d_in[13];
  const float* sb = (const float*)d_in[14];
  const float* ew1 = (const float*)d_in[15];
  const float* eb1 = (const float*)d_in[16];
  const float* ew2 = (const float*)d_in[17];
  const float* eb2 = (const float*)d_in[18];
  const int* mask = (const int*)d_in[19];
  float* out = (float*)d_out;

  float *q, *k, *v, *ctx, *ao, *x1, *xs, *xsort, *moe, *h1;
  int *route, *dest, *off;
  cudaGetSymbolAddress((void**)&q, g_q);
  cudaGetSymbolAddress((void**)&k, g_k);
  cudaGetSymbolAddress((void**)&v, g_v);
  cudaGetSymbolAddress((void**)&ctx, g_ctx);
  cudaGetSymbolAddress((void**)&ao, g_ao);
  cudaGetSymbolAddress((void**)&x1, g_x1);
  cudaGetSymbolAddress((void**)&xs, g_xs);
  cudaGetSymbolAddress((void**)&xsort, g_xsort);
  cudaGetSymbolAddress((void**)&moe, g_moe);
  cudaGetSymbolAddress((void**)&h1, g_h1);
  cudaGetSymbolAddress((void**)&route, g_route);
  cudaGetSymbolAddress((void**)&dest, g_dest);
  cudaGetSymbolAddress((void**)&off, g_off);

  const int FLASH_SMEM = 4 * 64 * 68 * 4;  // 69632 B
  cudaFuncSetAttribute(flash_attn, cudaFuncAttributeMaxDynamicSharedMemorySize,
                       FLASH_SMEM);

  dim3 blk(256);

  // --- attention block ---
  tgemm<0, 0><<<dim3(Dn / 128, Tn / 128, 1), blk>>>(x, wq, bq, q, Dn, Dn, Tn, nullptr, 0);
  tgemm<0, 0><<<dim3(Dn / 128, Tn / 128, 1), blk>>>(x, wk, bk, k, Dn, Dn, Tn, nullptr, 0);
  tgemm<0, 0><<<dim3(Dn / 128, Tn / 128, 1), blk>>>(x, wv, bv, v, Dn, Dn, Tn, nullptr, 0);
  flash_attn<<<dim3(Sn / 64, Bn * Hn), blk, FLASH_SMEM>>>(q, k, v, mask, ctx);
  tgemm<0, 0><<<dim3(Dn / 128, Tn / 128, 1), blk>>>(ctx, wo, bo, ao, Dn, Dn, Tn, nullptr, 0);
  add_ln<<<Tn, 256>>>(x, ao, ln1g, ln1b, x1);

  // --- MoE block ---
  router_kernel<<<Tn, 128>>>(x1, sw, sb, xs, route);
  sort_routes<<<1, 256>>>(route, dest, off);
  gather_rows<<<Tn, 256>>>(xs, dest, xsort);
  tgemm<1, 1><<<dim3(Fn / 128, Tn / 128, En), blk>>>(xsort, ew1, eb1, h1, Fn, Dn, 0, off,
                                                     (size_t)Fn * Dn);
  tgemm<0, 1><<<dim3(Dn / 128, Tn / 128, En), blk>>>(h1, ew2, eb2, moe, Dn, Fn, 0, off,
                                                     (size_t)Dn * Fn);
  add_ln<<<Tn, 256>>>(x1, moe, ln2g, ln2b, out);
}

// round 3
// speedup vs baseline: 2.9013x; 1.5343x over previous
#include <cuda_runtime.h>
#include <math.h>

// Problem dims (fixed by the reference)
#define Tn 8192
#define Dn 1024
#define Hn 16
#define HDn 64
#define Fn 4096
#define En 8
#define Bn 4
#define Sn 2048

// ---------------- scratch (static device allocations; no cudaMalloc allowed) ---------
__device__ float g_q[Tn * Dn];
__device__ float g_k[Tn * Dn];
__device__ float g_v[Tn * Dn];
__device__ float g_ctx[Tn * Dn];
__device__ float g_ao[Tn * Dn];
__device__ float g_x1[Tn * Dn];
__device__ float g_xs[Tn * Dn];
__device__ float g_xsort[Tn * Dn];
__device__ float g_moe[Tn * Dn];
__device__ float g_h1[(size_t)Tn * Fn];
__device__ int g_route[Tn];
__device__ int g_dest[Tn];
__device__ int g_off[En + 1];

__device__ __forceinline__ unsigned f2tf(float x) {
  unsigned r;
  asm("cvt.rna.tf32.f32 %0, %1;" : "=r"(r) : "f"(x));
  return r;
}

__device__ __forceinline__ void mma_tf32(float* c, const unsigned* a, const unsigned* b) {
  asm volatile(
      "mma.sync.aligned.m16n8k8.row.col.f32.tf32.tf32.f32 "
      "{%0,%1,%2,%3},{%4,%5,%6,%7},{%8,%9},{%0,%1,%2,%3};"
      : "+f"(c[0]), "+f"(c[1]), "+f"(c[2]), "+f"(c[3])
      : "r"(a[0]), "r"(a[1]), "r"(a[2]), "r"(a[3]), "r"(b[0]), "r"(b[1]));
}

// =====================================================================================
// TF32 tensor-core GEMM:  C[m,n] = A[m,:] . W[n,:] + bias[n]   (NT, both row-major)
// =====================================================================================
#define BK 32
#define LDA 36  // 32 + 4 pad

template <int RELU, int USE_OFF>
__global__ void __launch_bounds__(256) tgemm(
    const float* __restrict__ A, const float* __restrict__ W,
    const float* __restrict__ bias, float* __restrict__ C,
    int N, int K, int Mfull, const int* __restrict__ off, size_t wstride) {
  int e = blockIdx.z;
  int m_start, m_end;
  if (USE_OFF) {
    m_start = off[e];
    m_end = off[e + 1];
  } else {
    m_start = 0;
    m_end = Mfull;
  }
  int m0 = m_start + (int)blockIdx.y * 128;
  if (m0 >= m_end) return;

  const float* Wp = W + (size_t)e * wstride;
  const float* bp = bias + (size_t)e * N;
  int n0 = blockIdx.x * 128;

  __shared__ unsigned As[128 * LDA];
  __shared__ unsigned Bs[128 * LDA];

  int tid = threadIdx.x;
  int lane = tid & 31, wid = tid >> 5;
  int wm = (wid >> 1) * 32;
  int wn = (wid & 1) * 64;
  int g = lane >> 2, t = lane & 3;

  float acc[2][8][4];
#pragma unroll
  for (int i = 0; i < 2; i++)
#pragma unroll
    for (int j = 0; j < 8; j++)
#pragma unroll
      for (int l = 0; l < 4; l++) acc[i][j][l] = 0.f;

  int srow[4], skq[4];
#pragma unroll
  for (int i = 0; i < 4; i++) {
    int idx = tid + i * 256;
    srow[i] = idx >> 3;
    skq[i] = (idx & 7) << 2;
  }

  float4 pa[4], pb[4];
#pragma unroll
  for (int i = 0; i < 4; i++) {
    int grow = m0 + srow[i];
    pa[i] = make_float4(0.f, 0.f, 0.f, 0.f);
    if (grow < m_end) pa[i] = *(const float4*)(A + (size_t)grow * K + skq[i]);
    pb[i] = *(const float4*)(Wp + (size_t)(n0 + srow[i]) * K + skq[i]);
  }

  for (int k0 = 0; k0 < K; k0 += BK) {
#pragma unroll
    for (int i = 0; i < 4; i++) {
      unsigned* ap = As + srow[i] * LDA + skq[i];
      ap[0] = f2tf(pa[i].x); ap[1] = f2tf(pa[i].y);
      ap[2] = f2tf(pa[i].z); ap[3] = f2tf(pa[i].w);
      unsigned* bpp = Bs + srow[i] * LDA + skq[i];
      bpp[0] = f2tf(pb[i].x); bpp[1] = f2tf(pb[i].y);
      bpp[2] = f2tf(pb[i].z); bpp[3] = f2tf(pb[i].w);
    }
    __syncthreads();

    int kn = k0 + BK;
    if (kn < K) {
#pragma unroll
      for (int i = 0; i < 4; i++) {
        int grow = m0 + srow[i];
        pa[i] = make_float4(0.f, 0.f, 0.f, 0.f);
        if (grow < m_end) pa[i] = *(const float4*)(A + (size_t)grow * K + kn + skq[i]);
        pb[i] = *(const float4*)(Wp + (size_t)(n0 + srow[i]) * K + kn + skq[i]);
      }
    }

#pragma unroll
    for (int kk = 0; kk < BK; kk += 8) {
      unsigned af[2][4];
#pragma unroll
      for (int mf = 0; mf < 2; mf++) {
        const unsigned* a0 = As + (wm + mf * 16 + g) * LDA + kk + t;
        const unsigned* a1 = As + (wm + mf * 16 + g + 8) * LDA + kk + t;
        af[mf][0] = a0[0];
        af[mf][1] = a1[0];
        af[mf][2] = a0[4];
        af[mf][3] = a1[4];
      }
#pragma unroll
      for (int nf = 0; nf < 8; nf++) {
        unsigned bf[2];
        const unsigned* b0 = Bs + (wn + nf * 8 + g) * LDA + kk + t;
        bf[0] = b0[0];
        bf[1] = b0[4];
        mma_tf32(acc[0][nf], af[0], bf);
        mma_tf32(acc[1][nf], af[1], bf);
      }
    }
    __syncthreads();
  }

#pragma unroll
  for (int nf = 0; nf < 8; nf++) {
    int col = n0 + wn + nf * 8 + 2 * t;
    float2 bb = *(const float2*)(bp + col);
#pragma unroll
    for (int mf = 0; mf < 2; mf++) {
      int row0 = m0 + wm + mf * 16 + g;
      float v0 = acc[mf][nf][0] + bb.x;
      float v1 = acc[mf][nf][1] + bb.y;
      float v2 = acc[mf][nf][2] + bb.x;
      float v3 = acc[mf][nf][3] + bb.y;
      if (RELU) {
        v0 = fmaxf(v0, 0.f); v1 = fmaxf(v1, 0.f);
        v2 = fmaxf(v2, 0.f); v3 = fmaxf(v3, 0.f);
      }
      if (row0 < m_end)
        *(float2*)(C + (size_t)row0 * N + col) = make_float2(v0, v1);
      if (row0 + 8 < m_end)
        *(float2*)(C + (size_t)(row0 + 8) * N + col) = make_float2(v2, v3);
    }
  }
}

// =====================================================================================
// Tensor-core flash attention (tf32).
// 128-query blocks, 64-key tiles, 8 warps x 16 q-rows, m16n8k8 mma for QK^T and PV.
// Smem stride 72 words (= 8 mod 32 banks) -> conflict-free fragment LDS for all of
// Qs/Ks/Vs/Ps. V stays [key][d] row-major (the .row.col B fragment reads it directly).
// P round-trips through smem per-warp (only __syncwarp needed).
// =====================================================================================
#define FQT 128
#define FKT 64
#define FS 72

__global__ void __launch_bounds__(256, 2) flash_tc(
    const float* __restrict__ Q, const float* __restrict__ K,
    const float* __restrict__ V, const int* __restrict__ mask,
    float* __restrict__ O) {
  extern __shared__ unsigned smu[];
  unsigned* Qs = smu;                       // [128][FS]
  unsigned* Ks = Qs + FQT * FS;             // [64][FS]
  unsigned* Vs = Ks + FKT * FS;             // [64][FS]
  float* Ps = (float*)(Vs + FKT * FS);      // [128][FS]
  int* msk = (int*)(Ps + FQT * FS);         // [64]

  int bh = blockIdx.y;
  int b = bh >> 4, h = bh & 15;
  int q0 = blockIdx.x * FQT;
  int tid = threadIdx.x;
  int lane = tid & 31, wid = tid >> 5;
  int g = lane >> 2, t = lane & 3;
  int wrow = wid * 16;

  // stage Q tile (tf32)
#pragma unroll
  for (int l = 0; l < 8; l++) {
    int idx = tid + l * 256;
    int r = idx >> 4, qc = (idx & 15) << 2;
    float4 qv = *(const float4*)(Q + (size_t)(b * Sn + q0 + r) * Dn + h * HDn + qc);
    unsigned* p = Qs + r * FS + qc;
    p[0] = f2tf(qv.x); p[1] = f2tf(qv.y);
    p[2] = f2tf(qv.z); p[3] = f2tf(qv.w);
  }

  float o[8][4];
#pragma unroll
  for (int nf = 0; nf < 8; nf++)
#pragma unroll
    for (int c = 0; c < 4; c++) o[nf][c] = 0.f;
  float mrow0 = -1e30f, mrow1 = -1e30f;
  float lrow0 = 0.f, lrow1 = 0.f;

  for (int t0 = 0; t0 < Sn; t0 += FKT) {
    __syncthreads();  // prior iter's Ks/Vs reads done (also covers Q staging, iter 0)
#pragma unroll
    for (int l = 0; l < 4; l++) {
      int idx = tid + l * 256;
      int r = idx >> 4, qc = (idx & 15) << 2;
      size_t base = (size_t)(b * Sn + t0 + r) * Dn + h * HDn + qc;
      float4 kv = *(const float4*)(K + base);
      unsigned* pk = Ks + r * FS + qc;
      pk[0] = f2tf(kv.x); pk[1] = f2tf(kv.y);
      pk[2] = f2tf(kv.z); pk[3] = f2tf(kv.w);
      float4 vv = *(const float4*)(V + base);
      unsigned* pv = Vs + r * FS + qc;
      pv[0] = f2tf(vv.x); pv[1] = f2tf(vv.y);
      pv[2] = f2tf(vv.z); pv[3] = f2tf(vv.w);
    }
    if (tid < FKT) msk[tid] = mask[b * Sn + t0 + tid];
    __syncthreads();

    // ---- S = Q K^T ----
    float s[8][4];
#pragma unroll
    for (int nf = 0; nf < 8; nf++)
#pragma unroll
      for (int c = 0; c < 4; c++) s[nf][c] = 0.f;

#pragma unroll
    for (int kk = 0; kk < HDn; kk += 8) {
      unsigned af[4];
      const unsigned* a0 = Qs + (wrow + g) * FS + kk + t;
      af[0] = a0[0];
      af[1] = a0[8 * FS];
      af[2] = a0[4];
      af[3] = a0[8 * FS + 4];
#pragma unroll
      for (int nf = 0; nf < 8; nf++) {
        unsigned bf[2];
        const unsigned* b0 = Ks + (nf * 8 + g) * FS + kk + t;
        bf[0] = b0[0];
        bf[1] = b0[4];
        mma_tf32(s[nf], af, bf);
      }
    }

    // ---- mask + scale ----
#pragma unroll
    for (int nf = 0; nf < 8; nf++) {
      int col = nf * 8 + 2 * t;
      bool z0 = (msk[col] == 0), z1 = (msk[col + 1] == 0);
      s[nf][0] = z0 ? -1e10f : s[nf][0] * 0.125f;
      s[nf][1] = z1 ? -1e10f : s[nf][1] * 0.125f;
      s[nf][2] = z0 ? -1e10f : s[nf][2] * 0.125f;
      s[nf][3] = z1 ? -1e10f : s[nf][3] * 0.125f;
    }

    // ---- online softmax (rows g and g+8; full row lives in the quad) ----
    float mx0 = -1e30f, mx1 = -1e30f;
#pragma unroll
    for (int nf = 0; nf < 8; nf++) {
      mx0 = fmaxf(mx0, fmaxf(s[nf][0], s[nf][1]));
      mx1 = fmaxf(mx1, fmaxf(s[nf][2], s[nf][3]));
    }
    mx0 = fmaxf(mx0, __shfl_xor_sync(0xffffffffu, mx0, 1));
    mx0 = fmaxf(mx0, __shfl_xor_sync(0xffffffffu, mx0, 2));
    mx1 = fmaxf(mx1, __shfl_xor_sync(0xffffffffu, mx1, 1));
    mx1 = fmaxf(mx1, __shfl_xor_sync(0xffffffffu, mx1, 2));

    float mn0 = fmaxf(mrow0, mx0), mn1 = fmaxf(mrow1, mx1);
    float sc0 = __expf(mrow0 - mn0), sc1 = __expf(mrow1 - mn1);
    mrow0 = mn0; mrow1 = mn1;

    float rs0 = 0.f, rs1 = 0.f;
#pragma unroll
    for (int nf = 0; nf < 8; nf++) {
      s[nf][0] = __expf(s[nf][0] - mn0);
      s[nf][1] = __expf(s[nf][1] - mn0);
      s[nf][2] = __expf(s[nf][2] - mn1);
      s[nf][3] = __expf(s[nf][3] - mn1);
      rs0 += s[nf][0] + s[nf][1];
      rs1 += s[nf][2] + s[nf][3];
    }
    rs0 += __shfl_xor_sync(0xffffffffu, rs0, 1);
    rs0 += __shfl_xor_sync(0xffffffffu, rs0, 2);
    rs1 += __shfl_xor_sync(0xffffffffu, rs1, 1);
    rs1 += __shfl_xor_sync(0xffffffffu, rs1, 2);
    lrow0 = lrow0 * sc0 + rs0;
    lrow1 = lrow1 * sc1 + rs1;

#pragma unroll
    for (int nf = 0; nf < 8; nf++) {
      o[nf][0] *= sc0; o[nf][1] *= sc0;
      o[nf][2] *= sc1; o[nf][3] *= sc1;
    }

    // ---- write P to smem (own warp rows only) ----
#pragma unroll
    for (int nf = 0; nf < 8; nf++) {
      int col = nf * 8 + 2 * t;
      *(float2*)(Ps + (wrow + g) * FS + col) = make_float2(s[nf][0], s[nf][1]);
      *(float2*)(Ps + (wrow + g + 8) * FS + col) = make_float2(s[nf][2], s[nf][3]);
    }
    __syncwarp();

    // ---- O += P V ----  (P raw f32 bits as tf32: HW truncates low mantissa)
#pragma unroll
    for (int kk = 0; kk < FKT; kk += 8) {
      unsigned af[4];
      const float* a0 = Ps + (wrow + g) * FS + kk + t;
      af[0] = __float_as_uint(a0[0]);
      af[1] = __float_as_uint(a0[8 * FS]);
      af[2] = __float_as_uint(a0[4]);
      af[3] = __float_as_uint(a0[8 * FS + 4]);
#pragma unroll
      for (int nf = 0; nf < 8; nf++) {
        unsigned bf[2];
        const unsigned* b0 = Vs + (kk + t) * FS + nf * 8 + g;
        bf[0] = b0[0];
        bf[1] = b0[4 * FS];
        mma_tf32(o[nf], af, bf);
      }
    }
    __syncwarp();  // Ps reads done before next iter's writes
  }

  float inv0 = 1.f / lrow0, inv1 = 1.f / lrow1;
  int row = b * Sn + q0 + wrow + g;
#pragma unroll
  for (int nf = 0; nf < 8; nf++) {
    int col = h * HDn + nf * 8 + 2 * t;
    *(float2*)(O + (size_t)row * Dn + col) =
        make_float2(o[nf][0] * inv0, o[nf][1] * inv0);
    *(float2*)(O + (size_t)(row + 8) * Dn + col) =
        make_float2(o[nf][2] * inv1, o[nf][3] * inv1);
  }
}

// =====================================================================================
// out = LayerNorm(A + B) * g + be
// =====================================================================================
__global__ void __launch_bounds__(256) add_ln(
    const float* __restrict__ A, const float* __restrict__ Bv,
    const float* __restrict__ g, const float* __restrict__ be,
    float* __restrict__ out) {
  int t = blockIdx.x;
  int tid = threadIdx.x;
  float4 a = *(const float4*)(A + (size_t)t * Dn + tid * 4);
  float4 b = *(const float4*)(Bv + (size_t)t * Dn + tid * 4);
  float4 x = make_float4(a.x + b.x, a.y + b.y, a.z + b.z, a.w + b.w);
  float sumv = x.x + x.y + x.z + x.w;
  float sq = x.x * x.x + x.y * x.y + x.z * x.z + x.w * x.w;
#pragma unroll
  for (int off = 16; off; off >>= 1) {
    sumv += __shfl_xor_sync(0xffffffffu, sumv, off);
    sq += __shfl_xor_sync(0xffffffffu, sq, off);
  }
  __shared__ float ws[8], wq[8];
  __shared__ float s_mean, s_rstd;
  int wid = tid >> 5, lane = tid & 31;
  if (lane == 0) {
    ws[wid] = sumv;
    wq[wid] = sq;
  }
  __syncthreads();
  if (tid == 0) {
    float s = 0.f, q = 0.f;
#pragma unroll
    for (int i = 0; i < 8; i++) {
      s += ws[i];
      q += wq[i];
    }
    float mean = s * (1.f / Dn);
    float var = q * (1.f / Dn) - mean * mean;
    s_mean = mean;
    s_rstd = rsqrtf(var + 1e-5f);
  }
  __syncthreads();
  float mean = s_mean, rstd = s_rstd;
  float4 gg = *(const float4*)(g + tid * 4);
  float4 bb = *(const float4*)(be + tid * 4);
  float4 y;
  y.x = (x.x - mean) * rstd * gg.x + bb.x;
  y.y = (x.y - mean) * rstd * gg.y + bb.y;
  y.z = (x.z - mean) * rstd * gg.z + bb.z;
  y.w = (x.w - mean) * rstd * gg.w + bb.w;
  *(float4*)(out + (size_t)t * Dn + tid * 4) = y;
}

// =====================================================================================
// Router
// =====================================================================================
__global__ void __launch_bounds__(128) router_kernel(
    const float* __restrict__ x1, const float* __restrict__ sw,
    const float* __restrict__ sb, float* __restrict__ xs,
    int* __restrict__ route) {
  __shared__ float ssw[En * Dn];
  int t = blockIdx.x;
  int tid = threadIdx.x;
  for (int i = tid; i < En * Dn / 4; i += 128)
    ((float4*)ssw)[i] = ((const float4*)sw)[i];
  __syncthreads();

  float acc[En];
#pragma unroll
  for (int e = 0; e < En; e++) acc[e] = 0.f;
  float xv[8];
#pragma unroll
  for (int l = 0; l < 2; l++) {
    int d = (tid + l * 128) * 4;
    float4 x = *(const float4*)(x1 + (size_t)t * Dn + d);
    xv[l * 4 + 0] = x.x;
    xv[l * 4 + 1] = x.y;
    xv[l * 4 + 2] = x.z;
    xv[l * 4 + 3] = x.w;
#pragma unroll
    for (int e = 0; e < En; e++) {
      const float* swp = ssw + e * Dn + d;
      acc[e] += x.x * swp[0] + x.y * swp[1] + x.z * swp[2] + x.w * swp[3];
    }
  }
#pragma unroll
  for (int e = 0; e < En; e++)
#pragma unroll
    for (int off = 16; off; off >>= 1) acc[e] += __shfl_xor_sync(0xffffffffu, acc[e], off);

  __shared__ float wsum[4][En];
  __shared__ float s_p;
  int wid = tid >> 5, lane = tid & 31;
  if (lane == 0)
#pragma unroll
    for (int e = 0; e < En; e++) wsum[wid][e] = acc[e];
  __syncthreads();
  if (tid == 0) {
    float lg[En];
#pragma unroll
    for (int e = 0; e < En; e++)
      lg[e] = wsum[0][e] + wsum[1][e] + wsum[2][e] + wsum[3][e] + sb[e];
    int am = 0;
    float mx = lg[0];
#pragma unroll
    for (int e = 1; e < En; e++)
      if (lg[e] > mx) {
        mx = lg[e];
        am = e;
      }
    float sum = 0.f;
#pragma unroll
    for (int e = 0; e < En; e++) sum += __expf(lg[e] - mx);
    s_p = 1.f / sum;
    route[t] = am;
  }
  __syncthreads();
  float p = s_p;
#pragma unroll
  for (int l = 0; l < 2; l++) {
    int d = (tid + l * 128) * 4;
    float4 y = make_float4(xv[l * 4] * p, xv[l * 4 + 1] * p, xv[l * 4 + 2] * p,
                           xv[l * 4 + 3] * p);
    *(float4*)(xs + (size_t)t * Dn + d) = y;
  }
}

// =====================================================================================
// Deterministic stable counting sort by expert id (single block).
// =====================================================================================
__global__ void __launch_bounds__(256) sort_routes(
    const int* __restrict__ route, int* __restrict__ dest, int* __restrict__ off) {
  __shared__ int hist[256][En];
  __shared__ int tot[En];
  __shared__ int eoff[En + 1];
  int tid = threadIdx.x;
  int h[En];
#pragma unroll
  for (int e = 0; e < En; e++) h[e] = 0;
  int base = tid * 32;
  for (int i = 0; i < 32; i++) h[route[base + i]]++;
#pragma unroll
  for (int e = 0; e < En; e++) hist[tid][e] = h[e];
  __syncthreads();
  if (tid < En) {
    int e = tid;
    int run = 0;
    for (int i = 0; i < 256; i++) {
      int v = hist[i][e];
      hist[i][e] = run;
      run += v;
    }
    tot[e] = run;
  }
  __syncthreads();
  if (tid == 0) {
    int r = 0;
    for (int e = 0; e < En; e++) {
      eoff[e] = r;
      off[e] = r;
      r += tot[e];
    }
    eoff[En] = r;
    off[En] = r;
  }
  __syncthreads();
  int run[En];
#pragma unroll
  for (int e = 0; e < En; e++) run[e] = eoff[e] + hist[tid][e];
  for (int i = 0; i < 32; i++) {
    int e = route[base + i];
    dest[base + i] = run[e]++;
  }
}

// xsort[dest[t], :] = xs[t, :]
__global__ void __launch_bounds__(256) gather_rows(
    const float* __restrict__ xs, const int* __restrict__ dest,
    float* __restrict__ xsort) {
  int t = blockIdx.x;
  int c = threadIdx.x;
  int dt = dest[t];
  ((float4*)xsort)[(size_t)dt * (Dn / 4) + c] =
      ((const float4*)xs)[(size_t)t * (Dn / 4) + c];
}

// =====================================================================================
extern "C" void kernel_launch(void* const* d_in, const int* in_sizes, int n_in,
                              void* d_out, int out_size) {
  const float* x = (const float*)d_in[0];
  const float* wq = (const float*)d_in[1];
  const float* bq = (const float*)d_in[2];
  const float* wk = (const float*)d_in[3];
  const float* bk = (const float*)d_in[4];
  const float* wv = (const float*)d_in[5];
  const float* bv = (const float*)d_in[6];
  const float* wo = (const float*)d_in[7];
  const float* bo = (const float*)d_in[8];
  const float* ln1g = (const float*)d_in[9];
  const float* ln1b = (const float*)d_in[10];
  const float* ln2g = (const float*)d_in[11];
  const float* ln2b = (const float*)d_in[12];
  const float* sw = (const float*)d_in[13];
  const float* sb = (const float*)d_in[14];
  const float* ew1 = (const float*)d_in[15];
  const float* eb1 = (const float*)d_in[16];
  const float* ew2 = (const float*)d_in[17];
  const float* eb2 = (const float*)d_in[18];
  const int* mask = (const int*)d_in[19];
  float* out = (float*)d_out;

  float *q, *k, *v, *ctx, *ao, *x1, *xs, *xsort, *moe, *h1;
  int *route, *dest, *off;
  cudaGetSymbolAddress((void**)&q, g_q);
  cudaGetSymbolAddress((void**)&k, g_k);
  cudaGetSymbolAddress((void**)&v, g_v);
  cudaGetSymbolAddress((void**)&ctx, g_ctx);
  cudaGetSymbolAddress((void**)&ao, g_ao);
  cudaGetSymbolAddress((void**)&x1, g_x1);
  cudaGetSymbolAddress((void**)&xs, g_xs);
  cudaGetSymbolAddress((void**)&xsort, g_xsort);
  cudaGetSymbolAddress((void**)&moe, g_moe);
  cudaGetSymbolAddress((void**)&h1, g_h1);
  cudaGetSymbolAddress((void**)&route, g_route);
  cudaGetSymbolAddress((void**)&dest, g_dest);
  cudaGetSymbolAddress((void**)&off, g_off);

  // flash smem: (128 + 64 + 64 + 128) * 72 words + 64 ints
  const int FLASH_SMEM = (FQT * FS + FKT * FS + FKT * FS + FQT * FS) * 4 + FKT * 4;
  cudaFuncSetAttribute(flash_tc, cudaFuncAttributeMaxDynamicSharedMemorySize,
                       FLASH_SMEM);

  dim3 blk(256);

  // --- attention block ---
  tgemm<0, 0><<<dim3(Dn / 128, Tn / 128, 1), blk>>>(x, wq, bq, q, Dn, Dn, Tn, nullptr, 0);
  tgemm<0, 0><<<dim3(Dn / 128, Tn / 128, 1), blk>>>(x, wk, bk, k, Dn, Dn, Tn, nullptr, 0);
  tgemm<0, 0><<<dim3(Dn / 128, Tn / 128, 1), blk>>>(x, wv, bv, v, Dn, Dn, Tn, nullptr, 0);
  flash_tc<<<dim3(Sn / FQT, Bn * Hn), blk, FLASH_SMEM>>>(q, k, v, mask, ctx);
  tgemm<0, 0><<<dim3(Dn / 128, Tn / 128, 1), blk>>>(ctx, wo, bo, ao, Dn, Dn, Tn, nullptr, 0);
  add_ln<<<Tn, 256>>>(x, ao, ln1g, ln1b, x1);

  // --- MoE block ---
  router_kernel<<<Tn, 128>>>(x1, sw, sb, xs, route);
  sort_routes<<<1, 256>>>(route, dest, off);
  gather_rows<<<Tn, 256>>>(xs, dest, xsort);
  tgemm<1, 1><<<dim3(Fn / 128, Tn / 128, En), blk>>>(xsort, ew1, eb1, h1, Fn, Dn, 0, off,
                                                     (size_t)Fn * Dn);
  tgemm<0, 1><<<dim3(Dn / 128, Tn / 128, En), blk>>>(h1, ew2, eb2, moe, Dn, Fn, 0, off,
                                                     (size_t)Dn * Fn);
  add_ln<<<Tn, 256>>>(x1, moe, ln2g, ln2b, out);
}

// round 4
// speedup vs baseline: 3.2920x; 1.1346x over previous
#include <cuda_runtime.h>
#include <math.h>

// Problem dims (fixed by the reference)
#define Tn 8192
#define Dn 1024
#define Hn 16
#define HDn 64
#define Fn 4096
#define En 8
#define Bn 4
#define Sn 2048

// ---------------- scratch (static device allocations; no cudaMalloc allowed) ---------
__device__ float g_q[Tn * Dn];
__device__ float g_k[Tn * Dn];
__device__ float g_v[Tn * Dn];
__device__ float g_ctx[Tn * Dn];
__device__ float g_ao[Tn * Dn];
__device__ float g_x1[Tn * Dn];
__device__ float g_xs[Tn * Dn];
__device__ float g_xsort[Tn * Dn];
__device__ float g_moe[Tn * Dn];
__device__ float g_h1[(size_t)Tn * Fn];
__device__ int g_route[Tn];
__device__ int g_dest[Tn];
__device__ int g_off[En + 1];

__device__ __forceinline__ unsigned f2tf(float x) {
  unsigned r;
  asm("cvt.rna.tf32.f32 %0, %1;" : "=r"(r) : "f"(x));
  return r;
}

__device__ __forceinline__ void mma_tf32(float* c, const unsigned* a, const unsigned* b) {
  asm volatile(
      "mma.sync.aligned.m16n8k8.row.col.f32.tf32.tf32.f32 "
      "{%0,%1,%2,%3},{%4,%5,%6,%7},{%8,%9},{%0,%1,%2,%3};"
      : "+f"(c[0]), "+f"(c[1]), "+f"(c[2]), "+f"(c[3])
      : "r"(a[0]), "r"(a[1]), "r"(a[2]), "r"(a[3]), "r"(b[0]), "r"(b[1]));
}

__device__ __forceinline__ void cp_async16(void* smem, const void* gmem) {
  unsigned sa = (unsigned)__cvta_generic_to_shared(smem);
  asm volatile("cp.async.cg.shared.global [%0], [%1], 16;" ::"r"(sa), "l"(gmem));
}
#define CP_COMMIT asm volatile("cp.async.commit_group;")
#define CP_WAIT(n) asm volatile("cp.async.wait_group %0;" ::"n"(n))

// =====================================================================================
// TF32 tensor-core GEMM v2:  C[m,n] = A[m,:] . W[n,:] + bias[n]   (NT, row-major)
// 256x128 block tile, 8 warps (4m x 2n) each computing 64x64. BK=32 K-slabs,
// cp.async double-buffered (raw f32 in smem; HMMA tf32 truncates low mantissa).
// Stride 36 words: bank = 4g+t -> conflict-free fragment LDS.
// USE_OFF=1: expert-batched rows [off[e], off[e+1]) with per-expert weight/bias.
// =====================================================================================
#define BK 32
#define LDA 36
#define ASTG (256 * LDA)
#define BSTG (128 * LDA)

template <int RELU, int USE_OFF>
__global__ void __launch_bounds__(256) tgemm2(
    const float* __restrict__ A, const float* __restrict__ W,
    const float* __restrict__ bias, float* __restrict__ C,
    int N, int K, int Mfull, const int* __restrict__ off, size_t wstride) {
  int e = blockIdx.z;
  int m_start, m_end;
  if (USE_OFF) {
    m_start = off[e];
    m_end = off[e + 1];
  } else {
    m_start = 0;
    m_end = Mfull;
  }
  int m0 = m_start + (int)blockIdx.y * 256;
  if (m0 >= m_end) return;

  const float* Wp = W + (size_t)e * wstride;
  const float* bp = bias + (size_t)e * N;
  int n0 = blockIdx.x * 128;

  extern __shared__ float smx[];
  float* As = smx;              // [2][256][LDA]
  float* Bs = smx + 2 * ASTG;   // [2][128][LDA]

  int tid = threadIdx.x;
  int lane = tid & 31, wid = tid >> 5;
  int wm = (wid >> 1) * 64;  // 4 warps along m
  int wn = (wid & 1) * 64;   // 2 warps along n
  int g = lane >> 2, t = lane & 3;

  float acc[4][8][4];
#pragma unroll
  for (int i = 0; i < 4; i++)
#pragma unroll
    for (int j = 0; j < 8; j++)
#pragma unroll
      for (int l = 0; l < 4; l++) acc[i][j][l] = 0.f;

  // staging: A 256x32 = 8 float4/thread, B 128x32 = 4 float4/thread
  auto stage = [&](int s, int k0) {
#pragma unroll
    for (int i = 0; i < 8; i++) {
      int idx = tid + i * 256;
      int row = idx >> 3, kq = (idx & 7) << 2;
      int grow = m0 + row;
      if (grow < m_end)
        cp_async16(As + s * ASTG + row * LDA + kq, A + (size_t)grow * K + k0 + kq);
    }
#pragma unroll
    for (int i = 0; i < 4; i++) {
      int idx = tid + i * 256;
      int row = idx >> 3, kq = (idx & 7) << 2;
      cp_async16(Bs + s * BSTG + row * LDA + kq, Wp + (size_t)(n0 + row) * K + k0 + kq);
    }
  };

  stage(0, 0);
  CP_COMMIT;

  int nslab = K / BK;
  for (int it = 0; it < nslab; it++) {
    int cur = it & 1;
    if (it + 1 < nslab) {
      stage(1 ^ cur, (it + 1) * BK);
      CP_COMMIT;
      CP_WAIT(1);
    } else {
      CP_WAIT(0);
    }
    __syncthreads();

    const float* Ab = As + cur * ASTG;
    const float* Bb = Bs + cur * BSTG;
#pragma unroll
    for (int kk = 0; kk < BK; kk += 8) {
      unsigned af[4][4];
#pragma unroll
      for (int mf = 0; mf < 4; mf++) {
        const float* a0 = Ab + (wm + mf * 16 + g) * LDA + kk + t;
        af[mf][0] = __float_as_uint(a0[0]);
        af[mf][1] = __float_as_uint(a0[8 * LDA]);
        af[mf][2] = __float_as_uint(a0[4]);
        af[mf][3] = __float_as_uint(a0[8 * LDA + 4]);
      }
#pragma unroll
      for (int nf = 0; nf < 8; nf++) {
        unsigned bf[2];
        const float* b0 = Bb + (wn + nf * 8 + g) * LDA + kk + t;
        bf[0] = __float_as_uint(b0[0]);
        bf[1] = __float_as_uint(b0[4]);
#pragma unroll
        for (int mf = 0; mf < 4; mf++) mma_tf32(acc[mf][nf], af[mf], bf);
      }
    }
    __syncthreads();  // all warps done reading `cur` before it+1 refills it
  }

#pragma unroll
  for (int nf = 0; nf < 8; nf++) {
    int col = n0 + wn + nf * 8 + 2 * t;
    float2 bb = *(const float2*)(bp + col);
#pragma unroll
    for (int mf = 0; mf < 4; mf++) {
      int row0 = m0 + wm + mf * 16 + g;
      float v0 = acc[mf][nf][0] + bb.x;
      float v1 = acc[mf][nf][1] + bb.y;
      float v2 = acc[mf][nf][2] + bb.x;
      float v3 = acc[mf][nf][3] + bb.y;
      if (RELU) {
        v0 = fmaxf(v0, 0.f); v1 = fmaxf(v1, 0.f);
        v2 = fmaxf(v2, 0.f); v3 = fmaxf(v3, 0.f);
      }
      if (row0 < m_end)
        *(float2*)(C + (size_t)row0 * N + col) = make_float2(v0, v1);
      if (row0 + 8 < m_end)
        *(float2*)(C + (size_t)(row0 + 8) * N + col) = make_float2(v2, v3);
    }
  }
}

// =====================================================================================
// Tensor-core flash attention (tf32), unchanged from round 3.
// =====================================================================================
#define FQT 128
#define FKT 64
#define FS 72

__global__ void __launch_bounds__(256, 2) flash_tc(
    const float* __restrict__ Q, const float* __restrict__ K,
    const float* __restrict__ V, const int* __restrict__ mask,
    float* __restrict__ O) {
  extern __shared__ unsigned smu[];
  unsigned* Qs = smu;                       // [128][FS]
  unsigned* Ks = Qs + FQT * FS;             // [64][FS]
  unsigned* Vs = Ks + FKT * FS;             // [64][FS]
  float* Ps = (float*)(Vs + FKT * FS);      // [128][FS]
  int* msk = (int*)(Ps + FQT * FS);         // [64]

  int bh = blockIdx.y;
  int b = bh >> 4, h = bh & 15;
  int q0 = blockIdx.x * FQT;
  int tid = threadIdx.x;
  int lane = tid & 31, wid = tid >> 5;
  int g = lane >> 2, t = lane & 3;
  int wrow = wid * 16;

#pragma unroll
  for (int l = 0; l < 8; l++) {
    int idx = tid + l * 256;
    int r = idx >> 4, qc = (idx & 15) << 2;
    float4 qv = *(const float4*)(Q + (size_t)(b * Sn + q0 + r) * Dn + h * HDn + qc);
    unsigned* p = Qs + r * FS + qc;
    p[0] = f2tf(qv.x); p[1] = f2tf(qv.y);
    p[2] = f2tf(qv.z); p[3] = f2tf(qv.w);
  }

  float o[8][4];
#pragma unroll
  for (int nf = 0; nf < 8; nf++)
#pragma unroll
    for (int c = 0; c < 4; c++) o[nf][c] = 0.f;
  float mrow0 = -1e30f, mrow1 = -1e30f;
  float lrow0 = 0.f, lrow1 = 0.f;

  for (int t0 = 0; t0 < Sn; t0 += FKT) {
    __syncthreads();
#pragma unroll
    for (int l = 0; l < 4; l++) {
      int idx = tid + l * 256;
      int r = idx >> 4, qc = (idx & 15) << 2;
      size_t base = (size_t)(b * Sn + t0 + r) * Dn + h * HDn + qc;
      float4 kv = *(const float4*)(K + base);
      unsigned* pk = Ks + r * FS + qc;
      pk[0] = f2tf(kv.x); pk[1] = f2tf(kv.y);
      pk[2] = f2tf(kv.z); pk[3] = f2tf(kv.w);
      float4 vv = *(const float4*)(V + base);
      unsigned* pv = Vs + r * FS + qc;
      pv[0] = f2tf(vv.x); pv[1] = f2tf(vv.y);
      pv[2] = f2tf(vv.z); pv[3] = f2tf(vv.w);
    }
    if (tid < FKT) msk[tid] = mask[b * Sn + t0 + tid];
    __syncthreads();

    float s[8][4];
#pragma unroll
    for (int nf = 0; nf < 8; nf++)
#pragma unroll
      for (int c = 0; c < 4; c++) s[nf][c] = 0.f;

#pragma unroll
    for (int kk = 0; kk < HDn; kk += 8) {
      unsigned af[4];
      const unsigned* a0 = Qs + (wrow + g) * FS + kk + t;
      af[0] = a0[0];
      af[1] = a0[8 * FS];
      af[2] = a0[4];
      af[3] = a0[8 * FS + 4];
#pragma unroll
      for (int nf = 0; nf < 8; nf++) {
        unsigned bf[2];
        const unsigned* b0 = Ks + (nf * 8 + g) * FS + kk + t;
        bf[0] = b0[0];
        bf[1] = b0[4];
        mma_tf32(s[nf], af, bf);
      }
    }

#pragma unroll
    for (int nf = 0; nf < 8; nf++) {
      int col = nf * 8 + 2 * t;
      bool z0 = (msk[col] == 0), z1 = (msk[col + 1] == 0);
      s[nf][0] = z0 ? -1e10f : s[nf][0] * 0.125f;
      s[nf][1] = z1 ? -1e10f : s[nf][1] * 0.125f;
      s[nf][2] = z0 ? -1e10f : s[nf][2] * 0.125f;
      s[nf][3] = z1 ? -1e10f : s[nf][3] * 0.125f;
    }

    float mx0 = -1e30f, mx1 = -1e30f;
#pragma unroll
    for (int nf = 0; nf < 8; nf++) {
      mx0 = fmaxf(mx0, fmaxf(s[nf][0], s[nf][1]));
      mx1 = fmaxf(mx1, fmaxf(s[nf][2], s[nf][3]));
    }
    mx0 = fmaxf(mx0, __shfl_xor_sync(0xffffffffu, mx0, 1));
    mx0 = fmaxf(mx0, __shfl_xor_sync(0xffffffffu, mx0, 2));
    mx1 = fmaxf(mx1, __shfl_xor_sync(0xffffffffu, mx1, 1));
    mx1 = fmaxf(mx1, __shfl_xor_sync(0xffffffffu, mx1, 2));

    float mn0 = fmaxf(mrow0, mx0), mn1 = fmaxf(mrow1, mx1);
    float sc0 = __expf(mrow0 - mn0), sc1 = __expf(mrow1 - mn1);
    mrow0 = mn0; mrow1 = mn1;

    float rs0 = 0.f, rs1 = 0.f;
#pragma unroll
    for (int nf = 0; nf < 8; nf++) {
      s[nf][0] = __expf(s[nf][0] - mn0);
      s[nf][1] = __expf(s[nf][1] - mn0);
      s[nf][2] = __expf(s[nf][2] - mn1);
      s[nf][3] = __expf(s[nf][3] - mn1);
      rs0 += s[nf][0] + s[nf][1];
      rs1 += s[nf][2] + s[nf][3];
    }
    rs0 += __shfl_xor_sync(0xffffffffu, rs0, 1);
    rs0 += __shfl_xor_sync(0xffffffffu, rs0, 2);
    rs1 += __shfl_xor_sync(0xffffffffu, rs1, 1);
    rs1 += __shfl_xor_sync(0xffffffffu, rs1, 2);
    lrow0 = lrow0 * sc0 + rs0;
    lrow1 = lrow1 * sc1 + rs1;

#pragma unroll
    for (int nf = 0; nf < 8; nf++) {
      o[nf][0] *= sc0; o[nf][1] *= sc0;
      o[nf][2] *= sc1; o[nf][3] *= sc1;
    }

#pragma unroll
    for (int nf = 0; nf < 8; nf++) {
      int col = nf * 8 + 2 * t;
      *(float2*)(Ps + (wrow + g) * FS + col) = make_float2(s[nf][0], s[nf][1]);
      *(float2*)(Ps + (wrow + g + 8) * FS + col) = make_float2(s[nf][2], s[nf][3]);
    }
    __syncwarp();

#pragma unroll
    for (int kk = 0; kk < FKT; kk += 8) {
      unsigned af[4];
      const float* a0 = Ps + (wrow + g) * FS + kk + t;
      af[0] = __float_as_uint(a0[0]);
      af[1] = __float_as_uint(a0[8 * FS]);
      af[2] = __float_as_uint(a0[4]);
      af[3] = __float_as_uint(a0[8 * FS + 4]);
#pragma unroll
      for (int nf = 0; nf < 8; nf++) {
        unsigned bf[2];
        const unsigned* b0 = Vs + (kk + t) * FS + nf * 8 + g;
        bf[0] = b0[0];
        bf[1] = b0[4 * FS];
        mma_tf32(o[nf], af, bf);
      }
    }
    __syncwarp();
  }

  float inv0 = 1.f / lrow0, inv1 = 1.f / lrow1;
  int row = b * Sn + q0 + wrow + g;
#pragma unroll
  for (int nf = 0; nf < 8; nf++) {
    int col = h * HDn + nf * 8 + 2 * t;
    *(float2*)(O + (size_t)row * Dn + col) =
        make_float2(o[nf][0] * inv0, o[nf][1] * inv0);
    *(float2*)(O + (size_t)(row + 8) * Dn + col) =
        make_float2(o[nf][2] * inv1, o[nf][3] * inv1);
  }
}

// =====================================================================================
// out = LayerNorm(A + B) * g + be
// =====================================================================================
__global__ void __launch_bounds__(256) add_ln(
    const float* __restrict__ A, const float* __restrict__ Bv,
    const float* __restrict__ g, const float* __restrict__ be,
    float* __restrict__ out) {
  int t = blockIdx.x;
  int tid = threadIdx.x;
  float4 a = *(const float4*)(A + (size_t)t * Dn + tid * 4);
  float4 b = *(const float4*)(Bv + (size_t)t * Dn + tid * 4);
  float4 x = make_float4(a.x + b.x, a.y + b.y, a.z + b.z, a.w + b.w);
  float sumv = x.x + x.y + x.z + x.w;
  float sq = x.x * x.x + x.y * x.y + x.z * x.z + x.w * x.w;
#pragma unroll
  for (int off = 16; off; off >>= 1) {
    sumv += __shfl_xor_sync(0xffffffffu, sumv, off);
    sq += __shfl_xor_sync(0xffffffffu, sq, off);
  }
  __shared__ float ws[8], wq[8];
  __shared__ float s_mean, s_rstd;
  int wid = tid >> 5, lane = tid & 31;
  if (lane == 0) {
    ws[wid] = sumv;
    wq[wid] = sq;
  }
  __syncthreads();
  if (tid == 0) {
    float s = 0.f, q = 0.f;
#pragma unroll
    for (int i = 0; i < 8; i++) {
      s += ws[i];
      q += wq[i];
    }
    float mean = s * (1.f / Dn);
    float var = q * (1.f / Dn) - mean * mean;
    s_mean = mean;
    s_rstd = rsqrtf(var + 1e-5f);
  }
  __syncthreads();
  float mean = s_mean, rstd = s_rstd;
  float4 gg = *(const float4*)(g + tid * 4);
  float4 bb = *(const float4*)(be + tid * 4);
  float4 y;
  y.x = (x.x - mean) * rstd * gg.x + bb.x;
  y.y = (x.y - mean) * rstd * gg.y + bb.y;
  y.z = (x.z - mean) * rstd * gg.z + bb.z;
  y.w = (x.w - mean) * rstd * gg.w + bb.w;
  *(float4*)(out + (size_t)t * Dn + tid * 4) = y;
}

// =====================================================================================
// Router
// =====================================================================================
__global__ void __launch_bounds__(128) router_kernel(
    const float* __restrict__ x1, const float* __restrict__ sw,
    const float* __restrict__ sb, float* __restrict__ xs,
    int* __restrict__ route) {
  __shared__ float ssw[En * Dn];
  int t = blockIdx.x;
  int tid = threadIdx.x;
  for (int i = tid; i < En * Dn / 4; i += 128)
    ((float4*)ssw)[i] = ((const float4*)sw)[i];
  __syncthreads();

  float acc[En];
#pragma unroll
  for (int e = 0; e < En; e++) acc[e] = 0.f;
  float xv[8];
#pragma unroll
  for (int l = 0; l < 2; l++) {
    int d = (tid + l * 128) * 4;
    float4 x = *(const float4*)(x1 + (size_t)t * Dn + d);
    xv[l * 4 + 0] = x.x;
    xv[l * 4 + 1] = x.y;
    xv[l * 4 + 2] = x.z;
    xv[l * 4 + 3] = x.w;
#pragma unroll
    for (int e = 0; e < En; e++) {
      const float* swp = ssw + e * Dn + d;
      acc[e] += x.x * swp[0] + x.y * swp[1] + x.z * swp[2] + x.w * swp[3];
    }
  }
#pragma unroll
  for (int e = 0; e < En; e++)
#pragma unroll
    for (int off = 16; off; off >>= 1) acc[e] += __shfl_xor_sync(0xffffffffu, acc[e], off);

  __shared__ float wsum[4][En];
  __shared__ float s_p;
  int wid = tid >> 5, lane = tid & 31;
  if (lane == 0)
#pragma unroll
    for (int e = 0; e < En; e++) wsum[wid][e] = acc[e];
  __syncthreads();
  if (tid == 0) {
    float lg[En];
#pragma unroll
    for (int e = 0; e < En; e++)
      lg[e] = wsum[0][e] + wsum[1][e] + wsum[2][e] + wsum[3][e] + sb[e];
    int am = 0;
    float mx = lg[0];
#pragma unroll
    for (int e = 1; e < En; e++)
      if (lg[e] > mx) {
        mx = lg[e];
        am = e;
      }
    float sum = 0.f;
#pragma unroll
    for (int e = 0; e < En; e++) sum += __expf(lg[e] - mx);
    s_p = 1.f / sum;
    route[t] = am;
  }
  __syncthreads();
  float p = s_p;
#pragma unroll
  for (int l = 0; l < 2; l++) {
    int d = (tid + l * 128) * 4;
    float4 y = make_float4(xv[l * 4] * p, xv[l * 4 + 1] * p, xv[l * 4 + 2] * p,
                           xv[l * 4 + 3] * p);
    *(float4*)(xs + (size_t)t * Dn + d) = y;
  }
}

// =====================================================================================
// Deterministic stable counting sort by expert id (single block).
// =====================================================================================
__global__ void __launch_bounds__(256) sort_routes(
    const int* __restrict__ route, int* __restrict__ dest, int* __restrict__ off) {
  __shared__ int hist[256][En];
  __shared__ int tot[En];
  __shared__ int eoff[En + 1];
  int tid = threadIdx.x;
  int h[En];
#pragma unroll
  for (int e = 0; e < En; e++) h[e] = 0;
  int base = tid * 32;
  for (int i = 0; i < 32; i++) h[route[base + i]]++;
#pragma unroll
  for (int e = 0; e < En; e++) hist[tid][e] = h[e];
  __syncthreads();
  if (tid < En) {
    int e = tid;
    int run = 0;
    for (int i = 0; i < 256; i++) {
      int v = hist[i][e];
      hist[i][e] = run;
      run += v;
    }
    tot[e] = run;
  }
  __syncthreads();
  if (tid == 0) {
    int r = 0;
    for (int e = 0; e < En; e++) {
      eoff[e] = r;
      off[e] = r;
      r += tot[e];
    }
    eoff[En] = r;
    off[En] = r;
  }
  __syncthreads();
  int run[En];
#pragma unroll
  for (int e = 0; e < En; e++) run[e] = eoff[e] + hist[tid][e];
  for (int i = 0; i < 32; i++) {
    int e = route[base + i];
    dest[base + i] = run[e]++;
  }
}

// xsort[dest[t], :] = xs[t, :]
__global__ void __launch_bounds__(256) gather_rows(
    const float* __restrict__ xs, const int* __restrict__ dest,
    float* __restrict__ xsort) {
  int t = blockIdx.x;
  int c = threadIdx.x;
  int dt = dest[t];
  ((float4*)xsort)[(size_t)dt * (Dn / 4) + c] =
      ((const float4*)xs)[(size_t)t * (Dn / 4) + c];
}

// =====================================================================================
extern "C" void kernel_launch(void* const* d_in, const int* in_sizes, int n_in,
                              void* d_out, int out_size) {
  const float* x = (const float*)d_in[0];
  const float* wq = (const float*)d_in[1];
  const float* bq = (const float*)d_in[2];
  const float* wk = (const float*)d_in[3];
  const float* bk = (const float*)d_in[4];
  const float* wv = (const float*)d_in[5];
  const float* bv = (const float*)d_in[6];
  const float* wo = (const float*)d_in[7];
  const float* bo = (const float*)d_in[8];
  const float* ln1g = (const float*)d_in[9];
  const float* ln1b = (const float*)d_in[10];
  const float* ln2g = (const float*)d_in[11];
  const float* ln2b = (const float*)d_in[12];
  const float* sw = (const float*)d_in[13];
  const float* sb = (const float*)d_in[14];
  const float* ew1 = (const float*)d_in[15];
  const float* eb1 = (const float*)d_in[16];
  const float* ew2 = (const float*)d_in[17];
  const float* eb2 = (const float*)d_in[18];
  const int* mask = (const int*)d_in[19];
  float* out = (float*)d_out;

  float *q, *k, *v, *ctx, *ao, *x1, *xs, *xsort, *moe, *h1;
  int *route, *dest, *off;
  cudaGetSymbolAddress((void**)&q, g_q);
  cudaGetSymbolAddress((void**)&k, g_k);
  cudaGetSymbolAddress((void**)&v, g_v);
  cudaGetSymbolAddress((void**)&ctx, g_ctx);
  cudaGetSymbolAddress((void**)&ao, g_ao);
  cudaGetSymbolAddress((void**)&x1, g_x1);
  cudaGetSymbolAddress((void**)&xs, g_xs);
  cudaGetSymbolAddress((void**)&xsort, g_xsort);
  cudaGetSymbolAddress((void**)&moe, g_moe);
  cudaGetSymbolAddress((void**)&h1, g_h1);
  cudaGetSymbolAddress((void**)&route, g_route);
  cudaGetSymbolAddress((void**)&dest, g_dest);
  cudaGetSymbolAddress((void**)&off, g_off);

  const int GEMM_SMEM = (2 * ASTG + 2 * BSTG) * 4;  // 110592 B
  cudaFuncSetAttribute(tgemm2<0, 0>, cudaFuncAttributeMaxDynamicSharedMemorySize, GEMM_SMEM);
  cudaFuncSetAttribute(tgemm2<1, 1>, cudaFuncAttributeMaxDynamicSharedMemorySize, GEMM_SMEM);
  cudaFuncSetAttribute(tgemm2<0, 1>, cudaFuncAttributeMaxDynamicSharedMemorySize, GEMM_SMEM);

  const int FLASH_SMEM = (FQT * FS + FKT * FS + FKT * FS + FQT * FS) * 4 + FKT * 4;
  cudaFuncSetAttribute(flash_tc, cudaFuncAttributeMaxDynamicSharedMemorySize, FLASH_SMEM);

  dim3 blk(256);
  dim3 gdense(Dn / 128, Tn / 256, 1);

  // --- attention block ---
  tgemm2<0, 0><<<gdense, blk, GEMM_SMEM>>>(x, wq, bq, q, Dn, Dn, Tn, nullptr, 0);
  tgemm2<0, 0><<<gdense, blk, GEMM_SMEM>>>(x, wk, bk, k, Dn, Dn, Tn, nullptr, 0);
  tgemm2<0, 0><<<gdense, blk, GEMM_SMEM>>>(x, wv, bv, v, Dn, Dn, Tn, nullptr, 0);
  flash_tc<<<dim3(Sn / FQT, Bn * Hn), blk, FLASH_SMEM>>>(q, k, v, mask, ctx);
  tgemm2<0, 0><<<gdense, blk, GEMM_SMEM>>>(ctx, wo, bo, ao, Dn, Dn, Tn, nullptr, 0);
  add_ln<<<Tn, 256>>>(x, ao, ln1g, ln1b, x1);

  // --- MoE block ---
  router_kernel<<<Tn, 128>>>(x1, sw, sb, xs, route);
  sort_routes<<<1, 256>>>(route, dest, off);
  gather_rows<<<Tn, 256>>>(xs, dest, xsort);
  tgemm2<1, 1><<<dim3(Fn / 128, Tn / 256, En), blk, GEMM_SMEM>>>(
      xsort, ew1, eb1, h1, Fn, Dn, 0, off, (size_t)Fn * Dn);
  tgemm2<0, 1><<<dim3(Dn / 128, Tn / 256, En), blk, GEMM_SMEM>>>(
      h1, ew2, eb2, moe, Dn, Fn, 0, off, (size_t)Dn * Fn);
  add_ln<<<Tn, 256>>>(x1, moe, ln2g, ln2b, out);
}

// round 5
// speedup vs baseline: 3.9710x; 1.2063x over previous
#include <cuda_runtime.h>
#include <math.h>

// Problem dims (fixed by the reference)
#define Tn 8192
#define Dn 1024
#define Hn 16
#define HDn 64
#define Fn 4096
#define En 8
#define Bn 4
#define Sn 2048

// ---------------- scratch (static device allocations; no cudaMalloc allowed) ---------
__device__ float g_q[Tn * Dn];
__device__ float g_k[Tn * Dn];
__device__ float g_v[Tn * Dn];
__device__ float g_ctx[Tn * Dn];
__device__ float g_ao[Tn * Dn];
__device__ float g_x1[Tn * Dn];
__device__ float g_xs[Tn * Dn];
__device__ float g_xsort[Tn * Dn];
__device__ float g_moe[Tn * Dn];
__device__ float g_h1[(size_t)Tn * Fn];
__device__ int g_route[Tn];
__device__ int g_dest[Tn];
__device__ int g_off[En + 1];

__device__ __forceinline__ void mma_tf32(float* c, const unsigned* a, const unsigned* b) {
  asm volatile(
      "mma.sync.aligned.m16n8k8.row.col.f32.tf32.tf32.f32 "
      "{%0,%1,%2,%3},{%4,%5,%6,%7},{%8,%9},{%0,%1,%2,%3};"
      : "+f"(c[0]), "+f"(c[1]), "+f"(c[2]), "+f"(c[3])
      : "r"(a[0]), "r"(a[1]), "r"(a[2]), "r"(a[3]), "r"(b[0]), "r"(b[1]));
}

__device__ __forceinline__ void mma_bf16(float* c, const unsigned* a, const unsigned* b) {
  asm volatile(
      "mma.sync.aligned.m16n8k16.row.col.f32.bf16.bf16.f32 "
      "{%0,%1,%2,%3},{%4,%5,%6,%7},{%8,%9},{%0,%1,%2,%3};"
      : "+f"(c[0]), "+f"(c[1]), "+f"(c[2]), "+f"(c[3])
      : "r"(a[0]), "r"(a[1]), "r"(a[2]), "r"(a[3]), "r"(b[0]), "r"(b[1]));
}

// pack two f32 -> bf16x2 (lo = first arg, hi = second)
__device__ __forceinline__ unsigned pk2(float lo, float hi) {
  unsigned r;
  asm("cvt.rn.bf16x2.f32 %0, %1, %2;" : "=r"(r) : "f"(hi), "f"(lo));
  return r;
}

__device__ __forceinline__ unsigned smem_u32(const void* p) {
  return (unsigned)__cvta_generic_to_shared(p);
}

__device__ __forceinline__ void ldm4(unsigned* r, unsigned addr) {
  asm volatile("ldmatrix.sync.aligned.m8n8.x4.shared.b16 {%0,%1,%2,%3}, [%4];"
               : "=r"(r[0]), "=r"(r[1]), "=r"(r[2]), "=r"(r[3]) : "r"(addr));
}
__device__ __forceinline__ void ldm4t(unsigned* r, unsigned addr) {
  asm volatile("ldmatrix.sync.aligned.m8n8.x4.trans.shared.b16 {%0,%1,%2,%3}, [%4];"
               : "=r"(r[0]), "=r"(r[1]), "=r"(r[2]), "=r"(r[3]) : "r"(addr));
}

__device__ __forceinline__ void cp_async16(void* smem, const void* gmem) {
  unsigned sa = (unsigned)__cvta_generic_to_shared(smem);
  asm volatile("cp.async.cg.shared.global [%0], [%1], 16;" ::"r"(sa), "l"(gmem));
}
#define CP_COMMIT asm volatile("cp.async.commit_group;")
#define CP_WAIT(n) asm volatile("cp.async.wait_group %0;" ::"n"(n))

// =====================================================================================
// TF32 tensor-core GEMM body: C[m,n] = A[m,:] . W[n,:] + bias[n]  (NT, row-major)
// 256x128 block, 8 warps (4m x 2n) each 64x64, BK=32, cp.async double-buffered.
// =====================================================================================
#define BK 32
#define LDA 36
#define ASTG (256 * LDA)
#define BSTG (128 * LDA)

template <int RELU>
__device__ __forceinline__ void gemm_body(
    const float* __restrict__ A, const float* __restrict__ W,
    const float* __restrict__ bp, float* __restrict__ C,
    int N, int K, int m0, int m_end, float* smx) {
  int n0 = blockIdx.x * 128;
  float* As = smx;
  float* Bs = smx + 2 * ASTG;

  int tid = threadIdx.x;
  int lane = tid & 31, wid = tid >> 5;
  int wm = (wid >> 1) * 64;
  int wn = (wid & 1) * 64;
  int g = lane >> 2, t = lane & 3;

  float acc[4][8][4];
#pragma unroll
  for (int i = 0; i < 4; i++)
#pragma unroll
    for (int j = 0; j < 8; j++)
#pragma unroll
      for (int l = 0; l < 4; l++) acc[i][j][l] = 0.f;

  auto stage = [&](int s, int k0) {
#pragma unroll
    for (int i = 0; i < 8; i++) {
      int idx = tid + i * 256;
      int row = idx >> 3, kq = (idx & 7) << 2;
      int grow = m0 + row;
      if (grow < m_end)
        cp_async16(As + s * ASTG + row * LDA + kq, A + (size_t)grow * K + k0 + kq);
    }
#pragma unroll
    for (int i = 0; i < 4; i++) {
      int idx = tid + i * 256;
      int row = idx >> 3, kq = (idx & 7) << 2;
      cp_async16(Bs + s * BSTG + row * LDA + kq, W + (size_t)(n0 + row) * K + k0 + kq);
    }
  };

  stage(0, 0);
  CP_COMMIT;

  int nslab = K / BK;
  for (int it = 0; it < nslab; it++) {
    int cur = it & 1;
    if (it + 1 < nslab) {
      stage(1 ^ cur, (it + 1) * BK);
      CP_COMMIT;
      CP_WAIT(1);
    } else {
      CP_WAIT(0);
    }
    __syncthreads();

    const float* Ab = As + cur * ASTG;
    const float* Bb = Bs + cur * BSTG;
#pragma unroll
    for (int kk = 0; kk < BK; kk += 8) {
      unsigned af[4][4];
#pragma unroll
      for (int mf = 0; mf < 4; mf++) {
        const float* a0 = Ab + (wm + mf * 16 + g) * LDA + kk + t;
        af[mf][0] = __float_as_uint(a0[0]);
        af[mf][1] = __float_as_uint(a0[8 * LDA]);
        af[mf][2] = __float_as_uint(a0[4]);
        af[mf][3] = __float_as_uint(a0[8 * LDA + 4]);
      }
#pragma unroll
      for (int nf = 0; nf < 8; nf++) {
        unsigned bf[2];
        const float* b0 = Bb + (wn + nf * 8 + g) * LDA + kk + t;
        bf[0] = __float_as_uint(b0[0]);
        bf[1] = __float_as_uint(b0[4]);
#pragma unroll
        for (int mf = 0; mf < 4; mf++) mma_tf32(acc[mf][nf], af[mf], bf);
      }
    }
    __syncthreads();
  }

#pragma unroll
  for (int nf = 0; nf < 8; nf++) {
    int col = n0 + wn + nf * 8 + 2 * t;
    float2 bb = *(const float2*)(bp + col);
#pragma unroll
    for (int mf = 0; mf < 4; mf++) {
      int row0 = m0 + wm + mf * 16 + g;
      float v0 = acc[mf][nf][0] + bb.x;
      float v1 = acc[mf][nf][1] + bb.y;
      float v2 = acc[mf][nf][2] + bb.x;
      float v3 = acc[mf][nf][3] + bb.y;
      if (RELU) {
        v0 = fmaxf(v0, 0.f); v1 = fmaxf(v1, 0.f);
        v2 = fmaxf(v2, 0.f); v3 = fmaxf(v3, 0.f);
      }
      if (row0 < m_end)
        *(float2*)(C + (size_t)row0 * N + col) = make_float2(v0, v1);
      if (row0 + 8 < m_end)
        *(float2*)(C + (size_t)(row0 + 8) * N + col) = make_float2(v2, v3);
    }
  }
}

template <int RELU, int USE_OFF>
__global__ void __launch_bounds__(256) tgemm2(
    const float* __restrict__ A, const float* __restrict__ W,
    const float* __restrict__ bias, float* __restrict__ C,
    int N, int K, int Mfull, const int* __restrict__ off, size_t wstride) {
  extern __shared__ float smx[];
  int e = blockIdx.z;
  int m_start, m_end;
  if (USE_OFF) {
    m_start = off[e];
    m_end = off[e + 1];
  } else {
    m_start = 0;
    m_end = Mfull;
  }
  int m0 = m_start + (int)blockIdx.y * 256;
  if (m0 >= m_end) return;
  gemm_body<RELU>(A, W + (size_t)e * wstride, bias + (size_t)e * N, C, N, K, m0, m_end, smx);
}

// Fused QKV projection: blockIdx.z selects (wq,bq,q) / (wk,bk,k) / (wv,bv,v)
__global__ void __launch_bounds__(256) tgemm_qkv(
    const float* __restrict__ A,
    const float* __restrict__ w0, const float* __restrict__ w1, const float* __restrict__ w2,
    const float* __restrict__ b0, const float* __restrict__ b1, const float* __restrict__ b2,
    float* __restrict__ c0, float* __restrict__ c1, float* __restrict__ c2) {
  extern __shared__ float smx[];
  int z = blockIdx.z;
  const float* W = (z == 0) ? w0 : (z == 1) ? w1 : w2;
  const float* bb = (z == 0) ? b0 : (z == 1) ? b1 : b2;
  float* C = (z == 0) ? c0 : (z == 1) ? c1 : c2;
  int m0 = (int)blockIdx.y * 256;
  gemm_body<0>(A, W, bb, C, Dn, Dn, m0, Tn, smx);
}

// =====================================================================================
// bf16 tensor-core flash attention.
// 128-query blocks, 64-key tiles, 8 warps x 16 q-rows, m16n8k16 bf16 mma.
// Q/K stored as bf16 k-pairs (uint32) [row][36]; V stored bf16 [key][72 halves].
// Fragments via ldmatrix.x4 (Q/K) and ldmatrix.x4.trans (V). P stays in registers:
// QK output cols (nf*8+2t, +1) are an adjacent k-pair -> cvt.rn.bf16x2 packs the PV
// A-fragment directly. Softmax row stats in fp32.
// =====================================================================================
#define FQT 128
#define FKT 64
#define FSW 36  // words per row (32 data + 4 pad)

__global__ void __launch_bounds__(256) flash_bf(
    const float* __restrict__ Q, const float* __restrict__ K,
    const float* __restrict__ V, const int* __restrict__ mask,
    float* __restrict__ O) {
  __shared__ unsigned Qs[FQT * FSW];
  __shared__ unsigned Ks[FKT * FSW];
  __shared__ unsigned Vs[FKT * FSW];
  __shared__ int msk[FKT];

  int bh = blockIdx.y;
  int b = bh >> 4, h = bh & 15;
  int q0 = blockIdx.x * FQT;
  int tid = threadIdx.x;
  int lane = tid & 31, wid = tid >> 5;
  int g = lane >> 2, t = lane & 3;
  int wrow = wid * 16;

  // stage Q tile as bf16 k-pairs: 128 rows x 16 float4 = 2048 loads / 256 thr = 8
#pragma unroll
  for (int l = 0; l < 8; l++) {
    int idx = tid + l * 256;
    int r = idx >> 4, kq = (idx & 15) << 2;
    float4 qv = *(const float4*)(Q + (size_t)(b * Sn + q0 + r) * Dn + h * HDn + kq);
    *(uint2*)(Qs + r * FSW + (kq >> 1)) = make_uint2(pk2(qv.x, qv.y), pk2(qv.z, qv.w));
  }

  float o[8][4];
#pragma unroll
  for (int nf = 0; nf < 8; nf++)
#pragma unroll
    for (int c = 0; c < 4; c++) o[nf][c] = 0.f;
  float mrow0 = -1e30f, mrow1 = -1e30f;
  float lrow0 = 0.f, lrow1 = 0.f;

  // precomputed ldmatrix lane addressing
  unsigned qa_base = smem_u32(Qs + (wrow + (lane & 15)) * FSW + (lane >> 4) * 4);
  unsigned kb_row = (lane & 7) + ((lane >> 4) & 1) * 8;   // within 16-key group
  unsigned kb_koff = ((lane >> 3) & 1) * 4;               // k-half (words)
  unsigned vb_key = (lane & 7) + ((lane >> 3) & 1) * 8;   // within 16-key chunk
  unsigned vb_doff = ((lane >> 4) & 1) * 4;               // d-half (words)

  for (int t0 = 0; t0 < Sn; t0 += FKT) {
    __syncthreads();
    // stage K,V: 64 rows x 16 float4 each -> 4 per thread per matrix
#pragma unroll
    for (int l = 0; l < 4; l++) {
      int idx = tid + l * 256;
      int r = idx >> 4, kq = (idx & 15) << 2;
      size_t base = (size_t)(b * Sn + t0 + r) * Dn + h * HDn + kq;
      float4 kv = *(const float4*)(K + base);
      *(uint2*)(Ks + r * FSW + (kq >> 1)) = make_uint2(pk2(kv.x, kv.y), pk2(kv.z, kv.w));
      float4 vv = *(const float4*)(V + base);
      *(uint2*)(Vs + r * FSW + (kq >> 1)) = make_uint2(pk2(vv.x, vv.y), pk2(vv.z, vv.w));
    }
    if (tid < FKT) msk[tid] = mask[b * Sn + t0 + tid];
    __syncthreads();

    // ---- S = Q K^T ----
    float s[8][4];
#pragma unroll
    for (int nf = 0; nf < 8; nf++)
#pragma unroll
      for (int c = 0; c < 4; c++) s[nf][c] = 0.f;

#pragma unroll
    for (int c = 0; c < 4; c++) {  // k16 chunks over HD=64
      unsigned a[4];
      ldm4(a, qa_base + (c * 8) * 4);
#pragma unroll
      for (int ng = 0; ng < 4; ng++) {  // 16 keys per ldmatrix.x4
        unsigned bq[4];
        unsigned addr = smem_u32(Ks + (ng * 16 + kb_row) * FSW + c * 8 + kb_koff);
        ldm4(bq, addr);
        mma_bf16(s[2 * ng], a, bq);
        mma_bf16(s[2 * ng + 1], a, bq + 2);
      }
    }

    // ---- mask + scale ----
#pragma unroll
    for (int nf = 0; nf < 8; nf++) {
      int col = nf * 8 + 2 * t;
      bool z0 = (msk[col] == 0), z1 = (msk[col + 1] == 0);
      s[nf][0] = z0 ? -1e10f : s[nf][0] * 0.125f;
      s[nf][1] = z1 ? -1e10f : s[nf][1] * 0.125f;
      s[nf][2] = z0 ? -1e10f : s[nf][2] * 0.125f;
      s[nf][3] = z1 ? -1e10f : s[nf][3] * 0.125f;
    }

    // ---- online softmax (rows g and g+8 live in the quad) ----
    float mx0 = -1e30f, mx1 = -1e30f;
#pragma unroll
    for (int nf = 0; nf < 8; nf++) {
      mx0 = fmaxf(mx0, fmaxf(s[nf][0], s[nf][1]));
      mx1 = fmaxf(mx1, fmaxf(s[nf][2], s[nf][3]));
    }
    mx0 = fmaxf(mx0, __shfl_xor_sync(0xffffffffu, mx0, 1));
    mx0 = fmaxf(mx0, __shfl_xor_sync(0xffffffffu, mx0, 2));
    mx1 = fmaxf(mx1, __shfl_xor_sync(0xffffffffu, mx1, 1));
    mx1 = fmaxf(mx1, __shfl_xor_sync(0xffffffffu, mx1, 2));

    float mn0 = fmaxf(mrow0, mx0), mn1 = fmaxf(mrow1, mx1);
    float sc0 = __expf(mrow0 - mn0), sc1 = __expf(mrow1 - mn1);
    mrow0 = mn0; mrow1 = mn1;

    float rs0 = 0.f, rs1 = 0.f;
    unsigned pk[8][2];
#pragma unroll
    for (int nf = 0; nf < 8; nf++) {
      s[nf][0] = __expf(s[nf][0] - mn0);
      s[nf][1] = __expf(s[nf][1] - mn0);
      s[nf][2] = __expf(s[nf][2] - mn1);
      s[nf][3] = __expf(s[nf][3] - mn1);
      rs0 += s[nf][0] + s[nf][1];
      rs1 += s[nf][2] + s[nf][3];
      pk[nf][0] = pk2(s[nf][0], s[nf][1]);  // P[g][cols nf*8+2t, +1]
      pk[nf][1] = pk2(s[nf][2], s[nf][3]);  // P[g+8][...]
    }
    rs0 += __shfl_xor_sync(0xffffffffu, rs0, 1);
    rs0 += __shfl_xor_sync(0xffffffffu, rs0, 2);
    rs1 += __shfl_xor_sync(0xffffffffu, rs1, 1);
    rs1 += __shfl_xor_sync(0xffffffffu, rs1, 2);
    lrow0 = lrow0 * sc0 + rs0;
    lrow1 = lrow1 * sc1 + rs1;

#pragma unroll
    for (int nf = 0; nf < 8; nf++) {
      o[nf][0] *= sc0; o[nf][1] *= sc0;
      o[nf][2] *= sc1; o[nf][3] *= sc1;
    }

    // ---- O += P V ----  (A from registers; B via ldmatrix.trans on V rows)
#pragma unroll
    for (int c = 0; c < 4; c++) {  // key chunks of 16
      unsigned a[4] = {pk[2 * c][0], pk[2 * c][1], pk[2 * c + 1][0], pk[2 * c + 1][1]};
#pragma unroll
      for (int dg = 0; dg < 4; dg++) {  // 16 d-cols per ldmatrix.x4.trans
        unsigned bv[4];
        unsigned addr = smem_u32(Vs + (c * 16 + vb_key) * FSW + dg * 8 + vb_doff);
        ldm4t(bv, addr);
        mma_bf16(o[2 * dg], a, bv);
        mma_bf16(o[2 * dg + 1], a, bv + 2);
      }
    }
  }

  float inv0 = 1.f / lrow0, inv1 = 1.f / lrow1;
  int row = b * Sn + q0 + wrow + g;
#pragma unroll
  for (int nf = 0; nf < 8; nf++) {
    int col = h * HDn + nf * 8 + 2 * t;
    *(float2*)(O + (size_t)row * Dn + col) =
        make_float2(o[nf][0] * inv0, o[nf][1] * inv0);
    *(float2*)(O + (size_t)(row + 8) * Dn + col) =
        make_float2(o[nf][2] * inv1, o[nf][3] * inv1);
  }
}

// =====================================================================================
// out = LayerNorm(A + B) * g + be
// =====================================================================================
__global__ void __launch_bounds__(256) add_ln(
    const float* __restrict__ A, const float* __restrict__ Bv,
    const float* __restrict__ g, const float* __restrict__ be,
    float* __restrict__ out) {
  int t = blockIdx.x;
  int tid = threadIdx.x;
  float4 a = *(const float4*)(A + (size_t)t * Dn + tid * 4);
  float4 b = *(const float4*)(Bv + (size_t)t * Dn + tid * 4);
  float4 x = make_float4(a.x + b.x, a.y + b.y, a.z + b.z, a.w + b.w);
  float sumv = x.x + x.y + x.z + x.w;
  float sq = x.x * x.x + x.y * x.y + x.z * x.z + x.w * x.w;
#pragma unroll
  for (int off = 16; off; off >>= 1) {
    sumv += __shfl_xor_sync(0xffffffffu, sumv, off);
    sq += __shfl_xor_sync(0xffffffffu, sq, off);
  }
  __shared__ float ws[8], wq[8];
  __shared__ float s_mean, s_rstd;
  int wid = tid >> 5, lane = tid & 31;
  if (lane == 0) {
    ws[wid] = sumv;
    wq[wid] = sq;
  }
  __syncthreads();
  if (tid == 0) {
    float s = 0.f, q = 0.f;
#pragma unroll
    for (int i = 0; i < 8; i++) {
      s += ws[i];
      q += wq[i];
    }
    float mean = s * (1.f / Dn);
    float var = q * (1.f / Dn) - mean * mean;
    s_mean = mean;
    s_rstd = rsqrtf(var + 1e-5f);
  }
  __syncthreads();
  float mean = s_mean, rstd = s_rstd;
  float4 gg = *(const float4*)(g + tid * 4);
  float4 bb = *(const float4*)(be + tid * 4);
  float4 y;
  y.x = (x.x - mean) * rstd * gg.x + bb.x;
  y.y = (x.y - mean) * rstd * gg.y + bb.y;
  y.z = (x.z - mean) * rstd * gg.z + bb.z;
  y.w = (x.w - mean) * rstd * gg.w + bb.w;
  *(float4*)(out + (size_t)t * Dn + tid * 4) = y;
}

// =====================================================================================
// Router
// =====================================================================================
__global__ void __launch_bounds__(128) router_kernel(
    const float* __restrict__ x1, const float* __restrict__ sw,
    const float* __restrict__ sb, float* __restrict__ xs,
    int* __restrict__ route) {
  __shared__ float ssw[En * Dn];
  int t = blockIdx.x;
  int tid = threadIdx.x;
  for (int i = tid; i < En * Dn / 4; i += 128)
    ((float4*)ssw)[i] = ((const float4*)sw)[i];
  __syncthreads();

  float acc[En];
#pragma unroll
  for (int e = 0; e < En; e++) acc[e] = 0.f;
  float xv[8];
#pragma unroll
  for (int l = 0; l < 2; l++) {
    int d = (tid + l * 128) * 4;
    float4 x = *(const float4*)(x1 + (size_t)t * Dn + d);
    xv[l * 4 + 0] = x.x;
    xv[l * 4 + 1] = x.y;
    xv[l * 4 + 2] = x.z;
    xv[l * 4 + 3] = x.w;
#pragma unroll
    for (int e = 0; e < En; e++) {
      const float* swp = ssw + e * Dn + d;
      acc[e] += x.x * swp[0] + x.y * swp[1] + x.z * swp[2] + x.w * swp[3];
    }
  }
#pragma unroll
  for (int e = 0; e < En; e++)
#pragma unroll
    for (int off = 16; off; off >>= 1) acc[e] += __shfl_xor_sync(0xffffffffu, acc[e], off);

  __shared__ float wsum[4][En];
  __shared__ float s_p;
  int wid = tid >> 5, lane = tid & 31;
  if (lane == 0)
#pragma unroll
    for (int e = 0; e < En; e++) wsum[wid][e] = acc[e];
  __syncthreads();
  if (tid == 0) {
    float lg[En];
#pragma unroll
    for (int e = 0; e < En; e++)
      lg[e] = wsum[0][e] + wsum[1][e] + wsum[2][e] + wsum[3][e] + sb[e];
    int am = 0;
    float mx = lg[0];
#pragma unroll
    for (int e = 1; e < En; e++)
      if (lg[e] > mx) {
        mx = lg[e];
        am = e;
      }
    float sum = 0.f;
#pragma unroll
    for (int e = 0; e < En; e++) sum += __expf(lg[e] - mx);
    s_p = 1.f / sum;
    route[t] = am;
  }
  __syncthreads();
  float p = s_p;
#pragma unroll
  for (int l = 0; l < 2; l++) {
    int d = (tid + l * 128) * 4;
    float4 y = make_float4(xv[l * 4] * p, xv[l * 4 + 1] * p, xv[l * 4 + 2] * p,
                           xv[l * 4 + 3] * p);
    *(float4*)(xs + (size_t)t * Dn + d) = y;
  }
}

// =====================================================================================
// Deterministic stable counting sort by expert id (single block).
// =====================================================================================
__global__ void __launch_bounds__(256) sort_routes(
    const int* __restrict__ route, int* __restrict__ dest, int* __restrict__ off) {
  __shared__ int hist[256][En];
  __shared__ int tot[En];
  __shared__ int eoff[En + 1];
  int tid = threadIdx.x;
  int h[En];
#pragma unroll
  for (int e = 0; e < En; e++) h[e] = 0;
  int base = tid * 32;
  for (int i = 0; i < 32; i++) h[route[base + i]]++;
#pragma unroll
  for (int e = 0; e < En; e++) hist[tid][e] = h[e];
  __syncthreads();
  if (tid < En) {
    int e = tid;
    int run = 0;
    for (int i = 0; i < 256; i++) {
      int v = hist[i][e];
      hist[i][e] = run;
      run += v;
    }
    tot[e] = run;
  }
  __syncthreads();
  if (tid == 0) {
    int r = 0;
    for (int e = 0; e < En; e++) {
      eoff[e] = r;
      off[e] = r;
      r += tot[e];
    }
    eoff[En] = r;
    off[En] = r;
  }
  __syncthreads();
  int run[En];
#pragma unroll
  for (int e = 0; e < En; e++) run[e] = eoff[e] + hist[tid][e];
  for (int i = 0; i < 32; i++) {
    int e = route[base + i];
    dest[base + i] = run[e]++;
  }
}

// xsort[dest[t], :] = xs[t, :]
__global__ void __launch_bounds__(256) gather_rows(
    const float* __restrict__ xs, const int* __restrict__ dest,
    float* __restrict__ xsort) {
  int t = blockIdx.x;
  int c = threadIdx.x;
  int dt = dest[t];
  ((float4*)xsort)[(size_t)dt * (Dn / 4) + c] =
      ((const float4*)xs)[(size_t)t * (Dn / 4) + c];
}

// =====================================================================================
extern "C" void kernel_launch(void* const* d_in, const int* in_sizes, int n_in,
                              void* d_out, int out_size) {
  const float* x = (const float*)d_in[0];
  const float* wq = (const float*)d_in[1];
  const float* bq = (const float*)d_in[2];
  const float* wk = (const float*)d_in[3];
  const float* bk = (const float*)d_in[4];
  const float* wv = (const float*)d_in[5];
  const float* bv = (const float*)d_in[6];
  const float* wo = (const float*)d_in[7];
  const float* bo = (const float*)d_in[8];
  const float* ln1g = (const float*)d_in[9];
  const float* ln1b = (const float*)d_in[10];
  const float* ln2g = (const float*)d_in[11];
  const float* ln2b = (const float*)d_in[12];
  const float* sw = (const float*)d_in[13];
  const float* sb = (const float*)d_in[14];
  const float* ew1 = (const float*)d_in[15];
  const float* eb1 = (const float*)d_in[16];
  const float* ew2 = (const float*)d_in[17];
  const float* eb2 = (const float*)d_in[18];
  const int* mask = (const int*)d_in[19];
  float* out = (float*)d_out;

  float *q, *k, *v, *ctx, *ao, *x1, *xs, *xsort, *moe, *h1;
  int *route, *dest, *off;
  cudaGetSymbolAddress((void**)&q, g_q);
  cudaGetSymbolAddress((void**)&k, g_k);
  cudaGetSymbolAddress((void**)&v, g_v);
  cudaGetSymbolAddress((void**)&ctx, g_ctx);
  cudaGetSymbolAddress((void**)&ao, g_ao);
  cudaGetSymbolAddress((void**)&x1, g_x1);
  cudaGetSymbolAddress((void**)&xs, g_xs);
  cudaGetSymbolAddress((void**)&xsort, g_xsort);
  cudaGetSymbolAddress((void**)&moe, g_moe);
  cudaGetSymbolAddress((void**)&h1, g_h1);
  cudaGetSymbolAddress((void**)&route, g_route);
  cudaGetSymbolAddress((void**)&dest, g_dest);
  cudaGetSymbolAddress((void**)&off, g_off);

  const int GEMM_SMEM = (2 * ASTG + 2 * BSTG) * 4;  // 110592 B
  cudaFuncSetAttribute(tgemm_qkv, cudaFuncAttributeMaxDynamicSharedMemorySize, GEMM_SMEM);
  cudaFuncSetAttribute(tgemm2<0, 0>, cudaFuncAttributeMaxDynamicSharedMemorySize, GEMM_SMEM);
  cudaFuncSetAttribute(tgemm2<1, 1>, cudaFuncAttributeMaxDynamicSharedMemorySize, GEMM_SMEM);
  cudaFuncSetAttribute(tgemm2<0, 1>, cudaFuncAttributeMaxDynamicSharedMemorySize, GEMM_SMEM);

  dim3 blk(256);

  // --- attention block ---
  tgemm_qkv<<<dim3(Dn / 128, Tn / 256, 3), blk, GEMM_SMEM>>>(
      x, wq, wk, wv, bq, bk, bv, q, k, v);
  flash_bf<<<dim3(Sn / FQT, Bn * Hn), blk>>>(q, k, v, mask, ctx);
  tgemm2<0, 0><<<dim3(Dn / 128, Tn / 256, 1), blk, GEMM_SMEM>>>(
      ctx, wo, bo, ao, Dn, Dn, Tn, nullptr, 0);
  add_ln<<<Tn, 256>>>(x, ao, ln1g, ln1b, x1);

  // --- MoE block ---
  router_kernel<<<Tn, 128>>>(x1, sw, sb, xs, route);
  sort_routes<<<1, 256>>>(route, dest, off);
  gather_rows<<<Tn, 256>>>(xs, dest, xsort);
  tgemm2<1, 1><<<dim3(Fn / 128, Tn / 256, En), blk, GEMM_SMEM>>>(
      xsort, ew1, eb1, h1, Fn, Dn, 0, off, (size_t)Fn * Dn);
  tgemm2<0, 1><<<dim3(Dn / 128, Tn / 256, En), blk, GEMM_SMEM>>>(
      h1, ew2, eb2, moe, Dn, Fn, 0, off, (size_t)Dn * Fn);
  add_ln<<<Tn, 256>>>(x1, moe, ln2g, ln2b, out);
}

// round 6
// speedup vs baseline: 4.0989x; 1.0322x over previous
#include <cuda_runtime.h>
#include <math.h>

// Problem dims (fixed by the reference)
#define Tn 8192
#define Dn 1024
#define Hn 16
#define HDn 64
#define Fn 4096
#define En 8
#define Bn 4
#define Sn 2048

// ---------------- scratch (static device allocations; no cudaMalloc allowed) ---------
__device__ float g_q[Tn * Dn];
__device__ float g_k[Tn * Dn];
__device__ float g_v[Tn * Dn];
__device__ float g_ctx[Tn * Dn];
__device__ float g_ao[Tn * Dn];
__device__ float g_x1[Tn * Dn];
__device__ float g_xs[Tn * Dn];
__device__ float g_xsort[Tn * Dn];
__device__ float g_moe[Tn * Dn];
__device__ float g_h1[(size_t)Tn * Fn];
__device__ int g_route[Tn];
__device__ int g_dest[Tn];
__device__ int g_off[En + 1];

__device__ __forceinline__ void mma_tf32(float* c, const unsigned* a, const unsigned* b) {
  asm volatile(
      "mma.sync.aligned.m16n8k8.row.col.f32.tf32.tf32.f32 "
      "{%0,%1,%2,%3},{%4,%5,%6,%7},{%8,%9},{%0,%1,%2,%3};"
      : "+f"(c[0]), "+f"(c[1]), "+f"(c[2]), "+f"(c[3])
      : "r"(a[0]), "r"(a[1]), "r"(a[2]), "r"(a[3]), "r"(b[0]), "r"(b[1]));
}

__device__ __forceinline__ void mma_bf16(float* c, const unsigned* a, const unsigned* b) {
  asm volatile(
      "mma.sync.aligned.m16n8k16.row.col.f32.bf16.bf16.f32 "
      "{%0,%1,%2,%3},{%4,%5,%6,%7},{%8,%9},{%0,%1,%2,%3};"
      : "+f"(c[0]), "+f"(c[1]), "+f"(c[2]), "+f"(c[3])
      : "r"(a[0]), "r"(a[1]), "r"(a[2]), "r"(a[3]), "r"(b[0]), "r"(b[1]));
}

// pack two f32 -> bf16x2 (lo = first arg, hi = second)
__device__ __forceinline__ unsigned pk2(float lo, float hi) {
  unsigned r;
  asm("cvt.rn.bf16x2.f32 %0, %1, %2;" : "=r"(r) : "f"(hi), "f"(lo));
  return r;
}

__device__ __forceinline__ unsigned smem_u32(const void* p) {
  return (unsigned)__cvta_generic_to_shared(p);
}

__device__ __forceinline__ void ldm4(unsigned* r, unsigned addr) {
  asm volatile("ldmatrix.sync.aligned.m8n8.x4.shared.b16 {%0,%1,%2,%3}, [%4];"
               : "=r"(r[0]), "=r"(r[1]), "=r"(r[2]), "=r"(r[3]) : "r"(addr));
}
__device__ __forceinline__ void ldm4t(unsigned* r, unsigned addr) {
  asm volatile("ldmatrix.sync.aligned.m8n8.x4.trans.shared.b16 {%0,%1,%2,%3}, [%4];"
               : "=r"(r[0]), "=r"(r[1]), "=r"(r[2]), "=r"(r[3]) : "r"(addr));
}

__device__ __forceinline__ void cp_async16(void* smem, const void* gmem) {
  unsigned sa = (unsigned)__cvta_generic_to_shared(smem);
  asm volatile("cp.async.cg.shared.global [%0], [%1], 16;" ::"r"(sa), "l"(gmem));
}
#define CP_COMMIT asm volatile("cp.async.commit_group;")
#define CP_WAIT(n) asm volatile("cp.async.wait_group %0;" ::"n"(n))

// =====================================================================================
// TF32 tensor-core GEMM body: C[m,n] = A[m,:] . W[n,:] + bias[n]  (NT, row-major)
// 256x128 block, 8 warps (4m x 2n) each 64x64, BK=32, cp.async double-buffered.
// Fragment loads via ldmatrix.x4 on the raw f32 words (b16 lane mapping == tf32
// fragment layout when tile address groups are {rows 0-7, rows 8-15, +16B, +16B}).
// LDA=36: row stride 144B = 16B mod 128 -> ldmatrix tiles conflict-free.
// =====================================================================================
#define BK 32
#define LDA 36
#define ASTG (256 * LDA)
#define BSTG (128 * LDA)

template <int RELU>
__device__ __forceinline__ void gemm_body(
    const float* __restrict__ A, const float* __restrict__ W,
    const float* __restrict__ bp, float* __restrict__ C,
    int N, int K, int m0, int m_end, float* smx) {
  int n0 = blockIdx.x * 128;
  float* As = smx;
  float* Bs = smx + 2 * ASTG;

  int tid = threadIdx.x;
  int lane = tid & 31, wid = tid >> 5;
  int wm = (wid >> 1) * 64;
  int wn = (wid & 1) * 64;
  int g = lane >> 2, t = lane & 3;

  float acc[4][8][4];
#pragma unroll
  for (int i = 0; i < 4; i++)
#pragma unroll
    for (int j = 0; j < 8; j++)
#pragma unroll
      for (int l = 0; l < 4; l++) acc[i][j][l] = 0.f;

  // per-lane ldmatrix base addresses (buffer 0; add aoff/boff for buffer 1)
  unsigned a_base[4], b_base[4];
#pragma unroll
  for (int mf = 0; mf < 4; mf++) {
    int row = wm + mf * 16 + (lane & 15);
    a_base[mf] = smem_u32(As + row * LDA) + ((lane >> 4) & 1) * 16;
  }
#pragma unroll
  for (int p = 0; p < 4; p++) {
    int row = wn + p * 16 + ((lane >> 4) & 1) * 8 + (lane & 7);
    b_base[p] = smem_u32(Bs + row * LDA) + ((lane >> 3) & 1) * 16;
  }

  auto stage = [&](int s, int k0) {
#pragma unroll
    for (int i = 0; i < 8; i++) {
      int idx = tid + i * 256;
      int row = idx >> 3, kq = (idx & 7) << 2;
      int grow = m0 + row;
      if (grow < m_end)
        cp_async16(As + s * ASTG + row * LDA + kq, A + (size_t)grow * K + k0 + kq);
    }
#pragma unroll
    for (int i = 0; i < 4; i++) {
      int idx = tid + i * 256;
      int row = idx >> 3, kq = (idx & 7) << 2;
      cp_async16(Bs + s * BSTG + row * LDA + kq, W + (size_t)(n0 + row) * K + k0 + kq);
    }
  };

  stage(0, 0);
  CP_COMMIT;

  int nslab = K / BK;
  for (int it = 0; it < nslab; it++) {
    int cur = it & 1;
    if (it + 1 < nslab) {
      stage(1 ^ cur, (it + 1) * BK);
      CP_COMMIT;
      CP_WAIT(1);
    } else {
      CP_WAIT(0);
    }
    __syncthreads();

    unsigned aoff = cur * (ASTG * 4);
    unsigned boff = cur * (BSTG * 4);
#pragma unroll
    for (int kk = 0; kk < BK; kk += 8) {
      unsigned af[4][4];
#pragma unroll
      for (int mf = 0; mf < 4; mf++) ldm4(af[mf], a_base[mf] + aoff + kk * 4);
#pragma unroll
      for (int p = 0; p < 4; p++) {
        unsigned bq[4];
        ldm4(bq, b_base[p] + boff + kk * 4);
#pragma unroll
        for (int mf = 0; mf < 4; mf++) {
          mma_tf32(acc[mf][2 * p], af[mf], bq);
          mma_tf32(acc[mf][2 * p + 1], af[mf], bq + 2);
        }
      }
    }
    __syncthreads();
  }

#pragma unroll
  for (int nf = 0; nf < 8; nf++) {
    int col = n0 + wn + nf * 8 + 2 * t;
    float2 bb = *(const float2*)(bp + col);
#pragma unroll
    for (int mf = 0; mf < 4; mf++) {
      int row0 = m0 + wm + mf * 16 + g;
      float v0 = acc[mf][nf][0] + bb.x;
      float v1 = acc[mf][nf][1] + bb.y;
      float v2 = acc[mf][nf][2] + bb.x;
      float v3 = acc[mf][nf][3] + bb.y;
      if (RELU) {
        v0 = fmaxf(v0, 0.f); v1 = fmaxf(v1, 0.f);
        v2 = fmaxf(v2, 0.f); v3 = fmaxf(v3, 0.f);
      }
      if (row0 < m_end)
        *(float2*)(C + (size_t)row0 * N + col) = make_float2(v0, v1);
      if (row0 + 8 < m_end)
        *(float2*)(C + (size_t)(row0 + 8) * N + col) = make_float2(v2, v3);
    }
  }
}

template <int RELU, int USE_OFF>
__global__ void __launch_bounds__(256) tgemm2(
    const float* __restrict__ A, const float* __restrict__ W,
    const float* __restrict__ bias, float* __restrict__ C,
    int N, int K, int Mfull, const int* __restrict__ off, size_t wstride) {
  extern __shared__ float smx[];
  int e = blockIdx.z;
  int m_start, m_end;
  if (USE_OFF) {
    m_start = off[e];
    m_end = off[e + 1];
  } else {
    m_start = 0;
    m_end = Mfull;
  }
  int m0 = m_start + (int)blockIdx.y * 256;
  if (m0 >= m_end) return;
  gemm_body<RELU>(A, W + (size_t)e * wstride, bias + (size_t)e * N, C, N, K, m0, m_end, smx);
}

// Fused QKV projection: blockIdx.z selects (wq,bq,q) / (wk,bk,k) / (wv,bv,v)
__global__ void __launch_bounds__(256) tgemm_qkv(
    const float* __restrict__ A,
    const float* __restrict__ w0, const float* __restrict__ w1, const float* __restrict__ w2,
    const float* __restrict__ b0, const float* __restrict__ b1, const float* __restrict__ b2,
    float* __restrict__ c0, float* __restrict__ c1, float* __restrict__ c2) {
  extern __shared__ float smx[];
  int z = blockIdx.z;
  const float* W = (z == 0) ? w0 : (z == 1) ? w1 : w2;
  const float* bb = (z == 0) ? b0 : (z == 1) ? b1 : b2;
  float* C = (z == 0) ? c0 : (z == 1) ? c1 : c2;
  int m0 = (int)blockIdx.y * 256;
  gemm_body<0>(A, W, bb, C, Dn, Dn, m0, Tn, smx);
}

// =====================================================================================
// bf16 tensor-core flash attention (unchanged from round 5).
// =====================================================================================
#define FQT 128
#define FKT 64
#define FSW 36  // words per row (32 data + 4 pad)

__global__ void __launch_bounds__(256) flash_bf(
    const float* __restrict__ Q, const float* __restrict__ K,
    const float* __restrict__ V, const int* __restrict__ mask,
    float* __restrict__ O) {
  __shared__ unsigned Qs[FQT * FSW];
  __shared__ unsigned Ks[FKT * FSW];
  __shared__ unsigned Vs[FKT * FSW];
  __shared__ int msk[FKT];

  int bh = blockIdx.y;
  int b = bh >> 4, h = bh & 15;
  int q0 = blockIdx.x * FQT;
  int tid = threadIdx.x;
  int lane = tid & 31, wid = tid >> 5;
  int g = lane >> 2, t = lane & 3;
  int wrow = wid * 16;

#pragma unroll
  for (int l = 0; l < 8; l++) {
    int idx = tid + l * 256;
    int r = idx >> 4, kq = (idx & 15) << 2;
    float4 qv = *(const float4*)(Q + (size_t)(b * Sn + q0 + r) * Dn + h * HDn + kq);
    *(uint2*)(Qs + r * FSW + (kq >> 1)) = make_uint2(pk2(qv.x, qv.y), pk2(qv.z, qv.w));
  }

  float o[8][4];
#pragma unroll
  for (int nf = 0; nf < 8; nf++)
#pragma unroll
    for (int c = 0; c < 4; c++) o[nf][c] = 0.f;
  float mrow0 = -1e30f, mrow1 = -1e30f;
  float lrow0 = 0.f, lrow1 = 0.f;

  unsigned qa_base = smem_u32(Qs + (wrow + (lane & 15)) * FSW + (lane >> 4) * 4);
  unsigned kb_row = (lane & 7) + ((lane >> 4) & 1) * 8;
  unsigned kb_koff = ((lane >> 3) & 1) * 4;
  unsigned vb_key = (lane & 7) + ((lane >> 3) & 1) * 8;
  unsigned vb_doff = ((lane >> 4) & 1) * 4;

  for (int t0 = 0; t0 < Sn; t0 += FKT) {
    __syncthreads();
#pragma unroll
    for (int l = 0; l < 4; l++) {
      int idx = tid + l * 256;
      int r = idx >> 4, kq = (idx & 15) << 2;
      size_t base = (size_t)(b * Sn + t0 + r) * Dn + h * HDn + kq;
      float4 kv = *(const float4*)(K + base);
      *(uint2*)(Ks + r * FSW + (kq >> 1)) = make_uint2(pk2(kv.x, kv.y), pk2(kv.z, kv.w));
      float4 vv = *(const float4*)(V + base);
      *(uint2*)(Vs + r * FSW + (kq >> 1)) = make_uint2(pk2(vv.x, vv.y), pk2(vv.z, vv.w));
    }
    if (tid < FKT) msk[tid] = mask[b * Sn + t0 + tid];
    __syncthreads();

    float s[8][4];
#pragma unroll
    for (int nf = 0; nf < 8; nf++)
#pragma unroll
      for (int c = 0; c < 4; c++) s[nf][c] = 0.f;

#pragma unroll
    for (int c = 0; c < 4; c++) {
      unsigned a[4];
      ldm4(a, qa_base + (c * 8) * 4);
#pragma unroll
      for (int ng = 0; ng < 4; ng++) {
        unsigned bq[4];
        unsigned addr = smem_u32(Ks + (ng * 16 + kb_row) * FSW + c * 8 + kb_koff);
        ldm4(bq, addr);
        mma_bf16(s[2 * ng], a, bq);
        mma_bf16(s[2 * ng + 1], a, bq + 2);
      }
    }

#pragma unroll
    for (int nf = 0; nf < 8; nf++) {
      int col = nf * 8 + 2 * t;
      bool z0 = (msk[col] == 0), z1 = (msk[col + 1] == 0);
      s[nf][0] = z0 ? -1e10f : s[nf][0] * 0.125f;
      s[nf][1] = z1 ? -1e10f : s[nf][1] * 0.125f;
      s[nf][2] = z0 ? -1e10f : s[nf][2] * 0.125f;
      s[nf][3] = z1 ? -1e10f : s[nf][3] * 0.125f;
    }

    float mx0 = -1e30f, mx1 = -1e30f;
#pragma unroll
    for (int nf = 0; nf < 8; nf++) {
      mx0 = fmaxf(mx0, fmaxf(s[nf][0], s[nf][1]));
      mx1 = fmaxf(mx1, fmaxf(s[nf][2], s[nf][3]));
    }
    mx0 = fmaxf(mx0, __shfl_xor_sync(0xffffffffu, mx0, 1));
    mx0 = fmaxf(mx0, __shfl_xor_sync(0xffffffffu, mx0, 2));
    mx1 = fmaxf(mx1, __shfl_xor_sync(0xffffffffu, mx1, 1));
    mx1 = fmaxf(mx1, __shfl_xor_sync(0xffffffffu, mx1, 2));

    float mn0 = fmaxf(mrow0, mx0), mn1 = fmaxf(mrow1, mx1);
    float sc0 = __expf(mrow0 - mn0), sc1 = __expf(mrow1 - mn1);
    mrow0 = mn0; mrow1 = mn1;

    float rs0 = 0.f, rs1 = 0.f;
    unsigned pk[8][2];
#pragma unroll
    for (int nf = 0; nf < 8; nf++) {
      s[nf][0] = __expf(s[nf][0] - mn0);
      s[nf][1] = __expf(s[nf][1] - mn0);
      s[nf][2] = __expf(s[nf][2] - mn1);
      s[nf][3] = __expf(s[nf][3] - mn1);
      rs0 += s[nf][0] + s[nf][1];
      rs1 += s[nf][2] + s[nf][3];
      pk[nf][0] = pk2(s[nf][0], s[nf][1]);
      pk[nf][1] = pk2(s[nf][2], s[nf][3]);
    }
    rs0 += __shfl_xor_sync(0xffffffffu, rs0, 1);
    rs0 += __shfl_xor_sync(0xffffffffu, rs0, 2);
    rs1 += __shfl_xor_sync(0xffffffffu, rs1, 1);
    rs1 += __shfl_xor_sync(0xffffffffu, rs1, 2);
    lrow0 = lrow0 * sc0 + rs0;
    lrow1 = lrow1 * sc1 + rs1;

#pragma unroll
    for (int nf = 0; nf < 8; nf++) {
      o[nf][0] *= sc0; o[nf][1] *= sc0;
      o[nf][2] *= sc1; o[nf][3] *= sc1;
    }

#pragma unroll
    for (int c = 0; c < 4; c++) {
      unsigned a[4] = {pk[2 * c][0], pk[2 * c][1], pk[2 * c + 1][0], pk[2 * c + 1][1]};
#pragma unroll
      for (int dg = 0; dg < 4; dg++) {
        unsigned bv[4];
        unsigned addr = smem_u32(Vs + (c * 16 + vb_key) * FSW + dg * 8 + vb_doff);
        ldm4t(bv, addr);
        mma_bf16(o[2 * dg], a, bv);
        mma_bf16(o[2 * dg + 1], a, bv + 2);
      }
    }
  }

  float inv0 = 1.f / lrow0, inv1 = 1.f / lrow1;
  int row = b * Sn + q0 + wrow + g;
#pragma unroll
  for (int nf = 0; nf < 8; nf++) {
    int col = h * HDn + nf * 8 + 2 * t;
    *(float2*)(O + (size_t)row * Dn + col) =
        make_float2(o[nf][0] * inv0, o[nf][1] * inv0);
    *(float2*)(O + (size_t)(row + 8) * Dn + col) =
        make_float2(o[nf][2] * inv1, o[nf][3] * inv1);
  }
}

// =====================================================================================
// out = LayerNorm(A + B) * g + be
// =====================================================================================
__global__ void __launch_bounds__(256) add_ln(
    const float* __restrict__ A, const float* __restrict__ Bv,
    const float* __restrict__ g, const float* __restrict__ be,
    float* __restrict__ out) {
  int t = blockIdx.x;
  int tid = threadIdx.x;
  float4 a = *(const float4*)(A + (size_t)t * Dn + tid * 4);
  float4 b = *(const float4*)(Bv + (size_t)t * Dn + tid * 4);
  float4 x = make_float4(a.x + b.x, a.y + b.y, a.z + b.z, a.w + b.w);
  float sumv = x.x + x.y + x.z + x.w;
  float sq = x.x * x.x + x.y * x.y + x.z * x.z + x.w * x.w;
#pragma unroll
  for (int off = 16; off; off >>= 1) {
    sumv += __shfl_xor_sync(0xffffffffu, sumv, off);
    sq += __shfl_xor_sync(0xffffffffu, sq, off);
  }
  __shared__ float ws[8], wq[8];
  __shared__ float s_mean, s_rstd;
  int wid = tid >> 5, lane = tid & 31;
  if (lane == 0) {
    ws[wid] = sumv;
    wq[wid] = sq;
  }
  __syncthreads();
  if (tid == 0) {
    float s = 0.f, q = 0.f;
#pragma unroll
    for (int i = 0; i < 8; i++) {
      s += ws[i];
      q += wq[i];
    }
    float mean = s * (1.f / Dn);
    float var = q * (1.f / Dn) - mean * mean;
    s_mean = mean;
    s_rstd = rsqrtf(var + 1e-5f);
  }
  __syncthreads();
  float mean = s_mean, rstd = s_rstd;
  float4 gg = *(const float4*)(g + tid * 4);
  float4 bb = *(const float4*)(be + tid * 4);
  float4 y;
  y.x = (x.x - mean) * rstd * gg.x + bb.x;
  y.y = (x.y - mean) * rstd * gg.y + bb.y;
  y.z = (x.z - mean) * rstd * gg.z + bb.z;
  y.w = (x.w - mean) * rstd * gg.w + bb.w;
  *(float4*)(out + (size_t)t * Dn + tid * 4) = y;
}

// =====================================================================================
// Router
// =====================================================================================
__global__ void __launch_bounds__(128) router_kernel(
    const float* __restrict__ x1, const float* __restrict__ sw,
    const float* __restrict__ sb, float* __restrict__ xs,
    int* __restrict__ route) {
  __shared__ float ssw[En * Dn];
  int t = blockIdx.x;
  int tid = threadIdx.x;
  for (int i = tid; i < En * Dn / 4; i += 128)
    ((float4*)ssw)[i] = ((const float4*)sw)[i];
  __syncthreads();

  float acc[En];
#pragma unroll
  for (int e = 0; e < En; e++) acc[e] = 0.f;
  float xv[8];
#pragma unroll
  for (int l = 0; l < 2; l++) {
    int d = (tid + l * 128) * 4;
    float4 x = *(const float4*)(x1 + (size_t)t * Dn + d);
    xv[l * 4 + 0] = x.x;
    xv[l * 4 + 1] = x.y;
    xv[l * 4 + 2] = x.z;
    xv[l * 4 + 3] = x.w;
#pragma unroll
    for (int e = 0; e < En; e++) {
      const float* swp = ssw + e * Dn + d;
      acc[e] += x.x * swp[0] + x.y * swp[1] + x.z * swp[2] + x.w * swp[3];
    }
  }
#pragma unroll
  for (int e = 0; e < En; e++)
#pragma unroll
    for (int off = 16; off; off >>= 1) acc[e] += __shfl_xor_sync(0xffffffffu, acc[e], off);

  __shared__ float wsum[4][En];
  __shared__ float s_p;
  int wid = tid >> 5, lane = tid & 31;
  if (lane == 0)
#pragma unroll
    for (int e = 0; e < En; e++) wsum[wid][e] = acc[e];
  __syncthreads();
  if (tid == 0) {
    float lg[En];
#pragma unroll
    for (int e = 0; e < En; e++)
      lg[e] = wsum[0][e] + wsum[1][e] + wsum[2][e] + wsum[3][e] + sb[e];
    int am = 0;
    float mx = lg[0];
#pragma unroll
    for (int e = 1; e < En; e++)
      if (lg[e] > mx) {
        mx = lg[e];
        am = e;
      }
    float sum = 0.f;
#pragma unroll
    for (int e = 0; e < En; e++) sum += __expf(lg[e] - mx);
    s_p = 1.f / sum;
    route[t] = am;
  }
  __syncthreads();
  float p = s_p;
#pragma unroll
  for (int l = 0; l < 2; l++) {
    int d = (tid + l * 128) * 4;
    float4 y = make_float4(xv[l * 4] * p, xv[l * 4 + 1] * p, xv[l * 4 + 2] * p,
                           xv[l * 4 + 3] * p);
    *(float4*)(xs + (size_t)t * Dn + d) = y;
  }
}

// =====================================================================================
// Deterministic stable counting sort by expert id (single block).
// =====================================================================================
__global__ void __launch_bounds__(256) sort_routes(
    const int* __restrict__ route, int* __restrict__ dest, int* __restrict__ off) {
  __shared__ int hist[256][En];
  __shared__ int tot[En];
  __shared__ int eoff[En + 1];
  int tid = threadIdx.x;
  int h[En];
#pragma unroll
  for (int e = 0; e < En; e++) h[e] = 0;
  int base = tid * 32;
  for (int i = 0; i < 32; i++) h[route[base + i]]++;
#pragma unroll
  for (int e = 0; e < En; e++) hist[tid][e] = h[e];
  __syncthreads();
  if (tid < En) {
    int e = tid;
    int run = 0;
    for (int i = 0; i < 256; i++) {
      int v = hist[i][e];
      hist[i][e] = run;
      run += v;
    }
    tot[e] = run;
  }
  __syncthreads();
  if (tid == 0) {
    int r = 0;
    for (int e = 0; e < En; e++) {
      eoff[e] = r;
      off[e] = r;
      r += tot[e];
    }
    eoff[En] = r;
    off[En] = r;
  }
  __syncthreads();
  int run[En];
#pragma unroll
  for (int e = 0; e < En; e++) run[e] = eoff[e] + hist[tid][e];
  for (int i = 0; i < 32; i++) {
    int e = route[base + i];
    dest[base + i] = run[e]++;
  }
}

// xsort[dest[t], :] = xs[t, :]
__global__ void __launch_bounds__(256) gather_rows(
    const float* __restrict__ xs, const int* __restrict__ dest,
    float* __restrict__ xsort) {
  int t = blockIdx.x;
  int c = threadIdx.x;
  int dt = dest[t];
  ((float4*)xsort)[(size_t)dt * (Dn / 4) + c] =
      ((const float4*)xs)[(size_t)t * (Dn / 4) + c];
}

// =====================================================================================
extern "C" void kernel_launch(void* const* d_in, const int* in_sizes, int n_in,
                              void* d_out, int out_size) {
  const float* x = (const float*)d_in[0];
  const float* wq = (const float*)d_in[1];
  const float* bq = (const float*)d_in[2];
  const float* wk = (const float*)d_in[3];
  const float* bk = (const float*)d_in[4];
  const float* wv = (const float*)d_in[5];
  const float* bv = (const float*)d_in[6];
  const float* wo = (const float*)d_in[7];
  const float* bo = (const float*)d_in[8];
  const float* ln1g = (const float*)d_in[9];
  const float* ln1b = (const float*)d_in[10];
  const float* ln2g = (const float*)d_in[11];
  const float* ln2b = (const float*)d_in[12];
  const float* sw = (const float*)d_in[13];
  const float* sb = (const float*)d_in[14];
  const float* ew1 = (const float*)d_in[15];
  const float* eb1 = (const float*)d_in[16];
  const float* ew2 = (const float*)d_in[17];
  const float* eb2 = (const float*)d_in[18];
  const int* mask = (const int*)d_in[19];
  float* out = (float*)d_out;

  float *q, *k, *v, *ctx, *ao, *x1, *xs, *xsort, *moe, *h1;
  int *route, *dest, *off;
  cudaGetSymbolAddress((void**)&q, g_q);
  cudaGetSymbolAddress((void**)&k, g_k);
  cudaGetSymbolAddress((void**)&v, g_v);
  cudaGetSymbolAddress((void**)&ctx, g_ctx);
  cudaGetSymbolAddress((void**)&ao, g_ao);
  cudaGetSymbolAddress((void**)&x1, g_x1);
  cudaGetSymbolAddress((void**)&xs, g_xs);
  cudaGetSymbolAddress((void**)&xsort, g_xsort);
  cudaGetSymbolAddress((void**)&moe, g_moe);
  cudaGetSymbolAddress((void**)&h1, g_h1);
  cudaGetSymbolAddress((void**)&route, g_route);
  cudaGetSymbolAddress((void**)&dest, g_dest);
  cudaGetSymbolAddress((void**)&off, g_off);

  const int GEMM_SMEM = (2 * ASTG + 2 * BSTG) * 4;  // 110592 B
  cudaFuncSetAttribute(tgemm_qkv, cudaFuncAttributeMaxDynamicSharedMemorySize, GEMM_SMEM);
  cudaFuncSetAttribute(tgemm2<0, 0>, cudaFuncAttributeMaxDynamicSharedMemorySize, GEMM_SMEM);
  cudaFuncSetAttribute(tgemm2<1, 1>, cudaFuncAttributeMaxDynamicSharedMemorySize, GEMM_SMEM);
  cudaFuncSetAttribute(tgemm2<0, 1>, cudaFuncAttributeMaxDynamicSharedMemorySize, GEMM_SMEM);

  dim3 blk(256);

  // --- attention block ---
  tgemm_qkv<<<dim3(Dn / 128, Tn / 256, 3), blk, GEMM_SMEM>>>(
      x, wq, wk, wv, bq, bk, bv, q, k, v);
  flash_bf<<<dim3(Sn / FQT, Bn * Hn), blk>>>(q, k, v, mask, ctx);
  tgemm2<0, 0><<<dim3(Dn / 128, Tn / 256, 1), blk, GEMM_SMEM>>>(
      ctx, wo, bo, ao, Dn, Dn, Tn, nullptr, 0);
  add_ln<<<Tn, 256>>>(x, ao, ln1g, ln1b, x1);

  // --- MoE block ---
  router_kernel<<<Tn, 128>>>(x1, sw, sb, xs, route);
  sort_routes<<<1, 256>>>(route, dest, off);
  gather_rows<<<Tn, 256>>>(xs, dest, xsort);
  tgemm2<1, 1><<<dim3(Fn / 128, Tn / 256, En), blk, GEMM_SMEM>>>(
      xsort, ew1, eb1, h1, Fn, Dn, 0, off, (size_t)Fn * Dn);
  tgemm2<0, 1><<<dim3(Dn / 128, Tn / 256, En), blk, GEMM_SMEM>>>(
      h1, ew2, eb2, moe, Dn, Fn, 0, off, (size_t)Dn * Fn);
  add_ln<<<Tn, 256>>>(x1, moe, ln2g, ln2b, out);
}

// round 7
// speedup vs baseline: 5.1601x; 1.2589x over previous
#include <cuda_runtime.h>
#include <math.h>

// Problem dims (fixed by the reference)
#define Tn 8192
#define Dn 1024
#define Hn 16
#define HDn 64
#define Fn 4096
#define En 8
#define Bn 4
#define Sn 2048

// ---------------- scratch (static device allocations; no cudaMalloc allowed) ---------
__device__ float g_q[Tn * Dn];
__device__ float g_k[Tn * Dn];
__device__ float g_v[Tn * Dn];
__device__ float g_ctx[Tn * Dn];
__device__ float g_ao[Tn * Dn];
__device__ float g_x1[Tn * Dn];
__device__ float g_xs[Tn * Dn];
__device__ float g_moe[Tn * Dn];
__device__ unsigned short g_xsortb[Tn * Dn];                 // bf16
__device__ unsigned short g_h1b[(size_t)Tn * Fn];            // bf16
__device__ unsigned short g_w1b[(size_t)En * Fn * Dn];       // bf16 e_w1
__device__ unsigned short g_w2b[(size_t)En * Dn * Fn];       // bf16 e_w2
__device__ int g_route[Tn];
__device__ int g_dest[Tn];
__device__ int g_off[En + 1];

__device__ __forceinline__ void mma_tf32(float* c, const unsigned* a, const unsigned* b) {
  asm volatile(
      "mma.sync.aligned.m16n8k8.row.col.f32.tf32.tf32.f32 "
      "{%0,%1,%2,%3},{%4,%5,%6,%7},{%8,%9},{%0,%1,%2,%3};"
      : "+f"(c[0]), "+f"(c[1]), "+f"(c[2]), "+f"(c[3])
      : "r"(a[0]), "r"(a[1]), "r"(a[2]), "r"(a[3]), "r"(b[0]), "r"(b[1]));
}

__device__ __forceinline__ void mma_bf16(float* c, const unsigned* a, const unsigned* b) {
  asm volatile(
      "mma.sync.aligned.m16n8k16.row.col.f32.bf16.bf16.f32 "
      "{%0,%1,%2,%3},{%4,%5,%6,%7},{%8,%9},{%0,%1,%2,%3};"
      : "+f"(c[0]), "+f"(c[1]), "+f"(c[2]), "+f"(c[3])
      : "r"(a[0]), "r"(a[1]), "r"(a[2]), "r"(a[3]), "r"(b[0]), "r"(b[1]));
}

// pack two f32 -> bf16x2 (lo = first arg, hi = second)
__device__ __forceinline__ unsigned pk2(float lo, float hi) {
  unsigned r;
  asm("cvt.rn.bf16x2.f32 %0, %1, %2;" : "=r"(r) : "f"(hi), "f"(lo));
  return r;
}

__device__ __forceinline__ unsigned smem_u32(const void* p) {
  return (unsigned)__cvta_generic_to_shared(p);
}

__device__ __forceinline__ void ldm4(unsigned* r, unsigned addr) {
  asm volatile("ldmatrix.sync.aligned.m8n8.x4.shared.b16 {%0,%1,%2,%3}, [%4];"
               : "=r"(r[0]), "=r"(r[1]), "=r"(r[2]), "=r"(r[3]) : "r"(addr));
}
__device__ __forceinline__ void ldm4t(unsigned* r, unsigned addr) {
  asm volatile("ldmatrix.sync.aligned.m8n8.x4.trans.shared.b16 {%0,%1,%2,%3}, [%4];"
               : "=r"(r[0]), "=r"(r[1]), "=r"(r[2]), "=r"(r[3]) : "r"(addr));
}

__device__ __forceinline__ void cp_async16(void* smem, const void* gmem) {
  unsigned sa = (unsigned)__cvta_generic_to_shared(smem);
  asm volatile("cp.async.cg.shared.global [%0], [%1], 16;" ::"r"(sa), "l"(gmem));
}
#define CP_COMMIT asm volatile("cp.async.commit_group;")
#define CP_WAIT(n) asm volatile("cp.async.wait_group %0;" ::"n"(n))

// =====================================================================================
// TF32 tensor-core GEMM body (dense path; protects router precision).
// 256x128 block, 8 warps (4m x 2n) each 64x64, BK=32 f32, cp.async double-buffered,
// ldmatrix.x4 fragment loads. LDA=36 words (144B stride, conflict-free).
// =====================================================================================
#define BK 32
#define LDA 36
#define ASTG (256 * LDA)
#define BSTG (128 * LDA)

__device__ __forceinline__ void gemm_body(
    const float* __restrict__ A, const float* __restrict__ W,
    const float* __restrict__ bp, float* __restrict__ C,
    int N, int K, int m0, int m_end, float* smx) {
  int n0 = blockIdx.x * 128;
  float* As = smx;
  float* Bs = smx + 2 * ASTG;

  int tid = threadIdx.x;
  int lane = tid & 31, wid = tid >> 5;
  int wm = (wid >> 1) * 64;
  int wn = (wid & 1) * 64;
  int g = lane >> 2, t = lane & 3;

  float acc[4][8][4];
#pragma unroll
  for (int i = 0; i < 4; i++)
#pragma unroll
    for (int j = 0; j < 8; j++)
#pragma unroll
      for (int l = 0; l < 4; l++) acc[i][j][l] = 0.f;

  unsigned a_base[4], b_base[4];
#pragma unroll
  for (int mf = 0; mf < 4; mf++) {
    int row = wm + mf * 16 + (lane & 15);
    a_base[mf] = smem_u32(As + row * LDA) + ((lane >> 4) & 1) * 16;
  }
#pragma unroll
  for (int p = 0; p < 4; p++) {
    int row = wn + p * 16 + ((lane >> 4) & 1) * 8 + (lane & 7);
    b_base[p] = smem_u32(Bs + row * LDA) + ((lane >> 3) & 1) * 16;
  }

  auto stage = [&](int s, int k0) {
#pragma unroll
    for (int i = 0; i < 8; i++) {
      int idx = tid + i * 256;
      int row = idx >> 3, kq = (idx & 7) << 2;
      int grow = m0 + row;
      if (grow < m_end)
        cp_async16(As + s * ASTG + row * LDA + kq, A + (size_t)grow * K + k0 + kq);
    }
#pragma unroll
    for (int i = 0; i < 4; i++) {
      int idx = tid + i * 256;
      int row = idx >> 3, kq = (idx & 7) << 2;
      cp_async16(Bs + s * BSTG + row * LDA + kq, W + (size_t)(n0 + row) * K + k0 + kq);
    }
  };

  stage(0, 0);
  CP_COMMIT;

  int nslab = K / BK;
  for (int it = 0; it < nslab; it++) {
    int cur = it & 1;
    if (it + 1 < nslab) {
      stage(1 ^ cur, (it + 1) * BK);
      CP_COMMIT;
      CP_WAIT(1);
    } else {
      CP_WAIT(0);
    }
    __syncthreads();

    unsigned aoff = cur * (ASTG * 4);
    unsigned boff = cur * (BSTG * 4);
#pragma unroll
    for (int kk = 0; kk < BK; kk += 8) {
      unsigned af[4][4];
#pragma unroll
      for (int mf = 0; mf < 4; mf++) ldm4(af[mf], a_base[mf] + aoff + kk * 4);
#pragma unroll
      for (int p = 0; p < 4; p++) {
        unsigned bq[4];
        ldm4(bq, b_base[p] + boff + kk * 4);
#pragma unroll
        for (int mf = 0; mf < 4; mf++) {
          mma_tf32(acc[mf][2 * p], af[mf], bq);
          mma_tf32(acc[mf][2 * p + 1], af[mf], bq + 2);
        }
      }
    }
    __syncthreads();
  }

#pragma unroll
  for (int nf = 0; nf < 8; nf++) {
    int col = n0 + wn + nf * 8 + 2 * t;
    float2 bb = *(const float2*)(bp + col);
#pragma unroll
    for (int mf = 0; mf < 4; mf++) {
      int row0 = m0 + wm + mf * 16 + g;
      float v0 = acc[mf][nf][0] + bb.x;
      float v1 = acc[mf][nf][1] + bb.y;
      float v2 = acc[mf][nf][2] + bb.x;
      float v3 = acc[mf][nf][3] + bb.y;
      if (row0 < m_end)
        *(float2*)(C + (size_t)row0 * N + col) = make_float2(v0, v1);
      if (row0 + 8 < m_end)
        *(float2*)(C + (size_t)(row0 + 8) * N + col) = make_float2(v2, v3);
    }
  }
}

__global__ void __launch_bounds__(256) tgemm2(
    const float* __restrict__ A, const float* __restrict__ W,
    const float* __restrict__ bias, float* __restrict__ C, int N, int K) {
  extern __shared__ float smx[];
  int m0 = (int)blockIdx.y * 256;
  gemm_body(A, W, bias, C, N, K, m0, Tn, smx);
}

// Fused QKV projection: blockIdx.z selects (wq,bq,q) / (wk,bk,k) / (wv,bv,v)
__global__ void __launch_bounds__(256) tgemm_qkv(
    const float* __restrict__ A,
    const float* __restrict__ w0, const float* __restrict__ w1, const float* __restrict__ w2,
    const float* __restrict__ b0, const float* __restrict__ b1, const float* __restrict__ b2,
    float* __restrict__ c0, float* __restrict__ c1, float* __restrict__ c2) {
  extern __shared__ float smx[];
  int z = blockIdx.z;
  const float* W = (z == 0) ? w0 : (z == 1) ? w1 : w2;
  const float* bb = (z == 0) ? b0 : (z == 1) ? b1 : b2;
  float* C = (z == 0) ? c0 : (z == 1) ? c1 : c2;
  int m0 = (int)blockIdx.y * 256;
  gemm_body(A, W, bb, C, Dn, Dn, m0, Tn, smx);
}

// =====================================================================================
// bf16 tensor-core GEMM (MoE expert path; routing already fixed -> no flip risk).
// 256x128 block, 8 warps 64x64, BK=64 bf16 elements (128B/row), rows at 72-half
// stride (144B, conflict-free ldmatrix — proven in flash). m16n8k16.
// OUTBF=1: write bf16 (+ReLU); OUTBF=0: write fp32. Expert-batched via off[].
// =====================================================================================
#define BKH 64
#define LDHW 36  // words per row (= 72 halves = 64 data + 8 pad)
#define ASTGH (256 * LDHW)
#define BSTGH (128 * LDHW)

template <int RELU, int OUTBF>
__global__ void __launch_bounds__(256) bgemm(
    const unsigned short* __restrict__ A, const unsigned short* __restrict__ W,
    const float* __restrict__ bias, void* __restrict__ Cv,
    int N, int K, const int* __restrict__ off, size_t wstride) {
  extern __shared__ unsigned smh[];
  int e = blockIdx.z;
  int m_start = off[e], m_end = off[e + 1];
  int m0 = m_start + (int)blockIdx.y * 256;
  if (m0 >= m_end) return;

  const unsigned short* Wp = W + (size_t)e * wstride;
  const float* bp = bias + (size_t)e * N;
  int n0 = blockIdx.x * 128;

  unsigned* As = smh;
  unsigned* Bs = smh + 2 * ASTGH;

  int tid = threadIdx.x;
  int lane = tid & 31, wid = tid >> 5;
  int wm = (wid >> 1) * 64;
  int wn = (wid & 1) * 64;
  int g = lane >> 2, t = lane & 3;

  float acc[4][8][4];
#pragma unroll
  for (int i = 0; i < 4; i++)
#pragma unroll
    for (int j = 0; j < 8; j++)
#pragma unroll
      for (int l = 0; l < 4; l++) acc[i][j][l] = 0.f;

  // fragment addressing (flash-proven patterns)
  unsigned a_base[4], b_base[4];
#pragma unroll
  for (int mf = 0; mf < 4; mf++) {
    int row = wm + mf * 16 + (lane & 15);
    a_base[mf] = smem_u32(As + row * LDHW) + ((lane >> 4) & 1) * 16;
  }
#pragma unroll
  for (int p = 0; p < 4; p++) {
    int row = wn + p * 16 + ((lane >> 4) & 1) * 8 + (lane & 7);
    b_base[p] = smem_u32(Bs + row * LDHW) + ((lane >> 3) & 1) * 16;
  }

  // staging: A 256 rows x 128B (8x16B per thread), B 128 rows x 128B (4x16B)
  auto stage = [&](int s, int k0) {
#pragma unroll
    for (int i = 0; i < 8; i++) {
      int idx = tid + i * 256;
      int row = idx >> 3, kq = (idx & 7);  // 16B chunk index
      int grow = m0 + row;
      if (grow < m_end)
        cp_async16(As + s * ASTGH + row * LDHW + kq * 4,
                   A + (size_t)grow * K + k0 + kq * 8);
    }
#pragma unroll
    for (int i = 0; i < 4; i++) {
      int idx = tid + i * 256;
      int row = idx >> 3, kq = (idx & 7);
      cp_async16(Bs + s * BSTGH + row * LDHW + kq * 4,
                 Wp + (size_t)(n0 + row) * K + k0 + kq * 8);
    }
  };

  stage(0, 0);
  CP_COMMIT;

  int nslab = K / BKH;
  for (int it = 0; it < nslab; it++) {
    int cur = it & 1;
    if (it + 1 < nslab) {
      stage(1 ^ cur, (it + 1) * BKH);
      CP_COMMIT;
      CP_WAIT(1);
    } else {
      CP_WAIT(0);
    }
    __syncthreads();

    unsigned aoff = cur * (ASTGH * 4);
    unsigned boff = cur * (BSTGH * 4);
#pragma unroll
    for (int c = 0; c < 4; c++) {  // k16 chunks
      unsigned af[4][4];
#pragma unroll
      for (int mf = 0; mf < 4; mf++) ldm4(af[mf], a_base[mf] + aoff + c * 32);
#pragma unroll
      for (int p = 0; p < 4; p++) {
        unsigned bq[4];
        ldm4(bq, b_base[p] + boff + c * 32);
#pragma unroll
        for (int mf = 0; mf < 4; mf++) {
          mma_bf16(acc[mf][2 * p], af[mf], bq);
          mma_bf16(acc[mf][2 * p + 1], af[mf], bq + 2);
        }
      }
    }
    __syncthreads();
  }

#pragma unroll
  for (int nf = 0; nf < 8; nf++) {
    int col = n0 + wn + nf * 8 + 2 * t;
    float2 bb = *(const float2*)(bp + col);
#pragma unroll
    for (int mf = 0; mf < 4; mf++) {
      int row0 = m0 + wm + mf * 16 + g;
      float v0 = acc[mf][nf][0] + bb.x;
      float v1 = acc[mf][nf][1] + bb.y;
      float v2 = acc[mf][nf][2] + bb.x;
      float v3 = acc[mf][nf][3] + bb.y;
      if (RELU) {
        v0 = fmaxf(v0, 0.f); v1 = fmaxf(v1, 0.f);
        v2 = fmaxf(v2, 0.f); v3 = fmaxf(v3, 0.f);
      }
      if (OUTBF) {
        unsigned short* C = (unsigned short*)Cv;
        if (row0 < m_end) *(unsigned*)(C + (size_t)row0 * N + col) = pk2(v0, v1);
        if (row0 + 8 < m_end) *(unsigned*)(C + (size_t)(row0 + 8) * N + col) = pk2(v2, v3);
      } else {
        float* C = (float*)Cv;
        if (row0 < m_end)
          *(float2*)(C + (size_t)row0 * N + col) = make_float2(v0, v1);
        if (row0 + 8 < m_end)
          *(float2*)(C + (size_t)(row0 + 8) * N + col) = make_float2(v2, v3);
      }
    }
  }
}

// fp32 -> bf16 bulk conversion (per-launch; graph-safe, deterministic)
__global__ void __launch_bounds__(256) cvt_bf16(
    const float* __restrict__ src, unsigned short* __restrict__ dst, int n4) {
  int i = blockIdx.x * 256 + threadIdx.x;
  if (i < n4) {
    float4 v = ((const float4*)src)[i];
    ((uint2*)dst)[i] = make_uint2(pk2(v.x, v.y), pk2(v.z, v.w));
  }
}

// =====================================================================================
// bf16 tensor-core flash attention (unchanged from round 5).
// =====================================================================================
#define FQT 128
#define FKT 64
#define FSW 36  // words per row (32 data + 4 pad)

__global__ void __launch_bounds__(256) flash_bf(
    const float* __restrict__ Q, const float* __restrict__ K,
    const float* __restrict__ V, const int* __restrict__ mask,
    float* __restrict__ O) {
  __shared__ unsigned Qs[FQT * FSW];
  __shared__ unsigned Ks[FKT * FSW];
  __shared__ unsigned Vs[FKT * FSW];
  __shared__ int msk[FKT];

  int bh = blockIdx.y;
  int b = bh >> 4, h = bh & 15;
  int q0 = blockIdx.x * FQT;
  int tid = threadIdx.x;
  int lane = tid & 31, wid = tid >> 5;
  int g = lane >> 2, t = lane & 3;
  int wrow = wid * 16;

#pragma unroll
  for (int l = 0; l < 8; l++) {
    int idx = tid + l * 256;
    int r = idx >> 4, kq = (idx & 15) << 2;
    float4 qv = *(const float4*)(Q + (size_t)(b * Sn + q0 + r) * Dn + h * HDn + kq);
    *(uint2*)(Qs + r * FSW + (kq >> 1)) = make_uint2(pk2(qv.x, qv.y), pk2(qv.z, qv.w));
  }

  float o[8][4];
#pragma unroll
  for (int nf = 0; nf < 8; nf++)
#pragma unroll
    for (int c = 0; c < 4; c++) o[nf][c] = 0.f;
  float mrow0 = -1e30f, mrow1 = -1e30f;
  float lrow0 = 0.f, lrow1 = 0.f;

  unsigned qa_base = smem_u32(Qs + (wrow + (lane & 15)) * FSW + (lane >> 4) * 4);
  unsigned kb_row = (lane & 7) + ((lane >> 4) & 1) * 8;
  unsigned kb_koff = ((lane >> 3) & 1) * 4;
  unsigned vb_key = (lane & 7) + ((lane >> 3) & 1) * 8;
  unsigned vb_doff = ((lane >> 4) & 1) * 4;

  for (int t0 = 0; t0 < Sn; t0 += FKT) {
    __syncthreads();
#pragma unroll
    for (int l = 0; l < 4; l++) {
      int idx = tid + l * 256;
      int r = idx >> 4, kq = (idx & 15) << 2;
      size_t base = (size_t)(b * Sn + t0 + r) * Dn + h * HDn + kq;
      float4 kv = *(const float4*)(K + base);
      *(uint2*)(Ks + r * FSW + (kq >> 1)) = make_uint2(pk2(kv.x, kv.y), pk2(kv.z, kv.w));
      float4 vv = *(const float4*)(V + base);
      *(uint2*)(Vs + r * FSW + (kq >> 1)) = make_uint2(pk2(vv.x, vv.y), pk2(vv.z, vv.w));
    }
    if (tid < FKT) msk[tid] = mask[b * Sn + t0 + tid];
    __syncthreads();

    float s[8][4];
#pragma unroll
    for (int nf = 0; nf < 8; nf++)
#pragma unroll
      for (int c = 0; c < 4; c++) s[nf][c] = 0.f;

#pragma unroll
    for (int c = 0; c < 4; c++) {
      unsigned a[4];
      ldm4(a, qa_base + (c * 8) * 4);
#pragma unroll
      for (int ng = 0; ng < 4; ng++) {
        unsigned bq[4];
        unsigned addr = smem_u32(Ks + (ng * 16 + kb_row) * FSW + c * 8 + kb_koff);
        ldm4(bq, addr);
        mma_bf16(s[2 * ng], a, bq);
        mma_bf16(s[2 * ng + 1], a, bq + 2);
      }
    }

#pragma unroll
    for (int nf = 0; nf < 8; nf++) {
      int col = nf * 8 + 2 * t;
      bool z0 = (msk[col] == 0), z1 = (msk[col + 1] == 0);
      s[nf][0] = z0 ? -1e10f : s[nf][0] * 0.125f;
      s[nf][1] = z1 ? -1e10f : s[nf][1] * 0.125f;
      s[nf][2] = z0 ? -1e10f : s[nf][2] * 0.125f;
      s[nf][3] = z1 ? -1e10f : s[nf][3] * 0.125f;
    }

    float mx0 = -1e30f, mx1 = -1e30f;
#pragma unroll
    for (int nf = 0; nf < 8; nf++) {
      mx0 = fmaxf(mx0, fmaxf(s[nf][0], s[nf][1]));
      mx1 = fmaxf(mx1, fmaxf(s[nf][2], s[nf][3]));
    }
    mx0 = fmaxf(mx0, __shfl_xor_sync(0xffffffffu, mx0, 1));
    mx0 = fmaxf(mx0, __shfl_xor_sync(0xffffffffu, mx0, 2));
    mx1 = fmaxf(mx1, __shfl_xor_sync(0xffffffffu, mx1, 1));
    mx1 = fmaxf(mx1, __shfl_xor_sync(0xffffffffu, mx1, 2));

    float mn0 = fmaxf(mrow0, mx0), mn1 = fmaxf(mrow1, mx1);
    float sc0 = __expf(mrow0 - mn0), sc1 = __expf(mrow1 - mn1);
    mrow0 = mn0; mrow1 = mn1;

    float rs0 = 0.f, rs1 = 0.f;
    unsigned pk[8][2];
#pragma unroll
    for (int nf = 0; nf < 8; nf++) {
      s[nf][0] = __expf(s[nf][0] - mn0);
      s[nf][1] = __expf(s[nf][1] - mn0);
      s[nf][2] = __expf(s[nf][2] - mn1);
      s[nf][3] = __expf(s[nf][3] - mn1);
      rs0 += s[nf][0] + s[nf][1];
      rs1 += s[nf][2] + s[nf][3];
      pk[nf][0] = pk2(s[nf][0], s[nf][1]);
      pk[nf][1] = pk2(s[nf][2], s[nf][3]);
    }
    rs0 += __shfl_xor_sync(0xffffffffu, rs0, 1);
    rs0 += __shfl_xor_sync(0xffffffffu, rs0, 2);
    rs1 += __shfl_xor_sync(0xffffffffu, rs1, 1);
    rs1 += __shfl_xor_sync(0xffffffffu, rs1, 2);
    lrow0 = lrow0 * sc0 + rs0;
    lrow1 = lrow1 * sc1 + rs1;

#pragma unroll
    for (int nf = 0; nf < 8; nf++) {
      o[nf][0] *= sc0; o[nf][1] *= sc0;
      o[nf][2] *= sc1; o[nf][3] *= sc1;
    }

#pragma unroll
    for (int c = 0; c < 4; c++) {
      unsigned a[4] = {pk[2 * c][0], pk[2 * c][1], pk[2 * c + 1][0], pk[2 * c + 1][1]};
#pragma unroll
      for (int dg = 0; dg < 4; dg++) {
        unsigned bv[4];
        unsigned addr = smem_u32(Vs + (c * 16 + vb_key) * FSW + dg * 8 + vb_doff);
        ldm4t(bv, addr);
        mma_bf16(o[2 * dg], a, bv);
        mma_bf16(o[2 * dg + 1], a, bv + 2);
      }
    }
  }

  float inv0 = 1.f / lrow0, inv1 = 1.f / lrow1;
  int row = b * Sn + q0 + wrow + g;
#pragma unroll
  for (int nf = 0; nf < 8; nf++) {
    int col = h * HDn + nf * 8 + 2 * t;
    *(float2*)(O + (size_t)row * Dn + col) =
        make_float2(o[nf][0] * inv0, o[nf][1] * inv0);
    *(float2*)(O + (size_t)(row + 8) * Dn + col) =
        make_float2(o[nf][2] * inv1, o[nf][3] * inv1);
  }
}

// =====================================================================================
// out = LayerNorm(A + B) * g + be
// =====================================================================================
__global__ void __launch_bounds__(256) add_ln(
    const float* __restrict__ A, const float* __restrict__ Bv,
    const float* __restrict__ g, const float* __restrict__ be,
    float* __restrict__ out) {
  int t = blockIdx.x;
  int tid = threadIdx.x;
  float4 a = *(const float4*)(A + (size_t)t * Dn + tid * 4);
  float4 b = *(const float4*)(Bv + (size_t)t * Dn + tid * 4);
  float4 x = make_float4(a.x + b.x, a.y + b.y, a.z + b.z, a.w + b.w);
  float sumv = x.x + x.y + x.z + x.w;
  float sq = x.x * x.x + x.y * x.y + x.z * x.z + x.w * x.w;
#pragma unroll
  for (int off = 16; off; off >>= 1) {
    sumv += __shfl_xor_sync(0xffffffffu, sumv, off);
    sq += __shfl_xor_sync(0xffffffffu, sq, off);
  }
  __shared__ float ws[8], wq[8];
  __shared__ float s_mean, s_rstd;
  int wid = tid >> 5, lane = tid & 31;
  if (lane == 0) {
    ws[wid] = sumv;
    wq[wid] = sq;
  }
  __syncthreads();
  if (tid == 0) {
    float s = 0.f, q = 0.f;
#pragma unroll
    for (int i = 0; i < 8; i++) {
      s += ws[i];
      q += wq[i];
    }
    float mean = s * (1.f / Dn);
    float var = q * (1.f / Dn) - mean * mean;
    s_mean = mean;
    s_rstd = rsqrtf(var + 1e-5f);
  }
  __syncthreads();
  float mean = s_mean, rstd = s_rstd;
  float4 gg = *(const float4*)(g + tid * 4);
  float4 bb = *(const float4*)(be + tid * 4);
  float4 y;
  y.x = (x.x - mean) * rstd * gg.x + bb.x;
  y.y = (x.y - mean) * rstd * gg.y + bb.y;
  y.z = (x.z - mean) * rstd * gg.z + bb.z;
  y.w = (x.w - mean) * rstd * gg.w + bb.w;
  *(float4*)(out + (size_t)t * Dn + tid * 4) = y;
}

// =====================================================================================
// Router
// =====================================================================================
__global__ void __launch_bounds__(128) router_kernel(
    const float* __restrict__ x1, const float* __restrict__ sw,
    const float* __restrict__ sb, float* __restrict__ xs,
    int* __restrict__ route) {
  __shared__ float ssw[En * Dn];
  int t = blockIdx.x;
  int tid = threadIdx.x;
  for (int i = tid; i < En * Dn / 4; i += 128)
    ((float4*)ssw)[i] = ((const float4*)sw)[i];
  __syncthreads();

  float acc[En];
#pragma unroll
  for (int e = 0; e < En; e++) acc[e] = 0.f;
  float xv[8];
#pragma unroll
  for (int l = 0; l < 2; l++) {
    int d = (tid + l * 128) * 4;
    float4 x = *(const float4*)(x1 + (size_t)t * Dn + d);
    xv[l * 4 + 0] = x.x;
    xv[l * 4 + 1] = x.y;
    xv[l * 4 + 2] = x.z;
    xv[l * 4 + 3] = x.w;
#pragma unroll
    for (int e = 0; e < En; e++) {
      const float* swp = ssw + e * Dn + d;
      acc[e] += x.x * swp[0] + x.y * swp[1] + x.z * swp[2] + x.w * swp[3];
    }
  }
#pragma unroll
  for (int e = 0; e < En; e++)
#pragma unroll
    for (int off = 16; off; off >>= 1) acc[e] += __shfl_xor_sync(0xffffffffu, acc[e], off);

  __shared__ float wsum[4][En];
  __shared__ float s_p;
  int wid = tid >> 5, lane = tid & 31;
  if (lane == 0)
#pragma unroll
    for (int e = 0; e < En; e++) wsum[wid][e] = acc[e];
  __syncthreads();
  if (tid == 0) {
    float lg[En];
#pragma unroll
    for (int e = 0; e < En; e++)
      lg[e] = wsum[0][e] + wsum[1][e] + wsum[2][e] + wsum[3][e] + sb[e];
    int am = 0;
    float mx = lg[0];
#pragma unroll
    for (int e = 1; e < En; e++)
      if (lg[e] > mx) {
        mx = lg[e];
        am = e;
      }
    float sum = 0.f;
#pragma unroll
    for (int e = 0; e < En; e++) sum += __expf(lg[e] - mx);
    s_p = 1.f / sum;
    route[t] = am;
  }
  __syncthreads();
  float p = s_p;
#pragma unroll
  for (int l = 0; l < 2; l++) {
    int d = (tid + l * 128) * 4;
    float4 y = make_float4(xv[l * 4] * p, xv[l * 4 + 1] * p, xv[l * 4 + 2] * p,
                           xv[l * 4 + 3] * p);
    *(float4*)(xs + (size_t)t * Dn + d) = y;
  }
}

// =====================================================================================
// Deterministic stable counting sort by expert id (single block).
// =====================================================================================
__global__ void __launch_bounds__(256) sort_routes(
    const int* __restrict__ route, int* __restrict__ dest, int* __restrict__ off) {
  __shared__ int hist[256][En];
  __shared__ int tot[En];
  __shared__ int eoff[En + 1];
  int tid = threadIdx.x;
  int h[En];
#pragma unroll
  for (int e = 0; e < En; e++) h[e] = 0;
  int base = tid * 32;
  for (int i = 0; i < 32; i++) h[route[base + i]]++;
#pragma unroll
  for (int e = 0; e < En; e++) hist[tid][e] = h[e];
  __syncthreads();
  if (tid < En) {
    int e = tid;
    int run = 0;
    for (int i = 0; i < 256; i++) {
      int v = hist[i][e];
      hist[i][e] = run;
      run += v;
    }
    tot[e] = run;
  }
  __syncthreads();
  if (tid == 0) {
    int r = 0;
    for (int e = 0; e < En; e++) {
      eoff[e] = r;
      off[e] = r;
      r += tot[e];
    }
    eoff[En] = r;
    off[En] = r;
  }
  __syncthreads();
  int run[En];
#pragma unroll
  for (int e = 0; e < En; e++) run[e] = eoff[e] + hist[tid][e];
  for (int i = 0; i < 32; i++) {
    int e = route[base + i];
    dest[base + i] = run[e]++;
  }
}

// xsortb[dest[t], :] = bf16(xs[t, :])
__global__ void __launch_bounds__(256) gather_rows_bf(
    const float* __restrict__ xs, const int* __restrict__ dest,
    unsigned short* __restrict__ xsortb) {
  int t = blockIdx.x;
  int c = threadIdx.x;
  int dt = dest[t];
  float4 v = ((const float4*)xs)[(size_t)t * (Dn / 4) + c];
  ((uint2*)xsortb)[(size_t)dt * (Dn / 4) + c] =
      make_uint2(pk2(v.x, v.y), pk2(v.z, v.w));
}

// =====================================================================================
extern "C" void kernel_launch(void* const* d_in, const int* in_sizes, int n_in,
                              void* d_out, int out_size) {
  const float* x = (const float*)d_in[0];
  const float* wq = (const float*)d_in[1];
  const float* bq = (const float*)d_in[2];
  const float* wk = (const float*)d_in[3];
  const float* bk = (const float*)d_in[4];
  const float* wv = (const float*)d_in[5];
  const float* bv = (const float*)d_in[6];
  const float* wo = (const float*)d_in[7];
  const float* bo = (const float*)d_in[8];
  const float* ln1g = (const float*)d_in[9];
  const float* ln1b = (const float*)d_in[10];
  const float* ln2g = (const float*)d_in[11];
  const float* ln2b = (const float*)d_in[12];
  const float* sw = (const float*)d_in[13];
  const float* sb = (const float*)d_in[14];
  const float* ew1 = (const float*)d_in[15];
  const float* eb1 = (const float*)d_in[16];
  const float* ew2 = (const float*)d_in[17];
  const float* eb2 = (const float*)d_in[18];
  const int* mask = (const int*)d_in[19];
  float* out = (float*)d_out;

  float *q, *k, *v, *ctx, *ao, *x1, *xs, *moe;
  unsigned short *xsortb, *h1b, *w1b, *w2b;
  int *route, *dest, *off;
  cudaGetSymbolAddress((void**)&q, g_q);
  cudaGetSymbolAddress((void**)&k, g_k);
  cudaGetSymbolAddress((void**)&v, g_v);
  cudaGetSymbolAddress((void**)&ctx, g_ctx);
  cudaGetSymbolAddress((void**)&ao, g_ao);
  cudaGetSymbolAddress((void**)&x1, g_x1);
  cudaGetSymbolAddress((void**)&xs, g_xs);
  cudaGetSymbolAddress((void**)&moe, g_moe);
  cudaGetSymbolAddress((void**)&xsortb, g_xsortb);
  cudaGetSymbolAddress((void**)&h1b, g_h1b);
  cudaGetSymbolAddress((void**)&w1b, g_w1b);
  cudaGetSymbolAddress((void**)&w2b, g_w2b);
  cudaGetSymbolAddress((void**)&route, g_route);
  cudaGetSymbolAddress((void**)&dest, g_dest);
  cudaGetSymbolAddress((void**)&off, g_off);

  const int GEMM_SMEM = (2 * ASTG + 2 * BSTG) * 4;     // 110592 B
  const int BGEMM_SMEM = (2 * ASTGH + 2 * BSTGH) * 4;  // 110592 B
  cudaFuncSetAttribute(tgemm_qkv, cudaFuncAttributeMaxDynamicSharedMemorySize, GEMM_SMEM);
  cudaFuncSetAttribute(tgemm2, cudaFuncAttributeMaxDynamicSharedMemorySize, GEMM_SMEM);
  cudaFuncSetAttribute(bgemm<1, 1>, cudaFuncAttributeMaxDynamicSharedMemorySize, BGEMM_SMEM);
  cudaFuncSetAttribute(bgemm<0, 0>, cudaFuncAttributeMaxDynamicSharedMemorySize, BGEMM_SMEM);

  dim3 blk(256);

  // --- expert weight conversion (overlaps attention work in-order; bandwidth-bound) ---
  const int W1N4 = En * Fn * Dn / 4;  // 8.39M float4s
  cvt_bf16<<<(W1N4 + 255) / 256, blk>>>(ew1, w1b, W1N4);
  cvt_bf16<<<(W1N4 + 255) / 256, blk>>>(ew2, w2b, W1N4);

  // --- attention block ---
  tgemm_qkv<<<dim3(Dn / 128, Tn / 256, 3), blk, GEMM_SMEM>>>(
      x, wq, wk, wv, bq, bk, bv, q, k, v);
  flash_bf<<<dim3(Sn / FQT, Bn * Hn), blk>>>(q, k, v, mask, ctx);
  tgemm2<<<dim3(Dn / 128, Tn / 256, 1), blk, GEMM_SMEM>>>(ctx, wo, bo, ao, Dn, Dn);
  add_ln<<<Tn, 256>>>(x, ao, ln1g, ln1b, x1);

  // --- MoE block ---
  router_kernel<<<Tn, 128>>>(x1, sw, sb, xs, route);
  sort_routes<<<1, 256>>>(route, dest, off);
  gather_rows_bf<<<Tn, 256>>>(xs, dest, xsortb);
  bgemm<1, 1><<<dim3(Fn / 128, Tn / 256, En), blk, BGEMM_SMEM>>>(
      xsortb, w1b, eb1, h1b, Fn, Dn, off, (size_t)Fn * Dn);
  bgemm<0, 0><<<dim3(Dn / 128, Tn / 256, En), blk, BGEMM_SMEM>>>(
      h1b, w2b, eb2, moe, Dn, Fn, off, (size_t)Dn * Fn);
  add_ln<<<Tn, 256>>>(x1, moe, ln2g, ln2b, out);
}

// round 8
// speedup vs baseline: 6.1419x; 1.1903x over previous
#include <cuda_runtime.h>
#include <math.h>

// Problem dims (fixed by the reference)
#define Tn 8192
#define Dn 1024
#define Hn 16
#define HDn 64
#define Fn 4096
#define En 8
#define Bn 4
#define Sn 2048

typedef unsigned short ushort_t;

// ---------------- scratch (static device allocations; no cudaMalloc allowed) ---------
__device__ ushort_t g_xb[Tn * Dn];        // bf16 x
__device__ ushort_t g_qb[Tn * Dn];        // bf16 q
__device__ ushort_t g_kb[Tn * Dn];        // bf16 k
__device__ ushort_t g_vb[Tn * Dn];        // bf16 v
__device__ ushort_t g_ctxb[Tn * Dn];      // bf16 ctx
__device__ ushort_t g_wqb[Dn * Dn];
__device__ ushort_t g_wkb[Dn * Dn];
__device__ ushort_t g_wvb[Dn * Dn];
__device__ ushort_t g_wob[Dn * Dn];
__device__ float g_ao[Tn * Dn];
__device__ float g_x1[Tn * Dn];
__device__ float g_xs[Tn * Dn];
__device__ float g_moe[Tn * Dn];
__device__ ushort_t g_xsortb[Tn * Dn];
__device__ ushort_t g_h1b[(size_t)Tn * Fn];
__device__ ushort_t g_w1b[(size_t)En * Fn * Dn];
__device__ ushort_t g_w2b[(size_t)En * Dn * Fn];
__device__ int g_route[Tn];
__device__ int g_dest[Tn];
__device__ int g_off[En + 1];

__device__ __forceinline__ void mma_bf16(float* c, const unsigned* a, const unsigned* b) {
  asm volatile(
      "mma.sync.aligned.m16n8k16.row.col.f32.bf16.bf16.f32 "
      "{%0,%1,%2,%3},{%4,%5,%6,%7},{%8,%9},{%0,%1,%2,%3};"
      : "+f"(c[0]), "+f"(c[1]), "+f"(c[2]), "+f"(c[3])
      : "r"(a[0]), "r"(a[1]), "r"(a[2]), "r"(a[3]), "r"(b[0]), "r"(b[1]));
}

// pack two f32 -> bf16x2 (lo = first arg, hi = second)
__device__ __forceinline__ unsigned pk2(float lo, float hi) {
  unsigned r;
  asm("cvt.rn.bf16x2.f32 %0, %1, %2;" : "=r"(r) : "f"(hi), "f"(lo));
  return r;
}

__device__ __forceinline__ unsigned smem_u32(const void* p) {
  return (unsigned)__cvta_generic_to_shared(p);
}

__device__ __forceinline__ void ldm4(unsigned* r, unsigned addr) {
  asm volatile("ldmatrix.sync.aligned.m8n8.x4.shared.b16 {%0,%1,%2,%3}, [%4];"
               : "=r"(r[0]), "=r"(r[1]), "=r"(r[2]), "=r"(r[3]) : "r"(addr));
}
__device__ __forceinline__ void ldm4t(unsigned* r, unsigned addr) {
  asm volatile("ldmatrix.sync.aligned.m8n8.x4.trans.shared.b16 {%0,%1,%2,%3}, [%4];"
               : "=r"(r[0]), "=r"(r[1]), "=r"(r[2]), "=r"(r[3]) : "r"(addr));
}

__device__ __forceinline__ void cp_async16(void* smem, const void* gmem) {
  unsigned sa = (unsigned)__cvta_generic_to_shared(smem);
  asm volatile("cp.async.cg.shared.global [%0], [%1], 16;" ::"r"(sa), "l"(gmem));
}
#define CP_COMMIT asm volatile("cp.async.commit_group;")
#define CP_WAIT(n) asm volatile("cp.async.wait_group %0;" ::"n"(n))

// =====================================================================================
// bf16 tensor-core GEMM body: C[m,n] = A[m,:] . W[n,:] + bias[n]  (NT, row-major bf16)
// 256x128 block, 8 warps (4m x 2n) each 64x64, BK=64 bf16 (128B rows), cp.async
// double-buffered, ldmatrix fragments, 72-half row stride (conflict-free).
// =====================================================================================
#define BKH 64
#define LDHW 36  // words per row (= 72 halves = 64 data + 8 pad)
#define ASTGH (256 * LDHW)
#define BSTGH (128 * LDHW)
#define BGEMM_SMEM ((2 * ASTGH + 2 * BSTGH) * 4)

template <int RELU, int OUTBF>
__device__ __forceinline__ void bgemm_body(
    const ushort_t* __restrict__ A, const ushort_t* __restrict__ W,
    const float* __restrict__ bp, void* __restrict__ Cv,
    int N, int K, int m0, int m_end, unsigned* smh) {
  int n0 = blockIdx.x * 128;
  unsigned* As = smh;
  unsigned* Bs = smh + 2 * ASTGH;

  int tid = threadIdx.x;
  int lane = tid & 31, wid = tid >> 5;
  int wm = (wid >> 1) * 64;
  int wn = (wid & 1) * 64;
  int g = lane >> 2, t = lane & 3;

  float acc[4][8][4];
#pragma unroll
  for (int i = 0; i < 4; i++)
#pragma unroll
    for (int j = 0; j < 8; j++)
#pragma unroll
      for (int l = 0; l < 4; l++) acc[i][j][l] = 0.f;

  unsigned a_base[4], b_base[4];
#pragma unroll
  for (int mf = 0; mf < 4; mf++) {
    int row = wm + mf * 16 + (lane & 15);
    a_base[mf] = smem_u32(As + row * LDHW) + ((lane >> 4) & 1) * 16;
  }
#pragma unroll
  for (int p = 0; p < 4; p++) {
    int row = wn + p * 16 + ((lane >> 4) & 1) * 8 + (lane & 7);
    b_base[p] = smem_u32(Bs + row * LDHW) + ((lane >> 3) & 1) * 16;
  }

  auto stage = [&](int s, int k0) {
#pragma unroll
    for (int i = 0; i < 8; i++) {
      int idx = tid + i * 256;
      int row = idx >> 3, kq = (idx & 7);
      int grow = m0 + row;
      if (grow < m_end)
        cp_async16(As + s * ASTGH + row * LDHW + kq * 4,
                   A + (size_t)grow * K + k0 + kq * 8);
    }
#pragma unroll
    for (int i = 0; i < 4; i++) {
      int idx = tid + i * 256;
      int row = idx >> 3, kq = (idx & 7);
      cp_async16(Bs + s * BSTGH + row * LDHW + kq * 4,
                 W + (size_t)(n0 + row) * K + k0 + kq * 8);
    }
  };

  stage(0, 0);
  CP_COMMIT;

  int nslab = K / BKH;
  for (int it = 0; it < nslab; it++) {
    int cur = it & 1;
    if (it + 1 < nslab) {
      stage(1 ^ cur, (it + 1) * BKH);
      CP_COMMIT;
      CP_WAIT(1);
    } else {
      CP_WAIT(0);
    }
    __syncthreads();

    unsigned aoff = cur * (ASTGH * 4);
    unsigned boff = cur * (BSTGH * 4);
#pragma unroll
    for (int c = 0; c < 4; c++) {
      unsigned af[4][4];
#pragma unroll
      for (int mf = 0; mf < 4; mf++) ldm4(af[mf], a_base[mf] + aoff + c * 32);
#pragma unroll
      for (int p = 0; p < 4; p++) {
        unsigned bq[4];
        ldm4(bq, b_base[p] + boff + c * 32);
#pragma unroll
        for (int mf = 0; mf < 4; mf++) {
          mma_bf16(acc[mf][2 * p], af[mf], bq);
          mma_bf16(acc[mf][2 * p + 1], af[mf], bq + 2);
        }
      }
    }
    __syncthreads();
  }

#pragma unroll
  for (int nf = 0; nf < 8; nf++) {
    int col = n0 + wn + nf * 8 + 2 * t;
    float2 bb = *(const float2*)(bp + col);
#pragma unroll
    for (int mf = 0; mf < 4; mf++) {
      int row0 = m0 + wm + mf * 16 + g;
      float v0 = acc[mf][nf][0] + bb.x;
      float v1 = acc[mf][nf][1] + bb.y;
      float v2 = acc[mf][nf][2] + bb.x;
      float v3 = acc[mf][nf][3] + bb.y;
      if (RELU) {
        v0 = fmaxf(v0, 0.f); v1 = fmaxf(v1, 0.f);
        v2 = fmaxf(v2, 0.f); v3 = fmaxf(v3, 0.f);
      }
      if (OUTBF) {
        ushort_t* C = (ushort_t*)Cv;
        if (row0 < m_end) *(unsigned*)(C + (size_t)row0 * N + col) = pk2(v0, v1);
        if (row0 + 8 < m_end) *(unsigned*)(C + (size_t)(row0 + 8) * N + col) = pk2(v2, v3);
      } else {
        float* C = (float*)Cv;
        if (row0 < m_end)
          *(float2*)(C + (size_t)row0 * N + col) = make_float2(v0, v1);
        if (row0 + 8 < m_end)
          *(float2*)(C + (size_t)(row0 + 8) * N + col) = make_float2(v2, v3);
      }
    }
  }
}

// Fused QKV projection (bf16 in/out): z selects (wq,bq,q)/(wk,bk,k)/(wv,bv,v)
__global__ void __launch_bounds__(256) bgemm_qkv(
    const ushort_t* __restrict__ A,
    const ushort_t* __restrict__ w0, const ushort_t* __restrict__ w1,
    const ushort_t* __restrict__ w2,
    const float* __restrict__ b0, const float* __restrict__ b1,
    const float* __restrict__ b2,
    ushort_t* __restrict__ c0, ushort_t* __restrict__ c1, ushort_t* __restrict__ c2) {
  extern __shared__ unsigned smh[];
  int z = blockIdx.z;
  const ushort_t* W = (z == 0) ? w0 : (z == 1) ? w1 : w2;
  const float* bb = (z == 0) ? b0 : (z == 1) ? b1 : b2;
  ushort_t* C = (z == 0) ? c0 : (z == 1) ? c1 : c2;
  int m0 = (int)blockIdx.y * 256;
  bgemm_body<0, 1>(A, W, bb, C, Dn, Dn, m0, Tn, smh);
}

// Dense O-projection (bf16 in, fp32 out)
__global__ void __launch_bounds__(256) bgemm_o(
    const ushort_t* __restrict__ A, const ushort_t* __restrict__ W,
    const float* __restrict__ bias, float* __restrict__ C) {
  extern __shared__ unsigned smh[];
  int m0 = (int)blockIdx.y * 256;
  bgemm_body<0, 0>(A, W, bias, C, Dn, Dn, m0, Tn, smh);
}

// Expert-batched MoE GEMM
template <int RELU, int OUTBF>
__global__ void __launch_bounds__(256) bgemm_moe(
    const ushort_t* __restrict__ A, const ushort_t* __restrict__ W,
    const float* __restrict__ bias, void* __restrict__ Cv,
    int N, int K, const int* __restrict__ off, size_t wstride) {
  extern __shared__ unsigned smh[];
  int e = blockIdx.z;
  int m_start = off[e], m_end = off[e + 1];
  int m0 = m_start + (int)blockIdx.y * 256;
  if (m0 >= m_end) return;
  bgemm_body<RELU, OUTBF>(A, W + (size_t)e * wstride, bias + (size_t)e * N, Cv,
                          N, K, m0, m_end, smh);
}

// fp32 -> bf16 bulk conversion (per-launch; graph-safe, deterministic)
__global__ void __launch_bounds__(256) cvt_bf16(
    const float* __restrict__ src, ushort_t* __restrict__ dst, int n4) {
  int i = blockIdx.x * 256 + threadIdx.x;
  if (i < n4) {
    float4 v = ((const float4*)src)[i];
    ((uint2*)dst)[i] = make_uint2(pk2(v.x, v.y), pk2(v.z, v.w));
  }
}

// =====================================================================================
// bf16 flash attention; q/k/v already bf16 in gmem -> cp.async staging, no cvt.
// 128-query blocks, 64-key tiles, 8 warps x 16 q-rows, m16n8k16, register-resident P.
// =====================================================================================
#define FQT 128
#define FKT 64
#define FSW 36  // words per row (= 72 halves = 64 data + 8 pad)

__global__ void __launch_bounds__(256) flash_bf(
    const ushort_t* __restrict__ Q, const ushort_t* __restrict__ K,
    const ushort_t* __restrict__ V, const int* __restrict__ mask,
    ushort_t* __restrict__ O) {
  __shared__ unsigned Qs[FQT * FSW];
  __shared__ unsigned Ks[FKT * FSW];
  __shared__ unsigned Vs[FKT * FSW];
  __shared__ int msk[FKT];

  int bh = blockIdx.y;
  int b = bh >> 4, h = bh & 15;
  int q0 = blockIdx.x * FQT;
  int tid = threadIdx.x;
  int lane = tid & 31, wid = tid >> 5;
  int g = lane >> 2, t = lane & 3;
  int wrow = wid * 16;

  // stage Q tile: 128 rows x 8 chunks(16B) -> 4 per thread
#pragma unroll
  for (int l = 0; l < 4; l++) {
    int idx = tid + l * 256;
    int r = idx >> 3, ch = idx & 7;
    cp_async16(Qs + r * FSW + ch * 4,
               Q + (size_t)(b * Sn + q0 + r) * Dn + h * HDn + ch * 8);
  }
  CP_COMMIT;

  float o[8][4];
#pragma unroll
  for (int nf = 0; nf < 8; nf++)
#pragma unroll
    for (int c = 0; c < 4; c++) o[nf][c] = 0.f;
  float mrow0 = -1e30f, mrow1 = -1e30f;
  float lrow0 = 0.f, lrow1 = 0.f;

  unsigned qa_base = smem_u32(Qs + (wrow + (lane & 15)) * FSW + (lane >> 4) * 4);
  unsigned kb_row = (lane & 7) + ((lane >> 4) & 1) * 8;
  unsigned kb_koff = ((lane >> 3) & 1) * 4;
  unsigned vb_key = (lane & 7) + ((lane >> 3) & 1) * 8;
  unsigned vb_doff = ((lane >> 4) & 1) * 4;

  for (int t0 = 0; t0 < Sn; t0 += FKT) {
    __syncthreads();  // prev iter's Ks/Vs readers done
    // stage K,V: 64 rows x 8 chunks each -> 2 per thread per matrix
#pragma unroll
    for (int l = 0; l < 2; l++) {
      int idx = tid + l * 256;
      int r = idx >> 3, ch = idx & 7;
      size_t base = (size_t)(b * Sn + t0 + r) * Dn + h * HDn + ch * 8;
      cp_async16(Ks + r * FSW + ch * 4, K + base);
      cp_async16(Vs + r * FSW + ch * 4, V + base);
    }
    CP_COMMIT;
    if (tid < FKT) msk[tid] = mask[b * Sn + t0 + tid];
    CP_WAIT(0);
    __syncthreads();

    float s[8][4];
#pragma unroll
    for (int nf = 0; nf < 8; nf++)
#pragma unroll
      for (int c = 0; c < 4; c++) s[nf][c] = 0.f;

#pragma unroll
    for (int c = 0; c < 4; c++) {
      unsigned a[4];
      ldm4(a, qa_base + (c * 8) * 4);
#pragma unroll
      for (int ng = 0; ng < 4; ng++) {
        unsigned bq[4];
        unsigned addr = smem_u32(Ks + (ng * 16 + kb_row) * FSW + c * 8 + kb_koff);
        ldm4(bq, addr);
        mma_bf16(s[2 * ng], a, bq);
        mma_bf16(s[2 * ng + 1], a, bq + 2);
      }
    }

#pragma unroll
    for (int nf = 0; nf < 8; nf++) {
      int col = nf * 8 + 2 * t;
      bool z0 = (msk[col] == 0), z1 = (msk[col + 1] == 0);
      s[nf][0] = z0 ? -1e10f : s[nf][0] * 0.125f;
      s[nf][1] = z1 ? -1e10f : s[nf][1] * 0.125f;
      s[nf][2] = z0 ? -1e10f : s[nf][2] * 0.125f;
      s[nf][3] = z1 ? -1e10f : s[nf][3] * 0.125f;
    }

    float mx0 = -1e30f, mx1 = -1e30f;
#pragma unroll
    for (int nf = 0; nf < 8; nf++) {
      mx0 = fmaxf(mx0, fmaxf(s[nf][0], s[nf][1]));
      mx1 = fmaxf(mx1, fmaxf(s[nf][2], s[nf][3]));
    }
    mx0 = fmaxf(mx0, __shfl_xor_sync(0xffffffffu, mx0, 1));
    mx0 = fmaxf(mx0, __shfl_xor_sync(0xffffffffu, mx0, 2));
    mx1 = fmaxf(mx1, __shfl_xor_sync(0xffffffffu, mx1, 1));
    mx1 = fmaxf(mx1, __shfl_xor_sync(0xffffffffu, mx1, 2));

    float mn0 = fmaxf(mrow0, mx0), mn1 = fmaxf(mrow1, mx1);
    float sc0 = __expf(mrow0 - mn0), sc1 = __expf(mrow1 - mn1);
    mrow0 = mn0; mrow1 = mn1;

    float rs0 = 0.f, rs1 = 0.f;
    unsigned pk[8][2];
#pragma unroll
    for (int nf = 0; nf < 8; nf++) {
      s[nf][0] = __expf(s[nf][0] - mn0);
      s[nf][1] = __expf(s[nf][1] - mn0);
      s[nf][2] = __expf(s[nf][2] - mn1);
      s[nf][3] = __expf(s[nf][3] - mn1);
      rs0 += s[nf][0] + s[nf][1];
      rs1 += s[nf][2] + s[nf][3];
      pk[nf][0] = pk2(s[nf][0], s[nf][1]);
      pk[nf][1] = pk2(s[nf][2], s[nf][3]);
    }
    rs0 += __shfl_xor_sync(0xffffffffu, rs0, 1);
    rs0 += __shfl_xor_sync(0xffffffffu, rs0, 2);
    rs1 += __shfl_xor_sync(0xffffffffu, rs1, 1);
    rs1 += __shfl_xor_sync(0xffffffffu, rs1, 2);
    lrow0 = lrow0 * sc0 + rs0;
    lrow1 = lrow1 * sc1 + rs1;

#pragma unroll
    for (int nf = 0; nf < 8; nf++) {
      o[nf][0] *= sc0; o[nf][1] *= sc0;
      o[nf][2] *= sc1; o[nf][3] *= sc1;
    }

#pragma unroll
    for (int c = 0; c < 4; c++) {
      unsigned a[4] = {pk[2 * c][0], pk[2 * c][1], pk[2 * c + 1][0], pk[2 * c + 1][1]};
#pragma unroll
      for (int dg = 0; dg < 4; dg++) {
        unsigned bv[4];
        unsigned addr = smem_u32(Vs + (c * 16 + vb_key) * FSW + dg * 8 + vb_doff);
        ldm4t(bv, addr);
        mma_bf16(o[2 * dg], a, bv);
        mma_bf16(o[2 * dg + 1], a, bv + 2);
      }
    }
  }

  float inv0 = 1.f / lrow0, inv1 = 1.f / lrow1;
  int row = b * Sn + q0 + wrow + g;
#pragma unroll
  for (int nf = 0; nf < 8; nf++) {
    int col = h * HDn + nf * 8 + 2 * t;
    *(unsigned*)(O + (size_t)row * Dn + col) = pk2(o[nf][0] * inv0, o[nf][1] * inv0);
    *(unsigned*)(O + (size_t)(row + 8) * Dn + col) = pk2(o[nf][2] * inv1, o[nf][3] * inv1);
  }
}

// =====================================================================================
// out = LayerNorm(A + B) * g + be
// =====================================================================================
__global__ void __launch_bounds__(256) add_ln(
    const float* __restrict__ A, const float* __restrict__ Bv,
    const float* __restrict__ g, const float* __restrict__ be,
    float* __restrict__ out) {
  int t = blockIdx.x;
  int tid = threadIdx.x;
  float4 a = *(const float4*)(A + (size_t)t * Dn + tid * 4);
  float4 b = *(const float4*)(Bv + (size_t)t * Dn + tid * 4);
  float4 x = make_float4(a.x + b.x, a.y + b.y, a.z + b.z, a.w + b.w);
  float sumv = x.x + x.y + x.z + x.w;
  float sq = x.x * x.x + x.y * x.y + x.z * x.z + x.w * x.w;
#pragma unroll
  for (int off = 16; off; off >>= 1) {
    sumv += __shfl_xor_sync(0xffffffffu, sumv, off);
    sq += __shfl_xor_sync(0xffffffffu, sq, off);
  }
  __shared__ float ws[8], wq[8];
  __shared__ float s_mean, s_rstd;
  int wid = tid >> 5, lane = tid & 31;
  if (lane == 0) {
    ws[wid] = sumv;
    wq[wid] = sq;
  }
  __syncthreads();
  if (tid == 0) {
    float s = 0.f, q = 0.f;
#pragma unroll
    for (int i = 0; i < 8; i++) {
      s += ws[i];
      q += wq[i];
    }
    float mean = s * (1.f / Dn);
    float var = q * (1.f / Dn) - mean * mean;
    s_mean = mean;
    s_rstd = rsqrtf(var + 1e-5f);
  }
  __syncthreads();
  float mean = s_mean, rstd = s_rstd;
  float4 gg = *(const float4*)(g + tid * 4);
  float4 bb = *(const float4*)(be + tid * 4);
  float4 y;
  y.x = (x.x - mean) * rstd * gg.x + bb.x;
  y.y = (x.y - mean) * rstd * gg.y + bb.y;
  y.z = (x.z - mean) * rstd * gg.z + bb.z;
  y.w = (x.w - mean) * rstd * gg.w + bb.w;
  *(float4*)(out + (size_t)t * Dn + tid * 4) = y;
}

// =====================================================================================
// Router
// =====================================================================================
__global__ void __launch_bounds__(128) router_kernel(
    const float* __restrict__ x1, const float* __restrict__ sw,
    const float* __restrict__ sb, float* __restrict__ xs,
    int* __restrict__ route) {
  __shared__ float ssw[En * Dn];
  int t = blockIdx.x;
  int tid = threadIdx.x;
  for (int i = tid; i < En * Dn / 4; i += 128)
    ((float4*)ssw)[i] = ((const float4*)sw)[i];
  __syncthreads();

  float acc[En];
#pragma unroll
  for (int e = 0; e < En; e++) acc[e] = 0.f;
  float xv[8];
#pragma unroll
  for (int l = 0; l < 2; l++) {
    int d = (tid + l * 128) * 4;
    float4 x = *(const float4*)(x1 + (size_t)t * Dn + d);
    xv[l * 4 + 0] = x.x;
    xv[l * 4 + 1] = x.y;
    xv[l * 4 + 2] = x.z;
    xv[l * 4 + 3] = x.w;
#pragma unroll
    for (int e = 0; e < En; e++) {
      const float* swp = ssw + e * Dn + d;
      acc[e] += x.x * swp[0] + x.y * swp[1] + x.z * swp[2] + x.w * swp[3];
    }
  }
#pragma unroll
  for (int e = 0; e < En; e++)
#pragma unroll
    for (int off = 16; off; off >>= 1) acc[e] += __shfl_xor_sync(0xffffffffu, acc[e], off);

  __shared__ float wsum[4][En];
  __shared__ float s_p;
  int wid = tid >> 5, lane = tid & 31;
  if (lane == 0)
#pragma unroll
    for (int e = 0; e < En; e++) wsum[wid][e] = acc[e];
  __syncthreads();
  if (tid == 0) {
    float lg[En];
#pragma unroll
    for (int e = 0; e < En; e++)
      lg[e] = wsum[0][e] + wsum[1][e] + wsum[2][e] + wsum[3][e] + sb[e];
    int am = 0;
    float mx = lg[0];
#pragma unroll
    for (int e = 1; e < En; e++)
      if (lg[e] > mx) {
        mx = lg[e];
        am = e;
      }
    float sum = 0.f;
#pragma unroll
    for (int e = 0; e < En; e++) sum += __expf(lg[e] - mx);
    s_p = 1.f / sum;
    route[t] = am;
  }
  __syncthreads();
  float p = s_p;
#pragma unroll
  for (int l = 0; l < 2; l++) {
    int d = (tid + l * 128) * 4;
    float4 y = make_float4(xv[l * 4] * p, xv[l * 4 + 1] * p, xv[l * 4 + 2] * p,
                           xv[l * 4 + 3] * p);
    *(float4*)(xs + (size_t)t * Dn + d) = y;
  }
}

// =====================================================================================
// Deterministic stable counting sort by expert id (single block).
// =====================================================================================
__global__ void __launch_bounds__(256) sort_routes(
    const int* __restrict__ route, int* __restrict__ dest, int* __restrict__ off) {
  __shared__ int hist[256][En];
  __shared__ int tot[En];
  __shared__ int eoff[En + 1];
  int tid = threadIdx.x;
  int h[En];
#pragma unroll
  for (int e = 0; e < En; e++) h[e] = 0;
  int base = tid * 32;
  for (int i = 0; i < 32; i++) h[route[base + i]]++;
#pragma unroll
  for (int e = 0; e < En; e++) hist[tid][e] = h[e];
  __syncthreads();
  if (tid < En) {
    int e = tid;
    int run = 0;
    for (int i = 0; i < 256; i++) {
      int v = hist[i][e];
      hist[i][e] = run;
      run += v;
    }
    tot[e] = run;
  }
  __syncthreads();
  if (tid == 0) {
    int r = 0;
    for (int e = 0; e < En; e++) {
      eoff[e] = r;
      off[e] = r;
      r += tot[e];
    }
    eoff[En] = r;
    off[En] = r;
  }
  __syncthreads();
  int run[En];
#pragma unroll
  for (int e = 0; e < En; e++) run[e] = eoff[e] + hist[tid][e];
  for (int i = 0; i < 32; i++) {
    int e = route[base + i];
    dest[base + i] = run[e]++;
  }
}

// xsortb[dest[t], :] = bf16(xs[t, :])
__global__ void __launch_bounds__(256) gather_rows_bf(
    const float* __restrict__ xs, const int* __restrict__ dest,
    ushort_t* __restrict__ xsortb) {
  int t = blockIdx.x;
  int c = threadIdx.x;
  int dt = dest[t];
  float4 v = ((const float4*)xs)[(size_t)t * (Dn / 4) + c];
  ((uint2*)xsortb)[(size_t)dt * (Dn / 4) + c] =
      make_uint2(pk2(v.x, v.y), pk2(v.z, v.w));
}

// =====================================================================================
extern "C" void kernel_launch(void* const* d_in, const int* in_sizes, int n_in,
                              void* d_out, int out_size) {
  const float* x = (const float*)d_in[0];
  const float* wq = (const float*)d_in[1];
  const float* bq = (const float*)d_in[2];
  const float* wk = (const float*)d_in[3];
  const float* bk = (const float*)d_in[4];
  const float* wv = (const float*)d_in[5];
  const float* bv = (const float*)d_in[6];
  const float* wo = (const float*)d_in[7];
  const float* bo = (const float*)d_in[8];
  const float* ln1g = (const float*)d_in[9];
  const float* ln1b = (const float*)d_in[10];
  const float* ln2g = (const float*)d_in[11];
  const float* ln2b = (const float*)d_in[12];
  const float* sw = (const float*)d_in[13];
  const float* sb = (const float*)d_in[14];
  const float* ew1 = (const float*)d_in[15];
  const float* eb1 = (const float*)d_in[16];
  const float* ew2 = (const float*)d_in[17];
  const float* eb2 = (const float*)d_in[18];
  const int* mask = (const int*)d_in[19];
  float* out = (float*)d_out;

  ushort_t *xb, *qb, *kb, *vb, *ctxb, *wqb, *wkb, *wvb, *wob;
  ushort_t *xsortb, *h1b, *w1b, *w2b;
  float *ao, *x1, *xs, *moe;
  int *route, *dest, *off;
  cudaGetSymbolAddress((void**)&xb, g_xb);
  cudaGetSymbolAddress((void**)&qb, g_qb);
  cudaGetSymbolAddress((void**)&kb, g_kb);
  cudaGetSymbolAddress((void**)&vb, g_vb);
  cudaGetSymbolAddress((void**)&ctxb, g_ctxb);
  cudaGetSymbolAddress((void**)&wqb, g_wqb);
  cudaGetSymbolAddress((void**)&wkb, g_wkb);
  cudaGetSymbolAddress((void**)&wvb, g_wvb);
  cudaGetSymbolAddress((void**)&wob, g_wob);
  cudaGetSymbolAddress((void**)&ao, g_ao);
  cudaGetSymbolAddress((void**)&x1, g_x1);
  cudaGetSymbolAddress((void**)&xs, g_xs);
  cudaGetSymbolAddress((void**)&moe, g_moe);
  cudaGetSymbolAddress((void**)&xsortb, g_xsortb);
  cudaGetSymbolAddress((void**)&h1b, g_h1b);
  cudaGetSymbolAddress((void**)&w1b, g_w1b);
  cudaGetSymbolAddress((void**)&w2b, g_w2b);
  cudaGetSymbolAddress((void**)&route, g_route);
  cudaGetSymbolAddress((void**)&dest, g_dest);
  cudaGetSymbolAddress((void**)&off, g_off);

  cudaFuncSetAttribute(bgemm_qkv, cudaFuncAttributeMaxDynamicSharedMemorySize, BGEMM_SMEM);
  cudaFuncSetAttribute(bgemm_o, cudaFuncAttributeMaxDynamicSharedMemorySize, BGEMM_SMEM);
  cudaFuncSetAttribute(bgemm_moe<1, 1>, cudaFuncAttributeMaxDynamicSharedMemorySize, BGEMM_SMEM);
  cudaFuncSetAttribute(bgemm_moe<0, 0>, cudaFuncAttributeMaxDynamicSharedMemorySize, BGEMM_SMEM);

  dim3 blk(256);

  // --- conversions (bandwidth-bound) ---
  const int XN4 = Tn * Dn / 4;
  const int WN4 = Dn * Dn / 4;
  const int W1N4 = En * Fn * Dn / 4;
  cvt_bf16<<<(XN4 + 255) / 256, blk>>>(x, xb, XN4);
  cvt_bf16<<<(WN4 + 255) / 256, blk>>>(wq, wqb, WN4);
  cvt_bf16<<<(WN4 + 255) / 256, blk>>>(wk, wkb, WN4);
  cvt_bf16<<<(WN4 + 255) / 256, blk>>>(wv, wvb, WN4);
  cvt_bf16<<<(WN4 + 255) / 256, blk>>>(wo, wob, WN4);
  cvt_bf16<<<(W1N4 + 255) / 256, blk>>>(ew1, w1b, W1N4);
  cvt_bf16<<<(W1N4 + 255) / 256, blk>>>(ew2, w2b, W1N4);

  // --- attention block ---
  bgemm_qkv<<<dim3(Dn / 128, Tn / 256, 3), blk, BGEMM_SMEM>>>(
      xb, wqb, wkb, wvb, bq, bk, bv, qb, kb, vb);
  flash_bf<<<dim3(Sn / FQT, Bn * Hn), blk>>>(qb, kb, vb, mask, ctxb);
  bgemm_o<<<dim3(Dn / 128, Tn / 256, 1), blk, BGEMM_SMEM>>>(ctxb, wob, bo, ao);
  add_ln<<<Tn, 256>>>(x, ao, ln1g, ln1b, x1);

  // --- MoE block ---
  router_kernel<<<Tn, 128>>>(x1, sw, sb, xs, route);
  sort_routes<<<1, 256>>>(route, dest, off);
  gather_rows_bf<<<Tn, 256>>>(xs, dest, xsortb);
  bgemm_moe<1, 1><<<dim3(Fn / 128, Tn / 256, En), blk, BGEMM_SMEM>>>(
      xsortb, w1b, eb1, h1b, Fn, Dn, off, (size_t)Fn * Dn);
  bgemm_moe<0, 0><<<dim3(Dn / 128, Tn / 256, En), blk, BGEMM_SMEM>>>(
      h1b, w2b, eb2, moe, Dn, Fn, off, (size_t)Dn * Fn);
  add_ln<<<Tn, 256>>>(x1, moe, ln2g, ln2b, out);
}

// round 9
// speedup vs baseline: 6.3808x; 1.0389x over previous
#include <cuda_runtime.h>
#include <math.h>

// Problem dims (fixed by the reference)
#define Tn 8192
#define Dn 1024
#define Hn 16
#define HDn 64
#define Fn 4096
#define En 8
#define Bn 4
#define Sn 2048

typedef unsigned short ushort_t;

// ---------------- scratch (static device allocations; no cudaMalloc allowed) ---------
__device__ ushort_t g_xb[Tn * Dn];        // bf16 x
__device__ ushort_t g_qb[Tn * Dn];        // bf16 q
__device__ ushort_t g_kb[Tn * Dn];        // bf16 k
__device__ ushort_t g_vb[Tn * Dn];        // bf16 v
__device__ ushort_t g_ctxb[Tn * Dn];      // bf16 ctx
__device__ ushort_t g_wqb[Dn * Dn];
__device__ ushort_t g_wkb[Dn * Dn];
__device__ ushort_t g_wvb[Dn * Dn];
__device__ ushort_t g_wob[Dn * Dn];
__device__ float g_ao[Tn * Dn];
__device__ float g_x1[Tn * Dn];
__device__ float g_xs[Tn * Dn];
__device__ float g_moe[Tn * Dn];
__device__ ushort_t g_xsortb[Tn * Dn];
__device__ ushort_t g_h1b[(size_t)Tn * Fn];
__device__ ushort_t g_w1b[(size_t)En * Fn * Dn];
__device__ ushort_t g_w2b[(size_t)En * Dn * Fn];
__device__ int g_route[Tn];
__device__ int g_dest[Tn];
__device__ int g_off[En + 1];

__device__ __forceinline__ void mma_bf16(float* c, const unsigned* a, const unsigned* b) {
  asm volatile(
      "mma.sync.aligned.m16n8k16.row.col.f32.bf16.bf16.f32 "
      "{%0,%1,%2,%3},{%4,%5,%6,%7},{%8,%9},{%0,%1,%2,%3};"
      : "+f"(c[0]), "+f"(c[1]), "+f"(c[2]), "+f"(c[3])
      : "r"(a[0]), "r"(a[1]), "r"(a[2]), "r"(a[3]), "r"(b[0]), "r"(b[1]));
}

// pack two f32 -> bf16x2 (lo = first arg, hi = second)
__device__ __forceinline__ unsigned pk2(float lo, float hi) {
  unsigned r;
  asm("cvt.rn.bf16x2.f32 %0, %1, %2;" : "=r"(r) : "f"(hi), "f"(lo));
  return r;
}

__device__ __forceinline__ unsigned smem_u32(const void* p) {
  return (unsigned)__cvta_generic_to_shared(p);
}

__device__ __forceinline__ void ldm4(unsigned* r, unsigned addr) {
  asm volatile("ldmatrix.sync.aligned.m8n8.x4.shared.b16 {%0,%1,%2,%3}, [%4];"
               : "=r"(r[0]), "=r"(r[1]), "=r"(r[2]), "=r"(r[3]) : "r"(addr));
}
__device__ __forceinline__ void ldm4t(unsigned* r, unsigned addr) {
  asm volatile("ldmatrix.sync.aligned.m8n8.x4.trans.shared.b16 {%0,%1,%2,%3}, [%4];"
               : "=r"(r[0]), "=r"(r[1]), "=r"(r[2]), "=r"(r[3]) : "r"(addr));
}

__device__ __forceinline__ void cp_async16(void* smem, const void* gmem) {
  unsigned sa = (unsigned)__cvta_generic_to_shared(smem);
  asm volatile("cp.async.cg.shared.global [%0], [%1], 16;" ::"r"(sa), "l"(gmem));
}
#define CP_COMMIT asm volatile("cp.async.commit_group;")
#define CP_WAIT(n) asm volatile("cp.async.wait_group %0;" ::"n"(n))

// =====================================================================================
// bf16 tensor-core GEMM body: C[m,n] = A[m,:] . W[n,:] + bias[n]  (NT, row-major bf16)
// 256x128 block, 8 warps (4m x 2n) each 64x64, BK=64 bf16, ldmatrix fragments.
// 3-stage cp.async pipeline, ONE barrier per slab:
//   wait(1) -> syncthreads -> stage(it+2) -> compute(it)
// Buffer (it+2)%3 was last read at compute(it-1), which all warps finished before
// sync(it), so the single top barrier protects the overwrite.
// =====================================================================================
#define BKH 64
#define LDHW 36  // words per row (= 72 halves = 64 data + 8 pad)
#define ASTGH (256 * LDHW)
#define BSTGH (128 * LDHW)
#define BGEMM_SMEM ((3 * ASTGH + 3 * BSTGH) * 4)  // 165888 B

template <int RELU, int OUTBF>
__device__ __forceinline__ void bgemm_body(
    const ushort_t* __restrict__ A, const ushort_t* __restrict__ W,
    const float* __restrict__ bp, void* __restrict__ Cv,
    int N, int K, int m0, int m_end, unsigned* smh) {
  int n0 = blockIdx.x * 128;
  unsigned* As = smh;
  unsigned* Bs = smh + 3 * ASTGH;

  int tid = threadIdx.x;
  int lane = tid & 31, wid = tid >> 5;
  int wm = (wid >> 1) * 64;
  int wn = (wid & 1) * 64;
  int g = lane >> 2, t = lane & 3;

  float acc[4][8][4];
#pragma unroll
  for (int i = 0; i < 4; i++)
#pragma unroll
    for (int j = 0; j < 8; j++)
#pragma unroll
      for (int l = 0; l < 4; l++) acc[i][j][l] = 0.f;

  unsigned a_base[4], b_base[4];
#pragma unroll
  for (int mf = 0; mf < 4; mf++) {
    int row = wm + mf * 16 + (lane & 15);
    a_base[mf] = smem_u32(As + row * LDHW) + ((lane >> 4) & 1) * 16;
  }
#pragma unroll
  for (int p = 0; p < 4; p++) {
    int row = wn + p * 16 + ((lane >> 4) & 1) * 8 + (lane & 7);
    b_base[p] = smem_u32(Bs + row * LDHW) + ((lane >> 3) & 1) * 16;
  }

  auto stage = [&](int s, int k0) {
#pragma unroll
    for (int i = 0; i < 8; i++) {
      int idx = tid + i * 256;
      int row = idx >> 3, kq = (idx & 7);
      int grow = m0 + row;
      if (grow < m_end)
        cp_async16(As + s * ASTGH + row * LDHW + kq * 4,
                   A + (size_t)grow * K + k0 + kq * 8);
    }
#pragma unroll
    for (int i = 0; i < 4; i++) {
      int idx = tid + i * 256;
      int row = idx >> 3, kq = (idx & 7);
      cp_async16(Bs + s * BSTGH + row * LDHW + kq * 4,
                 W + (size_t)(n0 + row) * K + k0 + kq * 8);
    }
  };

  int nslab = K / BKH;
  stage(0, 0);
  CP_COMMIT;
  stage(1, BKH);
  CP_COMMIT;

  for (int it = 0; it < nslab; it++) {
    int cur = it % 3;
    if (it + 2 < nslab) {
      CP_WAIT(1);
    } else {
      CP_WAIT(0);
    }
    __syncthreads();
    if (it + 2 < nslab) {
      stage((it + 2) % 3, (it + 2) * BKH);
      CP_COMMIT;
    }

    unsigned aoff = cur * (ASTGH * 4);
    unsigned boff = cur * (BSTGH * 4);
#pragma unroll
    for (int c = 0; c < 4; c++) {
      unsigned af[4][4];
#pragma unroll
      for (int mf = 0; mf < 4; mf++) ldm4(af[mf], a_base[mf] + aoff + c * 32);
#pragma unroll
      for (int p = 0; p < 4; p++) {
        unsigned bq[4];
        ldm4(bq, b_base[p] + boff + c * 32);
#pragma unroll
        for (int mf = 0; mf < 4; mf++) {
          mma_bf16(acc[mf][2 * p], af[mf], bq);
          mma_bf16(acc[mf][2 * p + 1], af[mf], bq + 2);
        }
      }
    }
  }

#pragma unroll
  for (int nf = 0; nf < 8; nf++) {
    int col = n0 + wn + nf * 8 + 2 * t;
    float2 bb = *(const float2*)(bp + col);
#pragma unroll
    for (int mf = 0; mf < 4; mf++) {
      int row0 = m0 + wm + mf * 16 + g;
      float v0 = acc[mf][nf][0] + bb.x;
      float v1 = acc[mf][nf][1] + bb.y;
      float v2 = acc[mf][nf][2] + bb.x;
      float v3 = acc[mf][nf][3] + bb.y;
      if (RELU) {
        v0 = fmaxf(v0, 0.f); v1 = fmaxf(v1, 0.f);
        v2 = fmaxf(v2, 0.f); v3 = fmaxf(v3, 0.f);
      }
      if (OUTBF) {
        ushort_t* C = (ushort_t*)Cv;
        if (row0 < m_end) *(unsigned*)(C + (size_t)row0 * N + col) = pk2(v0, v1);
        if (row0 + 8 < m_end) *(unsigned*)(C + (size_t)(row0 + 8) * N + col) = pk2(v2, v3);
      } else {
        float* C = (float*)Cv;
        if (row0 < m_end)
          *(float2*)(C + (size_t)row0 * N + col) = make_float2(v0, v1);
        if (row0 + 8 < m_end)
          *(float2*)(C + (size_t)(row0 + 8) * N + col) = make_float2(v2, v3);
      }
    }
  }
}

// Fused QKV projection (bf16 in/out): z selects (wq,bq,q)/(wk,bk,k)/(wv,bv,v)
__global__ void __launch_bounds__(256) bgemm_qkv(
    const ushort_t* __restrict__ A,
    const ushort_t* __restrict__ w0, const ushort_t* __restrict__ w1,
    const ushort_t* __restrict__ w2,
    const float* __restrict__ b0, const float* __restrict__ b1,
    const float* __restrict__ b2,
    ushort_t* __restrict__ c0, ushort_t* __restrict__ c1, ushort_t* __restrict__ c2) {
  extern __shared__ unsigned smh[];
  int z = blockIdx.z;
  const ushort_t* W = (z == 0) ? w0 : (z == 1) ? w1 : w2;
  const float* bb = (z == 0) ? b0 : (z == 1) ? b1 : b2;
  ushort_t* C = (z == 0) ? c0 : (z == 1) ? c1 : c2;
  int m0 = (int)blockIdx.y * 256;
  bgemm_body<0, 1>(A, W, bb, C, Dn, Dn, m0, Tn, smh);
}

// Dense O-projection (bf16 in, fp32 out)
__global__ void __launch_bounds__(256) bgemm_o(
    const ushort_t* __restrict__ A, const ushort_t* __restrict__ W,
    const float* __restrict__ bias, float* __restrict__ C) {
  extern __shared__ unsigned smh[];
  int m0 = (int)blockIdx.y * 256;
  bgemm_body<0, 0>(A, W, bias, C, Dn, Dn, m0, Tn, smh);
}

// Expert-batched MoE GEMM
template <int RELU, int OUTBF>
__global__ void __launch_bounds__(256) bgemm_moe(
    const ushort_t* __restrict__ A, const ushort_t* __restrict__ W,
    const float* __restrict__ bias, void* __restrict__ Cv,
    int N, int K, const int* __restrict__ off, size_t wstride) {
  extern __shared__ unsigned smh[];
  int e = blockIdx.z;
  int m_start = off[e], m_end = off[e + 1];
  int m0 = m_start + (int)blockIdx.y * 256;
  if (m0 >= m_end) return;
  bgemm_body<RELU, OUTBF>(A, W + (size_t)e * wstride, bias + (size_t)e * N, Cv,
                          N, K, m0, m_end, smh);
}

// fp32 -> bf16 bulk conversion (per-launch; graph-safe, deterministic)
__global__ void __launch_bounds__(256) cvt_bf16(
    const float* __restrict__ src, ushort_t* __restrict__ dst, int n4) {
  int i = blockIdx.x * 256 + threadIdx.x;
  if (i < n4) {
    float4 v = ((const float4*)src)[i];
    ((uint2*)dst)[i] = make_uint2(pk2(v.x, v.y), pk2(v.z, v.w));
  }
}

// =====================================================================================
// bf16 flash attention, 3-stage K/V pipeline (one barrier per key tile).
// 128-query blocks, 64-key tiles, 8 warps x 16 q-rows, m16n8k16, register-resident P.
// =====================================================================================
#define FQT 128
#define FKT 64
#define FSW 36  // words per row (= 72 halves = 64 data + 8 pad)
#define FNT (Sn / FKT)

__global__ void __launch_bounds__(256) flash_bf(
    const ushort_t* __restrict__ Q, const ushort_t* __restrict__ K,
    const ushort_t* __restrict__ V, const int* __restrict__ mask,
    ushort_t* __restrict__ O) {
  __shared__ unsigned Qs[FQT * FSW];
  __shared__ unsigned Ks[3][FKT * FSW];
  __shared__ unsigned Vs[3][FKT * FSW];
  __shared__ int msk[3][FKT];

  int bh = blockIdx.y;
  int b = bh >> 4, h = bh & 15;
  int q0 = blockIdx.x * FQT;
  int tid = threadIdx.x;
  int lane = tid & 31, wid = tid >> 5;
  int g = lane >> 2, t = lane & 3;
  int wrow = wid * 16;

  auto stage_kv = [&](int s, int t0) {
#pragma unroll
    for (int l = 0; l < 2; l++) {
      int idx = tid + l * 256;
      int r = idx >> 3, ch = idx & 7;
      size_t base = (size_t)(b * Sn + t0 + r) * Dn + h * HDn + ch * 8;
      cp_async16(Ks[s] + r * FSW + ch * 4, K + base);
      cp_async16(Vs[s] + r * FSW + ch * 4, V + base);
    }
  };

  // prologue: Q + KV tile0 (group0), KV tile1 (group1), masks 0/1
#pragma unroll
  for (int l = 0; l < 4; l++) {
    int idx = tid + l * 256;
    int r = idx >> 3, ch = idx & 7;
    cp_async16(Qs + r * FSW + ch * 4,
               Q + (size_t)(b * Sn + q0 + r) * Dn + h * HDn + ch * 8);
  }
  stage_kv(0, 0);
  CP_COMMIT;
  stage_kv(1, FKT);
  CP_COMMIT;
  if (tid < FKT) {
    msk[0][tid] = mask[b * Sn + tid];
    msk[1][tid] = mask[b * Sn + FKT + tid];
  }

  float o[8][4];
#pragma unroll
  for (int nf = 0; nf < 8; nf++)
#pragma unroll
    for (int c = 0; c < 4; c++) o[nf][c] = 0.f;
  float mrow0 = -1e30f, mrow1 = -1e30f;
  float lrow0 = 0.f, lrow1 = 0.f;

  unsigned qa_base = smem_u32(Qs + (wrow + (lane & 15)) * FSW + (lane >> 4) * 4);
  unsigned kb_row = (lane & 7) + ((lane >> 4) & 1) * 8;
  unsigned kb_koff = ((lane >> 3) & 1) * 4;
  unsigned vb_key = (lane & 7) + ((lane >> 3) & 1) * 8;
  unsigned vb_doff = ((lane >> 4) & 1) * 4;

  for (int it = 0; it < FNT; it++) {
    int cur = it % 3;
    if (it + 2 < FNT) {
      CP_WAIT(1);
    } else {
      CP_WAIT(0);
    }
    __syncthreads();
    if (it + 2 < FNT) {
      int s = (it + 2) % 3;
      stage_kv(s, (it + 2) * FKT);
      CP_COMMIT;
      if (tid < FKT) msk[s][tid] = mask[b * Sn + (it + 2) * FKT + tid];
    }

    const unsigned* Kc = Ks[cur];
    const unsigned* Vc = Vs[cur];
    const int* mc = msk[cur];

    float s[8][4];
#pragma unroll
    for (int nf = 0; nf < 8; nf++)
#pragma unroll
      for (int c = 0; c < 4; c++) s[nf][c] = 0.f;

#pragma unroll
    for (int c = 0; c < 4; c++) {
      unsigned a[4];
      ldm4(a, qa_base + (c * 8) * 4);
#pragma unroll
      for (int ng = 0; ng < 4; ng++) {
        unsigned bq[4];
        unsigned addr = smem_u32(Kc + (ng * 16 + kb_row) * FSW + c * 8 + kb_koff);
        ldm4(bq, addr);
        mma_bf16(s[2 * ng], a, bq);
        mma_bf16(s[2 * ng + 1], a, bq + 2);
      }
    }

#pragma unroll
    for (int nf = 0; nf < 8; nf++) {
      int col = nf * 8 + 2 * t;
      bool z0 = (mc[col] == 0), z1 = (mc[col + 1] == 0);
      s[nf][0] = z0 ? -1e10f : s[nf][0] * 0.125f;
      s[nf][1] = z1 ? -1e10f : s[nf][1] * 0.125f;
      s[nf][2] = z0 ? -1e10f : s[nf][2] * 0.125f;
      s[nf][3] = z1 ? -1e10f : s[nf][3] * 0.125f;
    }

    float mx0 = -1e30f, mx1 = -1e30f;
#pragma unroll
    for (int nf = 0; nf < 8; nf++) {
      mx0 = fmaxf(mx0, fmaxf(s[nf][0], s[nf][1]));
      mx1 = fmaxf(mx1, fmaxf(s[nf][2], s[nf][3]));
    }
    mx0 = fmaxf(mx0, __shfl_xor_sync(0xffffffffu, mx0, 1));
    mx0 = fmaxf(mx0, __shfl_xor_sync(0xffffffffu, mx0, 2));
    mx1 = fmaxf(mx1, __shfl_xor_sync(0xffffffffu, mx1, 1));
    mx1 = fmaxf(mx1, __shfl_xor_sync(0xffffffffu, mx1, 2));

    float mn0 = fmaxf(mrow0, mx0), mn1 = fmaxf(mrow1, mx1);
    float sc0 = __expf(mrow0 - mn0), sc1 = __expf(mrow1 - mn1);
    mrow0 = mn0; mrow1 = mn1;

    float rs0 = 0.f, rs1 = 0.f;
    unsigned pk[8][2];
#pragma unroll
    for (int nf = 0; nf < 8; nf++) {
      s[nf][0] = __expf(s[nf][0] - mn0);
      s[nf][1] = __expf(s[nf][1] - mn0);
      s[nf][2] = __expf(s[nf][2] - mn1);
      s[nf][3] = __expf(s[nf][3] - mn1);
      rs0 += s[nf][0] + s[nf][1];
      rs1 += s[nf][2] + s[nf][3];
      pk[nf][0] = pk2(s[nf][0], s[nf][1]);
      pk[nf][1] = pk2(s[nf][2], s[nf][3]);
    }
    rs0 += __shfl_xor_sync(0xffffffffu, rs0, 1);
    rs0 += __shfl_xor_sync(0xffffffffu, rs0, 2);
    rs1 += __shfl_xor_sync(0xffffffffu, rs1, 1);
    rs1 += __shfl_xor_sync(0xffffffffu, rs1, 2);
    lrow0 = lrow0 * sc0 + rs0;
    lrow1 = lrow1 * sc1 + rs1;

#pragma unroll
    for (int nf = 0; nf < 8; nf++) {
      o[nf][0] *= sc0; o[nf][1] *= sc0;
      o[nf][2] *= sc1; o[nf][3] *= sc1;
    }

#pragma unroll
    for (int c = 0; c < 4; c++) {
      unsigned a[4] = {pk[2 * c][0], pk[2 * c][1], pk[2 * c + 1][0], pk[2 * c + 1][1]};
#pragma unroll
      for (int dg = 0; dg < 4; dg++) {
        unsigned bv[4];
        unsigned addr = smem_u32(Vc + (c * 16 + vb_key) * FSW + dg * 8 + vb_doff);
        ldm4t(bv, addr);
        mma_bf16(o[2 * dg], a, bv);
        mma_bf16(o[2 * dg + 1], a, bv + 2);
      }
    }
  }

  float inv0 = 1.f / lrow0, inv1 = 1.f / lrow1;
  int row = b * Sn + q0 + wrow + g;
#pragma unroll
  for (int nf = 0; nf < 8; nf++) {
    int col = h * HDn + nf * 8 + 2 * t;
    *(unsigned*)(O + (size_t)row * Dn + col) = pk2(o[nf][0] * inv0, o[nf][1] * inv0);
    *(unsigned*)(O + (size_t)(row + 8) * Dn + col) = pk2(o[nf][2] * inv1, o[nf][3] * inv1);
  }
}

// =====================================================================================
// out = LayerNorm(A + B) * g + be
// =====================================================================================
__global__ void __launch_bounds__(256) add_ln(
    const float* __restrict__ A, const float* __restrict__ Bv,
    const float* __restrict__ g, const float* __restrict__ be,
    float* __restrict__ out) {
  int t = blockIdx.x;
  int tid = threadIdx.x;
  float4 a = *(const float4*)(A + (size_t)t * Dn + tid * 4);
  float4 b = *(const float4*)(Bv + (size_t)t * Dn + tid * 4);
  float4 x = make_float4(a.x + b.x, a.y + b.y, a.z + b.z, a.w + b.w);
  float sumv = x.x + x.y + x.z + x.w;
  float sq = x.x * x.x + x.y * x.y + x.z * x.z + x.w * x.w;
#pragma unroll
  for (int off = 16; off; off >>= 1) {
    sumv += __shfl_xor_sync(0xffffffffu, sumv, off);
    sq += __shfl_xor_sync(0xffffffffu, sq, off);
  }
  __shared__ float ws[8], wq[8];
  __shared__ float s_mean, s_rstd;
  int wid = tid >> 5, lane = tid & 31;
  if (lane == 0) {
    ws[wid] = sumv;
    wq[wid] = sq;
  }
  __syncthreads();
  if (tid == 0) {
    float s = 0.f, q = 0.f;
#pragma unroll
    for (int i = 0; i < 8; i++) {
      s += ws[i];
      q += wq[i];
    }
    float mean = s * (1.f / Dn);
    float var = q * (1.f / Dn) - mean * mean;
    s_mean = mean;
    s_rstd = rsqrtf(var + 1e-5f);
  }
  __syncthreads();
  float mean = s_mean, rstd = s_rstd;
  float4 gg = *(const float4*)(g + tid * 4);
  float4 bb = *(const float4*)(be + tid * 4);
  float4 y;
  y.x = (x.x - mean) * rstd * gg.x + bb.x;
  y.y = (x.y - mean) * rstd * gg.y + bb.y;
  y.z = (x.z - mean) * rstd * gg.z + bb.z;
  y.w = (x.w - mean) * rstd * gg.w + bb.w;
  *(float4*)(out + (size_t)t * Dn + tid * 4) = y;
}

// =====================================================================================
// Router
// =====================================================================================
__global__ void __launch_bounds__(128) router_kernel(
    const float* __restrict__ x1, const float* __restrict__ sw,
    const float* __restrict__ sb, float* __restrict__ xs,
    int* __restrict__ route) {
  __shared__ float ssw[En * Dn];
  int t = blockIdx.x;
  int tid = threadIdx.x;
  for (int i = tid; i < En * Dn / 4; i += 128)
    ((float4*)ssw)[i] = ((const float4*)sw)[i];
  __syncthreads();

  float acc[En];
#pragma unroll
  for (int e = 0; e < En; e++) acc[e] = 0.f;
  float xv[8];
#pragma unroll
  for (int l = 0; l < 2; l++) {
    int d = (tid + l * 128) * 4;
    float4 x = *(const float4*)(x1 + (size_t)t * Dn + d);
    xv[l * 4 + 0] = x.x;
    xv[l * 4 + 1] = x.y;
    xv[l * 4 + 2] = x.z;
    xv[l * 4 + 3] = x.w;
#pragma unroll
    for (int e = 0; e < En; e++) {
      const float* swp = ssw + e * Dn + d;
      acc[e] += x.x * swp[0] + x.y * swp[1] + x.z * swp[2] + x.w * swp[3];
    }
  }
#pragma unroll
  for (int e = 0; e < En; e++)
#pragma unroll
    for (int off = 16; off; off >>= 1) acc[e] += __shfl_xor_sync(0xffffffffu, acc[e], off);

  __shared__ float wsum[4][En];
  __shared__ float s_p;
  int wid = tid >> 5, lane = tid & 31;
  if (lane == 0)
#pragma unroll
    for (int e = 0; e < En; e++) wsum[wid][e] = acc[e];
  __syncthreads();
  if (tid == 0) {
    float lg[En];
#pragma unroll
    for (int e = 0; e < En; e++)
      lg[e] = wsum[0][e] + wsum[1][e] + wsum[2][e] + wsum[3][e] + sb[e];
    int am = 0;
    float mx = lg[0];
#pragma unroll
    for (int e = 1; e < En; e++)
      if (lg[e] > mx) {
        mx = lg[e];
        am = e;
      }
    float sum = 0.f;
#pragma unroll
    for (int e = 0; e < En; e++) sum += __expf(lg[e] - mx);
    s_p = 1.f / sum;
    route[t] = am;
  }
  __syncthreads();
  float p = s_p;
#pragma unroll
  for (int l = 0; l < 2; l++) {
    int d = (tid + l * 128) * 4;
    float4 y = make_float4(xv[l * 4] * p, xv[l * 4 + 1] * p, xv[l * 4 + 2] * p,
                           xv[l * 4 + 3] * p);
    *(float4*)(xs + (size_t)t * Dn + d) = y;
  }
}

// =====================================================================================
// Deterministic stable counting sort by expert id (single block).
// =====================================================================================
__global__ void __launch_bounds__(256) sort_routes(
    const int* __restrict__ route, int* __restrict__ dest, int* __restrict__ off) {
  __shared__ int hist[256][En];
  __shared__ int tot[En];
  __shared__ int eoff[En + 1];
  int tid = threadIdx.x;
  int h[En];
#pragma unroll
  for (int e = 0; e < En; e++) h[e] = 0;
  int base = tid * 32;
  for (int i = 0; i < 32; i++) h[route[base + i]]++;
#pragma unroll
  for (int e = 0; e < En; e++) hist[tid][e] = h[e];
  __syncthreads();
  if (tid < En) {
    int e = tid;
    int run = 0;
    for (int i = 0; i < 256; i++) {
      int v = hist[i][e];
      hist[i][e] = run;
      run += v;
    }
    tot[e] = run;
  }
  __syncthreads();
  if (tid == 0) {
    int r = 0;
    for (int e = 0; e < En; e++) {
      eoff[e] = r;
      off[e] = r;
      r += tot[e];
    }
    eoff[En] = r;
    off[En] = r;
  }
  __syncthreads();
  int run[En];
#pragma unroll
  for (int e = 0; e < En; e++) run[e] = eoff[e] + hist[tid][e];
  for (int i = 0; i < 32; i++) {
    int e = route[base + i];
    dest[base + i] = run[e]++;
  }
}

// xsortb[dest[t], :] = bf16(xs[t, :])
__global__ void __launch_bounds__(256) gather_rows_bf(
    const float* __restrict__ xs, const int* __restrict__ dest,
    ushort_t* __restrict__ xsortb) {
  int t = blockIdx.x;
  int c = threadIdx.x;
  int dt = dest[t];
  float4 v = ((const float4*)xs)[(size_t)t * (Dn / 4) + c];
  ((uint2*)xsortb)[(size_t)dt * (Dn / 4) + c] =
      make_uint2(pk2(v.x, v.y), pk2(v.z, v.w));
}

// =====================================================================================
extern "C" void kernel_launch(void* const* d_in, const int* in_sizes, int n_in,
                              void* d_out, int out_size) {
  const float* x = (const float*)d_in[0];
  const float* wq = (const float*)d_in[1];
  const float* bq = (const float*)d_in[2];
  const float* wk = (const float*)d_in[3];
  const float* bk = (const float*)d_in[4];
  const float* wv = (const float*)d_in[5];
  const float* bv = (const float*)d_in[6];
  const float* wo = (const float*)d_in[7];
  const float* bo = (const float*)d_in[8];
  const float* ln1g = (const float*)d_in[9];
  const float* ln1b = (const float*)d_in[10];
  const float* ln2g = (const float*)d_in[11];
  const float* ln2b = (const float*)d_in[12];
  const float* sw = (const float*)d_in[13];
  const float* sb = (const float*)d_in[14];
  const float* ew1 = (const float*)d_in[15];
  const float* eb1 = (const float*)d_in[16];
  const float* ew2 = (const float*)d_in[17];
  const float* eb2 = (const float*)d_in[18];
  const int* mask = (const int*)d_in[19];
  float* out = (float*)d_out;

  ushort_t *xb, *qb, *kb, *vb, *ctxb, *wqb, *wkb, *wvb, *wob;
  ushort_t *xsortb, *h1b, *w1b, *w2b;
  float *ao, *x1, *xs, *moe;
  int *route, *dest, *off;
  cudaGetSymbolAddress((void**)&xb, g_xb);
  cudaGetSymbolAddress((void**)&qb, g_qb);
  cudaGetSymbolAddress((void**)&kb, g_kb);
  cudaGetSymbolAddress((void**)&vb, g_vb);
  cudaGetSymbolAddress((void**)&ctxb, g_ctxb);
  cudaGetSymbolAddress((void**)&wqb, g_wqb);
  cudaGetSymbolAddress((void**)&wkb, g_wkb);
  cudaGetSymbolAddress((void**)&wvb, g_wvb);
  cudaGetSymbolAddress((void**)&wob, g_wob);
  cudaGetSymbolAddress((void**)&ao, g_ao);
  cudaGetSymbolAddress((void**)&x1, g_x1);
  cudaGetSymbolAddress((void**)&xs, g_xs);
  cudaGetSymbolAddress((void**)&moe, g_moe);
  cudaGetSymbolAddress((void**)&xsortb, g_xsortb);
  cudaGetSymbolAddress((void**)&h1b, g_h1b);
  cudaGetSymbolAddress((void**)&w1b, g_w1b);
  cudaGetSymbolAddress((void**)&w2b, g_w2b);
  cudaGetSymbolAddress((void**)&route, g_route);
  cudaGetSymbolAddress((void**)&dest, g_dest);
  cudaGetSymbolAddress((void**)&off, g_off);

  cudaFuncSetAttribute(bgemm_qkv, cudaFuncAttributeMaxDynamicSharedMemorySize, BGEMM_SMEM);
  cudaFuncSetAttribute(bgemm_o, cudaFuncAttributeMaxDynamicSharedMemorySize, BGEMM_SMEM);
  cudaFuncSetAttribute(bgemm_moe<1, 1>, cudaFuncAttributeMaxDynamicSharedMemorySize, BGEMM_SMEM);
  cudaFuncSetAttribute(bgemm_moe<0, 0>, cudaFuncAttributeMaxDynamicSharedMemorySize, BGEMM_SMEM);

  dim3 blk(256);

  // --- conversions (bandwidth-bound) ---
  const int XN4 = Tn * Dn / 4;
  const int WN4 = Dn * Dn / 4;
  const int W1N4 = En * Fn * Dn / 4;
  cvt_bf16<<<(XN4 + 255) / 256, blk>>>(x, xb, XN4);
  cvt_bf16<<<(WN4 + 255) / 256, blk>>>(wq, wqb, WN4);
  cvt_bf16<<<(WN4 + 255) / 256, blk>>>(wk, wkb, WN4);
  cvt_bf16<<<(WN4 + 255) / 256, blk>>>(wv, wvb, WN4);
  cvt_bf16<<<(WN4 + 255) / 256, blk>>>(wo, wob, WN4);
  cvt_bf16<<<(W1N4 + 255) / 256, blk>>>(ew1, w1b, W1N4);
  cvt_bf16<<<(W1N4 + 255) / 256, blk>>>(ew2, w2b, W1N4);

  // --- attention block ---
  bgemm_qkv<<<dim3(Dn / 128, Tn / 256, 3), blk, BGEMM_SMEM>>>(
      xb, wqb, wkb, wvb, bq, bk, bv, qb, kb, vb);
  flash_bf<<<dim3(Sn / FQT, Bn * Hn), blk>>>(qb, kb, vb, mask, ctxb);
  bgemm_o<<<dim3(Dn / 128, Tn / 256, 1), blk, BGEMM_SMEM>>>(ctxb, wob, bo, ao);
  add_ln<<<Tn, 256>>>(x, ao, ln1g, ln1b, x1);

  // --- MoE block ---
  router_kernel<<<Tn, 128>>>(x1, sw, sb, xs, route);
  sort_routes<<<1, 256>>>(route, dest, off);
  gather_rows_bf<<<Tn, 256>>>(xs, dest, xsortb);
  bgemm_moe<1, 1><<<dim3(Fn / 128, Tn / 256, En), blk, BGEMM_SMEM>>>(
      xsortb, w1b, eb1, h1b, Fn, Dn, off, (size_t)Fn * Dn);
  bgemm_moe<0, 0><<<dim3(Dn / 128, Tn / 256, En), blk, BGEMM_SMEM>>>(
      h1b, w2b, eb2, moe, Dn, Fn, off, (size_t)Dn * Fn);
  add_ln<<<Tn, 256>>>(x1, moe, ln2g, ln2b, out);
}

// round 11
// speedup vs baseline: 6.4101x; 1.0046x over previous
#include <cuda_runtime.h>
#include <math.h>

// Problem dims (fixed by the reference)
#define Tn 8192
#define Dn 1024
#define Hn 16
#define HDn 64
#define Fn 4096
#define En 8
#define Bn 4
#define Sn 2048

typedef unsigned short ushort_t;

// ---------------- scratch (static device allocations; no cudaMalloc allowed) ---------
__device__ ushort_t g_xb[Tn * Dn];        // bf16 x
__device__ ushort_t g_qb[Tn * Dn];        // bf16 q
__device__ ushort_t g_kb[Tn * Dn];        // bf16 k
__device__ ushort_t g_vb[Tn * Dn];        // bf16 v
__device__ ushort_t g_ctxb[Tn * Dn];      // bf16 ctx
__device__ ushort_t g_wqb[Dn * Dn];
__device__ ushort_t g_wkb[Dn * Dn];
__device__ ushort_t g_wvb[Dn * Dn];
__device__ ushort_t g_wob[Dn * Dn];
__device__ float g_ao[Tn * Dn];
__device__ float g_x1[Tn * Dn];
__device__ float g_xs[Tn * Dn];
__device__ float g_moe[Tn * Dn];
__device__ ushort_t g_xsortb[Tn * Dn];
__device__ ushort_t g_h1b[(size_t)Tn * Fn];
__device__ ushort_t g_w1b[(size_t)En * Fn * Dn];
__device__ ushort_t g_w2b[(size_t)En * Dn * Fn];
__device__ int g_route[Tn];
__device__ int g_dest[Tn];
__device__ int g_off[En + 1];

__device__ __forceinline__ void mma_bf16(float* c, const unsigned* a, const unsigned* b) {
  asm volatile(
      "mma.sync.aligned.m16n8k16.row.col.f32.bf16.bf16.f32 "
      "{%0,%1,%2,%3},{%4,%5,%6,%7},{%8,%9},{%0,%1,%2,%3};"
      : "+f"(c[0]), "+f"(c[1]), "+f"(c[2]), "+f"(c[3])
      : "r"(a[0]), "r"(a[1]), "r"(a[2]), "r"(a[3]), "r"(b[0]), "r"(b[1]));
}

// pack two f32 -> bf16x2 (lo = first arg, hi = second)
__device__ __forceinline__ unsigned pk2(float lo, float hi) {
  unsigned r;
  asm("cvt.rn.bf16x2.f32 %0, %1, %2;" : "=r"(r) : "f"(hi), "f"(lo));
  return r;
}

__device__ __forceinline__ unsigned smem_u32(const void* p) {
  return (unsigned)__cvta_generic_to_shared(p);
}

__device__ __forceinline__ void ldm4(unsigned* r, unsigned addr) {
  asm volatile("ldmatrix.sync.aligned.m8n8.x4.shared.b16 {%0,%1,%2,%3}, [%4];"
               : "=r"(r[0]), "=r"(r[1]), "=r"(r[2]), "=r"(r[3]) : "r"(addr));
}
__device__ __forceinline__ void ldm4t(unsigned* r, unsigned addr) {
  asm volatile("ldmatrix.sync.aligned.m8n8.x4.trans.shared.b16 {%0,%1,%2,%3}, [%4];"
               : "=r"(r[0]), "=r"(r[1]), "=r"(r[2]), "=r"(r[3]) : "r"(addr));
}

__device__ __forceinline__ void cp_async16(void* smem, const void* gmem) {
  unsigned sa = (unsigned)__cvta_generic_to_shared(smem);
  asm volatile("cp.async.cg.shared.global [%0], [%1], 16;" ::"r"(sa), "l"(gmem));
}
#define CP_COMMIT asm volatile("cp.async.commit_group;")
#define CP_WAIT(n) asm volatile("cp.async.wait_group %0;" ::"n"(n))

// =====================================================================================
// bf16 tensor-core GEMM body, 512 threads (16 warps = 4m x 4n, warp tile 64x32).
// Block tile 256x128, BK=64 bf16 (128B rows), 72-half row stride (conflict-free).
// 3-stage cp.async pipeline, ONE barrier per slab:
//   wait(1) -> syncthreads -> stage(it+2) -> compute(it)
// =====================================================================================
#define BKH 64
#define LDHW 36  // words per row (= 72 halves = 64 data + 8 pad)
#define ASTGH (256 * LDHW)
#define BSTGH (128 * LDHW)
#define BGEMM_SMEM ((3 * ASTGH + 3 * BSTGH) * 4)  // 165888 B
#define GEMM_THR 512

template <int RELU, int OUTBF>
__device__ __forceinline__ void bgemm_body(
    const ushort_t* __restrict__ A, const ushort_t* __restrict__ W,
    const float* __restrict__ bp, void* __restrict__ Cv,
    int N, int K, int m0, int m_end, unsigned* smh) {
  int n0 = blockIdx.x * 128;
  unsigned* As = smh;
  unsigned* Bs = smh + 3 * ASTGH;

  int tid = threadIdx.x;
  int lane = tid & 31, wid = tid >> 5;
  int wm = (wid & 3) * 64;   // 4 warp-groups along m
  int wn = (wid >> 2) * 32;  // 4 warp-groups along n
  int g = lane >> 2, t = lane & 3;

  float acc[4][4][4];
#pragma unroll
  for (int i = 0; i < 4; i++)
#pragma unroll
    for (int j = 0; j < 4; j++)
#pragma unroll
      for (int l = 0; l < 4; l++) acc[i][j][l] = 0.f;

  unsigned a_base[4], b_base[2];
#pragma unroll
  for (int mf = 0; mf < 4; mf++) {
    int row = wm + mf * 16 + (lane & 15);
    a_base[mf] = smem_u32(As + row * LDHW) + ((lane >> 4) & 1) * 16;
  }
#pragma unroll
  for (int p = 0; p < 2; p++) {
    int row = wn + p * 16 + ((lane >> 4) & 1) * 8 + (lane & 7);
    b_base[p] = smem_u32(Bs + row * LDHW) + ((lane >> 3) & 1) * 16;
  }

  auto stage = [&](int s, int k0) {
    // A: 256 rows x 8 chunks(16B) = 2048 -> 4/thread
#pragma unroll
    for (int i = 0; i < 4; i++) {
      int idx = tid + i * GEMM_THR;
      int row = idx >> 3, kq = (idx & 7);
      int grow = m0 + row;
      if (grow < m_end)
        cp_async16(As + s * ASTGH + row * LDHW + kq * 4,
                   A + (size_t)grow * K + k0 + kq * 8);
    }
    // B: 128 rows x 8 chunks = 1024 -> 2/thread
#pragma unroll
    for (int i = 0; i < 2; i++) {
      int idx = tid + i * GEMM_THR;
      int row = idx >> 3, kq = (idx & 7);
      cp_async16(Bs + s * BSTGH + row * LDHW + kq * 4,
                 W + (size_t)(n0 + row) * K + k0 + kq * 8);
    }
  };

  int nslab = K / BKH;
  stage(0, 0);
  CP_COMMIT;
  stage(1, BKH);
  CP_COMMIT;

  for (int it = 0; it < nslab; it++) {
    int cur = it % 3;
    if (it + 2 < nslab) {
      CP_WAIT(1);
    } else {
      CP_WAIT(0);
    }
    __syncthreads();
    if (it + 2 < nslab) {
      stage((it + 2) % 3, (it + 2) * BKH);
      CP_COMMIT;
    }

    unsigned aoff = cur * (ASTGH * 4);
    unsigned boff = cur * (BSTGH * 4);
#pragma unroll
    for (int c = 0; c < 4; c++) {  // k16 chunks
      unsigned af[4][4];
#pragma unroll
      for (int mf = 0; mf < 4; mf++) ldm4(af[mf], a_base[mf] + aoff + c * 32);
#pragma unroll
      for (int p = 0; p < 2; p++) {
        unsigned bq[4];
        ldm4(bq, b_base[p] + boff + c * 32);
#pragma unroll
        for (int mf = 0; mf < 4; mf++) {
          mma_bf16(acc[mf][2 * p], af[mf], bq);
          mma_bf16(acc[mf][2 * p + 1], af[mf], bq + 2);
        }
      }
    }
  }

#pragma unroll
  for (int nf = 0; nf < 4; nf++) {
    int col = n0 + wn + nf * 8 + 2 * t;
    float2 bb = *(const float2*)(bp + col);
#pragma unroll
    for (int mf = 0; mf < 4; mf++) {
      int row0 = m0 + wm + mf * 16 + g;
      float v0 = acc[mf][nf][0] + bb.x;
      float v1 = acc[mf][nf][1] + bb.y;
      float v2 = acc[mf][nf][2] + bb.x;
      float v3 = acc[mf][nf][3] + bb.y;
      if (RELU) {
        v0 = fmaxf(v0, 0.f); v1 = fmaxf(v1, 0.f);
        v2 = fmaxf(v2, 0.f); v3 = fmaxf(v3, 0.f);
      }
      if (OUTBF) {
        ushort_t* C = (ushort_t*)Cv;
        if (row0 < m_end) *(unsigned*)(C + (size_t)row0 * N + col) = pk2(v0, v1);
        if (row0 + 8 < m_end) *(unsigned*)(C + (size_t)(row0 + 8) * N + col) = pk2(v2, v3);
      } else {
        float* C = (float*)Cv;
        if (row0 < m_end)
          *(float2*)(C + (size_t)row0 * N + col) = make_float2(v0, v1);
        if (row0 + 8 < m_end)
          *(float2*)(C + (size_t)(row0 + 8) * N + col) = make_float2(v2, v3);
      }
    }
  }
}

// Fused QKV projection (bf16 in/out): z selects (wq,bq,q)/(wk,bk,k)/(wv,bv,v)
__global__ void __launch_bounds__(GEMM_THR) bgemm_qkv(
    const ushort_t* __restrict__ A,
    const ushort_t* __restrict__ w0, const ushort_t* __restrict__ w1,
    const ushort_t* __restrict__ w2,
    const float* __restrict__ b0, const float* __restrict__ b1,
    const float* __restrict__ b2,
    ushort_t* __restrict__ c0, ushort_t* __restrict__ c1, ushort_t* __restrict__ c2) {
  extern __shared__ unsigned smh[];
  int z = blockIdx.z;
  const ushort_t* W = (z == 0) ? w0 : (z == 1) ? w1 : w2;
  const float* bb = (z == 0) ? b0 : (z == 1) ? b1 : b2;
  ushort_t* C = (z == 0) ? c0 : (z == 1) ? c1 : c2;
  int m0 = (int)blockIdx.y * 256;
  bgemm_body<0, 1>(A, W, bb, C, Dn, Dn, m0, Tn, smh);
}

// Dense O-projection (bf16 in, fp32 out)
__global__ void __launch_bounds__(GEMM_THR) bgemm_o(
    const ushort_t* __restrict__ A, const ushort_t* __restrict__ W,
    const float* __restrict__ bias, float* __restrict__ C) {
  extern __shared__ unsigned smh[];
  int m0 = (int)blockIdx.y * 256;
  bgemm_body<0, 0>(A, W, bias, C, Dn, Dn, m0, Tn, smh);
}

// Expert-batched MoE GEMM
template <int RELU, int OUTBF>
__global__ void __launch_bounds__(GEMM_THR) bgemm_moe(
    const ushort_t* __restrict__ A, const ushort_t* __restrict__ W,
    const float* __restrict__ bias, void* __restrict__ Cv,
    int N, int K, const int* __restrict__ off, size_t wstride) {
  extern __shared__ unsigned smh[];
  int e = blockIdx.z;
  int m_start = off[e], m_end = off[e + 1];
  int m0 = m_start + (int)blockIdx.y * 256;
  if (m0 >= m_end) return;
  bgemm_body<RELU, OUTBF>(A, W + (size_t)e * wstride, bias + (size_t)e * N, Cv,
                          N, K, m0, m_end, smh);
}

// fp32 -> bf16 bulk conversion (per-launch; graph-safe, deterministic)
__global__ void __launch_bounds__(256) cvt_bf16(
    const float* __restrict__ src, ushort_t* __restrict__ dst, int n4) {
  int i = blockIdx.x * 256 + threadIdx.x;
  if (i < n4) {
    float4 v = ((const float4*)src)[i];
    ((uint2*)dst)[i] = make_uint2(pk2(v.x, v.y), pk2(v.z, v.w));
  }
}

// =====================================================================================
// bf16 flash attention, 3-stage K/V pipeline; 2 CTAs/SM via launch_bounds(256,2).
// =====================================================================================
#define FQT 128
#define FKT 64
#define FSW 36
#define FNT (Sn / FKT)

__global__ void __launch_bounds__(256, 2) flash_bf(
    const ushort_t* __restrict__ Q, const ushort_t* __restrict__ K,
    const ushort_t* __restrict__ V, const int* __restrict__ mask,
    ushort_t* __restrict__ O) {
  __shared__ unsigned Qs[FQT * FSW];
  __shared__ unsigned Ks[3][FKT * FSW];
  __shared__ unsigned Vs[3][FKT * FSW];
  __shared__ int msk[3][FKT];

  int bh = blockIdx.y;
  int b = bh >> 4, h = bh & 15;
  int q0 = blockIdx.x * FQT;
  int tid = threadIdx.x;
  int lane = tid & 31, wid = tid >> 5;
  int g = lane >> 2, t = lane & 3;
  int wrow = wid * 16;

  auto stage_kv = [&](int s, int t0) {
#pragma unroll
    for (int l = 0; l < 2; l++) {
      int idx = tid + l * 256;
      int r = idx >> 3, ch = idx & 7;
      size_t base = (size_t)(b * Sn + t0 + r) * Dn + h * HDn + ch * 8;
      cp_async16(Ks[s] + r * FSW + ch * 4, K + base);
      cp_async16(Vs[s] + r * FSW + ch * 4, V + base);
    }
  };

#pragma unroll
  for (int l = 0; l < 4; l++) {
    int idx = tid + l * 256;
    int r = idx >> 3, ch = idx & 7;
    cp_async16(Qs + r * FSW + ch * 4,
               Q + (size_t)(b * Sn + q0 + r) * Dn + h * HDn + ch * 8);
  }
  stage_kv(0, 0);
  CP_COMMIT;
  stage_kv(1, FKT);
  CP_COMMIT;
  if (tid < FKT) {
    msk[0][tid] = mask[b * Sn + tid];
    msk[1][tid] = mask[b * Sn + FKT + tid];
  }

  float o[8][4];
#pragma unroll
  for (int nf = 0; nf < 8; nf++)
#pragma unroll
    for (int c = 0; c < 4; c++) o[nf][c] = 0.f;
  float mrow0 = -1e30f, mrow1 = -1e30f;
  float lrow0 = 0.f, lrow1 = 0.f;

  unsigned qa_base = smem_u32(Qs + (wrow + (lane & 15)) * FSW + (lane >> 4) * 4);
  unsigned kb_row = (lane & 7) + ((lane >> 4) & 1) * 8;
  unsigned kb_koff = ((lane >> 3) & 1) * 4;
  unsigned vb_key = (lane & 7) + ((lane >> 3) & 1) * 8;
  unsigned vb_doff = ((lane >> 4) & 1) * 4;

  for (int it = 0; it < FNT; it++) {
    int cur = it % 3;
    if (it + 2 < FNT) {
      CP_WAIT(1);
    } else {
      CP_WAIT(0);
    }
    __syncthreads();
    if (it + 2 < FNT) {
      int s = (it + 2) % 3;
      stage_kv(s, (it + 2) * FKT);
      CP_COMMIT;
      if (tid < FKT) msk[s][tid] = mask[b * Sn + (it + 2) * FKT + tid];
    }

    const unsigned* Kc = Ks[cur];
    const unsigned* Vc = Vs[cur];
    const int* mc = msk[cur];

    float s[8][4];
#pragma unroll
    for (int nf = 0; nf < 8; nf++)
#pragma unroll
      for (int c = 0; c < 4; c++) s[nf][c] = 0.f;

#pragma unroll
    for (int c = 0; c < 4; c++) {
      unsigned a[4];
      ldm4(a, qa_base + (c * 8) * 4);
#pragma unroll
      for (int ng = 0; ng < 4; ng++) {
        unsigned bq[4];
        unsigned addr = smem_u32(Kc + (ng * 16 + kb_row) * FSW + c * 8 + kb_koff);
        ldm4(bq, addr);
        mma_bf16(s[2 * ng], a, bq);
        mma_bf16(s[2 * ng + 1], a, bq + 2);
      }
    }

#pragma unroll
    for (int nf = 0; nf < 8; nf++) {
      int col = nf * 8 + 2 * t;
      bool z0 = (mc[col] == 0), z1 = (mc[col + 1] == 0);
      s[nf][0] = z0 ? -1e10f : s[nf][0] * 0.125f;
      s[nf][1] = z1 ? -1e10f : s[nf][1] * 0.125f;
      s[nf][2] = z0 ? -1e10f : s[nf][2] * 0.125f;
      s[nf][3] = z1 ? -1e10f : s[nf][3] * 0.125f;
    }

    float mx0 = -1e30f, mx1 = -1e30f;
#pragma unroll
    for (int nf = 0; nf < 8; nf++) {
      mx0 = fmaxf(mx0, fmaxf(s[nf][0], s[nf][1]));
      mx1 = fmaxf(mx1, fmaxf(s[nf][2], s[nf][3]));
    }
    mx0 = fmaxf(mx0, __shfl_xor_sync(0xffffffffu, mx0, 1));
    mx0 = fmaxf(mx0, __shfl_xor_sync(0xffffffffu, mx0, 2));
    mx1 = fmaxf(mx1, __shfl_xor_sync(0xffffffffu, mx1, 1));
    mx1 = fmaxf(mx1, __shfl_xor_sync(0xffffffffu, mx1, 2));

    float mn0 = fmaxf(mrow0, mx0), mn1 = fmaxf(mrow1, mx1);
    float sc0 = __expf(mrow0 - mn0), sc1 = __expf(mrow1 - mn1);
    mrow0 = mn0; mrow1 = mn1;

    float rs0 = 0.f, rs1 = 0.f;
    unsigned pk[8][2];
#pragma unroll
    for (int nf = 0; nf < 8; nf++) {
      s[nf][0] = __expf(s[nf][0] - mn0);
      s[nf][1] = __expf(s[nf][1] - mn0);
      s[nf][2] = __expf(s[nf][2] - mn1);
      s[nf][3] = __expf(s[nf][3] - mn1);
      rs0 += s[nf][0] + s[nf][1];
      rs1 += s[nf][2] + s[nf][3];
      pk[nf][0] = pk2(s[nf][0], s[nf][1]);
      pk[nf][1] = pk2(s[nf][2], s[nf][3]);
    }
    rs0 += __shfl_xor_sync(0xffffffffu, rs0, 1);
    rs0 += __shfl_xor_sync(0xffffffffu, rs0, 2);
    rs1 += __shfl_xor_sync(0xffffffffu, rs1, 1);
    rs1 += __shfl_xor_sync(0xffffffffu, rs1, 2);
    lrow0 = lrow0 * sc0 + rs0;
    lrow1 = lrow1 * sc1 + rs1;

#pragma unroll
    for (int nf = 0; nf < 8; nf++) {
      o[nf][0] *= sc0; o[nf][1] *= sc0;
      o[nf][2] *= sc1; o[nf][3] *= sc1;
    }

#pragma unroll
    for (int c = 0; c < 4; c++) {
      unsigned a[4] = {pk[2 * c][0], pk[2 * c][1], pk[2 * c + 1][0], pk[2 * c + 1][1]};
#pragma unroll
      for (int dg = 0; dg < 4; dg++) {
        unsigned bv[4];
        unsigned addr = smem_u32(Vc + (c * 16 + vb_key) * FSW + dg * 8 + vb_doff);
        ldm4t(bv, addr);
        mma_bf16(o[2 * dg], a, bv);
        mma_bf16(o[2 * dg + 1], a, bv + 2);
      }
    }
  }

  float inv0 = 1.f / lrow0, inv1 = 1.f / lrow1;
  int row = b * Sn + q0 + wrow + g;
#pragma unroll
  for (int nf = 0; nf < 8; nf++) {
    int col = h * HDn + nf * 8 + 2 * t;
    *(unsigned*)(O + (size_t)row * Dn + col) = pk2(o[nf][0] * inv0, o[nf][1] * inv0);
    *(unsigned*)(O + (size_t)(row + 8) * Dn + col) = pk2(o[nf][2] * inv1, o[nf][3] * inv1);
  }
}

// =====================================================================================
// out = LayerNorm(A + B) * g + be
// =====================================================================================
__global__ void __launch_bounds__(256) add_ln(
    const float* __restrict__ A, const float* __restrict__ Bv,
    const float* __restrict__ g, const float* __restrict__ be,
    float* __restrict__ out) {
  int t = blockIdx.x;
  int tid = threadIdx.x;
  float4 a = *(const float4*)(A + (size_t)t * Dn + tid * 4);
  float4 b = *(const float4*)(Bv + (size_t)t * Dn + tid * 4);
  float4 x = make_float4(a.x + b.x, a.y + b.y, a.z + b.z, a.w + b.w);
  float sumv = x.x + x.y + x.z + x.w;
  float sq = x.x * x.x + x.y * x.y + x.z * x.z + x.w * x.w;
#pragma unroll
  for (int off = 16; off; off >>= 1) {
    sumv += __shfl_xor_sync(0xffffffffu, sumv, off);
    sq += __shfl_xor_sync(0xffffffffu, sq, off);
  }
  __shared__ float ws[8], wq[8];
  __shared__ float s_mean, s_rstd;
  int wid = tid >> 5, lane = tid & 31;
  if (lane == 0) {
    ws[wid] = sumv;
    wq[wid] = sq;
  }
  __syncthreads();
  if (tid == 0) {
    float s = 0.f, q = 0.f;
#pragma unroll
    for (int i = 0; i < 8; i++) {
      s += ws[i];
      q += wq[i];
    }
    float mean = s * (1.f / Dn);
    float var = q * (1.f / Dn) - mean * mean;
    s_mean = mean;
    s_rstd = rsqrtf(var + 1e-5f);
  }
  __syncthreads();
  float mean = s_mean, rstd = s_rstd;
  float4 gg = *(const float4*)(g + tid * 4);
  float4 bb = *(const float4*)(be + tid * 4);
  float4 y;
  y.x = (x.x - mean) * rstd * gg.x + bb.x;
  y.y = (x.y - mean) * rstd * gg.y + bb.y;
  y.z = (x.z - mean) * rstd * gg.z + bb.z;
  y.w = (x.w - mean) * rstd * gg.w + bb.w;
  *(float4*)(out + (size_t)t * Dn + tid * 4) = y;
}

// =====================================================================================
// Router
// =====================================================================================
__global__ void __launch_bounds__(128) router_kernel(
    const float* __restrict__ x1, const float* __restrict__ sw,
    const float* __restrict__ sb, float* __restrict__ xs,
    int* __restrict__ route) {
  __shared__ float ssw[En * Dn];
  int t = blockIdx.x;
  int tid = threadIdx.x;
  for (int i = tid; i < En * Dn / 4; i += 128)
    ((float4*)ssw)[i] = ((const float4*)sw)[i];
  __syncthreads();

  float acc[En];
#pragma unroll
  for (int e = 0; e < En; e++) acc[e] = 0.f;
  float xv[8];
#pragma unroll
  for (int l = 0; l < 2; l++) {
    int d = (tid + l * 128) * 4;
    float4 x = *(const float4*)(x1 + (size_t)t * Dn + d);
    xv[l * 4 + 0] = x.x;
    xv[l * 4 + 1] = x.y;
    xv[l * 4 + 2] = x.z;
    xv[l * 4 + 3] = x.w;
#pragma unroll
    for (int e = 0; e < En; e++) {
      const float* swp = ssw + e * Dn + d;
      acc[e] += x.x * swp[0] + x.y * swp[1] + x.z * swp[2] + x.w * swp[3];
    }
  }
#pragma unroll
  for (int e = 0; e < En; e++)
#pragma unroll
    for (int off = 16; off; off >>= 1) acc[e] += __shfl_xor_sync(0xffffffffu, acc[e], off);

  __shared__ float wsum[4][En];
  __shared__ float s_p;
  int wid = tid >> 5, lane = tid & 31;
  if (lane == 0)
#pragma unroll
    for (int e = 0; e < En; e++) wsum[wid][e] = acc[e];
  __syncthreads();
  if (tid == 0) {
    float lg[En];
#pragma unroll
    for (int e = 0; e < En; e++)
      lg[e] = wsum[0][e] + wsum[1][e] + wsum[2][e] + wsum[3][e] + sb[e];
    int am = 0;
    float mx = lg[0];
#pragma unroll
    for (int e = 1; e < En; e++)
      if (lg[e] > mx) {
        mx = lg[e];
        am = e;
      }
    float sum = 0.f;
#pragma unroll
    for (int e = 0; e < En; e++) sum += __expf(lg[e] - mx);
    s_p = 1.f / sum;
    route[t] = am;
  }
  __syncthreads();
  float p = s_p;
#pragma unroll
  for (int l = 0; l < 2; l++) {
    int d = (tid + l * 128) * 4;
    float4 y = make_float4(xv[l * 4] * p, xv[l * 4 + 1] * p, xv[l * 4 + 2] * p,
                           xv[l * 4 + 3] * p);
    *(float4*)(xs + (size_t)t * Dn + d) = y;
  }
}

// =====================================================================================
// Deterministic stable counting sort by expert id (single block).
// =====================================================================================
__global__ void __launch_bounds__(256) sort_routes(
    const int* __restrict__ route, int* __restrict__ dest, int* __restrict__ off) {
  __shared__ int hist[256][En];
  __shared__ int tot[En];
  __shared__ int eoff[En + 1];
  int tid = threadIdx.x;
  int h[En];
#pragma unroll
  for (int e = 0; e < En; e++) h[e] = 0;
  int base = tid * 32;
  for (int i = 0; i < 32; i++) h[route[base + i]]++;
#pragma unroll
  for (int e = 0; e < En; e++) hist[tid][e] = h[e];
  __syncthreads();
  if (tid < En) {
    int e = tid;
    int run = 0;
    for (int i = 0; i < 256; i++) {
      int v = hist[i][e];
      hist[i][e] = run;
      run += v;
    }
    tot[e] = run;
  }
  __syncthreads();
  if (tid == 0) {
    int r = 0;
    for (int e = 0; e < En; e++) {
      eoff[e] = r;
      off[e] = r;
      r += tot[e];
    }
    eoff[En] = r;
    off[En] = r;
  }
  __syncthreads();
  int run[En];
#pragma unroll
  for (int e = 0; e < En; e++) run[e] = eoff[e] + hist[tid][e];
  for (int i = 0; i < 32; i++) {
    int e = route[base + i];
    dest[base + i] = run[e]++;
  }
}

// xsortb[dest[t], :] = bf16(xs[t, :])
__global__ void __launch_bounds__(256) gather_rows_bf(
    const float* __restrict__ xs, const int* __restrict__ dest,
    ushort_t* __restrict__ xsortb) {
  int t = blockIdx.x;
  int c = threadIdx.x;
  int dt = dest[t];
  float4 v = ((const float4*)xs)[(size_t)t * (Dn / 4) + c];
  ((uint2*)xsortb)[(size_t)dt * (Dn / 4) + c] =
      make_uint2(pk2(v.x, v.y), pk2(v.z, v.w));
}

// =====================================================================================
extern "C" void kernel_launch(void* const* d_in, const int* in_sizes, int n_in,
                              void* d_out, int out_size) {
  const float* x = (const float*)d_in[0];
  const float* wq = (const float*)d_in[1];
  const float* bq = (const float*)d_in[2];
  const float* wk = (const float*)d_in[3];
  const float* bk = (const float*)d_in[4];
  const float* wv = (const float*)d_in[5];
  const float* bv = (const float*)d_in[6];
  const float* wo = (const float*)d_in[7];
  const float* bo = (const float*)d_in[8];
  const float* ln1g = (const float*)d_in[9];
  const float* ln1b = (const float*)d_in[10];
  const float* ln2g = (const float*)d_in[11];
  const float* ln2b = (const float*)d_in[12];
  const float* sw = (const float*)d_in[13];
  const float* sb = (const float*)d_in[14];
  const float* ew1 = (const float*)d_in[15];
  const float* eb1 = (const float*)d_in[16];
  const float* ew2 = (const float*)d_in[17];
  const float* eb2 = (const float*)d_in[18];
  const int* mask = (const int*)d_in[19];
  float* out = (float*)d_out;

  ushort_t *xb, *qb, *kb, *vb, *ctxb, *wqb, *wkb, *wvb, *wob;
  ushort_t *xsortb, *h1b, *w1b, *w2b;
  float *ao, *x1, *xs, *moe;
  int *route, *dest, *off;
  cudaGetSymbolAddress((void**)&xb, g_xb);
  cudaGetSymbolAddress((void**)&qb, g_qb);
  cudaGetSymbolAddress((void**)&kb, g_kb);
  cudaGetSymbolAddress((void**)&vb, g_vb);
  cudaGetSymbolAddress((void**)&ctxb, g_ctxb);
  cudaGetSymbolAddress((void**)&wqb, g_wqb);
  cudaGetSymbolAddress((void**)&wkb, g_wkb);
  cudaGetSymbolAddress((void**)&wvb, g_wvb);
  cudaGetSymbolAddress((void**)&wob, g_wob);
  cudaGetSymbolAddress((void**)&ao, g_ao);
  cudaGetSymbolAddress((void**)&x1, g_x1);
  cudaGetSymbolAddress((void**)&xs, g_xs);
  cudaGetSymbolAddress((void**)&moe, g_moe);
  cudaGetSymbolAddress((void**)&xsortb, g_xsortb);
  cudaGetSymbolAddress((void**)&h1b, g_h1b);
  cudaGetSymbolAddress((void**)&w1b, g_w1b);
  cudaGetSymbolAddress((void**)&w2b, g_w2b);
  cudaGetSymbolAddress((void**)&route, g_route);
  cudaGetSymbolAddress((void**)&dest, g_dest);
  cudaGetSymbolAddress((void**)&off, g_off);

  cudaFuncSetAttribute(bgemm_qkv, cudaFuncAttributeMaxDynamicSharedMemorySize, BGEMM_SMEM);
  cudaFuncSetAttribute(bgemm_o, cudaFuncAttributeMaxDynamicSharedMemorySize, BGEMM_SMEM);
  cudaFuncSetAttribute(bgemm_moe<1, 1>, cudaFuncAttributeMaxDynamicSharedMemorySize, BGEMM_SMEM);
  cudaFuncSetAttribute(bgemm_moe<0, 0>, cudaFuncAttributeMaxDynamicSharedMemorySize, BGEMM_SMEM);

  dim3 blk(256);
  dim3 gblk(GEMM_THR);

  // --- conversions (bandwidth-bound) ---
  const int XN4 = Tn * Dn / 4;
  const int WN4 = Dn * Dn / 4;
  const int W1N4 = En * Fn * Dn / 4;
  cvt_bf16<<<(XN4 + 255) / 256, blk>>>(x, xb, XN4);
  cvt_bf16<<<(WN4 + 255) / 256, blk>>>(wq, wqb, WN4);
  cvt_bf16<<<(WN4 + 255) / 256, blk>>>(wk, wkb, WN4);
  cvt_bf16<<<(WN4 + 255) / 256, blk>>>(wv, wvb, WN4);
  cvt_bf16<<<(WN4 + 255) / 256, blk>>>(wo, wob, WN4);
  cvt_bf16<<<(W1N4 + 255) / 256, blk>>>(ew1, w1b, W1N4);
  cvt_bf16<<<(W1N4 + 255) / 256, blk>>>(ew2, w2b, W1N4);

  // --- attention block ---
  bgemm_qkv<<<dim3(Dn / 128, Tn / 256, 3), gblk, BGEMM_SMEM>>>(
      xb, wqb, wkb, wvb, bq, bk, bv, qb, kb, vb);
  flash_bf<<<dim3(Sn / FQT, Bn * Hn), blk>>>(qb, kb, vb, mask, ctxb);
  bgemm_o<<<dim3(Dn / 128, Tn / 256, 1), gblk, BGEMM_SMEM>>>(ctxb, wob, bo, ao);
  add_ln<<<Tn, 256>>>(x, ao, ln1g, ln1b, x1);

  // --- MoE block ---
  router_kernel<<<Tn, 128>>>(x1, sw, sb, xs, route);
  sort_routes<<<1, 256>>>(route, dest, off);
  gather_rows_bf<<<Tn, 256>>>(xs, dest, xsortb);
  bgemm_moe<1, 1><<<dim3(Fn / 128, Tn / 256, En), gblk, BGEMM_SMEM>>>(
      xsortb, w1b, eb1, h1b, Fn, Dn, off, (size_t)Fn * Dn);
  bgemm_moe<0, 0><<<dim3(Dn / 128, Tn / 256, En), gblk, BGEMM_SMEM>>>(
      h1b, w2b, eb2, moe, Dn, Fn, off, (size_t)Dn * Fn);
  add_ln<<<Tn, 256>>>(x1, moe, ln2g, ln2b, out);
}

// round 12
// speedup vs baseline: 6.4447x; 1.0054x over previous
#include <cuda_runtime.h>
#include <math.h>

// Problem dims (fixed by the reference)
#define Tn 8192
#define Dn 1024
#define Hn 16
#define HDn 64
#define Fn 4096
#define En 8
#define Bn 4
#define Sn 2048

typedef unsigned short ushort_t;

// ---------------- scratch (static device allocations; no cudaMalloc allowed) ---------
__device__ ushort_t g_xb[Tn * Dn];        // bf16 x
__device__ ushort_t g_qb[Tn * Dn];        // bf16 q
__device__ ushort_t g_kb[Tn * Dn];        // bf16 k
__device__ ushort_t g_vb[Tn * Dn];        // bf16 v
__device__ ushort_t g_ctxb[Tn * Dn];      // bf16 ctx
__device__ ushort_t g_wqb[Dn * Dn];
__device__ ushort_t g_wkb[Dn * Dn];
__device__ ushort_t g_wvb[Dn * Dn];
__device__ ushort_t g_wob[Dn * Dn];
__device__ float g_ao[Tn * Dn];
__device__ float g_x1[Tn * Dn];
__device__ float g_pmax[Tn];
__device__ float g_moe[Tn * Dn];
__device__ ushort_t g_xsortb[Tn * Dn];
__device__ ushort_t g_h1b[(size_t)Tn * Fn];
__device__ ushort_t g_w1b[(size_t)En * Fn * Dn];
__device__ ushort_t g_w2b[(size_t)En * Dn * Fn];
__device__ int g_route[Tn];
__device__ int g_dest[Tn];
__device__ int g_off[En + 1];

__device__ __forceinline__ void mma_bf16(float* c, const unsigned* a, const unsigned* b) {
  asm volatile(
      "mma.sync.aligned.m16n8k16.row.col.f32.bf16.bf16.f32 "
      "{%0,%1,%2,%3},{%4,%5,%6,%7},{%8,%9},{%0,%1,%2,%3};"
      : "+f"(c[0]), "+f"(c[1]), "+f"(c[2]), "+f"(c[3])
      : "r"(a[0]), "r"(a[1]), "r"(a[2]), "r"(a[3]), "r"(b[0]), "r"(b[1]));
}

// pack two f32 -> bf16x2 (lo = first arg, hi = second)
__device__ __forceinline__ unsigned pk2(float lo, float hi) {
  unsigned r;
  asm("cvt.rn.bf16x2.f32 %0, %1, %2;" : "=r"(r) : "f"(hi), "f"(lo));
  return r;
}

__device__ __forceinline__ unsigned smem_u32(const void* p) {
  return (unsigned)__cvta_generic_to_shared(p);
}

__device__ __forceinline__ void ldm4(unsigned* r, unsigned addr) {
  asm volatile("ldmatrix.sync.aligned.m8n8.x4.shared.b16 {%0,%1,%2,%3}, [%4];"
               : "=r"(r[0]), "=r"(r[1]), "=r"(r[2]), "=r"(r[3]) : "r"(addr));
}
__device__ __forceinline__ void ldm4t(unsigned* r, unsigned addr) {
  asm volatile("ldmatrix.sync.aligned.m8n8.x4.trans.shared.b16 {%0,%1,%2,%3}, [%4];"
               : "=r"(r[0]), "=r"(r[1]), "=r"(r[2]), "=r"(r[3]) : "r"(addr));
}

__device__ __forceinline__ void cp_async16(void* smem, const void* gmem) {
  unsigned sa = (unsigned)__cvta_generic_to_shared(smem);
  asm volatile("cp.async.cg.shared.global [%0], [%1], 16;" ::"r"(sa), "l"(gmem));
}
#define CP_COMMIT asm volatile("cp.async.commit_group;")
#define CP_WAIT(n) asm volatile("cp.async.wait_group %0;" ::"n"(n))

// =====================================================================================
// bf16 tensor-core GEMM body, 512 threads (16 warps = 4m x 4n, warp tile 64x32).
// Block tile 256x128, BK=64 bf16 (128B rows), 72-half row stride (conflict-free).
// 3-stage cp.async pipeline, ONE barrier per slab.
// =====================================================================================
#define BKH 64
#define LDHW 36  // words per row (= 72 halves = 64 data + 8 pad)
#define ASTGH (256 * LDHW)
#define BSTGH (128 * LDHW)
#define BGEMM_SMEM ((3 * ASTGH + 3 * BSTGH) * 4)  // 165888 B
#define GEMM_THR 512

template <int RELU, int OUTBF>
__device__ __forceinline__ void bgemm_body(
    const ushort_t* __restrict__ A, const ushort_t* __restrict__ W,
    const float* __restrict__ bp, void* __restrict__ Cv,
    int N, int K, int m0, int m_end, unsigned* smh) {
  int n0 = blockIdx.x * 128;
  unsigned* As = smh;
  unsigned* Bs = smh + 3 * ASTGH;

  int tid = threadIdx.x;
  int lane = tid & 31, wid = tid >> 5;
  int wm = (wid & 3) * 64;   // 4 warp-groups along m
  int wn = (wid >> 2) * 32;  // 4 warp-groups along n
  int g = lane >> 2, t = lane & 3;

  float acc[4][4][4];
#pragma unroll
  for (int i = 0; i < 4; i++)
#pragma unroll
    for (int j = 0; j < 4; j++)
#pragma unroll
      for (int l = 0; l < 4; l++) acc[i][j][l] = 0.f;

  unsigned a_base[4], b_base[2];
#pragma unroll
  for (int mf = 0; mf < 4; mf++) {
    int row = wm + mf * 16 + (lane & 15);
    a_base[mf] = smem_u32(As + row * LDHW) + ((lane >> 4) & 1) * 16;
  }
#pragma unroll
  for (int p = 0; p < 2; p++) {
    int row = wn + p * 16 + ((lane >> 4) & 1) * 8 + (lane & 7);
    b_base[p] = smem_u32(Bs + row * LDHW) + ((lane >> 3) & 1) * 16;
  }

  auto stage = [&](int s, int k0) {
#pragma unroll
    for (int i = 0; i < 4; i++) {
      int idx = tid + i * GEMM_THR;
      int row = idx >> 3, kq = (idx & 7);
      int grow = m0 + row;
      if (grow < m_end)
        cp_async16(As + s * ASTGH + row * LDHW + kq * 4,
                   A + (size_t)grow * K + k0 + kq * 8);
    }
#pragma unroll
    for (int i = 0; i < 2; i++) {
      int idx = tid + i * GEMM_THR;
      int row = idx >> 3, kq = (idx & 7);
      cp_async16(Bs + s * BSTGH + row * LDHW + kq * 4,
                 W + (size_t)(n0 + row) * K + k0 + kq * 8);
    }
  };

  int nslab = K / BKH;
  stage(0, 0);
  CP_COMMIT;
  stage(1, BKH);
  CP_COMMIT;

  for (int it = 0; it < nslab; it++) {
    int cur = it % 3;
    if (it + 2 < nslab) {
      CP_WAIT(1);
    } else {
      CP_WAIT(0);
    }
    __syncthreads();
    if (it + 2 < nslab) {
      stage((it + 2) % 3, (it + 2) * BKH);
      CP_COMMIT;
    }

    unsigned aoff = cur * (ASTGH * 4);
    unsigned boff = cur * (BSTGH * 4);
#pragma unroll
    for (int c = 0; c < 4; c++) {  // k16 chunks
      unsigned af[4][4];
#pragma unroll
      for (int mf = 0; mf < 4; mf++) ldm4(af[mf], a_base[mf] + aoff + c * 32);
#pragma unroll
      for (int p = 0; p < 2; p++) {
        unsigned bq[4];
        ldm4(bq, b_base[p] + boff + c * 32);
#pragma unroll
        for (int mf = 0; mf < 4; mf++) {
          mma_bf16(acc[mf][2 * p], af[mf], bq);
          mma_bf16(acc[mf][2 * p + 1], af[mf], bq + 2);
        }
      }
    }
  }

#pragma unroll
  for (int nf = 0; nf < 4; nf++) {
    int col = n0 + wn + nf * 8 + 2 * t;
    float2 bb = *(const float2*)(bp + col);
#pragma unroll
    for (int mf = 0; mf < 4; mf++) {
      int row0 = m0 + wm + mf * 16 + g;
      float v0 = acc[mf][nf][0] + bb.x;
      float v1 = acc[mf][nf][1] + bb.y;
      float v2 = acc[mf][nf][2] + bb.x;
      float v3 = acc[mf][nf][3] + bb.y;
      if (RELU) {
        v0 = fmaxf(v0, 0.f); v1 = fmaxf(v1, 0.f);
        v2 = fmaxf(v2, 0.f); v3 = fmaxf(v3, 0.f);
      }
      if (OUTBF) {
        ushort_t* C = (ushort_t*)Cv;
        if (row0 < m_end) *(unsigned*)(C + (size_t)row0 * N + col) = pk2(v0, v1);
        if (row0 + 8 < m_end) *(unsigned*)(C + (size_t)(row0 + 8) * N + col) = pk2(v2, v3);
      } else {
        float* C = (float*)Cv;
        if (row0 < m_end)
          *(float2*)(C + (size_t)row0 * N + col) = make_float2(v0, v1);
        if (row0 + 8 < m_end)
          *(float2*)(C + (size_t)(row0 + 8) * N + col) = make_float2(v2, v3);
      }
    }
  }
}

// Fused QKV projection (bf16 in/out): z selects (wq,bq,q)/(wk,bk,k)/(wv,bv,v)
__global__ void __launch_bounds__(GEMM_THR) bgemm_qkv(
    const ushort_t* __restrict__ A,
    const ushort_t* __restrict__ w0, const ushort_t* __restrict__ w1,
    const ushort_t* __restrict__ w2,
    const float* __restrict__ b0, const float* __restrict__ b1,
    const float* __restrict__ b2,
    ushort_t* __restrict__ c0, ushort_t* __restrict__ c1, ushort_t* __restrict__ c2) {
  extern __shared__ unsigned smh[];
  int z = blockIdx.z;
  const ushort_t* W = (z == 0) ? w0 : (z == 1) ? w1 : w2;
  const float* bb = (z == 0) ? b0 : (z == 1) ? b1 : b2;
  ushort_t* C = (z == 0) ? c0 : (z == 1) ? c1 : c2;
  int m0 = (int)blockIdx.y * 256;
  bgemm_body<0, 1>(A, W, bb, C, Dn, Dn, m0, Tn, smh);
}

// Dense O-projection (bf16 in, fp32 out)
__global__ void __launch_bounds__(GEMM_THR) bgemm_o(
    const ushort_t* __restrict__ A, const ushort_t* __restrict__ W,
    const float* __restrict__ bias, float* __restrict__ C) {
  extern __shared__ unsigned smh[];
  int m0 = (int)blockIdx.y * 256;
  bgemm_body<0, 0>(A, W, bias, C, Dn, Dn, m0, Tn, smh);
}

// Expert-batched MoE GEMM
template <int RELU, int OUTBF>
__global__ void __launch_bounds__(GEMM_THR) bgemm_moe(
    const ushort_t* __restrict__ A, const ushort_t* __restrict__ W,
    const float* __restrict__ bias, void* __restrict__ Cv,
    int N, int K, const int* __restrict__ off, size_t wstride) {
  extern __shared__ unsigned smh[];
  int e = blockIdx.z;
  int m_start = off[e], m_end = off[e + 1];
  int m0 = m_start + (int)blockIdx.y * 256;
  if (m0 >= m_end) return;
  bgemm_body<RELU, OUTBF>(A, W + (size_t)e * wstride, bias + (size_t)e * N, Cv,
                          N, K, m0, m_end, smh);
}

// fp32 -> bf16 bulk conversion (per-launch; graph-safe, deterministic)
__global__ void __launch_bounds__(256) cvt_bf16(
    const float* __restrict__ src, ushort_t* __restrict__ dst, int n4) {
  int i = blockIdx.x * 256 + threadIdx.x;
  if (i < n4) {
    float4 v = ((const float4*)src)[i];
    ((uint2*)dst)[i] = make_uint2(pk2(v.x, v.y), pk2(v.z, v.w));
  }
}

// 4-way dense weight conversion in one launch (grid.z selects tensor)
__global__ void __launch_bounds__(256) cvt_bf16x4(
    const float* __restrict__ s0, const float* __restrict__ s1,
    const float* __restrict__ s2, const float* __restrict__ s3,
    ushort_t* __restrict__ d0, ushort_t* __restrict__ d1,
    ushort_t* __restrict__ d2, ushort_t* __restrict__ d3, int n4) {
  int z = blockIdx.z;
  const float* src = (z == 0) ? s0 : (z == 1) ? s1 : (z == 2) ? s2 : s3;
  ushort_t* dst = (z == 0) ? d0 : (z == 1) ? d1 : (z == 2) ? d2 : d3;
  int i = blockIdx.x * 256 + threadIdx.x;
  if (i < n4) {
    float4 v = ((const float4*)src)[i];
    ((uint2*)dst)[i] = make_uint2(pk2(v.x, v.y), pk2(v.z, v.w));
  }
}

// =====================================================================================
// bf16 flash attention, 3-stage K/V pipeline; 2 CTAs/SM.
// =====================================================================================
#define FQT 128
#define FKT 64
#define FSW 36
#define FNT (Sn / FKT)

__global__ void __launch_bounds__(256, 2) flash_bf(
    const ushort_t* __restrict__ Q, const ushort_t* __restrict__ K,
    const ushort_t* __restrict__ V, const int* __restrict__ mask,
    ushort_t* __restrict__ O) {
  __shared__ unsigned Qs[FQT * FSW];
  __shared__ unsigned Ks[3][FKT * FSW];
  __shared__ unsigned Vs[3][FKT * FSW];
  __shared__ int msk[3][FKT];

  int bh = blockIdx.y;
  int b = bh >> 4, h = bh & 15;
  int q0 = blockIdx.x * FQT;
  int tid = threadIdx.x;
  int lane = tid & 31, wid = tid >> 5;
  int g = lane >> 2, t = lane & 3;
  int wrow = wid * 16;

  auto stage_kv = [&](int s, int t0) {
#pragma unroll
    for (int l = 0; l < 2; l++) {
      int idx = tid + l * 256;
      int r = idx >> 3, ch = idx & 7;
      size_t base = (size_t)(b * Sn + t0 + r) * Dn + h * HDn + ch * 8;
      cp_async16(Ks[s] + r * FSW + ch * 4, K + base);
      cp_async16(Vs[s] + r * FSW + ch * 4, V + base);
    }
  };

#pragma unroll
  for (int l = 0; l < 4; l++) {
    int idx = tid + l * 256;
    int r = idx >> 3, ch = idx & 7;
    cp_async16(Qs + r * FSW + ch * 4,
               Q + (size_t)(b * Sn + q0 + r) * Dn + h * HDn + ch * 8);
  }
  stage_kv(0, 0);
  CP_COMMIT;
  stage_kv(1, FKT);
  CP_COMMIT;
  if (tid < FKT) {
    msk[0][tid] = mask[b * Sn + tid];
    msk[1][tid] = mask[b * Sn + FKT + tid];
  }

  float o[8][4];
#pragma unroll
  for (int nf = 0; nf < 8; nf++)
#pragma unroll
    for (int c = 0; c < 4; c++) o[nf][c] = 0.f;
  float mrow0 = -1e30f, mrow1 = -1e30f;
  float lrow0 = 0.f, lrow1 = 0.f;

  unsigned qa_base = smem_u32(Qs + (wrow + (lane & 15)) * FSW + (lane >> 4) * 4);
  unsigned kb_row = (lane & 7) + ((lane >> 4) & 1) * 8;
  unsigned kb_koff = ((lane >> 3) & 1) * 4;
  unsigned vb_key = (lane & 7) + ((lane >> 3) & 1) * 8;
  unsigned vb_doff = ((lane >> 4) & 1) * 4;

  for (int it = 0; it < FNT; it++) {
    int cur = it % 3;
    if (it + 2 < FNT) {
      CP_WAIT(1);
    } else {
      CP_WAIT(0);
    }
    __syncthreads();
    if (it + 2 < FNT) {
      int s = (it + 2) % 3;
      stage_kv(s, (it + 2) * FKT);
      CP_COMMIT;
      if (tid < FKT) msk[s][tid] = mask[b * Sn + (it + 2) * FKT + tid];
    }

    const unsigned* Kc = Ks[cur];
    const unsigned* Vc = Vs[cur];
    const int* mc = msk[cur];

    float s[8][4];
#pragma unroll
    for (int nf = 0; nf < 8; nf++)
#pragma unroll
      for (int c = 0; c < 4; c++) s[nf][c] = 0.f;

#pragma unroll
    for (int c = 0; c < 4; c++) {
      unsigned a[4];
      ldm4(a, qa_base + (c * 8) * 4);
#pragma unroll
      for (int ng = 0; ng < 4; ng++) {
        unsigned bq[4];
        unsigned addr = smem_u32(Kc + (ng * 16 + kb_row) * FSW + c * 8 + kb_koff);
        ldm4(bq, addr);
        mma_bf16(s[2 * ng], a, bq);
        mma_bf16(s[2 * ng + 1], a, bq + 2);
      }
    }

#pragma unroll
    for (int nf = 0; nf < 8; nf++) {
      int col = nf * 8 + 2 * t;
      bool z0 = (mc[col] == 0), z1 = (mc[col + 1] == 0);
      s[nf][0] = z0 ? -1e10f : s[nf][0] * 0.125f;
      s[nf][1] = z1 ? -1e10f : s[nf][1] * 0.125f;
      s[nf][2] = z0 ? -1e10f : s[nf][2] * 0.125f;
      s[nf][3] = z1 ? -1e10f : s[nf][3] * 0.125f;
    }

    float mx0 = -1e30f, mx1 = -1e30f;
#pragma unroll
    for (int nf = 0; nf < 8; nf++) {
      mx0 = fmaxf(mx0, fmaxf(s[nf][0], s[nf][1]));
      mx1 = fmaxf(mx1, fmaxf(s[nf][2], s[nf][3]));
    }
    mx0 = fmaxf(mx0, __shfl_xor_sync(0xffffffffu, mx0, 1));
    mx0 = fmaxf(mx0, __shfl_xor_sync(0xffffffffu, mx0, 2));
    mx1 = fmaxf(mx1, __shfl_xor_sync(0xffffffffu, mx1, 1));
    mx1 = fmaxf(mx1, __shfl_xor_sync(0xffffffffu, mx1, 2));

    float mn0 = fmaxf(mrow0, mx0), mn1 = fmaxf(mrow1, mx1);
    float sc0 = __expf(mrow0 - mn0), sc1 = __expf(mrow1 - mn1);
    mrow0 = mn0; mrow1 = mn1;

    float rs0 = 0.f, rs1 = 0.f;
    unsigned pk[8][2];
#pragma unroll
    for (int nf = 0; nf < 8; nf++) {
      s[nf][0] = __expf(s[nf][0] - mn0);
      s[nf][1] = __expf(s[nf][1] - mn0);
      s[nf][2] = __expf(s[nf][2] - mn1);
      s[nf][3] = __expf(s[nf][3] - mn1);
      rs0 += s[nf][0] + s[nf][1];
      rs1 += s[nf][2] + s[nf][3];
      pk[nf][0] = pk2(s[nf][0], s[nf][1]);
      pk[nf][1] = pk2(s[nf][2], s[nf][3]);
    }
    rs0 += __shfl_xor_sync(0xffffffffu, rs0, 1);
    rs0 += __shfl_xor_sync(0xffffffffu, rs0, 2);
    rs1 += __shfl_xor_sync(0xffffffffu, rs1, 1);
    rs1 += __shfl_xor_sync(0xffffffffu, rs1, 2);
    lrow0 = lrow0 * sc0 + rs0;
    lrow1 = lrow1 * sc1 + rs1;

#pragma unroll
    for (int nf = 0; nf < 8; nf++) {
      o[nf][0] *= sc0; o[nf][1] *= sc0;
      o[nf][2] *= sc1; o[nf][3] *= sc1;
    }

#pragma unroll
    for (int c = 0; c < 4; c++) {
      unsigned a[4] = {pk[2 * c][0], pk[2 * c][1], pk[2 * c + 1][0], pk[2 * c + 1][1]};
#pragma unroll
      for (int dg = 0; dg < 4; dg++) {
        unsigned bv[4];
        unsigned addr = smem_u32(Vc + (c * 16 + vb_key) * FSW + dg * 8 + vb_doff);
        ldm4t(bv, addr);
        mma_bf16(o[2 * dg], a, bv);
        mma_bf16(o[2 * dg + 1], a, bv + 2);
      }
    }
  }

  float inv0 = 1.f / lrow0, inv1 = 1.f / lrow1;
  int row = b * Sn + q0 + wrow + g;
#pragma unroll
  for (int nf = 0; nf < 8; nf++) {
    int col = h * HDn + nf * 8 + 2 * t;
    *(unsigned*)(O + (size_t)row * Dn + col) = pk2(o[nf][0] * inv0, o[nf][1] * inv0);
    *(unsigned*)(O + (size_t)(row + 8) * Dn + col) = pk2(o[nf][2] * inv1, o[nf][3] * inv1);
  }
}

// =====================================================================================
// out = LayerNorm(A + B) * g + be
// =====================================================================================
__global__ void __launch_bounds__(256) add_ln(
    const float* __restrict__ A, const float* __restrict__ Bv,
    const float* __restrict__ g, const float* __restrict__ be,
    float* __restrict__ out) {
  int t = blockIdx.x;
  int tid = threadIdx.x;
  float4 a = *(const float4*)(A + (size_t)t * Dn + tid * 4);
  float4 b = *(const float4*)(Bv + (size_t)t * Dn + tid * 4);
  float4 x = make_float4(a.x + b.x, a.y + b.y, a.z + b.z, a.w + b.w);
  float sumv = x.x + x.y + x.z + x.w;
  float sq = x.x * x.x + x.y * x.y + x.z * x.z + x.w * x.w;
#pragma unroll
  for (int off = 16; off; off >>= 1) {
    sumv += __shfl_xor_sync(0xffffffffu, sumv, off);
    sq += __shfl_xor_sync(0xffffffffu, sq, off);
  }
  __shared__ float ws[8], wq[8];
  __shared__ float s_mean, s_rstd;
  int wid = tid >> 5, lane = tid & 31;
  if (lane == 0) {
    ws[wid] = sumv;
    wq[wid] = sq;
  }
  __syncthreads();
  if (tid == 0) {
    float s = 0.f, q = 0.f;
#pragma unroll
    for (int i = 0; i < 8; i++) {
      s += ws[i];
      q += wq[i];
    }
    float mean = s * (1.f / Dn);
    float var = q * (1.f / Dn) - mean * mean;
    s_mean = mean;
    s_rstd = rsqrtf(var + 1e-5f);
  }
  __syncthreads();
  float mean = s_mean, rstd = s_rstd;
  float4 gg = *(const float4*)(g + tid * 4);
  float4 bb = *(const float4*)(be + tid * 4);
  float4 y;
  y.x = (x.x - mean) * rstd * gg.x + bb.x;
  y.y = (x.y - mean) * rstd * gg.y + bb.y;
  y.z = (x.z - mean) * rstd * gg.z + bb.z;
  y.w = (x.w - mean) * rstd * gg.w + bb.w;
  *(float4*)(out + (size_t)t * Dn + tid * 4) = y;
}

// =====================================================================================
// Router v2: 64 blocks x 256 threads, 128 tokens/block, warp-per-token.
// switch_w loaded to smem ONCE per block (64x vs 8192x before).
// Emits route[t] and pmax[t] only (xs intermediate eliminated).
// =====================================================================================
#define RT_TPB 128

__global__ void __launch_bounds__(256) router2(
    const float* __restrict__ x1, const float* __restrict__ sw,
    const float* __restrict__ sb, float* __restrict__ pmax,
    int* __restrict__ route) {
  __shared__ float ssw[En * Dn];
  int tid = threadIdx.x, lane = tid & 31, wid = tid >> 5;
  for (int i = tid; i < En * Dn / 4; i += 256)
    ((float4*)ssw)[i] = ((const float4*)sw)[i];
  __syncthreads();

  int t0 = blockIdx.x * RT_TPB;
#pragma unroll 1
  for (int i = 0; i < RT_TPB / 8; i++) {
    int t = t0 + i * 8 + wid;
    float acc[En];
#pragma unroll
    for (int e = 0; e < En; e++) acc[e] = 0.f;
#pragma unroll
    for (int c = 0; c < Dn / 128; c++) {
      int d = c * 128 + lane * 4;
      float4 xv = *(const float4*)(x1 + (size_t)t * Dn + d);
#pragma unroll
      for (int e = 0; e < En; e++) {
        const float* swp = ssw + e * Dn + d;
        acc[e] += xv.x * swp[0] + xv.y * swp[1] + xv.z * swp[2] + xv.w * swp[3];
      }
    }
#pragma unroll
    for (int e = 0; e < En; e++)
#pragma unroll
      for (int off = 16; off; off >>= 1)
        acc[e] += __shfl_xor_sync(0xffffffffu, acc[e], off);
    if (lane == 0) {
      float lg[En];
#pragma unroll
      for (int e = 0; e < En; e++) lg[e] = acc[e] + sb[e];
      int am = 0;
      float mx = lg[0];
#pragma unroll
      for (int e = 1; e < En; e++)
        if (lg[e] > mx) {  // strict > == jnp.argmax first-max tie-break
          mx = lg[e];
          am = e;
        }
      float sum = 0.f;
#pragma unroll
      for (int e = 0; e < En; e++) sum += __expf(lg[e] - mx);
      route[t] = am;
      pmax[t] = 1.f / sum;
    }
  }
}

// =====================================================================================
// Deterministic stable counting sort by expert id (single block).
// =====================================================================================
__global__ void __launch_bounds__(256) sort_routes(
    const int* __restrict__ route, int* __restrict__ dest, int* __restrict__ off) {
  __shared__ int hist[256][En];
  __shared__ int tot[En];
  __shared__ int eoff[En + 1];
  int tid = threadIdx.x;
  int h[En];
#pragma unroll
  for (int e = 0; e < En; e++) h[e] = 0;
  int base = tid * 32;
  for (int i = 0; i < 32; i++) h[route[base + i]]++;
#pragma unroll
  for (int e = 0; e < En; e++) hist[tid][e] = h[e];
  __syncthreads();
  if (tid < En) {
    int e = tid;
    int run = 0;
    for (int i = 0; i < 256; i++) {
      int v = hist[i][e];
      hist[i][e] = run;
      run += v;
    }
    tot[e] = run;
  }
  __syncthreads();
  if (tid == 0) {
    int r = 0;
    for (int e = 0; e < En; e++) {
      eoff[e] = r;
      off[e] = r;
      r += tot[e];
    }
    eoff[En] = r;
    off[En] = r;
  }
  __syncthreads();
  int run[En];
#pragma unroll
  for (int e = 0; e < En; e++) run[e] = eoff[e] + hist[tid][e];
  for (int i = 0; i < 32; i++) {
    int e = route[base + i];
    dest[base + i] = run[e]++;
  }
}

// xsortb[dest[t], :] = bf16(x1[t, :] * pmax[t])
__global__ void __launch_bounds__(256) gather_rows_bf(
    const float* __restrict__ x1, const float* __restrict__ pmax,
    const int* __restrict__ dest, ushort_t* __restrict__ xsortb) {
  int t = blockIdx.x;
  int c = threadIdx.x;
  int dt = dest[t];
  float p = pmax[t];
  float4 v = ((const float4*)x1)[(size_t)t * (Dn / 4) + c];
  ((uint2*)xsortb)[(size_t)dt * (Dn / 4) + c] =
      make_uint2(pk2(v.x * p, v.y * p), pk2(v.z * p, v.w * p));
}

// =====================================================================================
extern "C" void kernel_launch(void* const* d_in, const int* in_sizes, int n_in,
                              void* d_out, int out_size) {
  const float* x = (const float*)d_in[0];
  const float* wq = (const float*)d_in[1];
  const float* bq = (const float*)d_in[2];
  const float* wk = (const float*)d_in[3];
  const float* bk = (const float*)d_in[4];
  const float* wv = (const float*)d_in[5];
  const float* bv = (const float*)d_in[6];
  const float* wo = (const float*)d_in[7];
  const float* bo = (const float*)d_in[8];
  const float* ln1g = (const float*)d_in[9];
  const float* ln1b = (const float*)d_in[10];
  const float* ln2g = (const float*)d_in[11];
  const float* ln2b = (const float*)d_in[12];
  const float* sw = (const float*)d_in[13];
  const float* sb = (const float*)d_in[14];
  const float* ew1 = (const float*)d_in[15];
  const float* eb1 = (const float*)d_in[16];
  const float* ew2 = (const float*)d_in[17];
  const float* eb2 = (const float*)d_in[18];
  const int* mask = (const int*)d_in[19];
  float* out = (float*)d_out;

  ushort_t *xb, *qb, *kb, *vb, *ctxb, *wqb, *wkb, *wvb, *wob;
  ushort_t *xsortb, *h1b, *w1b, *w2b;
  float *ao, *x1, *pmax, *moe;
  int *route, *dest, *off;
  cudaGetSymbolAddress((void**)&xb, g_xb);
  cudaGetSymbolAddress((void**)&qb, g_qb);
  cudaGetSymbolAddress((void**)&kb, g_kb);
  cudaGetSymbolAddress((void**)&vb, g_vb);
  cudaGetSymbolAddress((void**)&ctxb, g_ctxb);
  cudaGetSymbolAddress((void**)&wqb, g_wqb);
  cudaGetSymbolAddress((void**)&wkb, g_wkb);
  cudaGetSymbolAddress((void**)&wvb, g_wvb);
  cudaGetSymbolAddress((void**)&wob, g_wob);
  cudaGetSymbolAddress((void**)&ao, g_ao);
  cudaGetSymbolAddress((void**)&x1, g_x1);
  cudaGetSymbolAddress((void**)&pmax, g_pmax);
  cudaGetSymbolAddress((void**)&moe, g_moe);
  cudaGetSymbolAddress((void**)&xsortb, g_xsortb);
  cudaGetSymbolAddress((void**)&h1b, g_h1b);
  cudaGetSymbolAddress((void**)&w1b, g_w1b);
  cudaGetSymbolAddress((void**)&w2b, g_w2b);
  cudaGetSymbolAddress((void**)&route, g_route);
  cudaGetSymbolAddress((void**)&dest, g_dest);
  cudaGetSymbolAddress((void**)&off, g_off);

  cudaFuncSetAttribute(bgemm_qkv, cudaFuncAttributeMaxDynamicSharedMemorySize, BGEMM_SMEM);
  cudaFuncSetAttribute(bgemm_o, cudaFuncAttributeMaxDynamicSharedMemorySize, BGEMM_SMEM);
  cudaFuncSetAttribute(bgemm_moe<1, 1>, cudaFuncAttributeMaxDynamicSharedMemorySize, BGEMM_SMEM);
  cudaFuncSetAttribute(bgemm_moe<0, 0>, cudaFuncAttributeMaxDynamicSharedMemorySize, BGEMM_SMEM);

  dim3 blk(256);
  dim3 gblk(GEMM_THR);

  // --- conversions (bandwidth-bound) ---
  const int XN4 = Tn * Dn / 4;
  const int WN4 = Dn * Dn / 4;
  const int W1N4 = En * Fn * Dn / 4;
  cvt_bf16<<<(XN4 + 255) / 256, blk>>>(x, xb, XN4);
  cvt_bf16x4<<<dim3((WN4 + 255) / 256, 1, 4), blk>>>(
      wq, wk, wv, wo, wqb, wkb, wvb, wob, WN4);
  cvt_bf16<<<(W1N4 + 255) / 256, blk>>>(ew1, w1b, W1N4);
  cvt_bf16<<<(W1N4 + 255) / 256, blk>>>(ew2, w2b, W1N4);

  // --- attention block ---
  bgemm_qkv<<<dim3(Dn / 128, Tn / 256, 3), gblk, BGEMM_SMEM>>>(
      xb, wqb, wkb, wvb, bq, bk, bv, qb, kb, vb);
  flash_bf<<<dim3(Sn / FQT, Bn * Hn), blk>>>(qb, kb, vb, mask, ctxb);
  bgemm_o<<<dim3(Dn / 128, Tn / 256, 1), gblk, BGEMM_SMEM>>>(ctxb, wob, bo, ao);
  add_ln<<<Tn, 256>>>(x, ao, ln1g, ln1b, x1);

  // --- MoE block ---
  router2<<<Tn / RT_TPB, 256>>>(x1, sw, sb, pmax, route);
  sort_routes<<<1, 256>>>(route, dest, off);
  gather_rows_bf<<<Tn, 256>>>(x1, pmax, dest, xsortb);
  bgemm_moe<1, 1><<<dim3(Fn / 128, Tn / 256, En), gblk, BGEMM_SMEM>>>(
      xsortb, w1b, eb1, h1b, Fn, Dn, off, (size_t)Fn * Dn);
  bgemm_moe<0, 0><<<dim3(Dn / 128, Tn / 256, En), gblk, BGEMM_SMEM>>>(
      h1b, w2b, eb2, moe, Dn, Fn, off, (size_t)Dn * Fn);
  add_ln<<<Tn, 256>>>(x1, moe, ln2g, ln2b, out);
}

// round 13
// speedup vs baseline: 6.4715x; 1.0042x over previous
#include <cuda_runtime.h>
#include <math.h>

// Problem dims (fixed by the reference)
#define Tn 8192
#define Dn 1024
#define Hn 16
#define HDn 64
#define Fn 4096
#define En 8
#define Bn 4
#define Sn 2048

typedef unsigned short ushort_t;

// ---------------- scratch (static device allocations; no cudaMalloc allowed) ---------
__device__ ushort_t g_xb[Tn * Dn];        // bf16 x
__device__ ushort_t g_qb[Tn * Dn];        // bf16 q
__device__ ushort_t g_kb[Tn * Dn];        // bf16 k
__device__ ushort_t g_vb[Tn * Dn];        // bf16 v
__device__ ushort_t g_ctxb[Tn * Dn];      // bf16 ctx
__device__ ushort_t g_wqb[Dn * Dn];
__device__ ushort_t g_wkb[Dn * Dn];
__device__ ushort_t g_wvb[Dn * Dn];
__device__ ushort_t g_wob[Dn * Dn];
__device__ float g_ao[Tn * Dn];
__device__ float g_x1[Tn * Dn];
__device__ float g_pmax[Tn];
__device__ float g_moe[Tn * Dn];
__device__ ushort_t g_xsortb[Tn * Dn];
__device__ ushort_t g_h1b[(size_t)Tn * Fn];
__device__ ushort_t g_w1b[(size_t)En * Fn * Dn];
__device__ ushort_t g_w2b[(size_t)En * Dn * Fn];
__device__ int g_route[Tn];
__device__ int g_dest[Tn];
__device__ int g_off[En + 1];

__device__ __forceinline__ void mma_bf16(float* c, const unsigned* a, const unsigned* b) {
  asm volatile(
      "mma.sync.aligned.m16n8k16.row.col.f32.bf16.bf16.f32 "
      "{%0,%1,%2,%3},{%4,%5,%6,%7},{%8,%9},{%0,%1,%2,%3};"
      : "+f"(c[0]), "+f"(c[1]), "+f"(c[2]), "+f"(c[3])
      : "r"(a[0]), "r"(a[1]), "r"(a[2]), "r"(a[3]), "r"(b[0]), "r"(b[1]));
}

// pack two f32 -> bf16x2 (lo = first arg, hi = second)
__device__ __forceinline__ unsigned pk2(float lo, float hi) {
  unsigned r;
  asm("cvt.rn.bf16x2.f32 %0, %1, %2;" : "=r"(r) : "f"(hi), "f"(lo));
  return r;
}

__device__ __forceinline__ unsigned smem_u32(const void* p) {
  return (unsigned)__cvta_generic_to_shared(p);
}

__device__ __forceinline__ void ldm4(unsigned* r, unsigned addr) {
  asm volatile("ldmatrix.sync.aligned.m8n8.x4.shared.b16 {%0,%1,%2,%3}, [%4];"
               : "=r"(r[0]), "=r"(r[1]), "=r"(r[2]), "=r"(r[3]) : "r"(addr));
}
__device__ __forceinline__ void ldm4t(unsigned* r, unsigned addr) {
  asm volatile("ldmatrix.sync.aligned.m8n8.x4.trans.shared.b16 {%0,%1,%2,%3}, [%4];"
               : "=r"(r[0]), "=r"(r[1]), "=r"(r[2]), "=r"(r[3]) : "r"(addr));
}

__device__ __forceinline__ void cp_async16(void* smem, const void* gmem) {
  unsigned sa = (unsigned)__cvta_generic_to_shared(smem);
  asm volatile("cp.async.cg.shared.global [%0], [%1], 16;" ::"r"(sa), "l"(gmem));
}
#define CP_COMMIT asm volatile("cp.async.commit_group;")
#define CP_WAIT(n) asm volatile("cp.async.wait_group %0;" ::"n"(n))

// =====================================================================================
// bf16 tensor-core GEMM body, 512 threads (16 warps = 4m x 4n, warp tile 64x32).
// Block tile 256x128, BK=64 bf16 (128B rows), 72-half row stride (conflict-free).
// 3-stage cp.async pipeline, ONE barrier per slab.
// =====================================================================================
#define BKH 64
#define LDHW 36  // words per row (= 72 halves = 64 data + 8 pad)
#define ASTGH (256 * LDHW)
#define BSTGH (128 * LDHW)
#define BGEMM_SMEM ((3 * ASTGH + 3 * BSTGH) * 4)  // 165888 B
#define GEMM_THR 512

template <int RELU, int OUTBF>
__device__ __forceinline__ void bgemm_body(
    const ushort_t* __restrict__ A, const ushort_t* __restrict__ W,
    const float* __restrict__ bp, void* __restrict__ Cv,
    int N, int K, int m0, int m_end, unsigned* smh) {
  int n0 = blockIdx.x * 128;
  unsigned* As = smh;
  unsigned* Bs = smh + 3 * ASTGH;

  int tid = threadIdx.x;
  int lane = tid & 31, wid = tid >> 5;
  int wm = (wid & 3) * 64;   // 4 warp-groups along m
  int wn = (wid >> 2) * 32;  // 4 warp-groups along n
  int g = lane >> 2, t = lane & 3;

  float acc[4][4][4];
#pragma unroll
  for (int i = 0; i < 4; i++)
#pragma unroll
    for (int j = 0; j < 4; j++)
#pragma unroll
      for (int l = 0; l < 4; l++) acc[i][j][l] = 0.f;

  unsigned a_base[4], b_base[2];
#pragma unroll
  for (int mf = 0; mf < 4; mf++) {
    int row = wm + mf * 16 + (lane & 15);
    a_base[mf] = smem_u32(As + row * LDHW) + ((lane >> 4) & 1) * 16;
  }
#pragma unroll
  for (int p = 0; p < 2; p++) {
    int row = wn + p * 16 + ((lane >> 4) & 1) * 8 + (lane & 7);
    b_base[p] = smem_u32(Bs + row * LDHW) + ((lane >> 3) & 1) * 16;
  }

  auto stage = [&](int s, int k0) {
#pragma unroll
    for (int i = 0; i < 4; i++) {
      int idx = tid + i * GEMM_THR;
      int row = idx >> 3, kq = (idx & 7);
      int grow = m0 + row;
      if (grow < m_end)
        cp_async16(As + s * ASTGH + row * LDHW + kq * 4,
                   A + (size_t)grow * K + k0 + kq * 8);
    }
#pragma unroll
    for (int i = 0; i < 2; i++) {
      int idx = tid + i * GEMM_THR;
      int row = idx >> 3, kq = (idx & 7);
      cp_async16(Bs + s * BSTGH + row * LDHW + kq * 4,
                 W + (size_t)(n0 + row) * K + k0 + kq * 8);
    }
  };

  int nslab = K / BKH;
  stage(0, 0);
  CP_COMMIT;
  stage(1, BKH);
  CP_COMMIT;

  for (int it = 0; it < nslab; it++) {
    int cur = it % 3;
    if (it + 2 < nslab) {
      CP_WAIT(1);
    } else {
      CP_WAIT(0);
    }
    __syncthreads();
    if (it + 2 < nslab) {
      stage((it + 2) % 3, (it + 2) * BKH);
      CP_COMMIT;
    }

    unsigned aoff = cur * (ASTGH * 4);
    unsigned boff = cur * (BSTGH * 4);
#pragma unroll
    for (int c = 0; c < 4; c++) {  // k16 chunks
      unsigned af[4][4];
#pragma unroll
      for (int mf = 0; mf < 4; mf++) ldm4(af[mf], a_base[mf] + aoff + c * 32);
#pragma unroll
      for (int p = 0; p < 2; p++) {
        unsigned bq[4];
        ldm4(bq, b_base[p] + boff + c * 32);
#pragma unroll
        for (int mf = 0; mf < 4; mf++) {
          mma_bf16(acc[mf][2 * p], af[mf], bq);
          mma_bf16(acc[mf][2 * p + 1], af[mf], bq + 2);
        }
      }
    }
  }

#pragma unroll
  for (int nf = 0; nf < 4; nf++) {
    int col = n0 + wn + nf * 8 + 2 * t;
    float2 bb = *(const float2*)(bp + col);
#pragma unroll
    for (int mf = 0; mf < 4; mf++) {
      int row0 = m0 + wm + mf * 16 + g;
      float v0 = acc[mf][nf][0] + bb.x;
      float v1 = acc[mf][nf][1] + bb.y;
      float v2 = acc[mf][nf][2] + bb.x;
      float v3 = acc[mf][nf][3] + bb.y;
      if (RELU) {
        v0 = fmaxf(v0, 0.f); v1 = fmaxf(v1, 0.f);
        v2 = fmaxf(v2, 0.f); v3 = fmaxf(v3, 0.f);
      }
      if (OUTBF) {
        ushort_t* C = (ushort_t*)Cv;
        if (row0 < m_end) *(unsigned*)(C + (size_t)row0 * N + col) = pk2(v0, v1);
        if (row0 + 8 < m_end) *(unsigned*)(C + (size_t)(row0 + 8) * N + col) = pk2(v2, v3);
      } else {
        float* C = (float*)Cv;
        if (row0 < m_end)
          *(float2*)(C + (size_t)row0 * N + col) = make_float2(v0, v1);
        if (row0 + 8 < m_end)
          *(float2*)(C + (size_t)(row0 + 8) * N + col) = make_float2(v2, v3);
      }
    }
  }
}

// Fused QKV projection (bf16 in/out): z selects (wq,bq,q)/(wk,bk,k)/(wv,bv,v)
__global__ void __launch_bounds__(GEMM_THR) bgemm_qkv(
    const ushort_t* __restrict__ A,
    const ushort_t* __restrict__ w0, const ushort_t* __restrict__ w1,
    const ushort_t* __restrict__ w2,
    const float* __restrict__ b0, const float* __restrict__ b1,
    const float* __restrict__ b2,
    ushort_t* __restrict__ c0, ushort_t* __restrict__ c1, ushort_t* __restrict__ c2) {
  extern __shared__ unsigned smh[];
  int z = blockIdx.z;
  const ushort_t* W = (z == 0) ? w0 : (z == 1) ? w1 : w2;
  const float* bb = (z == 0) ? b0 : (z == 1) ? b1 : b2;
  ushort_t* C = (z == 0) ? c0 : (z == 1) ? c1 : c2;
  int m0 = (int)blockIdx.y * 256;
  bgemm_body<0, 1>(A, W, bb, C, Dn, Dn, m0, Tn, smh);
}

// Dense O-projection (bf16 in, fp32 out)
__global__ void __launch_bounds__(GEMM_THR) bgemm_o(
    const ushort_t* __restrict__ A, const ushort_t* __restrict__ W,
    const float* __restrict__ bias, float* __restrict__ C) {
  extern __shared__ unsigned smh[];
  int m0 = (int)blockIdx.y * 256;
  bgemm_body<0, 0>(A, W, bias, C, Dn, Dn, m0, Tn, smh);
}

// Expert-batched MoE GEMM
template <int RELU, int OUTBF>
__global__ void __launch_bounds__(GEMM_THR) bgemm_moe(
    const ushort_t* __restrict__ A, const ushort_t* __restrict__ W,
    const float* __restrict__ bias, void* __restrict__ Cv,
    int N, int K, const int* __restrict__ off, size_t wstride) {
  extern __shared__ unsigned smh[];
  int e = blockIdx.z;
  int m_start = off[e], m_end = off[e + 1];
  int m0 = m_start + (int)blockIdx.y * 256;
  if (m0 >= m_end) return;
  bgemm_body<RELU, OUTBF>(A, W + (size_t)e * wstride, bias + (size_t)e * N, Cv,
                          N, K, m0, m_end, smh);
}

// fp32 -> bf16 grid-stride conversion (graph-safe, deterministic)
__global__ void __launch_bounds__(256) cvt_bf16_gs(
    const float* __restrict__ src, ushort_t* __restrict__ dst, int n4) {
  int stride = gridDim.x * 256;
  for (int i = blockIdx.x * 256 + threadIdx.x; i < n4; i += stride) {
    float4 v = ((const float4*)src)[i];
    ((uint2*)dst)[i] = make_uint2(pk2(v.x, v.y), pk2(v.z, v.w));
  }
}

// 4-way dense weight conversion in one launch (grid.z selects tensor)
__global__ void __launch_bounds__(256) cvt_bf16x4(
    const float* __restrict__ s0, const float* __restrict__ s1,
    const float* __restrict__ s2, const float* __restrict__ s3,
    ushort_t* __restrict__ d0, ushort_t* __restrict__ d1,
    ushort_t* __restrict__ d2, ushort_t* __restrict__ d3, int n4) {
  int z = blockIdx.z;
  const float* src = (z == 0) ? s0 : (z == 1) ? s1 : (z == 2) ? s2 : s3;
  ushort_t* dst = (z == 0) ? d0 : (z == 1) ? d1 : (z == 2) ? d2 : d3;
  int stride = gridDim.x * 256;
  for (int i = blockIdx.x * 256 + threadIdx.x; i < n4; i += stride) {
    float4 v = ((const float4*)src)[i];
    ((uint2*)dst)[i] = make_uint2(pk2(v.x, v.y), pk2(v.z, v.w));
  }
}

// =====================================================================================
// bf16 flash attention, 3-stage K/V pipeline; 2 CTAs/SM.
// =====================================================================================
#define FQT 128
#define FKT 64
#define FSW 36
#define FNT (Sn / FKT)

__global__ void __launch_bounds__(256, 2) flash_bf(
    const ushort_t* __restrict__ Q, const ushort_t* __restrict__ K,
    const ushort_t* __restrict__ V, const int* __restrict__ mask,
    ushort_t* __restrict__ O) {
  __shared__ unsigned Qs[FQT * FSW];
  __shared__ unsigned Ks[3][FKT * FSW];
  __shared__ unsigned Vs[3][FKT * FSW];
  __shared__ int msk[3][FKT];

  int bh = blockIdx.y;
  int b = bh >> 4, h = bh & 15;
  int q0 = blockIdx.x * FQT;
  int tid = threadIdx.x;
  int lane = tid & 31, wid = tid >> 5;
  int g = lane >> 2, t = lane & 3;
  int wrow = wid * 16;

  auto stage_kv = [&](int s, int t0) {
#pragma unroll
    for (int l = 0; l < 2; l++) {
      int idx = tid + l * 256;
      int r = idx >> 3, ch = idx & 7;
      size_t base = (size_t)(b * Sn + t0 + r) * Dn + h * HDn + ch * 8;
      cp_async16(Ks[s] + r * FSW + ch * 4, K + base);
      cp_async16(Vs[s] + r * FSW + ch * 4, V + base);
    }
  };

#pragma unroll
  for (int l = 0; l < 4; l++) {
    int idx = tid + l * 256;
    int r = idx >> 3, ch = idx & 7;
    cp_async16(Qs + r * FSW + ch * 4,
               Q + (size_t)(b * Sn + q0 + r) * Dn + h * HDn + ch * 8);
  }
  stage_kv(0, 0);
  CP_COMMIT;
  stage_kv(1, FKT);
  CP_COMMIT;
  if (tid < FKT) {
    msk[0][tid] = mask[b * Sn + tid];
    msk[1][tid] = mask[b * Sn + FKT + tid];
  }

  float o[8][4];
#pragma unroll
  for (int nf = 0; nf < 8; nf++)
#pragma unroll
    for (int c = 0; c < 4; c++) o[nf][c] = 0.f;
  float mrow0 = -1e30f, mrow1 = -1e30f;
  float lrow0 = 0.f, lrow1 = 0.f;

  unsigned qa_base = smem_u32(Qs + (wrow + (lane & 15)) * FSW + (lane >> 4) * 4);
  unsigned kb_row = (lane & 7) + ((lane >> 4) & 1) * 8;
  unsigned kb_koff = ((lane >> 3) & 1) * 4;
  unsigned vb_key = (lane & 7) + ((lane >> 3) & 1) * 8;
  unsigned vb_doff = ((lane >> 4) & 1) * 4;

  for (int it = 0; it < FNT; it++) {
    int cur = it % 3;
    if (it + 2 < FNT) {
      CP_WAIT(1);
    } else {
      CP_WAIT(0);
    }
    __syncthreads();
    if (it + 2 < FNT) {
      int s = (it + 2) % 3;
      stage_kv(s, (it + 2) * FKT);
      CP_COMMIT;
      if (tid < FKT) msk[s][tid] = mask[b * Sn + (it + 2) * FKT + tid];
    }

    const unsigned* Kc = Ks[cur];
    const unsigned* Vc = Vs[cur];
    const int* mc = msk[cur];

    float s[8][4];
#pragma unroll
    for (int nf = 0; nf < 8; nf++)
#pragma unroll
      for (int c = 0; c < 4; c++) s[nf][c] = 0.f;

#pragma unroll
    for (int c = 0; c < 4; c++) {
      unsigned a[4];
      ldm4(a, qa_base + (c * 8) * 4);
#pragma unroll
      for (int ng = 0; ng < 4; ng++) {
        unsigned bq[4];
        unsigned addr = smem_u32(Kc + (ng * 16 + kb_row) * FSW + c * 8 + kb_koff);
        ldm4(bq, addr);
        mma_bf16(s[2 * ng], a, bq);
        mma_bf16(s[2 * ng + 1], a, bq + 2);
      }
    }

#pragma unroll
    for (int nf = 0; nf < 8; nf++) {
      int col = nf * 8 + 2 * t;
      bool z0 = (mc[col] == 0), z1 = (mc[col + 1] == 0);
      s[nf][0] = z0 ? -1e10f : s[nf][0] * 0.125f;
      s[nf][1] = z1 ? -1e10f : s[nf][1] * 0.125f;
      s[nf][2] = z0 ? -1e10f : s[nf][2] * 0.125f;
      s[nf][3] = z1 ? -1e10f : s[nf][3] * 0.125f;
    }

    float mx0 = -1e30f, mx1 = -1e30f;
#pragma unroll
    for (int nf = 0; nf < 8; nf++) {
      mx0 = fmaxf(mx0, fmaxf(s[nf][0], s[nf][1]));
      mx1 = fmaxf(mx1, fmaxf(s[nf][2], s[nf][3]));
    }
    mx0 = fmaxf(mx0, __shfl_xor_sync(0xffffffffu, mx0, 1));
    mx0 = fmaxf(mx0, __shfl_xor_sync(0xffffffffu, mx0, 2));
    mx1 = fmaxf(mx1, __shfl_xor_sync(0xffffffffu, mx1, 1));
    mx1 = fmaxf(mx1, __shfl_xor_sync(0xffffffffu, mx1, 2));

    float mn0 = fmaxf(mrow0, mx0), mn1 = fmaxf(mrow1, mx1);
    float sc0 = __expf(mrow0 - mn0), sc1 = __expf(mrow1 - mn1);
    mrow0 = mn0; mrow1 = mn1;

    float rs0 = 0.f, rs1 = 0.f;
    unsigned pk[8][2];
#pragma unroll
    for (int nf = 0; nf < 8; nf++) {
      s[nf][0] = __expf(s[nf][0] - mn0);
      s[nf][1] = __expf(s[nf][1] - mn0);
      s[nf][2] = __expf(s[nf][2] - mn1);
      s[nf][3] = __expf(s[nf][3] - mn1);
      rs0 += s[nf][0] + s[nf][1];
      rs1 += s[nf][2] + s[nf][3];
      pk[nf][0] = pk2(s[nf][0], s[nf][1]);
      pk[nf][1] = pk2(s[nf][2], s[nf][3]);
    }
    rs0 += __shfl_xor_sync(0xffffffffu, rs0, 1);
    rs0 += __shfl_xor_sync(0xffffffffu, rs0, 2);
    rs1 += __shfl_xor_sync(0xffffffffu, rs1, 1);
    rs1 += __shfl_xor_sync(0xffffffffu, rs1, 2);
    lrow0 = lrow0 * sc0 + rs0;
    lrow1 = lrow1 * sc1 + rs1;

#pragma unroll
    for (int nf = 0; nf < 8; nf++) {
      o[nf][0] *= sc0; o[nf][1] *= sc0;
      o[nf][2] *= sc1; o[nf][3] *= sc1;
    }

#pragma unroll
    for (int c = 0; c < 4; c++) {
      unsigned a[4] = {pk[2 * c][0], pk[2 * c][1], pk[2 * c + 1][0], pk[2 * c + 1][1]};
#pragma unroll
      for (int dg = 0; dg < 4; dg++) {
        unsigned bv[4];
        unsigned addr = smem_u32(Vc + (c * 16 + vb_key) * FSW + dg * 8 + vb_doff);
        ldm4t(bv, addr);
        mma_bf16(o[2 * dg], a, bv);
        mma_bf16(o[2 * dg + 1], a, bv + 2);
      }
    }
  }

  float inv0 = 1.f / lrow0, inv1 = 1.f / lrow1;
  int row = b * Sn + q0 + wrow + g;
#pragma unroll
  for (int nf = 0; nf < 8; nf++) {
    int col = h * HDn + nf * 8 + 2 * t;
    *(unsigned*)(O + (size_t)row * Dn + col) = pk2(o[nf][0] * inv0, o[nf][1] * inv0);
    *(unsigned*)(O + (size_t)(row + 8) * Dn + col) = pk2(o[nf][2] * inv1, o[nf][3] * inv1);
  }
}

// =====================================================================================
// out = LayerNorm(A + B) * g + be
// =====================================================================================
__global__ void __launch_bounds__(256) add_ln(
    const float* __restrict__ A, const float* __restrict__ Bv,
    const float* __restrict__ g, const float* __restrict__ be,
    float* __restrict__ out) {
  int t = blockIdx.x;
  int tid = threadIdx.x;
  float4 a = *(const float4*)(A + (size_t)t * Dn + tid * 4);
  float4 b = *(const float4*)(Bv + (size_t)t * Dn + tid * 4);
  float4 x = make_float4(a.x + b.x, a.y + b.y, a.z + b.z, a.w + b.w);
  float sumv = x.x + x.y + x.z + x.w;
  float sq = x.x * x.x + x.y * x.y + x.z * x.z + x.w * x.w;
#pragma unroll
  for (int off = 16; off; off >>= 1) {
    sumv += __shfl_xor_sync(0xffffffffu, sumv, off);
    sq += __shfl_xor_sync(0xffffffffu, sq, off);
  }
  __shared__ float ws[8], wq[8];
  __shared__ float s_mean, s_rstd;
  int wid = tid >> 5, lane = tid & 31;
  if (lane == 0) {
    ws[wid] = sumv;
    wq[wid] = sq;
  }
  __syncthreads();
  if (tid == 0) {
    float s = 0.f, q = 0.f;
#pragma unroll
    for (int i = 0; i < 8; i++) {
      s += ws[i];
      q += wq[i];
    }
    float mean = s * (1.f / Dn);
    float var = q * (1.f / Dn) - mean * mean;
    s_mean = mean;
    s_rstd = rsqrtf(var + 1e-5f);
  }
  __syncthreads();
  float mean = s_mean, rstd = s_rstd;
  float4 gg = *(const float4*)(g + tid * 4);
  float4 bb = *(const float4*)(be + tid * 4);
  float4 y;
  y.x = (x.x - mean) * rstd * gg.x + bb.x;
  y.y = (x.y - mean) * rstd * gg.y + bb.y;
  y.z = (x.z - mean) * rstd * gg.z + bb.z;
  y.w = (x.w - mean) * rstd * gg.w + bb.w;
  *(float4*)(out + (size_t)t * Dn + tid * 4) = y;
}

// =====================================================================================
// Router v2: 64 blocks x 256 threads, 128 tokens/block, warp-per-token.
// =====================================================================================
#define RT_TPB 128

__global__ void __launch_bounds__(256) router2(
    const float* __restrict__ x1, const float* __restrict__ sw,
    const float* __restrict__ sb, float* __restrict__ pmax,
    int* __restrict__ route) {
  __shared__ float ssw[En * Dn];
  int tid = threadIdx.x, lane = tid & 31, wid = tid >> 5;
  for (int i = tid; i < En * Dn / 4; i += 256)
    ((float4*)ssw)[i] = ((const float4*)sw)[i];
  __syncthreads();

  int t0 = blockIdx.x * RT_TPB;
#pragma unroll 1
  for (int i = 0; i < RT_TPB / 8; i++) {
    int t = t0 + i * 8 + wid;
    float acc[En];
#pragma unroll
    for (int e = 0; e < En; e++) acc[e] = 0.f;
#pragma unroll
    for (int c = 0; c < Dn / 128; c++) {
      int d = c * 128 + lane * 4;
      float4 xv = *(const float4*)(x1 + (size_t)t * Dn + d);
#pragma unroll
      for (int e = 0; e < En; e++) {
        const float* swp = ssw + e * Dn + d;
        acc[e] += xv.x * swp[0] + xv.y * swp[1] + xv.z * swp[2] + xv.w * swp[3];
      }
    }
#pragma unroll
    for (int e = 0; e < En; e++)
#pragma unroll
      for (int off = 16; off; off >>= 1)
        acc[e] += __shfl_xor_sync(0xffffffffu, acc[e], off);
    if (lane == 0) {
      float lg[En];
#pragma unroll
      for (int e = 0; e < En; e++) lg[e] = acc[e] + sb[e];
      int am = 0;
      float mx = lg[0];
#pragma unroll
      for (int e = 1; e < En; e++)
        if (lg[e] > mx) {
          mx = lg[e];
          am = e;
        }
      float sum = 0.f;
#pragma unroll
      for (int e = 0; e < En; e++) sum += __expf(lg[e] - mx);
      route[t] = am;
      pmax[t] = 1.f / sum;
    }
  }
}

// =====================================================================================
// Deterministic stable counting sort by expert id (single block).
// =====================================================================================
__global__ void __launch_bounds__(256) sort_routes(
    const int* __restrict__ route, int* __restrict__ dest, int* __restrict__ off) {
  __shared__ int hist[256][En];
  __shared__ int tot[En];
  __shared__ int eoff[En + 1];
  int tid = threadIdx.x;
  int h[En];
#pragma unroll
  for (int e = 0; e < En; e++) h[e] = 0;
  int base = tid * 32;
  for (int i = 0; i < 32; i++) h[route[base + i]]++;
#pragma unroll
  for (int e = 0; e < En; e++) hist[tid][e] = h[e];
  __syncthreads();
  if (tid < En) {
    int e = tid;
    int run = 0;
    for (int i = 0; i < 256; i++) {
      int v = hist[i][e];
      hist[i][e] = run;
      run += v;
    }
    tot[e] = run;
  }
  __syncthreads();
  if (tid == 0) {
    int r = 0;
    for (int e = 0; e < En; e++) {
      eoff[e] = r;
      off[e] = r;
      r += tot[e];
    }
    eoff[En] = r;
    off[En] = r;
  }
  __syncthreads();
  int run[En];
#pragma unroll
  for (int e = 0; e < En; e++) run[e] = eoff[e] + hist[tid][e];
  for (int i = 0; i < 32; i++) {
    int e = route[base + i];
    dest[base + i] = run[e]++;
  }
}

// xsortb[dest[t], :] = bf16(x1[t, :] * pmax[t])
__global__ void __launch_bounds__(256) gather_rows_bf(
    const float* __restrict__ x1, const float* __restrict__ pmax,
    const int* __restrict__ dest, ushort_t* __restrict__ xsortb) {
  int t = blockIdx.x;
  int c = threadIdx.x;
  int dt = dest[t];
  float p = pmax[t];
  float4 v = ((const float4*)x1)[(size_t)t * (Dn / 4) + c];
  ((uint2*)xsortb)[(size_t)dt * (Dn / 4) + c] =
      make_uint2(pk2(v.x * p, v.y * p), pk2(v.z * p, v.w * p));
}

// =====================================================================================
extern "C" void kernel_launch(void* const* d_in, const int* in_sizes, int n_in,
                              void* d_out, int out_size) {
  const float* x = (const float*)d_in[0];
  const float* wq = (const float*)d_in[1];
  const float* bq = (const float*)d_in[2];
  const float* wk = (const float*)d_in[3];
  const float* bk = (const float*)d_in[4];
  const float* wv = (const float*)d_in[5];
  const float* bv = (const float*)d_in[6];
  const float* wo = (const float*)d_in[7];
  const float* bo = (const float*)d_in[8];
  const float* ln1g = (const float*)d_in[9];
  const float* ln1b = (const float*)d_in[10];
  const float* ln2g = (const float*)d_in[11];
  const float* ln2b = (const float*)d_in[12];
  const float* sw = (const float*)d_in[13];
  const float* sb = (const float*)d_in[14];
  const float* ew1 = (const float*)d_in[15];
  const float* eb1 = (const float*)d_in[16];
  const float* ew2 = (const float*)d_in[17];
  const float* eb2 = (const float*)d_in[18];
  const int* mask = (const int*)d_in[19];
  float* out = (float*)d_out;

  ushort_t *xb, *qb, *kb, *vb, *ctxb, *wqb, *wkb, *wvb, *wob;
  ushort_t *xsortb, *h1b, *w1b, *w2b;
  float *ao, *x1, *pmax, *moe;
  int *route, *dest, *off;
  cudaGetSymbolAddress((void**)&xb, g_xb);
  cudaGetSymbolAddress((void**)&qb, g_qb);
  cudaGetSymbolAddress((void**)&kb, g_kb);
  cudaGetSymbolAddress((void**)&vb, g_vb);
  cudaGetSymbolAddress((void**)&ctxb, g_ctxb);
  cudaGetSymbolAddress((void**)&wqb, g_wqb);
  cudaGetSymbolAddress((void**)&wkb, g_wkb);
  cudaGetSymbolAddress((void**)&wvb, g_wvb);
  cudaGetSymbolAddress((void**)&wob, g_wob);
  cudaGetSymbolAddress((void**)&ao, g_ao);
  cudaGetSymbolAddress((void**)&x1, g_x1);
  cudaGetSymbolAddress((void**)&pmax, g_pmax);
  cudaGetSymbolAddress((void**)&moe, g_moe);
  cudaGetSymbolAddress((void**)&xsortb, g_xsortb);
  cudaGetSymbolAddress((void**)&h1b, g_h1b);
  cudaGetSymbolAddress((void**)&w1b, g_w1b);
  cudaGetSymbolAddress((void**)&w2b, g_w2b);
  cudaGetSymbolAddress((void**)&route, g_route);
  cudaGetSymbolAddress((void**)&dest, g_dest);
  cudaGetSymbolAddress((void**)&off, g_off);

  cudaFuncSetAttribute(bgemm_qkv, cudaFuncAttributeMaxDynamicSharedMemorySize, BGEMM_SMEM);
  cudaFuncSetAttribute(bgemm_o, cudaFuncAttributeMaxDynamicSharedMemorySize, BGEMM_SMEM);
  cudaFuncSetAttribute(bgemm_moe<1, 1>, cudaFuncAttributeMaxDynamicSharedMemorySize, BGEMM_SMEM);
  cudaFuncSetAttribute(bgemm_moe<0, 0>, cudaFuncAttributeMaxDynamicSharedMemorySize, BGEMM_SMEM);

  dim3 blk(256);
  dim3 gblk(GEMM_THR);
  const int NCVT = 1184;  // 8 blocks/SM

  // side stream for expert-weight conversion (fork/join inside graph capture;
  // stream/event creation is host-side only, no device memory)
  cudaStream_t s2;
  cudaStreamCreateWithFlags(&s2, cudaStreamNonBlocking);
  cudaEvent_t ev_fork, ev_join;
  cudaEventCreateWithFlags(&ev_fork, cudaEventDisableTiming);
  cudaEventCreateWithFlags(&ev_join, cudaEventDisableTiming);

  const int XN4 = Tn * Dn / 4;
  const int WN4 = Dn * Dn / 4;
  const int W1N4 = En * Fn * Dn / 4;

  // fork: expert weight cvts run concurrently with the attention block
  cudaEventRecord(ev_fork, 0);
  cudaStreamWaitEvent(s2, ev_fork, 0);
  cvt_bf16_gs<<<NCVT, blk, 0, s2>>>(ew1, w1b, W1N4);
  cvt_bf16_gs<<<NCVT, blk, 0, s2>>>(ew2, w2b, W1N4);
  cudaEventRecord(ev_join, s2);

  // main stream: conversions needed immediately
  cvt_bf16_gs<<<NCVT, blk>>>(x, xb, XN4);
  cvt_bf16x4<<<dim3(NCVT / 4, 1, 4), blk>>>(wq, wk, wv, wo, wqb, wkb, wvb, wob, WN4);

  // --- attention block ---
  bgemm_qkv<<<dim3(Dn / 128, Tn / 256, 3), gblk, BGEMM_SMEM>>>(
      xb, wqb, wkb, wvb, bq, bk, bv, qb, kb, vb);
  flash_bf<<<dim3(Sn / FQT, Bn * Hn), blk>>>(qb, kb, vb, mask, ctxb);
  bgemm_o<<<dim3(Dn / 128, Tn / 256, 1), gblk, BGEMM_SMEM>>>(ctxb, wob, bo, ao);
  add_ln<<<Tn, 256>>>(x, ao, ln1g, ln1b, x1);

  // --- MoE block ---
  router2<<<Tn / RT_TPB, 256>>>(x1, sw, sb, pmax, route);
  sort_routes<<<1, 256>>>(route, dest, off);
  gather_rows_bf<<<Tn, 256>>>(x1, pmax, dest, xsortb);

  // join: expert weights must be converted before the MoE GEMMs
  cudaStreamWaitEvent(0, ev_join, 0);
  bgemm_moe<1, 1><<<dim3(Fn / 128, Tn / 256, En), gblk, BGEMM_SMEM>>>(
      xsortb, w1b, eb1, h1b, Fn, Dn, off, (size_t)Fn * Dn);
  bgemm_moe<0, 0><<<dim3(Dn / 128, Tn / 256, En), gblk, BGEMM_SMEM>>>(
      h1b, w2b, eb2, moe, Dn, Fn, off, (size_t)Dn * Fn);
  add_ln<<<Tn, 256>>>(x1, moe, ln2g, ln2b, out);
}

// round 14
// speedup vs baseline: 6.6847x; 1.0329x over previous
#include <cuda_runtime.h>
#include <math.h>

// Problem dims (fixed by the reference)
#define Tn 8192
#define Dn 1024
#define Hn 16
#define HDn 64
#define Fn 4096
#define En 8
#define Bn 4
#define Sn 2048

typedef unsigned short ushort_t;

// ---------------- scratch (static device allocations; no cudaMalloc allowed) ---------
__device__ ushort_t g_xb[Tn * Dn];        // bf16 x
__device__ ushort_t g_qb[Tn * Dn];        // bf16 q
__device__ ushort_t g_kb[Tn * Dn];        // bf16 k
__device__ ushort_t g_vb[Tn * Dn];        // bf16 v
__device__ ushort_t g_ctxb[Tn * Dn];      // bf16 ctx
__device__ ushort_t g_wqb[Dn * Dn];
__device__ ushort_t g_wkb[Dn * Dn];
__device__ ushort_t g_wvb[Dn * Dn];
__device__ ushort_t g_wob[Dn * Dn];
__device__ float g_ao[Tn * Dn];
__device__ float g_x1[Tn * Dn];
__device__ float g_pmax[Tn];
__device__ float g_moe[Tn * Dn];
__device__ ushort_t g_xsortb[Tn * Dn];
__device__ ushort_t g_h1b[(size_t)Tn * Fn];
__device__ ushort_t g_w1b[(size_t)En * Fn * Dn];
__device__ ushort_t g_w2b[(size_t)En * Dn * Fn];
__device__ int g_route[Tn];
__device__ int g_dest[Tn];
__device__ int g_off[En + 1];

__device__ __forceinline__ void mma_bf16(float* c, const unsigned* a, const unsigned* b) {
  asm volatile(
      "mma.sync.aligned.m16n8k16.row.col.f32.bf16.bf16.f32 "
      "{%0,%1,%2,%3},{%4,%5,%6,%7},{%8,%9},{%0,%1,%2,%3};"
      : "+f"(c[0]), "+f"(c[1]), "+f"(c[2]), "+f"(c[3])
      : "r"(a[0]), "r"(a[1]), "r"(a[2]), "r"(a[3]), "r"(b[0]), "r"(b[1]));
}

// pack two f32 -> bf16x2 (lo = first arg, hi = second)
__device__ __forceinline__ unsigned pk2(float lo, float hi) {
  unsigned r;
  asm("cvt.rn.bf16x2.f32 %0, %1, %2;" : "=r"(r) : "f"(hi), "f"(lo));
  return r;
}

__device__ __forceinline__ unsigned smem_u32(const void* p) {
  return (unsigned)__cvta_generic_to_shared(p);
}

__device__ __forceinline__ void ldm4(unsigned* r, unsigned addr) {
  asm volatile("ldmatrix.sync.aligned.m8n8.x4.shared.b16 {%0,%1,%2,%3}, [%4];"
               : "=r"(r[0]), "=r"(r[1]), "=r"(r[2]), "=r"(r[3]) : "r"(addr));
}
__device__ __forceinline__ void ldm4t(unsigned* r, unsigned addr) {
  asm volatile("ldmatrix.sync.aligned.m8n8.x4.trans.shared.b16 {%0,%1,%2,%3}, [%4];"
               : "=r"(r[0]), "=r"(r[1]), "=r"(r[2]), "=r"(r[3]) : "r"(addr));
}

__device__ __forceinline__ void cp_async16(void* smem, const void* gmem) {
  unsigned sa = (unsigned)__cvta_generic_to_shared(smem);
  asm volatile("cp.async.cg.shared.global [%0], [%1], 16;" ::"r"(sa), "l"(gmem));
}
#define CP_COMMIT asm volatile("cp.async.commit_group;")
#define CP_WAIT(n) asm volatile("cp.async.wait_group %0;" ::"n"(n))

// =====================================================================================
// bf16 tensor-core GEMM body, 512 threads (16 warps = 4m x 4n, warp tile 64x32).
// Block tile 256x128, BK=64 bf16 (128B rows), 72-half row stride (conflict-free).
// 3-stage cp.async pipeline, ONE barrier per slab.
// =====================================================================================
#define BKH 64
#define LDHW 36  // words per row (= 72 halves = 64 data + 8 pad)
#define ASTGH (256 * LDHW)
#define BSTGH (128 * LDHW)
#define BGEMM_SMEM ((3 * ASTGH + 3 * BSTGH) * 4)  // 165888 B
#define GEMM_THR 512

template <int RELU, int OUTBF>
__device__ __forceinline__ void bgemm_body(
    const ushort_t* __restrict__ A, const ushort_t* __restrict__ W,
    const float* __restrict__ bp, void* __restrict__ Cv,
    int N, int K, int m0, int m_end, unsigned* smh) {
  int n0 = blockIdx.x * 128;
  unsigned* As = smh;
  unsigned* Bs = smh + 3 * ASTGH;

  int tid = threadIdx.x;
  int lane = tid & 31, wid = tid >> 5;
  int wm = (wid & 3) * 64;
  int wn = (wid >> 2) * 32;
  int g = lane >> 2, t = lane & 3;

  float acc[4][4][4];
#pragma unroll
  for (int i = 0; i < 4; i++)
#pragma unroll
    for (int j = 0; j < 4; j++)
#pragma unroll
      for (int l = 0; l < 4; l++) acc[i][j][l] = 0.f;

  unsigned a_base[4], b_base[2];
#pragma unroll
  for (int mf = 0; mf < 4; mf++) {
    int row = wm + mf * 16 + (lane & 15);
    a_base[mf] = smem_u32(As + row * LDHW) + ((lane >> 4) & 1) * 16;
  }
#pragma unroll
  for (int p = 0; p < 2; p++) {
    int row = wn + p * 16 + ((lane >> 4) & 1) * 8 + (lane & 7);
    b_base[p] = smem_u32(Bs + row * LDHW) + ((lane >> 3) & 1) * 16;
  }

  auto stage = [&](int s, int k0) {
#pragma unroll
    for (int i = 0; i < 4; i++) {
      int idx = tid + i * GEMM_THR;
      int row = idx >> 3, kq = (idx & 7);
      int grow = m0 + row;
      if (grow < m_end)
        cp_async16(As + s * ASTGH + row * LDHW + kq * 4,
                   A + (size_t)grow * K + k0 + kq * 8);
    }
#pragma unroll
    for (int i = 0; i < 2; i++) {
      int idx = tid + i * GEMM_THR;
      int row = idx >> 3, kq = (idx & 7);
      cp_async16(Bs + s * BSTGH + row * LDHW + kq * 4,
                 W + (size_t)(n0 + row) * K + k0 + kq * 8);
    }
  };

  int nslab = K / BKH;
  stage(0, 0);
  CP_COMMIT;
  stage(1, BKH);
  CP_COMMIT;

  for (int it = 0; it < nslab; it++) {
    int cur = it % 3;
    if (it + 2 < nslab) {
      CP_WAIT(1);
    } else {
      CP_WAIT(0);
    }
    __syncthreads();
    if (it + 2 < nslab) {
      stage((it + 2) % 3, (it + 2) * BKH);
      CP_COMMIT;
    }

    unsigned aoff = cur * (ASTGH * 4);
    unsigned boff = cur * (BSTGH * 4);
#pragma unroll
    for (int c = 0; c < 4; c++) {
      unsigned af[4][4];
#pragma unroll
      for (int mf = 0; mf < 4; mf++) ldm4(af[mf], a_base[mf] + aoff + c * 32);
#pragma unroll
      for (int p = 0; p < 2; p++) {
        unsigned bq[4];
        ldm4(bq, b_base[p] + boff + c * 32);
#pragma unroll
        for (int mf = 0; mf < 4; mf++) {
          mma_bf16(acc[mf][2 * p], af[mf], bq);
          mma_bf16(acc[mf][2 * p + 1], af[mf], bq + 2);
        }
      }
    }
  }

#pragma unroll
  for (int nf = 0; nf < 4; nf++) {
    int col = n0 + wn + nf * 8 + 2 * t;
    float2 bb = *(const float2*)(bp + col);
#pragma unroll
    for (int mf = 0; mf < 4; mf++) {
      int row0 = m0 + wm + mf * 16 + g;
      float v0 = acc[mf][nf][0] + bb.x;
      float v1 = acc[mf][nf][1] + bb.y;
      float v2 = acc[mf][nf][2] + bb.x;
      float v3 = acc[mf][nf][3] + bb.y;
      if (RELU) {
        v0 = fmaxf(v0, 0.f); v1 = fmaxf(v1, 0.f);
        v2 = fmaxf(v2, 0.f); v3 = fmaxf(v3, 0.f);
      }
      if (OUTBF) {
        ushort_t* C = (ushort_t*)Cv;
        if (row0 < m_end) *(unsigned*)(C + (size_t)row0 * N + col) = pk2(v0, v1);
        if (row0 + 8 < m_end) *(unsigned*)(C + (size_t)(row0 + 8) * N + col) = pk2(v2, v3);
      } else {
        float* C = (float*)Cv;
        if (row0 < m_end)
          *(float2*)(C + (size_t)row0 * N + col) = make_float2(v0, v1);
        if (row0 + 8 < m_end)
          *(float2*)(C + (size_t)(row0 + 8) * N + col) = make_float2(v2, v3);
      }
    }
  }
}

// Fused QKV projection (bf16 in/out): z selects (wq,bq,q)/(wk,bk,k)/(wv,bv,v)
__global__ void __launch_bounds__(GEMM_THR) bgemm_qkv(
    const ushort_t* __restrict__ A,
    const ushort_t* __restrict__ w0, const ushort_t* __restrict__ w1,
    const ushort_t* __restrict__ w2,
    const float* __restrict__ b0, const float* __restrict__ b1,
    const float* __restrict__ b2,
    ushort_t* __restrict__ c0, ushort_t* __restrict__ c1, ushort_t* __restrict__ c2) {
  extern __shared__ unsigned smh[];
  int z = blockIdx.z;
  const ushort_t* W = (z == 0) ? w0 : (z == 1) ? w1 : w2;
  const float* bb = (z == 0) ? b0 : (z == 1) ? b1 : b2;
  ushort_t* C = (z == 0) ? c0 : (z == 1) ? c1 : c2;
  int m0 = (int)blockIdx.y * 256;
  bgemm_body<0, 1>(A, W, bb, C, Dn, Dn, m0, Tn, smh);
}

// Dense O-projection (bf16 in, fp32 out)
__global__ void __launch_bounds__(GEMM_THR) bgemm_o(
    const ushort_t* __restrict__ A, const ushort_t* __restrict__ W,
    const float* __restrict__ bias, float* __restrict__ C) {
  extern __shared__ unsigned smh[];
  int m0 = (int)blockIdx.y * 256;
  bgemm_body<0, 0>(A, W, bias, C, Dn, Dn, m0, Tn, smh);
}

// Expert-batched MoE GEMM
template <int RELU, int OUTBF>
__global__ void __launch_bounds__(GEMM_THR) bgemm_moe(
    const ushort_t* __restrict__ A, const ushort_t* __restrict__ W,
    const float* __restrict__ bias, void* __restrict__ Cv,
    int N, int K, const int* __restrict__ off, size_t wstride) {
  extern __shared__ unsigned smh[];
  int e = blockIdx.z;
  int m_start = off[e], m_end = off[e + 1];
  int m0 = m_start + (int)blockIdx.y * 256;
  if (m0 >= m_end) return;
  bgemm_body<RELU, OUTBF>(A, W + (size_t)e * wstride, bias + (size_t)e * N, Cv,
                          N, K, m0, m_end, smh);
}

// fp32 -> bf16 grid-stride conversion (graph-safe, deterministic)
__global__ void __launch_bounds__(256) cvt_bf16_gs(
    const float* __restrict__ src, ushort_t* __restrict__ dst, int n4) {
  int stride = gridDim.x * 256;
  for (int i = blockIdx.x * 256 + threadIdx.x; i < n4; i += stride) {
    float4 v = ((const float4*)src)[i];
    ((uint2*)dst)[i] = make_uint2(pk2(v.x, v.y), pk2(v.z, v.w));
  }
}

// 4-way dense weight conversion in one launch (grid.z selects tensor)
__global__ void __launch_bounds__(256) cvt_bf16x4(
    const float* __restrict__ s0, const float* __restrict__ s1,
    const float* __restrict__ s2, const float* __restrict__ s3,
    ushort_t* __restrict__ d0, ushort_t* __restrict__ d1,
    ushort_t* __restrict__ d2, ushort_t* __restrict__ d3, int n4) {
  int z = blockIdx.z;
  const float* src = (z == 0) ? s0 : (z == 1) ? s1 : (z == 2) ? s2 : s3;
  ushort_t* dst = (z == 0) ? d0 : (z == 1) ? d1 : (z == 2) ? d2 : d3;
  int stride = gridDim.x * 256;
  for (int i = blockIdx.x * 256 + threadIdx.x; i < n4; i += stride) {
    float4 v = ((const float4*)src)[i];
    ((uint2*)dst)[i] = make_uint2(pk2(v.x, v.y), pk2(v.z, v.w));
  }
}

// =====================================================================================
// bf16 flash attention, 3-stage K/V pipeline; 2 CTAs/SM.
// =====================================================================================
#define FQT 128
#define FKT 64
#define FSW 36
#define FNT (Sn / FKT)

__global__ void __launch_bounds__(256, 2) flash_bf(
    const ushort_t* __restrict__ Q, const ushort_t* __restrict__ K,
    const ushort_t* __restrict__ V, const int* __restrict__ mask,
    ushort_t* __restrict__ O) {
  __shared__ unsigned Qs[FQT * FSW];
  __shared__ unsigned Ks[3][FKT * FSW];
  __shared__ unsigned Vs[3][FKT * FSW];
  __shared__ int msk[3][FKT];

  int bh = blockIdx.y;
  int b = bh >> 4, h = bh & 15;
  int q0 = blockIdx.x * FQT;
  int tid = threadIdx.x;
  int lane = tid & 31, wid = tid >> 5;
  int g = lane >> 2, t = lane & 3;
  int wrow = wid * 16;

  auto stage_kv = [&](int s, int t0) {
#pragma unroll
    for (int l = 0; l < 2; l++) {
      int idx = tid + l * 256;
      int r = idx >> 3, ch = idx & 7;
      size_t base = (size_t)(b * Sn + t0 + r) * Dn + h * HDn + ch * 8;
      cp_async16(Ks[s] + r * FSW + ch * 4, K + base);
      cp_async16(Vs[s] + r * FSW + ch * 4, V + base);
    }
  };

#pragma unroll
  for (int l = 0; l < 4; l++) {
    int idx = tid + l * 256;
    int r = idx >> 3, ch = idx & 7;
    cp_async16(Qs + r * FSW + ch * 4,
               Q + (size_t)(b * Sn + q0 + r) * Dn + h * HDn + ch * 8);
  }
  stage_kv(0, 0);
  CP_COMMIT;
  stage_kv(1, FKT);
  CP_COMMIT;
  if (tid < FKT) {
    msk[0][tid] = mask[b * Sn + tid];
    msk[1][tid] = mask[b * Sn + FKT + tid];
  }

  float o[8][4];
#pragma unroll
  for (int nf = 0; nf < 8; nf++)
#pragma unroll
    for (int c = 0; c < 4; c++) o[nf][c] = 0.f;
  float mrow0 = -1e30f, mrow1 = -1e30f;
  float lrow0 = 0.f, lrow1 = 0.f;

  unsigned qa_base = smem_u32(Qs + (wrow + (lane & 15)) * FSW + (lane >> 4) * 4);
  unsigned kb_row = (lane & 7) + ((lane >> 4) & 1) * 8;
  unsigned kb_koff = ((lane >> 3) & 1) * 4;
  unsigned vb_key = (lane & 7) + ((lane >> 3) & 1) * 8;
  unsigned vb_doff = ((lane >> 4) & 1) * 4;

  for (int it = 0; it < FNT; it++) {
    int cur = it % 3;
    if (it + 2 < FNT) {
      CP_WAIT(1);
    } else {
      CP_WAIT(0);
    }
    __syncthreads();
    if (it + 2 < FNT) {
      int s = (it + 2) % 3;
      stage_kv(s, (it + 2) * FKT);
      CP_COMMIT;
      if (tid < FKT) msk[s][tid] = mask[b * Sn + (it + 2) * FKT + tid];
    }

    const unsigned* Kc = Ks[cur];
    const unsigned* Vc = Vs[cur];
    const int* mc = msk[cur];

    float s[8][4];
#pragma unroll
    for (int nf = 0; nf < 8; nf++)
#pragma unroll
      for (int c = 0; c < 4; c++) s[nf][c] = 0.f;

#pragma unroll
    for (int c = 0; c < 4; c++) {
      unsigned a[4];
      ldm4(a, qa_base + (c * 8) * 4);
#pragma unroll
      for (int ng = 0; ng < 4; ng++) {
        unsigned bq[4];
        unsigned addr = smem_u32(Kc + (ng * 16 + kb_row) * FSW + c * 8 + kb_koff);
        ldm4(bq, addr);
        mma_bf16(s[2 * ng], a, bq);
        mma_bf16(s[2 * ng + 1], a, bq + 2);
      }
    }

#pragma unroll
    for (int nf = 0; nf < 8; nf++) {
      int col = nf * 8 + 2 * t;
      bool z0 = (mc[col] == 0), z1 = (mc[col + 1] == 0);
      s[nf][0] = z0 ? -1e10f : s[nf][0] * 0.125f;
      s[nf][1] = z1 ? -1e10f : s[nf][1] * 0.125f;
      s[nf][2] = z0 ? -1e10f : s[nf][2] * 0.125f;
      s[nf][3] = z1 ? -1e10f : s[nf][3] * 0.125f;
    }

    float mx0 = -1e30f, mx1 = -1e30f;
#pragma unroll
    for (int nf = 0; nf < 8; nf++) {
      mx0 = fmaxf(mx0, fmaxf(s[nf][0], s[nf][1]));
      mx1 = fmaxf(mx1, fmaxf(s[nf][2], s[nf][3]));
    }
    mx0 = fmaxf(mx0, __shfl_xor_sync(0xffffffffu, mx0, 1));
    mx0 = fmaxf(mx0, __shfl_xor_sync(0xffffffffu, mx0, 2));
    mx1 = fmaxf(mx1, __shfl_xor_sync(0xffffffffu, mx1, 1));
    mx1 = fmaxf(mx1, __shfl_xor_sync(0xffffffffu, mx1, 2));

    float mn0 = fmaxf(mrow0, mx0), mn1 = fmaxf(mrow1, mx1);
    float sc0 = __expf(mrow0 - mn0), sc1 = __expf(mrow1 - mn1);
    mrow0 = mn0; mrow1 = mn1;

    float rs0 = 0.f, rs1 = 0.f;
    unsigned pk[8][2];
#pragma unroll
    for (int nf = 0; nf < 8; nf++) {
      s[nf][0] = __expf(s[nf][0] - mn0);
      s[nf][1] = __expf(s[nf][1] - mn0);
      s[nf][2] = __expf(s[nf][2] - mn1);
      s[nf][3] = __expf(s[nf][3] - mn1);
      rs0 += s[nf][0] + s[nf][1];
      rs1 += s[nf][2] + s[nf][3];
      pk[nf][0] = pk2(s[nf][0], s[nf][1]);
      pk[nf][1] = pk2(s[nf][2], s[nf][3]);
    }
    rs0 += __shfl_xor_sync(0xffffffffu, rs0, 1);
    rs0 += __shfl_xor_sync(0xffffffffu, rs0, 2);
    rs1 += __shfl_xor_sync(0xffffffffu, rs1, 1);
    rs1 += __shfl_xor_sync(0xffffffffu, rs1, 2);
    lrow0 = lrow0 * sc0 + rs0;
    lrow1 = lrow1 * sc1 + rs1;

#pragma unroll
    for (int nf = 0; nf < 8; nf++) {
      o[nf][0] *= sc0; o[nf][1] *= sc0;
      o[nf][2] *= sc1; o[nf][3] *= sc1;
    }

#pragma unroll
    for (int c = 0; c < 4; c++) {
      unsigned a[4] = {pk[2 * c][0], pk[2 * c][1], pk[2 * c + 1][0], pk[2 * c + 1][1]};
#pragma unroll
      for (int dg = 0; dg < 4; dg++) {
        unsigned bv[4];
        unsigned addr = smem_u32(Vc + (c * 16 + vb_key) * FSW + dg * 8 + vb_doff);
        ldm4t(bv, addr);
        mma_bf16(o[2 * dg], a, bv);
        mma_bf16(o[2 * dg + 1], a, bv + 2);
      }
    }
  }

  float inv0 = 1.f / lrow0, inv1 = 1.f / lrow1;
  int row = b * Sn + q0 + wrow + g;
#pragma unroll
  for (int nf = 0; nf < 8; nf++) {
    int col = h * HDn + nf * 8 + 2 * t;
    *(unsigned*)(O + (size_t)row * Dn + col) = pk2(o[nf][0] * inv0, o[nf][1] * inv0);
    *(unsigned*)(O + (size_t)(row + 8) * Dn + col) = pk2(o[nf][2] * inv1, o[nf][3] * inv1);
  }
}

// =====================================================================================
// out = LayerNorm(A + B) * g + be   (used for the final LN)
// =====================================================================================
__global__ void __launch_bounds__(256) add_ln(
    const float* __restrict__ A, const float* __restrict__ Bv,
    const float* __restrict__ g, const float* __restrict__ be,
    float* __restrict__ out) {
  int t = blockIdx.x;
  int tid = threadIdx.x;
  float4 a = *(const float4*)(A + (size_t)t * Dn + tid * 4);
  float4 b = *(const float4*)(Bv + (size_t)t * Dn + tid * 4);
  float4 x = make_float4(a.x + b.x, a.y + b.y, a.z + b.z, a.w + b.w);
  float sumv = x.x + x.y + x.z + x.w;
  float sq = x.x * x.x + x.y * x.y + x.z * x.z + x.w * x.w;
#pragma unroll
  for (int off = 16; off; off >>= 1) {
    sumv += __shfl_xor_sync(0xffffffffu, sumv, off);
    sq += __shfl_xor_sync(0xffffffffu, sq, off);
  }
  __shared__ float ws[8], wq[8];
  __shared__ float s_mean, s_rstd;
  int wid = tid >> 5, lane = tid & 31;
  if (lane == 0) {
    ws[wid] = sumv;
    wq[wid] = sq;
  }
  __syncthreads();
  if (tid == 0) {
    float s = 0.f, q = 0.f;
#pragma unroll
    for (int i = 0; i < 8; i++) {
      s += ws[i];
      q += wq[i];
    }
    float mean = s * (1.f / Dn);
    float var = q * (1.f / Dn) - mean * mean;
    s_mean = mean;
    s_rstd = rsqrtf(var + 1e-5f);
  }
  __syncthreads();
  float mean = s_mean, rstd = s_rstd;
  float4 gg = *(const float4*)(g + tid * 4);
  float4 bb = *(const float4*)(be + tid * 4);
  float4 y;
  y.x = (x.x - mean) * rstd * gg.x + bb.x;
  y.y = (x.y - mean) * rstd * gg.y + bb.y;
  y.z = (x.z - mean) * rstd * gg.z + bb.z;
  y.w = (x.w - mean) * rstd * gg.w + bb.w;
  *(float4*)(out + (size_t)t * Dn + tid * 4) = y;
}

// =====================================================================================
// Fused add + LayerNorm + router: x1 = LN(x+ao); logits = x1 @ sw^T + sb;
// route = argmax (first-max), pmax = softmax max prob. One block per token.
// =====================================================================================
__global__ void __launch_bounds__(256) add_ln_router(
    const float* __restrict__ A, const float* __restrict__ Bv,
    const float* __restrict__ g, const float* __restrict__ be,
    const float* __restrict__ sw, const float* __restrict__ sb,
    float* __restrict__ x1, float* __restrict__ pmax, int* __restrict__ route) {
  int t = blockIdx.x;
  int tid = threadIdx.x;
  float4 a = *(const float4*)(A + (size_t)t * Dn + tid * 4);
  float4 b = *(const float4*)(Bv + (size_t)t * Dn + tid * 4);
  float4 x = make_float4(a.x + b.x, a.y + b.y, a.z + b.z, a.w + b.w);
  float sumv = x.x + x.y + x.z + x.w;
  float sq = x.x * x.x + x.y * x.y + x.z * x.z + x.w * x.w;
#pragma unroll
  for (int off = 16; off; off >>= 1) {
    sumv += __shfl_xor_sync(0xffffffffu, sumv, off);
    sq += __shfl_xor_sync(0xffffffffu, sq, off);
  }
  __shared__ float ws[8], wq[8];
  __shared__ float s_mean, s_rstd;
  int wid = tid >> 5, lane = tid & 31;
  if (lane == 0) {
    ws[wid] = sumv;
    wq[wid] = sq;
  }
  __syncthreads();
  if (tid == 0) {
    float s = 0.f, q = 0.f;
#pragma unroll
    for (int i = 0; i < 8; i++) {
      s += ws[i];
      q += wq[i];
    }
    float mean = s * (1.f / Dn);
    float var = q * (1.f / Dn) - mean * mean;
    s_mean = mean;
    s_rstd = rsqrtf(var + 1e-5f);
  }
  __syncthreads();
  float mean = s_mean, rstd = s_rstd;
  float4 gg = *(const float4*)(g + tid * 4);
  float4 bb = *(const float4*)(be + tid * 4);
  float4 y;
  y.x = (x.x - mean) * rstd * gg.x + bb.x;
  y.y = (x.y - mean) * rstd * gg.y + bb.y;
  y.z = (x.z - mean) * rstd * gg.z + bb.z;
  y.w = (x.w - mean) * rstd * gg.w + bb.w;
  *(float4*)(x1 + (size_t)t * Dn + tid * 4) = y;

  // router logits from the y registers (switch_w streamed from L2)
  float acc[En];
#pragma unroll
  for (int e = 0; e < En; e++) {
    float4 w = *(const float4*)(sw + (size_t)e * Dn + tid * 4);
    acc[e] = y.x * w.x + y.y * w.y + y.z * w.z + y.w * w.w;
  }
#pragma unroll
  for (int e = 0; e < En; e++)
#pragma unroll
    for (int off = 16; off; off >>= 1)
      acc[e] += __shfl_xor_sync(0xffffffffu, acc[e], off);

  __shared__ float wsum[8][En];
  if (lane == 0)
#pragma unroll
    for (int e = 0; e < En; e++) wsum[wid][e] = acc[e];
  __syncthreads();
  if (tid == 0) {
    float lg[En];
#pragma unroll
    for (int e = 0; e < En; e++) {
      float s = 0.f;
#pragma unroll
      for (int w = 0; w < 8; w++) s += wsum[w][e];
      lg[e] = s + sb[e];
    }
    int am = 0;
    float mx = lg[0];
#pragma unroll
    for (int e = 1; e < En; e++)
      if (lg[e] > mx) {  // strict > == jnp.argmax first-max tie-break
        mx = lg[e];
        am = e;
      }
    float sum = 0.f;
#pragma unroll
    for (int e = 0; e < En; e++) sum += __expf(lg[e] - mx);
    route[t] = am;
    pmax[t] = 1.f / sum;
  }
}

// =====================================================================================
// Deterministic stable counting sort by expert id (single block).
// =====================================================================================
__global__ void __launch_bounds__(256) sort_routes(
    const int* __restrict__ route, int* __restrict__ dest, int* __restrict__ off) {
  __shared__ int hist[256][En];
  __shared__ int tot[En];
  __shared__ int eoff[En + 1];
  int tid = threadIdx.x;
  int h[En];
#pragma unroll
  for (int e = 0; e < En; e++) h[e] = 0;
  int base = tid * 32;
  for (int i = 0; i < 32; i++) h[route[base + i]]++;
#pragma unroll
  for (int e = 0; e < En; e++) hist[tid][e] = h[e];
  __syncthreads();
  if (tid < En) {
    int e = tid;
    int run = 0;
    for (int i = 0; i < 256; i++) {
      int v = hist[i][e];
      hist[i][e] = run;
      run += v;
    }
    tot[e] = run;
  }
  __syncthreads();
  if (tid == 0) {
    int r = 0;
    for (int e = 0; e < En; e++) {
      eoff[e] = r;
      off[e] = r;
      r += tot[e];
    }
    eoff[En] = r;
    off[En] = r;
  }
  __syncthreads();
  int run[En];
#pragma unroll
  for (int e = 0; e < En; e++) run[e] = eoff[e] + hist[tid][e];
  for (int i = 0; i < 32; i++) {
    int e = route[base + i];
    dest[base + i] = run[e]++;
  }
}

// xsortb[dest[t], :] = bf16(x1[t, :] * pmax[t])
__global__ void __launch_bounds__(256) gather_rows_bf(
    const float* __restrict__ x1, const float* __restrict__ pmax,
    const int* __restrict__ dest, ushort_t* __restrict__ xsortb) {
  int t = blockIdx.x;
  int c = threadIdx.x;
  int dt = dest[t];
  float p = pmax[t];
  float4 v = ((const float4*)x1)[(size_t)t * (Dn / 4) + c];
  ((uint2*)xsortb)[(size_t)dt * (Dn / 4) + c] =
      make_uint2(pk2(v.x * p, v.y * p), pk2(v.z * p, v.w * p));
}

// =====================================================================================
extern "C" void kernel_launch(void* const* d_in, const int* in_sizes, int n_in,
                              void* d_out, int out_size) {
  const float* x = (const float*)d_in[0];
  const float* wq = (const float*)d_in[1];
  const float* bq = (const float*)d_in[2];
  const float* wk = (const float*)d_in[3];
  const float* bk = (const float*)d_in[4];
  const float* wv = (const float*)d_in[5];
  const float* bv = (const float*)d_in[6];
  const float* wo = (const float*)d_in[7];
  const float* bo = (const float*)d_in[8];
  const float* ln1g = (const float*)d_in[9];
  const float* ln1b = (const float*)d_in[10];
  const float* ln2g = (const float*)d_in[11];
  const float* ln2b = (const float*)d_in[12];
  const float* sw = (const float*)d_in[13];
  const float* sb = (const float*)d_in[14];
  const float* ew1 = (const float*)d_in[15];
  const float* eb1 = (const float*)d_in[16];
  const float* ew2 = (const float*)d_in[17];
  const float* eb2 = (const float*)d_in[18];
  const int* mask = (const int*)d_in[19];
  float* out = (float*)d_out;

  ushort_t *xb, *qb, *kb, *vb, *ctxb, *wqb, *wkb, *wvb, *wob;
  ushort_t *xsortb, *h1b, *w1b, *w2b;
  float *ao, *x1, *pmax, *moe;
  int *route, *dest, *off;
  cudaGetSymbolAddress((void**)&xb, g_xb);
  cudaGetSymbolAddress((void**)&qb, g_qb);
  cudaGetSymbolAddress((void**)&kb, g_kb);
  cudaGetSymbolAddress((void**)&vb, g_vb);
  cudaGetSymbolAddress((void**)&ctxb, g_ctxb);
  cudaGetSymbolAddress((void**)&wqb, g_wqb);
  cudaGetSymbolAddress((void**)&wkb, g_wkb);
  cudaGetSymbolAddress((void**)&wvb, g_wvb);
  cudaGetSymbolAddress((void**)&wob, g_wob);
  cudaGetSymbolAddress((void**)&ao, g_ao);
  cudaGetSymbolAddress((void**)&x1, g_x1);
  cudaGetSymbolAddress((void**)&pmax, g_pmax);
  cudaGetSymbolAddress((void**)&moe, g_moe);
  cudaGetSymbolAddress((void**)&xsortb, g_xsortb);
  cudaGetSymbolAddress((void**)&h1b, g_h1b);
  cudaGetSymbolAddress((void**)&w1b, g_w1b);
  cudaGetSymbolAddress((void**)&w2b, g_w2b);
  cudaGetSymbolAddress((void**)&route, g_route);
  cudaGetSymbolAddress((void**)&dest, g_dest);
  cudaGetSymbolAddress((void**)&off, g_off);

  cudaFuncSetAttribute(bgemm_qkv, cudaFuncAttributeMaxDynamicSharedMemorySize, BGEMM_SMEM);
  cudaFuncSetAttribute(bgemm_o, cudaFuncAttributeMaxDynamicSharedMemorySize, BGEMM_SMEM);
  cudaFuncSetAttribute(bgemm_moe<1, 1>, cudaFuncAttributeMaxDynamicSharedMemorySize, BGEMM_SMEM);
  cudaFuncSetAttribute(bgemm_moe<0, 0>, cudaFuncAttributeMaxDynamicSharedMemorySize, BGEMM_SMEM);

  dim3 blk(256);
  dim3 gblk(GEMM_THR);
  const int NCVT = 1184;  // 8 blocks/SM

  // side stream for expert-weight conversion (fork/join inside graph capture)
  cudaStream_t s2;
  cudaStreamCreateWithFlags(&s2, cudaStreamNonBlocking);
  cudaEvent_t ev_fork, ev_join;
  cudaEventCreateWithFlags(&ev_fork, cudaEventDisableTiming);
  cudaEventCreateWithFlags(&ev_join, cudaEventDisableTiming);

  const int XN4 = Tn * Dn / 4;
  const int WN4 = Dn * Dn / 4;
  const int W1N4 = En * Fn * Dn / 4;

  // fork: expert weight cvts run concurrently with the attention block
  cudaEventRecord(ev_fork, 0);
  cudaStreamWaitEvent(s2, ev_fork, 0);
  cvt_bf16_gs<<<NCVT, blk, 0, s2>>>(ew1, w1b, W1N4);
  cvt_bf16_gs<<<NCVT, blk, 0, s2>>>(ew2, w2b, W1N4);
  cudaEventRecord(ev_join, s2);

  // main stream: conversions needed immediately
  cvt_bf16_gs<<<NCVT, blk>>>(x, xb, XN4);
  cvt_bf16x4<<<dim3(NCVT / 4, 1, 4), blk>>>(wq, wk, wv, wo, wqb, wkb, wvb, wob, WN4);

  // --- attention block ---
  bgemm_qkv<<<dim3(Dn / 128, Tn / 256, 3), gblk, BGEMM_SMEM>>>(
      xb, wqb, wkb, wvb, bq, bk, bv, qb, kb, vb);
  flash_bf<<<dim3(Sn / FQT, Bn * Hn), blk>>>(qb, kb, vb, mask, ctxb);
  bgemm_o<<<dim3(Dn / 128, Tn / 256, 1), gblk, BGEMM_SMEM>>>(ctxb, wob, bo, ao);

  // --- MoE block (add_ln1 fused with router) ---
  add_ln_router<<<Tn, 256>>>(x, ao, ln1g, ln1b, sw, sb, x1, pmax, route);
  sort_routes<<<1, 256>>>(route, dest, off);
  gather_rows_bf<<<Tn, 256>>>(x1, pmax, dest, xsortb);

  // join: expert weights must be converted before the MoE GEMMs
  cudaStreamWaitEvent(0, ev_join, 0);
  bgemm_moe<1, 1><<<dim3(Fn / 128, Tn / 256, En), gblk, BGEMM_SMEM>>>(
      xsortb, w1b, eb1, h1b, Fn, Dn, off, (size_t)Fn * Dn);
  bgemm_moe<0, 0><<<dim3(Dn / 128, Tn / 256, En), gblk, BGEMM_SMEM>>>(
      h1b, w2b, eb2, moe, Dn, Fn, off, (size_t)Dn * Fn);
  add_ln<<<Tn, 256>>>(x1, moe, ln2g, ln2b, out);
}

// round 15
// speedup vs baseline: 6.7534x; 1.0103x over previous
#include <cuda_runtime.h>
#include <math.h>

// Problem dims (fixed by the reference)
#define Tn 8192
#define Dn 1024
#define Hn 16
#define HDn 64
#define Fn 4096
#define En 8
#define Bn 4
#define Sn 2048

typedef unsigned short ushort_t;

// ---------------- scratch (static device allocations; no cudaMalloc allowed) ---------
__device__ ushort_t g_xb[Tn * Dn];        // bf16 x
__device__ ushort_t g_qb[Tn * Dn];        // bf16 q
__device__ ushort_t g_kb[Tn * Dn];        // bf16 k
__device__ ushort_t g_vb[Tn * Dn];        // bf16 v
__device__ ushort_t g_ctxb[Tn * Dn];      // bf16 ctx
__device__ ushort_t g_wqb[Dn * Dn];
__device__ ushort_t g_wkb[Dn * Dn];
__device__ ushort_t g_wvb[Dn * Dn];
__device__ ushort_t g_wob[Dn * Dn];
__device__ float g_ao[Tn * Dn];
__device__ float g_x1[Tn * Dn];
__device__ float g_pmax[Tn];
__device__ float g_moe[Tn * Dn];
__device__ ushort_t g_xsortb[Tn * Dn];
__device__ ushort_t g_h1b[(size_t)Tn * Fn];
__device__ ushort_t g_w1b[(size_t)En * Fn * Dn];
__device__ ushort_t g_w2b[(size_t)En * Dn * Fn];
__device__ int g_route[Tn];
__device__ int g_dest[Tn];
__device__ int g_off[En + 1];

__device__ __forceinline__ void mma_bf16(float* c, const unsigned* a, const unsigned* b) {
  asm volatile(
      "mma.sync.aligned.m16n8k16.row.col.f32.bf16.bf16.f32 "
      "{%0,%1,%2,%3},{%4,%5,%6,%7},{%8,%9},{%0,%1,%2,%3};"
      : "+f"(c[0]), "+f"(c[1]), "+f"(c[2]), "+f"(c[3])
      : "r"(a[0]), "r"(a[1]), "r"(a[2]), "r"(a[3]), "r"(b[0]), "r"(b[1]));
}

// pack two f32 -> bf16x2 (lo = first arg, hi = second)
__device__ __forceinline__ unsigned pk2(float lo, float hi) {
  unsigned r;
  asm("cvt.rn.bf16x2.f32 %0, %1, %2;" : "=r"(r) : "f"(hi), "f"(lo));
  return r;
}

__device__ __forceinline__ unsigned smem_u32(const void* p) {
  return (unsigned)__cvta_generic_to_shared(p);
}

__device__ __forceinline__ void ldm4(unsigned* r, unsigned addr) {
  asm volatile("ldmatrix.sync.aligned.m8n8.x4.shared.b16 {%0,%1,%2,%3}, [%4];"
               : "=r"(r[0]), "=r"(r[1]), "=r"(r[2]), "=r"(r[3]) : "r"(addr));
}
__device__ __forceinline__ void ldm4t(unsigned* r, unsigned addr) {
  asm volatile("ldmatrix.sync.aligned.m8n8.x4.trans.shared.b16 {%0,%1,%2,%3}, [%4];"
               : "=r"(r[0]), "=r"(r[1]), "=r"(r[2]), "=r"(r[3]) : "r"(addr));
}

__device__ __forceinline__ void cp_async16(void* smem, const void* gmem) {
  unsigned sa = (unsigned)__cvta_generic_to_shared(smem);
  asm volatile("cp.async.cg.shared.global [%0], [%1], 16;" ::"r"(sa), "l"(gmem));
}
#define CP_COMMIT asm volatile("cp.async.commit_group;")
#define CP_WAIT(n) asm volatile("cp.async.wait_group %0;" ::"n"(n))

// =====================================================================================
// bf16 tensor-core GEMM body, 512 threads (16 warps = 4m x 4n, warp tile 64x32).
// Block tile 256x128, BK=64 bf16 (128B rows), 72-half row stride (conflict-free).
// 3-stage cp.async pipeline, ONE barrier per slab.
// =====================================================================================
#define BKH 64
#define LDHW 36  // words per row (= 72 halves = 64 data + 8 pad)
#define ASTGH (256 * LDHW)
#define BSTGH (128 * LDHW)
#define BGEMM_SMEM ((3 * ASTGH + 3 * BSTGH) * 4)  // 165888 B
#define GEMM_THR 512

template <int RELU, int OUTBF>
__device__ __forceinline__ void bgemm_body(
    const ushort_t* __restrict__ A, const ushort_t* __restrict__ W,
    const float* __restrict__ bp, void* __restrict__ Cv,
    int N, int K, int m0, int m_end, unsigned* smh) {
  int n0 = blockIdx.x * 128;
  unsigned* As = smh;
  unsigned* Bs = smh + 3 * ASTGH;

  int tid = threadIdx.x;
  int lane = tid & 31, wid = tid >> 5;
  int wm = (wid & 3) * 64;
  int wn = (wid >> 2) * 32;
  int g = lane >> 2, t = lane & 3;

  float acc[4][4][4];
#pragma unroll
  for (int i = 0; i < 4; i++)
#pragma unroll
    for (int j = 0; j < 4; j++)
#pragma unroll
      for (int l = 0; l < 4; l++) acc[i][j][l] = 0.f;

  unsigned a_base[4], b_base[2];
#pragma unroll
  for (int mf = 0; mf < 4; mf++) {
    int row = wm + mf * 16 + (lane & 15);
    a_base[mf] = smem_u32(As + row * LDHW) + ((lane >> 4) & 1) * 16;
  }
#pragma unroll
  for (int p = 0; p < 2; p++) {
    int row = wn + p * 16 + ((lane >> 4) & 1) * 8 + (lane & 7);
    b_base[p] = smem_u32(Bs + row * LDHW) + ((lane >> 3) & 1) * 16;
  }

  auto stage = [&](int s, int k0) {
#pragma unroll
    for (int i = 0; i < 4; i++) {
      int idx = tid + i * GEMM_THR;
      int row = idx >> 3, kq = (idx & 7);
      int grow = m0 + row;
      if (grow < m_end)
        cp_async16(As + s * ASTGH + row * LDHW + kq * 4,
                   A + (size_t)grow * K + k0 + kq * 8);
    }
#pragma unroll
    for (int i = 0; i < 2; i++) {
      int idx = tid + i * GEMM_THR;
      int row = idx >> 3, kq = (idx & 7);
      cp_async16(Bs + s * BSTGH + row * LDHW + kq * 4,
                 W + (size_t)(n0 + row) * K + k0 + kq * 8);
    }
  };

  int nslab = K / BKH;
  stage(0, 0);
  CP_COMMIT;
  stage(1, BKH);
  CP_COMMIT;

  for (int it = 0; it < nslab; it++) {
    int cur = it % 3;
    if (it + 2 < nslab) {
      CP_WAIT(1);
    } else {
      CP_WAIT(0);
    }
    __syncthreads();
    if (it + 2 < nslab) {
      stage((it + 2) % 3, (it + 2) * BKH);
      CP_COMMIT;
    }

    unsigned aoff = cur * (ASTGH * 4);
    unsigned boff = cur * (BSTGH * 4);
#pragma unroll
    for (int c = 0; c < 4; c++) {
      unsigned af[4][4];
#pragma unroll
      for (int mf = 0; mf < 4; mf++) ldm4(af[mf], a_base[mf] + aoff + c * 32);
#pragma unroll
      for (int p = 0; p < 2; p++) {
        unsigned bq[4];
        ldm4(bq, b_base[p] + boff + c * 32);
#pragma unroll
        for (int mf = 0; mf < 4; mf++) {
          mma_bf16(acc[mf][2 * p], af[mf], bq);
          mma_bf16(acc[mf][2 * p + 1], af[mf], bq + 2);
        }
      }
    }
  }

#pragma unroll
  for (int nf = 0; nf < 4; nf++) {
    int col = n0 + wn + nf * 8 + 2 * t;
    float2 bb = *(const float2*)(bp + col);
#pragma unroll
    for (int mf = 0; mf < 4; mf++) {
      int row0 = m0 + wm + mf * 16 + g;
      float v0 = acc[mf][nf][0] + bb.x;
      float v1 = acc[mf][nf][1] + bb.y;
      float v2 = acc[mf][nf][2] + bb.x;
      float v3 = acc[mf][nf][3] + bb.y;
      if (RELU) {
        v0 = fmaxf(v0, 0.f); v1 = fmaxf(v1, 0.f);
        v2 = fmaxf(v2, 0.f); v3 = fmaxf(v3, 0.f);
      }
      if (OUTBF) {
        ushort_t* C = (ushort_t*)Cv;
        if (row0 < m_end) *(unsigned*)(C + (size_t)row0 * N + col) = pk2(v0, v1);
        if (row0 + 8 < m_end) *(unsigned*)(C + (size_t)(row0 + 8) * N + col) = pk2(v2, v3);
      } else {
        float* C = (float*)Cv;
        if (row0 < m_end)
          *(float2*)(C + (size_t)row0 * N + col) = make_float2(v0, v1);
        if (row0 + 8 < m_end)
          *(float2*)(C + (size_t)(row0 + 8) * N + col) = make_float2(v2, v3);
      }
    }
  }
}

// Fused QKV projection (bf16 in/out): z selects (wq,bq,q)/(wk,bk,k)/(wv,bv,v)
__global__ void __launch_bounds__(GEMM_THR) bgemm_qkv(
    const ushort_t* __restrict__ A,
    const ushort_t* __restrict__ w0, const ushort_t* __restrict__ w1,
    const ushort_t* __restrict__ w2,
    const float* __restrict__ b0, const float* __restrict__ b1,
    const float* __restrict__ b2,
    ushort_t* __restrict__ c0, ushort_t* __restrict__ c1, ushort_t* __restrict__ c2) {
  extern __shared__ unsigned smh[];
  int z = blockIdx.z;
  const ushort_t* W = (z == 0) ? w0 : (z == 1) ? w1 : w2;
  const float* bb = (z == 0) ? b0 : (z == 1) ? b1 : b2;
  ushort_t* C = (z == 0) ? c0 : (z == 1) ? c1 : c2;
  int m0 = (int)blockIdx.y * 256;
  bgemm_body<0, 1>(A, W, bb, C, Dn, Dn, m0, Tn, smh);
}

// Dense O-projection (bf16 in, fp32 out)
__global__ void __launch_bounds__(GEMM_THR) bgemm_o(
    const ushort_t* __restrict__ A, const ushort_t* __restrict__ W,
    const float* __restrict__ bias, float* __restrict__ C) {
  extern __shared__ unsigned smh[];
  int m0 = (int)blockIdx.y * 256;
  bgemm_body<0, 0>(A, W, bias, C, Dn, Dn, m0, Tn, smh);
}

// Expert-batched MoE GEMM
template <int RELU, int OUTBF>
__global__ void __launch_bounds__(GEMM_THR) bgemm_moe(
    const ushort_t* __restrict__ A, const ushort_t* __restrict__ W,
    const float* __restrict__ bias, void* __restrict__ Cv,
    int N, int K, const int* __restrict__ off, size_t wstride) {
  extern __shared__ unsigned smh[];
  int e = blockIdx.z;
  int m_start = off[e], m_end = off[e + 1];
  int m0 = m_start + (int)blockIdx.y * 256;
  if (m0 >= m_end) return;
  bgemm_body<RELU, OUTBF>(A, W + (size_t)e * wstride, bias + (size_t)e * N, Cv,
                          N, K, m0, m_end, smh);
}

// fp32 -> bf16 grid-stride conversion (graph-safe, deterministic)
__global__ void __launch_bounds__(256) cvt_bf16_gs(
    const float* __restrict__ src, ushort_t* __restrict__ dst, int n4) {
  int stride = gridDim.x * 256;
  for (int i = blockIdx.x * 256 + threadIdx.x; i < n4; i += stride) {
    float4 v = ((const float4*)src)[i];
    ((uint2*)dst)[i] = make_uint2(pk2(v.x, v.y), pk2(v.z, v.w));
  }
}

// 5-way conversion in one launch: z=0 -> x (size nx4), z=1..4 -> dense weights (nw4)
__global__ void __launch_bounds__(256) cvt_bf16x5(
    const float* __restrict__ sx,
    const float* __restrict__ s0, const float* __restrict__ s1,
    const float* __restrict__ s2, const float* __restrict__ s3,
    ushort_t* __restrict__ dx,
    ushort_t* __restrict__ d0, ushort_t* __restrict__ d1,
    ushort_t* __restrict__ d2, ushort_t* __restrict__ d3,
    int nx4, int nw4) {
  int z = blockIdx.z;
  const float* src = (z == 0) ? sx : (z == 1) ? s0 : (z == 2) ? s1 : (z == 3) ? s2 : s3;
  ushort_t* dst = (z == 0) ? dx : (z == 1) ? d0 : (z == 2) ? d1 : (z == 3) ? d2 : d3;
  int n4 = (z == 0) ? nx4 : nw4;
  int stride = gridDim.x * 256;
  for (int i = blockIdx.x * 256 + threadIdx.x; i < n4; i += stride) {
    float4 v = ((const float4*)src)[i];
    ((uint2*)dst)[i] = make_uint2(pk2(v.x, v.y), pk2(v.z, v.w));
  }
}

// =====================================================================================
// bf16 flash attention, 3-stage K/V pipeline; 2 CTAs/SM.
// =====================================================================================
#define FQT 128
#define FKT 64
#define FSW 36
#define FNT (Sn / FKT)

__global__ void __launch_bounds__(256, 2) flash_bf(
    const ushort_t* __restrict__ Q, const ushort_t* __restrict__ K,
    const ushort_t* __restrict__ V, const int* __restrict__ mask,
    ushort_t* __restrict__ O) {
  __shared__ unsigned Qs[FQT * FSW];
  __shared__ unsigned Ks[3][FKT * FSW];
  __shared__ unsigned Vs[3][FKT * FSW];
  __shared__ int msk[3][FKT];

  int bh = blockIdx.y;
  int b = bh >> 4, h = bh & 15;
  int q0 = blockIdx.x * FQT;
  int tid = threadIdx.x;
  int lane = tid & 31, wid = tid >> 5;
  int g = lane >> 2, t = lane & 3;
  int wrow = wid * 16;

  auto stage_kv = [&](int s, int t0) {
#pragma unroll
    for (int l = 0; l < 2; l++) {
      int idx = tid + l * 256;
      int r = idx >> 3, ch = idx & 7;
      size_t base = (size_t)(b * Sn + t0 + r) * Dn + h * HDn + ch * 8;
      cp_async16(Ks[s] + r * FSW + ch * 4, K + base);
      cp_async16(Vs[s] + r * FSW + ch * 4, V + base);
    }
  };

#pragma unroll
  for (int l = 0; l < 4; l++) {
    int idx = tid + l * 256;
    int r = idx >> 3, ch = idx & 7;
    cp_async16(Qs + r * FSW + ch * 4,
               Q + (size_t)(b * Sn + q0 + r) * Dn + h * HDn + ch * 8);
  }
  stage_kv(0, 0);
  CP_COMMIT;
  stage_kv(1, FKT);
  CP_COMMIT;
  if (tid < FKT) {
    msk[0][tid] = mask[b * Sn + tid];
    msk[1][tid] = mask[b * Sn + FKT + tid];
  }

  float o[8][4];
#pragma unroll
  for (int nf = 0; nf < 8; nf++)
#pragma unroll
    for (int c = 0; c < 4; c++) o[nf][c] = 0.f;
  float mrow0 = -1e30f, mrow1 = -1e30f;
  float lrow0 = 0.f, lrow1 = 0.f;

  unsigned qa_base = smem_u32(Qs + (wrow + (lane & 15)) * FSW + (lane >> 4) * 4);
  unsigned kb_row = (lane & 7) + ((lane >> 4) & 1) * 8;
  unsigned kb_koff = ((lane >> 3) & 1) * 4;
  unsigned vb_key = (lane & 7) + ((lane >> 3) & 1) * 8;
  unsigned vb_doff = ((lane >> 4) & 1) * 4;

  for (int it = 0; it < FNT; it++) {
    int cur = it % 3;
    if (it + 2 < FNT) {
      CP_WAIT(1);
    } else {
      CP_WAIT(0);
    }
    __syncthreads();
    if (it + 2 < FNT) {
      int s = (it + 2) % 3;
      stage_kv(s, (it + 2) * FKT);
      CP_COMMIT;
      if (tid < FKT) msk[s][tid] = mask[b * Sn + (it + 2) * FKT + tid];
    }

    const unsigned* Kc = Ks[cur];
    const unsigned* Vc = Vs[cur];
    const int* mc = msk[cur];

    float s[8][4];
#pragma unroll
    for (int nf = 0; nf < 8; nf++)
#pragma unroll
      for (int c = 0; c < 4; c++) s[nf][c] = 0.f;

#pragma unroll
    for (int c = 0; c < 4; c++) {
      unsigned a[4];
      ldm4(a, qa_base + (c * 8) * 4);
#pragma unroll
      for (int ng = 0; ng < 4; ng++) {
        unsigned bq[4];
        unsigned addr = smem_u32(Kc + (ng * 16 + kb_row) * FSW + c * 8 + kb_koff);
        ldm4(bq, addr);
        mma_bf16(s[2 * ng], a, bq);
        mma_bf16(s[2 * ng + 1], a, bq + 2);
      }
    }

#pragma unroll
    for (int nf = 0; nf < 8; nf++) {
      int col = nf * 8 + 2 * t;
      bool z0 = (mc[col] == 0), z1 = (mc[col + 1] == 0);
      s[nf][0] = z0 ? -1e10f : s[nf][0] * 0.125f;
      s[nf][1] = z1 ? -1e10f : s[nf][1] * 0.125f;
      s[nf][2] = z0 ? -1e10f : s[nf][2] * 0.125f;
      s[nf][3] = z1 ? -1e10f : s[nf][3] * 0.125f;
    }

    float mx0 = -1e30f, mx1 = -1e30f;
#pragma unroll
    for (int nf = 0; nf < 8; nf++) {
      mx0 = fmaxf(mx0, fmaxf(s[nf][0], s[nf][1]));
      mx1 = fmaxf(mx1, fmaxf(s[nf][2], s[nf][3]));
    }
    mx0 = fmaxf(mx0, __shfl_xor_sync(0xffffffffu, mx0, 1));
    mx0 = fmaxf(mx0, __shfl_xor_sync(0xffffffffu, mx0, 2));
    mx1 = fmaxf(mx1, __shfl_xor_sync(0xffffffffu, mx1, 1));
    mx1 = fmaxf(mx1, __shfl_xor_sync(0xffffffffu, mx1, 2));

    float mn0 = fmaxf(mrow0, mx0), mn1 = fmaxf(mrow1, mx1);
    float sc0 = __expf(mrow0 - mn0), sc1 = __expf(mrow1 - mn1);
    mrow0 = mn0; mrow1 = mn1;

    float rs0 = 0.f, rs1 = 0.f;
    unsigned pk[8][2];
#pragma unroll
    for (int nf = 0; nf < 8; nf++) {
      s[nf][0] = __expf(s[nf][0] - mn0);
      s[nf][1] = __expf(s[nf][1] - mn0);
      s[nf][2] = __expf(s[nf][2] - mn1);
      s[nf][3] = __expf(s[nf][3] - mn1);
      rs0 += s[nf][0] + s[nf][1];
      rs1 += s[nf][2] + s[nf][3];
      pk[nf][0] = pk2(s[nf][0], s[nf][1]);
      pk[nf][1] = pk2(s[nf][2], s[nf][3]);
    }
    rs0 += __shfl_xor_sync(0xffffffffu, rs0, 1);
    rs0 += __shfl_xor_sync(0xffffffffu, rs0, 2);
    rs1 += __shfl_xor_sync(0xffffffffu, rs1, 1);
    rs1 += __shfl_xor_sync(0xffffffffu, rs1, 2);
    lrow0 = lrow0 * sc0 + rs0;
    lrow1 = lrow1 * sc1 + rs1;

#pragma unroll
    for (int nf = 0; nf < 8; nf++) {
      o[nf][0] *= sc0; o[nf][1] *= sc0;
      o[nf][2] *= sc1; o[nf][3] *= sc1;
    }

#pragma unroll
    for (int c = 0; c < 4; c++) {
      unsigned a[4] = {pk[2 * c][0], pk[2 * c][1], pk[2 * c + 1][0], pk[2 * c + 1][1]};
#pragma unroll
      for (int dg = 0; dg < 4; dg++) {
        unsigned bv[4];
        unsigned addr = smem_u32(Vc + (c * 16 + vb_key) * FSW + dg * 8 + vb_doff);
        ldm4t(bv, addr);
        mma_bf16(o[2 * dg], a, bv);
        mma_bf16(o[2 * dg + 1], a, bv + 2);
      }
    }
  }

  float inv0 = 1.f / lrow0, inv1 = 1.f / lrow1;
  int row = b * Sn + q0 + wrow + g;
#pragma unroll
  for (int nf = 0; nf < 8; nf++) {
    int col = h * HDn + nf * 8 + 2 * t;
    *(unsigned*)(O + (size_t)row * Dn + col) = pk2(o[nf][0] * inv0, o[nf][1] * inv0);
    *(unsigned*)(O + (size_t)(row + 8) * Dn + col) = pk2(o[nf][2] * inv1, o[nf][3] * inv1);
  }
}

// =====================================================================================
// out = LayerNorm(A + B) * g + be   (final LN)
// =====================================================================================
__global__ void __launch_bounds__(256) add_ln(
    const float* __restrict__ A, const float* __restrict__ Bv,
    const float* __restrict__ g, const float* __restrict__ be,
    float* __restrict__ out) {
  int t = blockIdx.x;
  int tid = threadIdx.x;
  float4 a = *(const float4*)(A + (size_t)t * Dn + tid * 4);
  float4 b = *(const float4*)(Bv + (size_t)t * Dn + tid * 4);
  float4 x = make_float4(a.x + b.x, a.y + b.y, a.z + b.z, a.w + b.w);
  float sumv = x.x + x.y + x.z + x.w;
  float sq = x.x * x.x + x.y * x.y + x.z * x.z + x.w * x.w;
#pragma unroll
  for (int off = 16; off; off >>= 1) {
    sumv += __shfl_xor_sync(0xffffffffu, sumv, off);
    sq += __shfl_xor_sync(0xffffffffu, sq, off);
  }
  __shared__ float ws[8], wq[8];
  __shared__ float s_mean, s_rstd;
  int wid = tid >> 5, lane = tid & 31;
  if (lane == 0) {
    ws[wid] = sumv;
    wq[wid] = sq;
  }
  __syncthreads();
  if (tid == 0) {
    float s = 0.f, q = 0.f;
#pragma unroll
    for (int i = 0; i < 8; i++) {
      s += ws[i];
      q += wq[i];
    }
    float mean = s * (1.f / Dn);
    float var = q * (1.f / Dn) - mean * mean;
    s_mean = mean;
    s_rstd = rsqrtf(var + 1e-5f);
  }
  __syncthreads();
  float mean = s_mean, rstd = s_rstd;
  float4 gg = *(const float4*)(g + tid * 4);
  float4 bb = *(const float4*)(be + tid * 4);
  float4 y;
  y.x = (x.x - mean) * rstd * gg.x + bb.x;
  y.y = (x.y - mean) * rstd * gg.y + bb.y;
  y.z = (x.z - mean) * rstd * gg.z + bb.z;
  y.w = (x.w - mean) * rstd * gg.w + bb.w;
  *(float4*)(out + (size_t)t * Dn + tid * 4) = y;
}

// =====================================================================================
// Fused add + LayerNorm + router (unchanged from round 14).
// =====================================================================================
__global__ void __launch_bounds__(256) add_ln_router(
    const float* __restrict__ A, const float* __restrict__ Bv,
    const float* __restrict__ g, const float* __restrict__ be,
    const float* __restrict__ sw, const float* __restrict__ sb,
    float* __restrict__ x1, float* __restrict__ pmax, int* __restrict__ route) {
  int t = blockIdx.x;
  int tid = threadIdx.x;
  float4 a = *(const float4*)(A + (size_t)t * Dn + tid * 4);
  float4 b = *(const float4*)(Bv + (size_t)t * Dn + tid * 4);
  float4 x = make_float4(a.x + b.x, a.y + b.y, a.z + b.z, a.w + b.w);
  float sumv = x.x + x.y + x.z + x.w;
  float sq = x.x * x.x + x.y * x.y + x.z * x.z + x.w * x.w;
#pragma unroll
  for (int off = 16; off; off >>= 1) {
    sumv += __shfl_xor_sync(0xffffffffu, sumv, off);
    sq += __shfl_xor_sync(0xffffffffu, sq, off);
  }
  __shared__ float ws[8], wq[8];
  __shared__ float s_mean, s_rstd;
  int wid = tid >> 5, lane = tid & 31;
  if (lane == 0) {
    ws[wid] = sumv;
    wq[wid] = sq;
  }
  __syncthreads();
  if (tid == 0) {
    float s = 0.f, q = 0.f;
#pragma unroll
    for (int i = 0; i < 8; i++) {
      s += ws[i];
      q += wq[i];
    }
    float mean = s * (1.f / Dn);
    float var = q * (1.f / Dn) - mean * mean;
    s_mean = mean;
    s_rstd = rsqrtf(var + 1e-5f);
  }
  __syncthreads();
  float mean = s_mean, rstd = s_rstd;
  float4 gg = *(const float4*)(g + tid * 4);
  float4 bb = *(const float4*)(be + tid * 4);
  float4 y;
  y.x = (x.x - mean) * rstd * gg.x + bb.x;
  y.y = (x.y - mean) * rstd * gg.y + bb.y;
  y.z = (x.z - mean) * rstd * gg.z + bb.z;
  y.w = (x.w - mean) * rstd * gg.w + bb.w;
  *(float4*)(x1 + (size_t)t * Dn + tid * 4) = y;

  float acc[En];
#pragma unroll
  for (int e = 0; e < En; e++) {
    float4 w = *(const float4*)(sw + (size_t)e * Dn + tid * 4);
    acc[e] = y.x * w.x + y.y * w.y + y.z * w.z + y.w * w.w;
  }
#pragma unroll
  for (int e = 0; e < En; e++)
#pragma unroll
    for (int off = 16; off; off >>= 1)
      acc[e] += __shfl_xor_sync(0xffffffffu, acc[e], off);

  __shared__ float wsum[8][En];
  if (lane == 0)
#pragma unroll
    for (int e = 0; e < En; e++) wsum[wid][e] = acc[e];
  __syncthreads();
  if (tid == 0) {
    float lg[En];
#pragma unroll
    for (int e = 0; e < En; e++) {
      float s = 0.f;
#pragma unroll
      for (int w = 0; w < 8; w++) s += wsum[w][e];
      lg[e] = s + sb[e];
    }
    int am = 0;
    float mx = lg[0];
#pragma unroll
    for (int e = 1; e < En; e++)
      if (lg[e] > mx) {  // strict > == jnp.argmax first-max tie-break
        mx = lg[e];
        am = e;
      }
    float sum = 0.f;
#pragma unroll
    for (int e = 0; e < En; e++) sum += __expf(lg[e] - mx);
    route[t] = am;
    pmax[t] = 1.f / sum;
  }
}

// =====================================================================================
// Deterministic stable counting sort by expert id (single block).
// =====================================================================================
__global__ void __launch_bounds__(256) sort_routes(
    const int* __restrict__ route, int* __restrict__ dest, int* __restrict__ off) {
  __shared__ int hist[256][En];
  __shared__ int tot[En];
  __shared__ int eoff[En + 1];
  int tid = threadIdx.x;
  int h[En];
#pragma unroll
  for (int e = 0; e < En; e++) h[e] = 0;
  int base = tid * 32;
  for (int i = 0; i < 32; i++) h[route[base + i]]++;
#pragma unroll
  for (int e = 0; e < En; e++) hist[tid][e] = h[e];
  __syncthreads();
  if (tid < En) {
    int e = tid;
    int run = 0;
    for (int i = 0; i < 256; i++) {
      int v = hist[i][e];
      hist[i][e] = run;
      run += v;
    }
    tot[e] = run;
  }
  __syncthreads();
  if (tid == 0) {
    int r = 0;
    for (int e = 0; e < En; e++) {
      eoff[e] = r;
      off[e] = r;
      r += tot[e];
    }
    eoff[En] = r;
    off[En] = r;
  }
  __syncthreads();
  int run[En];
#pragma unroll
  for (int e = 0; e < En; e++) run[e] = eoff[e] + hist[tid][e];
  for (int i = 0; i < 32; i++) {
    int e = route[base + i];
    dest[base + i] = run[e]++;
  }
}

// xsortb[dest[t], :] = bf16(x1[t, :] * pmax[t]); 8 tokens per block
__global__ void __launch_bounds__(256) gather_rows_bf(
    const float* __restrict__ x1, const float* __restrict__ pmax,
    const int* __restrict__ dest, ushort_t* __restrict__ xsortb) {
  int c = threadIdx.x;
#pragma unroll
  for (int i = 0; i < 8; i++) {
    int t = blockIdx.x * 8 + i;
    int dt = dest[t];
    float p = pmax[t];
    float4 v = ((const float4*)x1)[(size_t)t * (Dn / 4) + c];
    ((uint2*)xsortb)[(size_t)dt * (Dn / 4) + c] =
        make_uint2(pk2(v.x * p, v.y * p), pk2(v.z * p, v.w * p));
  }
}

// =====================================================================================
extern "C" void kernel_launch(void* const* d_in, const int* in_sizes, int n_in,
                              void* d_out, int out_size) {
  const float* x = (const float*)d_in[0];
  const float* wq = (const float*)d_in[1];
  const float* bq = (const float*)d_in[2];
  const float* wk = (const float*)d_in[3];
  const float* bk = (const float*)d_in[4];
  const float* wv = (const float*)d_in[5];
  const float* bv = (const float*)d_in[6];
  const float* wo = (const float*)d_in[7];
  const float* bo = (const float*)d_in[8];
  const float* ln1g = (const float*)d_in[9];
  const float* ln1b = (const float*)d_in[10];
  const float* ln2g = (const float*)d_in[11];
  const float* ln2b = (const float*)d_in[12];
  const float* sw = (const float*)d_in[13];
  const float* sb = (const float*)d_in[14];
  const float* ew1 = (const float*)d_in[15];
  const float* eb1 = (const float*)d_in[16];
  const float* ew2 = (const float*)d_in[17];
  const float* eb2 = (const float*)d_in[18];
  const int* mask = (const int*)d_in[19];
  float* out = (float*)d_out;

  ushort_t *xb, *qb, *kb, *vb, *ctxb, *wqb, *wkb, *wvb, *wob;
  ushort_t *xsortb, *h1b, *w1b, *w2b;
  float *ao, *x1, *pmax, *moe;
  int *route, *dest, *off;
  cudaGetSymbolAddress((void**)&xb, g_xb);
  cudaGetSymbolAddress((void**)&qb, g_qb);
  cudaGetSymbolAddress((void**)&kb, g_kb);
  cudaGetSymbolAddress((void**)&vb, g_vb);
  cudaGetSymbolAddress((void**)&ctxb, g_ctxb);
  cudaGetSymbolAddress((void**)&wqb, g_wqb);
  cudaGetSymbolAddress((void**)&wkb, g_wkb);
  cudaGetSymbolAddress((void**)&wvb, g_wvb);
  cudaGetSymbolAddress((void**)&wob, g_wob);
  cudaGetSymbolAddress((void**)&ao, g_ao);
  cudaGetSymbolAddress((void**)&x1, g_x1);
  cudaGetSymbolAddress((void**)&pmax, g_pmax);
  cudaGetSymbolAddress((void**)&moe, g_moe);
  cudaGetSymbolAddress((void**)&xsortb, g_xsortb);
  cudaGetSymbolAddress((void**)&h1b, g_h1b);
  cudaGetSymbolAddress((void**)&w1b, g_w1b);
  cudaGetSymbolAddress((void**)&w2b, g_w2b);
  cudaGetSymbolAddress((void**)&route, g_route);
  cudaGetSymbolAddress((void**)&dest, g_dest);
  cudaGetSymbolAddress((void**)&off, g_off);

  cudaFuncSetAttribute(bgemm_qkv, cudaFuncAttributeMaxDynamicSharedMemorySize, BGEMM_SMEM);
  cudaFuncSetAttribute(bgemm_o, cudaFuncAttributeMaxDynamicSharedMemorySize, BGEMM_SMEM);
  cudaFuncSetAttribute(bgemm_moe<1, 1>, cudaFuncAttributeMaxDynamicSharedMemorySize, BGEMM_SMEM);
  cudaFuncSetAttribute(bgemm_moe<0, 0>, cudaFuncAttributeMaxDynamicSharedMemorySize, BGEMM_SMEM);

  dim3 blk(256);
  dim3 gblk(GEMM_THR);
  const int NCVT = 1184;  // 8 blocks/SM

  // side stream for expert-weight conversion (fork/join inside graph capture)
  cudaStream_t s2;
  cudaStreamCreateWithFlags(&s2, cudaStreamNonBlocking);
  cudaEvent_t ev_fork, ev_join;
  cudaEventCreateWithFlags(&ev_fork, cudaEventDisableTiming);
  cudaEventCreateWithFlags(&ev_join, cudaEventDisableTiming);

  const int XN4 = Tn * Dn / 4;
  const int WN4 = Dn * Dn / 4;
  const int W1N4 = En * Fn * Dn / 4;

  // fork: expert weight cvts run concurrently with the attention block
  cudaEventRecord(ev_fork, 0);
  cudaStreamWaitEvent(s2, ev_fork, 0);
  cvt_bf16_gs<<<NCVT, blk, 0, s2>>>(ew1, w1b, W1N4);
  cvt_bf16_gs<<<NCVT, blk, 0, s2>>>(ew2, w2b, W1N4);
  cudaEventRecord(ev_join, s2);

  // main stream: ONE launch converts x + all four dense weights
  cvt_bf16x5<<<dim3(NCVT / 5, 1, 5), blk>>>(
      x, wq, wk, wv, wo, xb, wqb, wkb, wvb, wob, XN4, WN4);

  // --- attention block ---
  bgemm_qkv<<<dim3(Dn / 128, Tn / 256, 3), gblk, BGEMM_SMEM>>>(
      xb, wqb, wkb, wvb, bq, bk, bv, qb, kb, vb);
  flash_bf<<<dim3(Sn / FQT, Bn * Hn), blk>>>(qb, kb, vb, mask, ctxb);
  bgemm_o<<<dim3(Dn / 128, Tn / 256, 1), gblk, BGEMM_SMEM>>>(ctxb, wob, bo, ao);

  // --- MoE block (add_ln1 fused with router) ---
  add_ln_router<<<Tn, 256>>>(x, ao, ln1g, ln1b, sw, sb, x1, pmax, route);
  sort_routes<<<1, 256>>>(route, dest, off);
  gather_rows_bf<<<Tn / 8, 256>>>(x1, pmax, dest, xsortb);

  // join: expert weights must be converted before the MoE GEMMs
  cudaStreamWaitEvent(0, ev_join, 0);
  bgemm_moe<1, 1><<<dim3(Fn / 128, Tn / 256, En), gblk, BGEMM_SMEM>>>(
      xsortb, w1b, eb1, h1b, Fn, Dn, off, (size_t)Fn * Dn);
  bgemm_moe<0, 0><<<dim3(Dn / 128, Tn / 256, En), gblk, BGEMM_SMEM>>>(
      h1b, w2b, eb2, moe, Dn, Fn, off, (size_t)Dn * Fn);
  add_ln<<<Tn, 256>>>(x1, moe, ln2g, ln2b, out);
}

// round 16
// speedup vs baseline: 7.1358x; 1.0566x over previous
#include <cuda_runtime.h>
#include <math.h>

// Problem dims (fixed by the reference)
#define Tn 8192
#define Dn 1024
#define Hn 16
#define HDn 64
#define Fn 4096
#define En 8
#define Bn 4
#define Sn 2048

typedef unsigned short ushort_t;

// ---------------- scratch (static device allocations; no cudaMalloc allowed) ---------
__device__ ushort_t g_xb[Tn * Dn];        // bf16 x
__device__ ushort_t g_qb[Tn * Dn];        // bf16 q
__device__ ushort_t g_kb[Tn * Dn];        // bf16 k
__device__ ushort_t g_vb[Tn * Dn];        // bf16 v
__device__ ushort_t g_ctxb[Tn * Dn];      // bf16 ctx
__device__ ushort_t g_wqb[Dn * Dn];
__device__ ushort_t g_wkb[Dn * Dn];
__device__ ushort_t g_wvb[Dn * Dn];
__device__ ushort_t g_wob[Dn * Dn];
__device__ float g_ao[Tn * Dn];
__device__ float g_x1[Tn * Dn];
__device__ float g_pmax[Tn];
__device__ float g_moe[Tn * Dn];
__device__ ushort_t g_xsortb[Tn * Dn];
__device__ ushort_t g_h1b[(size_t)Tn * Fn];
__device__ ushort_t g_w1b[(size_t)En * Fn * Dn];
__device__ ushort_t g_w2b[(size_t)En * Dn * Fn];
__device__ int g_route[Tn];
__device__ int g_dest[Tn];
__device__ int g_off[En + 1];

__device__ __forceinline__ void mma_bf16(float* c, const unsigned* a, const unsigned* b) {
  asm volatile(
      "mma.sync.aligned.m16n8k16.row.col.f32.bf16.bf16.f32 "
      "{%0,%1,%2,%3},{%4,%5,%6,%7},{%8,%9},{%0,%1,%2,%3};"
      : "+f"(c[0]), "+f"(c[1]), "+f"(c[2]), "+f"(c[3])
      : "r"(a[0]), "r"(a[1]), "r"(a[2]), "r"(a[3]), "r"(b[0]), "r"(b[1]));
}

// pack two f32 -> bf16x2 (lo = first arg, hi = second)
__device__ __forceinline__ unsigned pk2(float lo, float hi) {
  unsigned r;
  asm("cvt.rn.bf16x2.f32 %0, %1, %2;" : "=r"(r) : "f"(hi), "f"(lo));
  return r;
}

__device__ __forceinline__ unsigned smem_u32(const void* p) {
  return (unsigned)__cvta_generic_to_shared(p);
}

__device__ __forceinline__ void ldm4(unsigned* r, unsigned addr) {
  asm volatile("ldmatrix.sync.aligned.m8n8.x4.shared.b16 {%0,%1,%2,%3}, [%4];"
               : "=r"(r[0]), "=r"(r[1]), "=r"(r[2]), "=r"(r[3]) : "r"(addr));
}
__device__ __forceinline__ void ldm4t(unsigned* r, unsigned addr) {
  asm volatile("ldmatrix.sync.aligned.m8n8.x4.trans.shared.b16 {%0,%1,%2,%3}, [%4];"
               : "=r"(r[0]), "=r"(r[1]), "=r"(r[2]), "=r"(r[3]) : "r"(addr));
}

__device__ __forceinline__ void cp_async16(void* smem, const void* gmem) {
  unsigned sa = (unsigned)__cvta_generic_to_shared(smem);
  asm volatile("cp.async.cg.shared.global [%0], [%1], 16;" ::"r"(sa), "l"(gmem));
}
#define CP_COMMIT asm volatile("cp.async.commit_group;")
#define CP_WAIT(n) asm volatile("cp.async.wait_group %0;" ::"n"(n))

// =====================================================================================
// bf16 tensor-core GEMM body, 256 threads (8 warps = 4m x 2n, warp tile 32x64).
// Block tile 128x128, BK=64 bf16 (128B rows), 72-half row stride (conflict-free).
// 3-stage cp.async pipeline, ONE barrier per slab. smem 110592 B -> 2 CTAs/SM
// (independent barrier domains; one CTA computes while the other waits).
// =====================================================================================
#define BKH 64
#define LDHW 36  // words per row (= 72 halves = 64 data + 8 pad)
#define TSTGH (128 * LDHW)                      // per-buffer tile (A or B)
#define BGEMM_SMEM ((3 * TSTGH + 3 * TSTGH) * 4)  // 110592 B
#define GEMM_THR 256

template <int RELU, int OUTBF>
__device__ __forceinline__ void bgemm_body(
    const ushort_t* __restrict__ A, const ushort_t* __restrict__ W,
    const float* __restrict__ bp, void* __restrict__ Cv,
    int N, int K, int m0, int m_end, unsigned* smh) {
  int n0 = blockIdx.x * 128;
  unsigned* As = smh;
  unsigned* Bs = smh + 3 * TSTGH;

  int tid = threadIdx.x;
  int lane = tid & 31, wid = tid >> 5;
  int wm = (wid & 3) * 32;   // 4 warp-groups along m
  int wn = (wid >> 2) * 64;  // 2 warp-groups along n
  int g = lane >> 2, t = lane & 3;

  float acc[2][8][4];
#pragma unroll
  for (int i = 0; i < 2; i++)
#pragma unroll
    for (int j = 0; j < 8; j++)
#pragma unroll
      for (int l = 0; l < 4; l++) acc[i][j][l] = 0.f;

  unsigned a_base[2], b_base[4];
#pragma unroll
  for (int mf = 0; mf < 2; mf++) {
    int row = wm + mf * 16 + (lane & 15);
    a_base[mf] = smem_u32(As + row * LDHW) + ((lane >> 4) & 1) * 16;
  }
#pragma unroll
  for (int p = 0; p < 4; p++) {
    int row = wn + p * 16 + ((lane >> 4) & 1) * 8 + (lane & 7);
    b_base[p] = smem_u32(Bs + row * LDHW) + ((lane >> 3) & 1) * 16;
  }

  auto stage = [&](int s, int k0) {
    // A: 128 rows x 8 chunks(16B) = 1024 -> 4/thread
#pragma unroll
    for (int i = 0; i < 4; i++) {
      int idx = tid + i * GEMM_THR;
      int row = idx >> 3, kq = (idx & 7);
      int grow = m0 + row;
      if (grow < m_end)
        cp_async16(As + s * TSTGH + row * LDHW + kq * 4,
                   A + (size_t)grow * K + k0 + kq * 8);
    }
    // B: 128 rows x 8 chunks = 1024 -> 4/thread
#pragma unroll
    for (int i = 0; i < 4; i++) {
      int idx = tid + i * GEMM_THR;
      int row = idx >> 3, kq = (idx & 7);
      cp_async16(Bs + s * TSTGH + row * LDHW + kq * 4,
                 W + (size_t)(n0 + row) * K + k0 + kq * 8);
    }
  };

  int nslab = K / BKH;
  stage(0, 0);
  CP_COMMIT;
  stage(1, BKH);
  CP_COMMIT;

  for (int it = 0; it < nslab; it++) {
    int cur = it % 3;
    if (it + 2 < nslab) {
      CP_WAIT(1);
    } else {
      CP_WAIT(0);
    }
    __syncthreads();
    if (it + 2 < nslab) {
      stage((it + 2) % 3, (it + 2) * BKH);
      CP_COMMIT;
    }

    unsigned aoff = cur * (TSTGH * 4);
    unsigned boff = cur * (TSTGH * 4);
#pragma unroll
    for (int c = 0; c < 4; c++) {  // k16 chunks
      unsigned af[2][4];
#pragma unroll
      for (int mf = 0; mf < 2; mf++) ldm4(af[mf], a_base[mf] + aoff + c * 32);
#pragma unroll
      for (int p = 0; p < 4; p++) {
        unsigned bq[4];
        ldm4(bq, b_base[p] + boff + c * 32);
#pragma unroll
        for (int mf = 0; mf < 2; mf++) {
          mma_bf16(acc[mf][2 * p], af[mf], bq);
          mma_bf16(acc[mf][2 * p + 1], af[mf], bq + 2);
        }
      }
    }
  }

#pragma unroll
  for (int nf = 0; nf < 8; nf++) {
    int col = n0 + wn + nf * 8 + 2 * t;
    float2 bb = *(const float2*)(bp + col);
#pragma unroll
    for (int mf = 0; mf < 2; mf++) {
      int row0 = m0 + wm + mf * 16 + g;
      float v0 = acc[mf][nf][0] + bb.x;
      float v1 = acc[mf][nf][1] + bb.y;
      float v2 = acc[mf][nf][2] + bb.x;
      float v3 = acc[mf][nf][3] + bb.y;
      if (RELU) {
        v0 = fmaxf(v0, 0.f); v1 = fmaxf(v1, 0.f);
        v2 = fmaxf(v2, 0.f); v3 = fmaxf(v3, 0.f);
      }
      if (OUTBF) {
        ushort_t* C = (ushort_t*)Cv;
        if (row0 < m_end) *(unsigned*)(C + (size_t)row0 * N + col) = pk2(v0, v1);
        if (row0 + 8 < m_end) *(unsigned*)(C + (size_t)(row0 + 8) * N + col) = pk2(v2, v3);
      } else {
        float* C = (float*)Cv;
        if (row0 < m_end)
          *(float2*)(C + (size_t)row0 * N + col) = make_float2(v0, v1);
        if (row0 + 8 < m_end)
          *(float2*)(C + (size_t)(row0 + 8) * N + col) = make_float2(v2, v3);
      }
    }
  }
}

// Fused QKV projection (bf16 in/out): z selects (wq,bq,q)/(wk,bk,k)/(wv,bv,v)
__global__ void __launch_bounds__(GEMM_THR, 2) bgemm_qkv(
    const ushort_t* __restrict__ A,
    const ushort_t* __restrict__ w0, const ushort_t* __restrict__ w1,
    const ushort_t* __restrict__ w2,
    const float* __restrict__ b0, const float* __restrict__ b1,
    const float* __restrict__ b2,
    ushort_t* __restrict__ c0, ushort_t* __restrict__ c1, ushort_t* __restrict__ c2) {
  extern __shared__ unsigned smh[];
  int z = blockIdx.z;
  const ushort_t* W = (z == 0) ? w0 : (z == 1) ? w1 : w2;
  const float* bb = (z == 0) ? b0 : (z == 1) ? b1 : b2;
  ushort_t* C = (z == 0) ? c0 : (z == 1) ? c1 : c2;
  int m0 = (int)blockIdx.y * 128;
  bgemm_body<0, 1>(A, W, bb, C, Dn, Dn, m0, Tn, smh);
}

// Dense O-projection (bf16 in, fp32 out)
__global__ void __launch_bounds__(GEMM_THR, 2) bgemm_o(
    const ushort_t* __restrict__ A, const ushort_t* __restrict__ W,
    const float* __restrict__ bias, float* __restrict__ C) {
  extern __shared__ unsigned smh[];
  int m0 = (int)blockIdx.y * 128;
  bgemm_body<0, 0>(A, W, bias, C, Dn, Dn, m0, Tn, smh);
}

// Expert-batched MoE GEMM
template <int RELU, int OUTBF>
__global__ void __launch_bounds__(GEMM_THR, 2) bgemm_moe(
    const ushort_t* __restrict__ A, const ushort_t* __restrict__ W,
    const float* __restrict__ bias, void* __restrict__ Cv,
    int N, int K, const int* __restrict__ off, size_t wstride) {
  extern __shared__ unsigned smh[];
  int e = blockIdx.z;
  int m_start = off[e], m_end = off[e + 1];
  int m0 = m_start + (int)blockIdx.y * 128;
  if (m0 >= m_end) return;
  bgemm_body<RELU, OUTBF>(A, W + (size_t)e * wstride, bias + (size_t)e * N, Cv,
                          N, K, m0, m_end, smh);
}

// fp32 -> bf16 grid-stride conversion (graph-safe, deterministic)
__global__ void __launch_bounds__(256) cvt_bf16_gs(
    const float* __restrict__ src, ushort_t* __restrict__ dst, int n4) {
  int stride = gridDim.x * 256;
  for (int i = blockIdx.x * 256 + threadIdx.x; i < n4; i += stride) {
    float4 v = ((const float4*)src)[i];
    ((uint2*)dst)[i] = make_uint2(pk2(v.x, v.y), pk2(v.z, v.w));
  }
}

// 5-way conversion in one launch: z=0 -> x (size nx4), z=1..4 -> dense weights (nw4)
__global__ void __launch_bounds__(256) cvt_bf16x5(
    const float* __restrict__ sx,
    const float* __restrict__ s0, const float* __restrict__ s1,
    const float* __restrict__ s2, const float* __restrict__ s3,
    ushort_t* __restrict__ dx,
    ushort_t* __restrict__ d0, ushort_t* __restrict__ d1,
    ushort_t* __restrict__ d2, ushort_t* __restrict__ d3,
    int nx4, int nw4) {
  int z = blockIdx.z;
  const float* src = (z == 0) ? sx : (z == 1) ? s0 : (z == 2) ? s1 : (z == 3) ? s2 : s3;
  ushort_t* dst = (z == 0) ? dx : (z == 1) ? d0 : (z == 2) ? d1 : (z == 3) ? d2 : d3;
  int n4 = (z == 0) ? nx4 : nw4;
  int stride = gridDim.x * 256;
  for (int i = blockIdx.x * 256 + threadIdx.x; i < n4; i += stride) {
    float4 v = ((const float4*)src)[i];
    ((uint2*)dst)[i] = make_uint2(pk2(v.x, v.y), pk2(v.z, v.w));
  }
}

// =====================================================================================
// bf16 flash attention, 3-stage K/V pipeline; 2 CTAs/SM.
// =====================================================================================
#define FQT 128
#define FKT 64
#define FSW 36
#define FNT (Sn / FKT)

__global__ void __launch_bounds__(256, 2) flash_bf(
    const ushort_t* __restrict__ Q, const ushort_t* __restrict__ K,
    const ushort_t* __restrict__ V, const int* __restrict__ mask,
    ushort_t* __restrict__ O) {
  __shared__ unsigned Qs[FQT * FSW];
  __shared__ unsigned Ks[3][FKT * FSW];
  __shared__ unsigned Vs[3][FKT * FSW];
  __shared__ int msk[3][FKT];

  int bh = blockIdx.y;
  int b = bh >> 4, h = bh & 15;
  int q0 = blockIdx.x * FQT;
  int tid = threadIdx.x;
  int lane = tid & 31, wid = tid >> 5;
  int g = lane >> 2, t = lane & 3;
  int wrow = wid * 16;

  auto stage_kv = [&](int s, int t0) {
#pragma unroll
    for (int l = 0; l < 2; l++) {
      int idx = tid + l * 256;
      int r = idx >> 3, ch = idx & 7;
      size_t base = (size_t)(b * Sn + t0 + r) * Dn + h * HDn + ch * 8;
      cp_async16(Ks[s] + r * FSW + ch * 4, K + base);
      cp_async16(Vs[s] + r * FSW + ch * 4, V + base);
    }
  };

#pragma unroll
  for (int l = 0; l < 4; l++) {
    int idx = tid + l * 256;
    int r = idx >> 3, ch = idx & 7;
    cp_async16(Qs + r * FSW + ch * 4,
               Q + (size_t)(b * Sn + q0 + r) * Dn + h * HDn + ch * 8);
  }
  stage_kv(0, 0);
  CP_COMMIT;
  stage_kv(1, FKT);
  CP_COMMIT;
  if (tid < FKT) {
    msk[0][tid] = mask[b * Sn + tid];
    msk[1][tid] = mask[b * Sn + FKT + tid];
  }

  float o[8][4];
#pragma unroll
  for (int nf = 0; nf < 8; nf++)
#pragma unroll
    for (int c = 0; c < 4; c++) o[nf][c] = 0.f;
  float mrow0 = -1e30f, mrow1 = -1e30f;
  float lrow0 = 0.f, lrow1 = 0.f;

  unsigned qa_base = smem_u32(Qs + (wrow + (lane & 15)) * FSW + (lane >> 4) * 4);
  unsigned kb_row = (lane & 7) + ((lane >> 4) & 1) * 8;
  unsigned kb_koff = ((lane >> 3) & 1) * 4;
  unsigned vb_key = (lane & 7) + ((lane >> 3) & 1) * 8;
  unsigned vb_doff = ((lane >> 4) & 1) * 4;

  for (int it = 0; it < FNT; it++) {
    int cur = it % 3;
    if (it + 2 < FNT) {
      CP_WAIT(1);
    } else {
      CP_WAIT(0);
    }
    __syncthreads();
    if (it + 2 < FNT) {
      int s = (it + 2) % 3;
      stage_kv(s, (it + 2) * FKT);
      CP_COMMIT;
      if (tid < FKT) msk[s][tid] = mask[b * Sn + (it + 2) * FKT + tid];
    }

    const unsigned* Kc = Ks[cur];
    const unsigned* Vc = Vs[cur];
    const int* mc = msk[cur];

    float s[8][4];
#pragma unroll
    for (int nf = 0; nf < 8; nf++)
#pragma unroll
      for (int c = 0; c < 4; c++) s[nf][c] = 0.f;

#pragma unroll
    for (int c = 0; c < 4; c++) {
      unsigned a[4];
      ldm4(a, qa_base + (c * 8) * 4);
#pragma unroll
      for (int ng = 0; ng < 4; ng++) {
        unsigned bq[4];
        unsigned addr = smem_u32(Kc + (ng * 16 + kb_row) * FSW + c * 8 + kb_koff);
        ldm4(bq, addr);
        mma_bf16(s[2 * ng], a, bq);
        mma_bf16(s[2 * ng + 1], a, bq + 2);
      }
    }

#pragma unroll
    for (int nf = 0; nf < 8; nf++) {
      int col = nf * 8 + 2 * t;
      bool z0 = (mc[col] == 0), z1 = (mc[col + 1] == 0);
      s[nf][0] = z0 ? -1e10f : s[nf][0] * 0.125f;
      s[nf][1] = z1 ? -1e10f : s[nf][1] * 0.125f;
      s[nf][2] = z0 ? -1e10f : s[nf][2] * 0.125f;
      s[nf][3] = z1 ? -1e10f : s[nf][3] * 0.125f;
    }

    float mx0 = -1e30f, mx1 = -1e30f;
#pragma unroll
    for (int nf = 0; nf < 8; nf++) {
      mx0 = fmaxf(mx0, fmaxf(s[nf][0], s[nf][1]));
      mx1 = fmaxf(mx1, fmaxf(s[nf][2], s[nf][3]));
    }
    mx0 = fmaxf(mx0, __shfl_xor_sync(0xffffffffu, mx0, 1));
    mx0 = fmaxf(mx0, __shfl_xor_sync(0xffffffffu, mx0, 2));
    mx1 = fmaxf(mx1, __shfl_xor_sync(0xffffffffu, mx1, 1));
    mx1 = fmaxf(mx1, __shfl_xor_sync(0xffffffffu, mx1, 2));

    float mn0 = fmaxf(mrow0, mx0), mn1 = fmaxf(mrow1, mx1);
    float sc0 = __expf(mrow0 - mn0), sc1 = __expf(mrow1 - mn1);
    mrow0 = mn0; mrow1 = mn1;

    float rs0 = 0.f, rs1 = 0.f;
    unsigned pk[8][2];
#pragma unroll
    for (int nf = 0; nf < 8; nf++) {
      s[nf][0] = __expf(s[nf][0] - mn0);
      s[nf][1] = __expf(s[nf][1] - mn0);
      s[nf][2] = __expf(s[nf][2] - mn1);
      s[nf][3] = __expf(s[nf][3] - mn1);
      rs0 += s[nf][0] + s[nf][1];
      rs1 += s[nf][2] + s[nf][3];
      pk[nf][0] = pk2(s[nf][0], s[nf][1]);
      pk[nf][1] = pk2(s[nf][2], s[nf][3]);
    }
    rs0 += __shfl_xor_sync(0xffffffffu, rs0, 1);
    rs0 += __shfl_xor_sync(0xffffffffu, rs0, 2);
    rs1 += __shfl_xor_sync(0xffffffffu, rs1, 1);
    rs1 += __shfl_xor_sync(0xffffffffu, rs1, 2);
    lrow0 = lrow0 * sc0 + rs0;
    lrow1 = lrow1 * sc1 + rs1;

#pragma unroll
    for (int nf = 0; nf < 8; nf++) {
      o[nf][0] *= sc0; o[nf][1] *= sc0;
      o[nf][2] *= sc1; o[nf][3] *= sc1;
    }

#pragma unroll
    for (int c = 0; c < 4; c++) {
      unsigned a[4] = {pk[2 * c][0], pk[2 * c][1], pk[2 * c + 1][0], pk[2 * c + 1][1]};
#pragma unroll
      for (int dg = 0; dg < 4; dg++) {
        unsigned bv[4];
        unsigned addr = smem_u32(Vc + (c * 16 + vb_key) * FSW + dg * 8 + vb_doff);
        ldm4t(bv, addr);
        mma_bf16(o[2 * dg], a, bv);
        mma_bf16(o[2 * dg + 1], a, bv + 2);
      }
    }
  }

  float inv0 = 1.f / lrow0, inv1 = 1.f / lrow1;
  int row = b * Sn + q0 + wrow + g;
#pragma unroll
  for (int nf = 0; nf < 8; nf++) {
    int col = h * HDn + nf * 8 + 2 * t;
    *(unsigned*)(O + (size_t)row * Dn + col) = pk2(o[nf][0] * inv0, o[nf][1] * inv0);
    *(unsigned*)(O + (size_t)(row + 8) * Dn + col) = pk2(o[nf][2] * inv1, o[nf][3] * inv1);
  }
}

// =====================================================================================
// out = LayerNorm(A + B) * g + be   (final LN)
// =====================================================================================
__global__ void __launch_bounds__(256) add_ln(
    const float* __restrict__ A, const float* __restrict__ Bv,
    const float* __restrict__ g, const float* __restrict__ be,
    float* __restrict__ out) {
  int t = blockIdx.x;
  int tid = threadIdx.x;
  float4 a = *(const float4*)(A + (size_t)t * Dn + tid * 4);
  float4 b = *(const float4*)(Bv + (size_t)t * Dn + tid * 4);
  float4 x = make_float4(a.x + b.x, a.y + b.y, a.z + b.z, a.w + b.w);
  float sumv = x.x + x.y + x.z + x.w;
  float sq = x.x * x.x + x.y * x.y + x.z * x.z + x.w * x.w;
#pragma unroll
  for (int off = 16; off; off >>= 1) {
    sumv += __shfl_xor_sync(0xffffffffu, sumv, off);
    sq += __shfl_xor_sync(0xffffffffu, sq, off);
  }
  __shared__ float ws[8], wq[8];
  __shared__ float s_mean, s_rstd;
  int wid = tid >> 5, lane = tid & 31;
  if (lane == 0) {
    ws[wid] = sumv;
    wq[wid] = sq;
  }
  __syncthreads();
  if (tid == 0) {
    float s = 0.f, q = 0.f;
#pragma unroll
    for (int i = 0; i < 8; i++) {
      s += ws[i];
      q += wq[i];
    }
    float mean = s * (1.f / Dn);
    float var = q * (1.f / Dn) - mean * mean;
    s_mean = mean;
    s_rstd = rsqrtf(var + 1e-5f);
  }
  __syncthreads();
  float mean = s_mean, rstd = s_rstd;
  float4 gg = *(const float4*)(g + tid * 4);
  float4 bb = *(const float4*)(be + tid * 4);
  float4 y;
  y.x = (x.x - mean) * rstd * gg.x + bb.x;
  y.y = (x.y - mean) * rstd * gg.y + bb.y;
  y.z = (x.z - mean) * rstd * gg.z + bb.z;
  y.w = (x.w - mean) * rstd * gg.w + bb.w;
  *(float4*)(out + (size_t)t * Dn + tid * 4) = y;
}

// =====================================================================================
// Fused add + LayerNorm + router.
// =====================================================================================
__global__ void __launch_bounds__(256) add_ln_router(
    const float* __restrict__ A, const float* __restrict__ Bv,
    const float* __restrict__ g, const float* __restrict__ be,
    const float* __restrict__ sw, const float* __restrict__ sb,
    float* __restrict__ x1, float* __restrict__ pmax, int* __restrict__ route) {
  int t = blockIdx.x;
  int tid = threadIdx.x;
  float4 a = *(const float4*)(A + (size_t)t * Dn + tid * 4);
  float4 b = *(const float4*)(Bv + (size_t)t * Dn + tid * 4);
  float4 x = make_float4(a.x + b.x, a.y + b.y, a.z + b.z, a.w + b.w);
  float sumv = x.x + x.y + x.z + x.w;
  float sq = x.x * x.x + x.y * x.y + x.z * x.z + x.w * x.w;
#pragma unroll
  for (int off = 16; off; off >>= 1) {
    sumv += __shfl_xor_sync(0xffffffffu, sumv, off);
    sq += __shfl_xor_sync(0xffffffffu, sq, off);
  }
  __shared__ float ws[8], wq[8];
  __shared__ float s_mean, s_rstd;
  int wid = tid >> 5, lane = tid & 31;
  if (lane == 0) {
    ws[wid] = sumv;
    wq[wid] = sq;
  }
  __syncthreads();
  if (tid == 0) {
    float s = 0.f, q = 0.f;
#pragma unroll
    for (int i = 0; i < 8; i++) {
      s += ws[i];
      q += wq[i];
    }
    float mean = s * (1.f / Dn);
    float var = q * (1.f / Dn) - mean * mean;
    s_mean = mean;
    s_rstd = rsqrtf(var + 1e-5f);
  }
  __syncthreads();
  float mean = s_mean, rstd = s_rstd;
  float4 gg = *(const float4*)(g + tid * 4);
  float4 bb = *(const float4*)(be + tid * 4);
  float4 y;
  y.x = (x.x - mean) * rstd * gg.x + bb.x;
  y.y = (x.y - mean) * rstd * gg.y + bb.y;
  y.z = (x.z - mean) * rstd * gg.z + bb.z;
  y.w = (x.w - mean) * rstd * gg.w + bb.w;
  *(float4*)(x1 + (size_t)t * Dn + tid * 4) = y;

  float acc[En];
#pragma unroll
  for (int e = 0; e < En; e++) {
    float4 w = *(const float4*)(sw + (size_t)e * Dn + tid * 4);
    acc[e] = y.x * w.x + y.y * w.y + y.z * w.z + y.w * w.w;
  }
#pragma unroll
  for (int e = 0; e < En; e++)
#pragma unroll
    for (int off = 16; off; off >>= 1)
      acc[e] += __shfl_xor_sync(0xffffffffu, acc[e], off);

  __shared__ float wsum[8][En];
  if (lane == 0)
#pragma unroll
    for (int e = 0; e < En; e++) wsum[wid][e] = acc[e];
  __syncthreads();
  if (tid == 0) {
    float lg[En];
#pragma unroll
    for (int e = 0; e < En; e++) {
      float s = 0.f;
#pragma unroll
      for (int w = 0; w < 8; w++) s += wsum[w][e];
      lg[e] = s + sb[e];
    }
    int am = 0;
    float mx = lg[0];
#pragma unroll
    for (int e = 1; e < En; e++)
      if (lg[e] > mx) {  // strict > == jnp.argmax first-max tie-break
        mx = lg[e];
        am = e;
      }
    float sum = 0.f;
#pragma unroll
    for (int e = 0; e < En; e++) sum += __expf(lg[e] - mx);
    route[t] = am;
    pmax[t] = 1.f / sum;
  }
}

// =====================================================================================
// Deterministic stable counting sort by expert id (single block).
// =====================================================================================
__global__ void __launch_bounds__(256) sort_routes(
    const int* __restrict__ route, int* __restrict__ dest, int* __restrict__ off) {
  __shared__ int hist[256][En];
  __shared__ int tot[En];
  __shared__ int eoff[En + 1];
  int tid = threadIdx.x;
  int h[En];
#pragma unroll
  for (int e = 0; e < En; e++) h[e] = 0;
  int base = tid * 32;
  for (int i = 0; i < 32; i++) h[route[base + i]]++;
#pragma unroll
  for (int e = 0; e < En; e++) hist[tid][e] = h[e];
  __syncthreads();
  if (tid < En) {
    int e = tid;
    int run = 0;
    for (int i = 0; i < 256; i++) {
      int v = hist[i][e];
      hist[i][e] = run;
      run += v;
    }
    tot[e] = run;
  }
  __syncthreads();
  if (tid == 0) {
    int r = 0;
    for (int e = 0; e < En; e++) {
      eoff[e] = r;
      off[e] = r;
      r += tot[e];
    }
    eoff[En] = r;
    off[En] = r;
  }
  __syncthreads();
  int run[En];
#pragma unroll
  for (int e = 0; e < En; e++) run[e] = eoff[e] + hist[tid][e];
  for (int i = 0; i < 32; i++) {
    int e = route[base + i];
    dest[base + i] = run[e]++;
  }
}

// xsortb[dest[t], :] = bf16(x1[t, :] * pmax[t]); 8 tokens per block
__global__ void __launch_bounds__(256) gather_rows_bf(
    const float* __restrict__ x1, const float* __restrict__ pmax,
    const int* __restrict__ dest, ushort_t* __restrict__ xsortb) {
  int c = threadIdx.x;
#pragma unroll
  for (int i = 0; i < 8; i++) {
    int t = blockIdx.x * 8 + i;
    int dt = dest[t];
    float p = pmax[t];
    float4 v = ((const float4*)x1)[(size_t)t * (Dn / 4) + c];
    ((uint2*)xsortb)[(size_t)dt * (Dn / 4) + c] =
        make_uint2(pk2(v.x * p, v.y * p), pk2(v.z * p, v.w * p));
  }
}

// =====================================================================================
extern "C" void kernel_launch(void* const* d_in, const int* in_sizes, int n_in,
                              void* d_out, int out_size) {
  const float* x = (const float*)d_in[0];
  const float* wq = (const float*)d_in[1];
  const float* bq = (const float*)d_in[2];
  const float* wk = (const float*)d_in[3];
  const float* bk = (const float*)d_in[4];
  const float* wv = (const float*)d_in[5];
  const float* bv = (const float*)d_in[6];
  const float* wo = (const float*)d_in[7];
  const float* bo = (const float*)d_in[8];
  const float* ln1g = (const float*)d_in[9];
  const float* ln1b = (const float*)d_in[10];
  const float* ln2g = (const float*)d_in[11];
  const float* ln2b = (const float*)d_in[12];
  const float* sw = (const float*)d_in[13];
  const float* sb = (const float*)d_in[14];
  const float* ew1 = (const float*)d_in[15];
  const float* eb1 = (const float*)d_in[16];
  const float* ew2 = (const float*)d_in[17];
  const float* eb2 = (const float*)d_in[18];
  const int* mask = (const int*)d_in[19];
  float* out = (float*)d_out;

  ushort_t *xb, *qb, *kb, *vb, *ctxb, *wqb, *wkb, *wvb, *wob;
  ushort_t *xsortb, *h1b, *w1b, *w2b;
  float *ao, *x1, *pmax, *moe;
  int *route, *dest, *off;
  cudaGetSymbolAddress((void**)&xb, g_xb);
  cudaGetSymbolAddress((void**)&qb, g_qb);
  cudaGetSymbolAddress((void**)&kb, g_kb);
  cudaGetSymbolAddress((void**)&vb, g_vb);
  cudaGetSymbolAddress((void**)&ctxb, g_ctxb);
  cudaGetSymbolAddress((void**)&wqb, g_wqb);
  cudaGetSymbolAddress((void**)&wkb, g_wkb);
  cudaGetSymbolAddress((void**)&wvb, g_wvb);
  cudaGetSymbolAddress((void**)&wob, g_wob);
  cudaGetSymbolAddress((void**)&ao, g_ao);
  cudaGetSymbolAddress((void**)&x1, g_x1);
  cudaGetSymbolAddress((void**)&pmax, g_pmax);
  cudaGetSymbolAddress((void**)&moe, g_moe);
  cudaGetSymbolAddress((void**)&xsortb, g_xsortb);
  cudaGetSymbolAddress((void**)&h1b, g_h1b);
  cudaGetSymbolAddress((void**)&w1b, g_w1b);
  cudaGetSymbolAddress((void**)&w2b, g_w2b);
  cudaGetSymbolAddress((void**)&route, g_route);
  cudaGetSymbolAddress((void**)&dest, g_dest);
  cudaGetSymbolAddress((void**)&off, g_off);

  cudaFuncSetAttribute(bgemm_qkv, cudaFuncAttributeMaxDynamicSharedMemorySize, BGEMM_SMEM);
  cudaFuncSetAttribute(bgemm_o, cudaFuncAttributeMaxDynamicSharedMemorySize, BGEMM_SMEM);
  cudaFuncSetAttribute(bgemm_moe<1, 1>, cudaFuncAttributeMaxDynamicSharedMemorySize, BGEMM_SMEM);
  cudaFuncSetAttribute(bgemm_moe<0, 0>, cudaFuncAttributeMaxDynamicSharedMemorySize, BGEMM_SMEM);

  dim3 blk(256);
  dim3 gblk(GEMM_THR);
  const int NCVT = 1184;  // 8 blocks/SM

  // side stream for expert-weight conversion (fork/join inside graph capture)
  cudaStream_t s2;
  cudaStreamCreateWithFlags(&s2, cudaStreamNonBlocking);
  cudaEvent_t ev_fork, ev_join;
  cudaEventCreateWithFlags(&ev_fork, cudaEventDisableTiming);
  cudaEventCreateWithFlags(&ev_join, cudaEventDisableTiming);

  const int XN4 = Tn * Dn / 4;
  const int WN4 = Dn * Dn / 4;
  const int W1N4 = En * Fn * Dn / 4;

  // fork: expert weight cvts run concurrently with the attention block
  cudaEventRecord(ev_fork, 0);
  cudaStreamWaitEvent(s2, ev_fork, 0);
  cvt_bf16_gs<<<NCVT, blk, 0, s2>>>(ew1, w1b, W1N4);
  cvt_bf16_gs<<<NCVT, blk, 0, s2>>>(ew2, w2b, W1N4);
  cudaEventRecord(ev_join, s2);

  // main stream: ONE launch converts x + all four dense weights
  cvt_bf16x5<<<dim3(NCVT / 5, 1, 5), blk>>>(
      x, wq, wk, wv, wo, xb, wqb, wkb, wvb, wob, XN4, WN4);

  // --- attention block ---
  bgemm_qkv<<<dim3(Dn / 128, Tn / 128, 3), gblk, BGEMM_SMEM>>>(
      xb, wqb, wkb, wvb, bq, bk, bv, qb, kb, vb);
  flash_bf<<<dim3(Sn / FQT, Bn * Hn), blk>>>(qb, kb, vb, mask, ctxb);
  bgemm_o<<<dim3(Dn / 128, Tn / 128, 1), gblk, BGEMM_SMEM>>>(ctxb, wob, bo, ao);

  // --- MoE block (add_ln1 fused with router) ---
  add_ln_router<<<Tn, 256>>>(x, ao, ln1g, ln1b, sw, sb, x1, pmax, route);
  sort_routes<<<1, 256>>>(route, dest, off);
  gather_rows_bf<<<Tn / 8, 256>>>(x1, pmax, dest, xsortb);

  // join: expert weights must be converted before the MoE GEMMs
  cudaStreamWaitEvent(0, ev_join, 0);
  bgemm_moe<1, 1><<<dim3(Fn / 128, Tn / 128, En), gblk, BGEMM_SMEM>>>(
      xsortb, w1b, eb1, h1b, Fn, Dn, off, (size_t)Fn * Dn);
  bgemm_moe<0, 0><<<dim3(Dn / 128, Tn / 128, En), gblk, BGEMM_SMEM>>>(
      h1b, w2b, eb2, moe, Dn, Fn, off, (size_t)Dn * Fn);
  add_ln<<<Tn, 256>>>(x1, moe, ln2g, ln2b, out);
}

// round 17
// speedup vs baseline: 7.1653x; 1.0041x over previous
#include <cuda_runtime.h>
#include <math.h>

// Problem dims (fixed by the reference)
#define Tn 8192
#define Dn 1024
#define Hn 16
#define HDn 64
#define Fn 4096
#define En 8
#define Bn 4
#define Sn 2048

typedef unsigned short ushort_t;

// ---------------- scratch (static device allocations; no cudaMalloc allowed) ---------
__device__ ushort_t g_xb[Tn * Dn];        // bf16 x
__device__ ushort_t g_qb[Tn * Dn];        // bf16 q
__device__ ushort_t g_kb[Tn * Dn];        // bf16 k
__device__ ushort_t g_vb[Tn * Dn];        // bf16 v
__device__ ushort_t g_ctxb[Tn * Dn];      // bf16 ctx
__device__ ushort_t g_wqb[Dn * Dn];
__device__ ushort_t g_wkb[Dn * Dn];
__device__ ushort_t g_wvb[Dn * Dn];
__device__ ushort_t g_wob[Dn * Dn];
__device__ float g_ao[Tn * Dn];
__device__ float g_x1[Tn * Dn];
__device__ float g_pmax[Tn];
__device__ float g_moe[Tn * Dn];
__device__ ushort_t g_xsortb[Tn * Dn];
__device__ ushort_t g_h1b[(size_t)Tn * Fn];
__device__ ushort_t g_w1b[(size_t)En * Fn * Dn];
__device__ ushort_t g_w2b[(size_t)En * Dn * Fn];
__device__ int g_route[Tn];
__device__ int g_dest[Tn];
__device__ int g_off[En + 1];

__device__ __forceinline__ void mma_bf16(float* c, const unsigned* a, const unsigned* b) {
  asm volatile(
      "mma.sync.aligned.m16n8k16.row.col.f32.bf16.bf16.f32 "
      "{%0,%1,%2,%3},{%4,%5,%6,%7},{%8,%9},{%0,%1,%2,%3};"
      : "+f"(c[0]), "+f"(c[1]), "+f"(c[2]), "+f"(c[3])
      : "r"(a[0]), "r"(a[1]), "r"(a[2]), "r"(a[3]), "r"(b[0]), "r"(b[1]));
}

// pack two f32 -> bf16x2 (lo = first arg, hi = second)
__device__ __forceinline__ unsigned pk2(float lo, float hi) {
  unsigned r;
  asm("cvt.rn.bf16x2.f32 %0, %1, %2;" : "=r"(r) : "f"(hi), "f"(lo));
  return r;
}

__device__ __forceinline__ unsigned smem_u32(const void* p) {
  return (unsigned)__cvta_generic_to_shared(p);
}

__device__ __forceinline__ void ldm4(unsigned* r, unsigned addr) {
  asm volatile("ldmatrix.sync.aligned.m8n8.x4.shared.b16 {%0,%1,%2,%3}, [%4];"
               : "=r"(r[0]), "=r"(r[1]), "=r"(r[2]), "=r"(r[3]) : "r"(addr));
}
__device__ __forceinline__ void ldm4t(unsigned* r, unsigned addr) {
  asm volatile("ldmatrix.sync.aligned.m8n8.x4.trans.shared.b16 {%0,%1,%2,%3}, [%4];"
               : "=r"(r[0]), "=r"(r[1]), "=r"(r[2]), "=r"(r[3]) : "r"(addr));
}

__device__ __forceinline__ void cp_async16(void* smem, const void* gmem) {
  unsigned sa = (unsigned)__cvta_generic_to_shared(smem);
  asm volatile("cp.async.cg.shared.global [%0], [%1], 16;" ::"r"(sa), "l"(gmem));
}
#define CP_COMMIT asm volatile("cp.async.commit_group;")
#define CP_WAIT(n) asm volatile("cp.async.wait_group %0;" ::"n"(n))

// =====================================================================================
// bf16 tensor-core GEMM body, 256 threads (8 warps = 4m x 2n, warp tile 32x64).
// Block tile 128x128, BK=64 bf16 (128B rows), 72-half row stride (conflict-free).
// 3-stage cp.async pipeline, ONE barrier per slab, 2 CTAs/SM.
// Inner loop: B fragments double-buffered (bqA/bqB) so each ldmatrix is issued one
// mma-group ahead of its consumer; next chunk's first B load hoisted into the
// current chunk's last group.
// =====================================================================================
#define BKH 64
#define LDHW 36  // words per row (= 72 halves = 64 data + 8 pad)
#define TSTGH (128 * LDHW)                      // per-buffer tile (A or B)
#define BGEMM_SMEM ((3 * TSTGH + 3 * TSTGH) * 4)  // 110592 B
#define GEMM_THR 256

template <int RELU, int OUTBF>
__device__ __forceinline__ void bgemm_body(
    const ushort_t* __restrict__ A, const ushort_t* __restrict__ W,
    const float* __restrict__ bp, void* __restrict__ Cv,
    int N, int K, int m0, int m_end, unsigned* smh) {
  int n0 = blockIdx.x * 128;
  unsigned* As = smh;
  unsigned* Bs = smh + 3 * TSTGH;

  int tid = threadIdx.x;
  int lane = tid & 31, wid = tid >> 5;
  int wm = (wid & 3) * 32;   // 4 warp-groups along m
  int wn = (wid >> 2) * 64;  // 2 warp-groups along n
  int g = lane >> 2, t = lane & 3;

  float acc[2][8][4];
#pragma unroll
  for (int i = 0; i < 2; i++)
#pragma unroll
    for (int j = 0; j < 8; j++)
#pragma unroll
      for (int l = 0; l < 4; l++) acc[i][j][l] = 0.f;

  unsigned a_base[2], b_base[4];
#pragma unroll
  for (int mf = 0; mf < 2; mf++) {
    int row = wm + mf * 16 + (lane & 15);
    a_base[mf] = smem_u32(As + row * LDHW) + ((lane >> 4) & 1) * 16;
  }
#pragma unroll
  for (int p = 0; p < 4; p++) {
    int row = wn + p * 16 + ((lane >> 4) & 1) * 8 + (lane & 7);
    b_base[p] = smem_u32(Bs + row * LDHW) + ((lane >> 3) & 1) * 16;
  }

  auto stage = [&](int s, int k0) {
#pragma unroll
    for (int i = 0; i < 4; i++) {
      int idx = tid + i * GEMM_THR;
      int row = idx >> 3, kq = (idx & 7);
      int grow = m0 + row;
      if (grow < m_end)
        cp_async16(As + s * TSTGH + row * LDHW + kq * 4,
                   A + (size_t)grow * K + k0 + kq * 8);
    }
#pragma unroll
    for (int i = 0; i < 4; i++) {
      int idx = tid + i * GEMM_THR;
      int row = idx >> 3, kq = (idx & 7);
      cp_async16(Bs + s * TSTGH + row * LDHW + kq * 4,
                 W + (size_t)(n0 + row) * K + k0 + kq * 8);
    }
  };

  int nslab = K / BKH;
  stage(0, 0);
  CP_COMMIT;
  stage(1, BKH);
  CP_COMMIT;

  for (int it = 0; it < nslab; it++) {
    int cur = it % 3;
    if (it + 2 < nslab) {
      CP_WAIT(1);
    } else {
      CP_WAIT(0);
    }
    __syncthreads();
    if (it + 2 < nslab) {
      stage((it + 2) % 3, (it + 2) * BKH);
      CP_COMMIT;
    }

    unsigned off = cur * (TSTGH * 4);
    unsigned af[2][4];
    unsigned bqA[4], bqB[4];

    // prologue of the slab: A frags for chunk 0, first B group
    ldm4(af[0], a_base[0] + off);
    ldm4(af[1], a_base[1] + off);
    ldm4(bqA, b_base[0] + off);

#pragma unroll
    for (int c = 0; c < 4; c++) {
#pragma unroll
      for (int p = 0; p < 4; p++) {
        unsigned* curq = (p & 1) ? bqB : bqA;
        unsigned* nxtq = (p & 1) ? bqA : bqB;
        // issue the NEXT B ldmatrix before consuming the current one
        if (p < 3) {
          ldm4(nxtq, b_base[p + 1] + off + c * 32);
        } else if (c < 3) {
          ldm4(nxtq, b_base[0] + off + (c + 1) * 32);
        }
#pragma unroll
        for (int mf = 0; mf < 2; mf++) {
          mma_bf16(acc[mf][2 * p], af[mf], curq);
          mma_bf16(acc[mf][2 * p + 1], af[mf], curq + 2);
        }
      }
      // A fragments for the next chunk (after this chunk's mmas are issued)
      if (c < 3) {
        ldm4(af[0], a_base[0] + off + (c + 1) * 32);
        ldm4(af[1], a_base[1] + off + (c + 1) * 32);
      }
    }
  }

#pragma unroll
  for (int nf = 0; nf < 8; nf++) {
    int col = n0 + wn + nf * 8 + 2 * t;
    float2 bb = *(const float2*)(bp + col);
#pragma unroll
    for (int mf = 0; mf < 2; mf++) {
      int row0 = m0 + wm + mf * 16 + g;
      float v0 = acc[mf][nf][0] + bb.x;
      float v1 = acc[mf][nf][1] + bb.y;
      float v2 = acc[mf][nf][2] + bb.x;
      float v3 = acc[mf][nf][3] + bb.y;
      if (RELU) {
        v0 = fmaxf(v0, 0.f); v1 = fmaxf(v1, 0.f);
        v2 = fmaxf(v2, 0.f); v3 = fmaxf(v3, 0.f);
      }
      if (OUTBF) {
        ushort_t* C = (ushort_t*)Cv;
        if (row0 < m_end) *(unsigned*)(C + (size_t)row0 * N + col) = pk2(v0, v1);
        if (row0 + 8 < m_end) *(unsigned*)(C + (size_t)(row0 + 8) * N + col) = pk2(v2, v3);
      } else {
        float* C = (float*)Cv;
        if (row0 < m_end)
          *(float2*)(C + (size_t)row0 * N + col) = make_float2(v0, v1);
        if (row0 + 8 < m_end)
          *(float2*)(C + (size_t)(row0 + 8) * N + col) = make_float2(v2, v3);
      }
    }
  }
}

// Fused QKV projection (bf16 in/out): z selects (wq,bq,q)/(wk,bk,k)/(wv,bv,v)
__global__ void __launch_bounds__(GEMM_THR, 2) bgemm_qkv(
    const ushort_t* __restrict__ A,
    const ushort_t* __restrict__ w0, const ushort_t* __restrict__ w1,
    const ushort_t* __restrict__ w2,
    const float* __restrict__ b0, const float* __restrict__ b1,
    const float* __restrict__ b2,
    ushort_t* __restrict__ c0, ushort_t* __restrict__ c1, ushort_t* __restrict__ c2) {
  extern __shared__ unsigned smh[];
  int z = blockIdx.z;
  const ushort_t* W = (z == 0) ? w0 : (z == 1) ? w1 : w2;
  const float* bb = (z == 0) ? b0 : (z == 1) ? b1 : b2;
  ushort_t* C = (z == 0) ? c0 : (z == 1) ? c1 : c2;
  int m0 = (int)blockIdx.y * 128;
  bgemm_body<0, 1>(A, W, bb, C, Dn, Dn, m0, Tn, smh);
}

// Dense O-projection (bf16 in, fp32 out)
__global__ void __launch_bounds__(GEMM_THR, 2) bgemm_o(
    const ushort_t* __restrict__ A, const ushort_t* __restrict__ W,
    const float* __restrict__ bias, float* __restrict__ C) {
  extern __shared__ unsigned smh[];
  int m0 = (int)blockIdx.y * 128;
  bgemm_body<0, 0>(A, W, bias, C, Dn, Dn, m0, Tn, smh);
}

// Expert-batched MoE GEMM
template <int RELU, int OUTBF>
__global__ void __launch_bounds__(GEMM_THR, 2) bgemm_moe(
    const ushort_t* __restrict__ A, const ushort_t* __restrict__ W,
    const float* __restrict__ bias, void* __restrict__ Cv,
    int N, int K, const int* __restrict__ off, size_t wstride) {
  extern __shared__ unsigned smh[];
  int e = blockIdx.z;
  int m_start = off[e], m_end = off[e + 1];
  int m0 = m_start + (int)blockIdx.y * 128;
  if (m0 >= m_end) return;
  bgemm_body<RELU, OUTBF>(A, W + (size_t)e * wstride, bias + (size_t)e * N, Cv,
                          N, K, m0, m_end, smh);
}

// fp32 -> bf16 grid-stride conversion (graph-safe, deterministic)
__global__ void __launch_bounds__(256) cvt_bf16_gs(
    const float* __restrict__ src, ushort_t* __restrict__ dst, int n4) {
  int stride = gridDim.x * 256;
  for (int i = blockIdx.x * 256 + threadIdx.x; i < n4; i += stride) {
    float4 v = ((const float4*)src)[i];
    ((uint2*)dst)[i] = make_uint2(pk2(v.x, v.y), pk2(v.z, v.w));
  }
}

// 5-way conversion in one launch: z=0 -> x (size nx4), z=1..4 -> dense weights (nw4)
__global__ void __launch_bounds__(256) cvt_bf16x5(
    const float* __restrict__ sx,
    const float* __restrict__ s0, const float* __restrict__ s1,
    const float* __restrict__ s2, const float* __restrict__ s3,
    ushort_t* __restrict__ dx,
    ushort_t* __restrict__ d0, ushort_t* __restrict__ d1,
    ushort_t* __restrict__ d2, ushort_t* __restrict__ d3,
    int nx4, int nw4) {
  int z = blockIdx.z;
  const float* src = (z == 0) ? sx : (z == 1) ? s0 : (z == 2) ? s1 : (z == 3) ? s2 : s3;
  ushort_t* dst = (z == 0) ? dx : (z == 1) ? d0 : (z == 2) ? d1 : (z == 3) ? d2 : d3;
  int n4 = (z == 0) ? nx4 : nw4;
  int stride = gridDim.x * 256;
  for (int i = blockIdx.x * 256 + threadIdx.x; i < n4; i += stride) {
    float4 v = ((const float4*)src)[i];
    ((uint2*)dst)[i] = make_uint2(pk2(v.x, v.y), pk2(v.z, v.w));
  }
}

// =====================================================================================
// bf16 flash attention, 3-stage K/V pipeline; 2 CTAs/SM.
// =====================================================================================
#define FQT 128
#define FKT 64
#define FSW 36
#define FNT (Sn / FKT)

__global__ void __launch_bounds__(256, 2) flash_bf(
    const ushort_t* __restrict__ Q, const ushort_t* __restrict__ K,
    const ushort_t* __restrict__ V, const int* __restrict__ mask,
    ushort_t* __restrict__ O) {
  __shared__ unsigned Qs[FQT * FSW];
  __shared__ unsigned Ks[3][FKT * FSW];
  __shared__ unsigned Vs[3][FKT * FSW];
  __shared__ int msk[3][FKT];

  int bh = blockIdx.y;
  int b = bh >> 4, h = bh & 15;
  int q0 = blockIdx.x * FQT;
  int tid = threadIdx.x;
  int lane = tid & 31, wid = tid >> 5;
  int g = lane >> 2, t = lane & 3;
  int wrow = wid * 16;

  auto stage_kv = [&](int s, int t0) {
#pragma unroll
    for (int l = 0; l < 2; l++) {
      int idx = tid + l * 256;
      int r = idx >> 3, ch = idx & 7;
      size_t base = (size_t)(b * Sn + t0 + r) * Dn + h * HDn + ch * 8;
      cp_async16(Ks[s] + r * FSW + ch * 4, K + base);
      cp_async16(Vs[s] + r * FSW + ch * 4, V + base);
    }
  };

#pragma unroll
  for (int l = 0; l < 4; l++) {
    int idx = tid + l * 256;
    int r = idx >> 3, ch = idx & 7;
    cp_async16(Qs + r * FSW + ch * 4,
               Q + (size_t)(b * Sn + q0 + r) * Dn + h * HDn + ch * 8);
  }
  stage_kv(0, 0);
  CP_COMMIT;
  stage_kv(1, FKT);
  CP_COMMIT;
  if (tid < FKT) {
    msk[0][tid] = mask[b * Sn + tid];
    msk[1][tid] = mask[b * Sn + FKT + tid];
  }

  float o[8][4];
#pragma unroll
  for (int nf = 0; nf < 8; nf++)
#pragma unroll
    for (int c = 0; c < 4; c++) o[nf][c] = 0.f;
  float mrow0 = -1e30f, mrow1 = -1e30f;
  float lrow0 = 0.f, lrow1 = 0.f;

  unsigned qa_base = smem_u32(Qs + (wrow + (lane & 15)) * FSW + (lane >> 4) * 4);
  unsigned kb_row = (lane & 7) + ((lane >> 4) & 1) * 8;
  unsigned kb_koff = ((lane >> 3) & 1) * 4;
  unsigned vb_key = (lane & 7) + ((lane >> 3) & 1) * 8;
  unsigned vb_doff = ((lane >> 4) & 1) * 4;

  for (int it = 0; it < FNT; it++) {
    int cur = it % 3;
    if (it + 2 < FNT) {
      CP_WAIT(1);
    } else {
      CP_WAIT(0);
    }
    __syncthreads();
    if (it + 2 < FNT) {
      int s = (it + 2) % 3;
      stage_kv(s, (it + 2) * FKT);
      CP_COMMIT;
      if (tid < FKT) msk[s][tid] = mask[b * Sn + (it + 2) * FKT + tid];
    }

    const unsigned* Kc = Ks[cur];
    const unsigned* Vc = Vs[cur];
    const int* mc = msk[cur];

    float s[8][4];
#pragma unroll
    for (int nf = 0; nf < 8; nf++)
#pragma unroll
      for (int c = 0; c < 4; c++) s[nf][c] = 0.f;

#pragma unroll
    for (int c = 0; c < 4; c++) {
      unsigned a[4];
      ldm4(a, qa_base + (c * 8) * 4);
#pragma unroll
      for (int ng = 0; ng < 4; ng++) {
        unsigned bq[4];
        unsigned addr = smem_u32(Kc + (ng * 16 + kb_row) * FSW + c * 8 + kb_koff);
        ldm4(bq, addr);
        mma_bf16(s[2 * ng], a, bq);
        mma_bf16(s[2 * ng + 1], a, bq + 2);
      }
    }

#pragma unroll
    for (int nf = 0; nf < 8; nf++) {
      int col = nf * 8 + 2 * t;
      bool z0 = (mc[col] == 0), z1 = (mc[col + 1] == 0);
      s[nf][0] = z0 ? -1e10f : s[nf][0] * 0.125f;
      s[nf][1] = z1 ? -1e10f : s[nf][1] * 0.125f;
      s[nf][2] = z0 ? -1e10f : s[nf][2] * 0.125f;
      s[nf][3] = z1 ? -1e10f : s[nf][3] * 0.125f;
    }

    float mx0 = -1e30f, mx1 = -1e30f;
#pragma unroll
    for (int nf = 0; nf < 8; nf++) {
      mx0 = fmaxf(mx0, fmaxf(s[nf][0], s[nf][1]));
      mx1 = fmaxf(mx1, fmaxf(s[nf][2], s[nf][3]));
    }
    mx0 = fmaxf(mx0, __shfl_xor_sync(0xffffffffu, mx0, 1));
    mx0 = fmaxf(mx0, __shfl_xor_sync(0xffffffffu, mx0, 2));
    mx1 = fmaxf(mx1, __shfl_xor_sync(0xffffffffu, mx1, 1));
    mx1 = fmaxf(mx1, __shfl_xor_sync(0xffffffffu, mx1, 2));

    float mn0 = fmaxf(mrow0, mx0), mn1 = fmaxf(mrow1, mx1);
    float sc0 = __expf(mrow0 - mn0), sc1 = __expf(mrow1 - mn1);
    mrow0 = mn0; mrow1 = mn1;

    float rs0 = 0.f, rs1 = 0.f;
    unsigned pk[8][2];
#pragma unroll
    for (int nf = 0; nf < 8; nf++) {
      s[nf][0] = __expf(s[nf][0] - mn0);
      s[nf][1] = __expf(s[nf][1] - mn0);
      s[nf][2] = __expf(s[nf][2] - mn1);
      s[nf][3] = __expf(s[nf][3] - mn1);
      rs0 += s[nf][0] + s[nf][1];
      rs1 += s[nf][2] + s[nf][3];
      pk[nf][0] = pk2(s[nf][0], s[nf][1]);
      pk[nf][1] = pk2(s[nf][2], s[nf][3]);
    }
    rs0 += __shfl_xor_sync(0xffffffffu, rs0, 1);
    rs0 += __shfl_xor_sync(0xffffffffu, rs0, 2);
    rs1 += __shfl_xor_sync(0xffffffffu, rs1, 1);
    rs1 += __shfl_xor_sync(0xffffffffu, rs1, 2);
    lrow0 = lrow0 * sc0 + rs0;
    lrow1 = lrow1 * sc1 + rs1;

#pragma unroll
    for (int nf = 0; nf < 8; nf++) {
      o[nf][0] *= sc0; o[nf][1] *= sc0;
      o[nf][2] *= sc1; o[nf][3] *= sc1;
    }

#pragma unroll
    for (int c = 0; c < 4; c++) {
      unsigned a[4] = {pk[2 * c][0], pk[2 * c][1], pk[2 * c + 1][0], pk[2 * c + 1][1]};
#pragma unroll
      for (int dg = 0; dg < 4; dg++) {
        unsigned bv[4];
        unsigned addr = smem_u32(Vc + (c * 16 + vb_key) * FSW + dg * 8 + vb_doff);
        ldm4t(bv, addr);
        mma_bf16(o[2 * dg], a, bv);
        mma_bf16(o[2 * dg + 1], a, bv + 2);
      }
    }
  }

  float inv0 = 1.f / lrow0, inv1 = 1.f / lrow1;
  int row = b * Sn + q0 + wrow + g;
#pragma unroll
  for (int nf = 0; nf < 8; nf++) {
    int col = h * HDn + nf * 8 + 2 * t;
    *(unsigned*)(O + (size_t)row * Dn + col) = pk2(o[nf][0] * inv0, o[nf][1] * inv0);
    *(unsigned*)(O + (size_t)(row + 8) * Dn + col) = pk2(o[nf][2] * inv1, o[nf][3] * inv1);
  }
}

// =====================================================================================
// out = LayerNorm(A + B) * g + be   (final LN)
// =====================================================================================
__global__ void __launch_bounds__(256) add_ln(
    const float* __restrict__ A, const float* __restrict__ Bv,
    const float* __restrict__ g, const float* __restrict__ be,
    float* __restrict__ out) {
  int t = blockIdx.x;
  int tid = threadIdx.x;
  float4 a = *(const float4*)(A + (size_t)t * Dn + tid * 4);
  float4 b = *(const float4*)(Bv + (size_t)t * Dn + tid * 4);
  float4 x = make_float4(a.x + b.x, a.y + b.y, a.z + b.z, a.w + b.w);
  float sumv = x.x + x.y + x.z + x.w;
  float sq = x.x * x.x + x.y * x.y + x.z * x.z + x.w * x.w;
#pragma unroll
  for (int off = 16; off; off >>= 1) {
    sumv += __shfl_xor_sync(0xffffffffu, sumv, off);
    sq += __shfl_xor_sync(0xffffffffu, sq, off);
  }
  __shared__ float ws[8], wq[8];
  __shared__ float s_mean, s_rstd;
  int wid = tid >> 5, lane = tid & 31;
  if (lane == 0) {
    ws[wid] = sumv;
    wq[wid] = sq;
  }
  __syncthreads();
  if (tid == 0) {
    float s = 0.f, q = 0.f;
#pragma unroll
    for (int i = 0; i < 8; i++) {
      s += ws[i];
      q += wq[i];
    }
    float mean = s * (1.f / Dn);
    float var = q * (1.f / Dn) - mean * mean;
    s_mean = mean;
    s_rstd = rsqrtf(var + 1e-5f);
  }
  __syncthreads();
  float mean = s_mean, rstd = s_rstd;
  float4 gg = *(const float4*)(g + tid * 4);
  float4 bb = *(const float4*)(be + tid * 4);
  float4 y;
  y.x = (x.x - mean) * rstd * gg.x + bb.x;
  y.y = (x.y - mean) * rstd * gg.y + bb.y;
  y.z = (x.z - mean) * rstd * gg.z + bb.z;
  y.w = (x.w - mean) * rstd * gg.w + bb.w;
  *(float4*)(out + (size_t)t * Dn + tid * 4) = y;
}

// =====================================================================================
// Fused add + LayerNorm + router.
// =====================================================================================
__global__ void __launch_bounds__(256) add_ln_router(
    const float* __restrict__ A, const float* __restrict__ Bv,
    const float* __restrict__ g, const float* __restrict__ be,
    const float* __restrict__ sw, const float* __restrict__ sb,
    float* __restrict__ x1, float* __restrict__ pmax, int* __restrict__ route) {
  int t = blockIdx.x;
  int tid = threadIdx.x;
  float4 a = *(const float4*)(A + (size_t)t * Dn + tid * 4);
  float4 b = *(const float4*)(Bv + (size_t)t * Dn + tid * 4);
  float4 x = make_float4(a.x + b.x, a.y + b.y, a.z + b.z, a.w + b.w);
  float sumv = x.x + x.y + x.z + x.w;
  float sq = x.x * x.x + x.y * x.y + x.z * x.z + x.w * x.w;
#pragma unroll
  for (int off = 16; off; off >>= 1) {
    sumv += __shfl_xor_sync(0xffffffffu, sumv, off);
    sq += __shfl_xor_sync(0xffffffffu, sq, off);
  }
  __shared__ float ws[8], wq[8];
  __shared__ float s_mean, s_rstd;
  int wid = tid >> 5, lane = tid & 31;
  if (lane == 0) {
    ws[wid] = sumv;
    wq[wid] = sq;
  }
  __syncthreads();
  if (tid == 0) {
    float s = 0.f, q = 0.f;
#pragma unroll
    for (int i = 0; i < 8; i++) {
      s += ws[i];
      q += wq[i];
    }
    float mean = s * (1.f / Dn);
    float var = q * (1.f / Dn) - mean * mean;
    s_mean = mean;
    s_rstd = rsqrtf(var + 1e-5f);
  }
  __syncthreads();
  float mean = s_mean, rstd = s_rstd;
  float4 gg = *(const float4*)(g + tid * 4);
  float4 bb = *(const float4*)(be + tid * 4);
  float4 y;
  y.x = (x.x - mean) * rstd * gg.x + bb.x;
  y.y = (x.y - mean) * rstd * gg.y + bb.y;
  y.z = (x.z - mean) * rstd * gg.z + bb.z;
  y.w = (x.w - mean) * rstd * gg.w + bb.w;
  *(float4*)(x1 + (size_t)t * Dn + tid * 4) = y;

  float acc[En];
#pragma unroll
  for (int e = 0; e < En; e++) {
    float4 w = *(const float4*)(sw + (size_t)e * Dn + tid * 4);
    acc[e] = y.x * w.x + y.y * w.y + y.z * w.z + y.w * w.w;
  }
#pragma unroll
  for (int e = 0; e < En; e++)
#pragma unroll
    for (int off = 16; off; off >>= 1)
      acc[e] += __shfl_xor_sync(0xffffffffu, acc[e], off);

  __shared__ float wsum[8][En];
  if (lane == 0)
#pragma unroll
    for (int e = 0; e < En; e++) wsum[wid][e] = acc[e];
  __syncthreads();
  if (tid == 0) {
    float lg[En];
#pragma unroll
    for (int e = 0; e < En; e++) {
      float s = 0.f;
#pragma unroll
      for (int w = 0; w < 8; w++) s += wsum[w][e];
      lg[e] = s + sb[e];
    }
    int am = 0;
    float mx = lg[0];
#pragma unroll
    for (int e = 1; e < En; e++)
      if (lg[e] > mx) {  // strict > == jnp.argmax first-max tie-break
        mx = lg[e];
        am = e;
      }
    float sum = 0.f;
#pragma unroll
    for (int e = 0; e < En; e++) sum += __expf(lg[e] - mx);
    route[t] = am;
    pmax[t] = 1.f / sum;
  }
}

// =====================================================================================
// Deterministic stable counting sort by expert id (single block).
// =====================================================================================
__global__ void __launch_bounds__(256) sort_routes(
    const int* __restrict__ route, int* __restrict__ dest, int* __restrict__ off) {
  __shared__ int hist[256][En];
  __shared__ int tot[En];
  __shared__ int eoff[En + 1];
  int tid = threadIdx.x;
  int h[En];
#pragma unroll
  for (int e = 0; e < En; e++) h[e] = 0;
  int base = tid * 32;
  for (int i = 0; i < 32; i++) h[route[base + i]]++;
#pragma unroll
  for (int e = 0; e < En; e++) hist[tid][e] = h[e];
  __syncthreads();
  if (tid < En) {
    int e = tid;
    int run = 0;
    for (int i = 0; i < 256; i++) {
      int v = hist[i][e];
      hist[i][e] = run;
      run += v;
    }
    tot[e] = run;
  }
  __syncthreads();
  if (tid == 0) {
    int r = 0;
    for (int e = 0; e < En; e++) {
      eoff[e] = r;
      off[e] = r;
      r += tot[e];
    }
    eoff[En] = r;
    off[En] = r;
  }
  __syncthreads();
  int run[En];
#pragma unroll
  for (int e = 0; e < En; e++) run[e] = eoff[e] + hist[tid][e];
  for (int i = 0; i < 32; i++) {
    int e = route[base + i];
    dest[base + i] = run[e]++;
  }
}

// xsortb[dest[t], :] = bf16(x1[t, :] * pmax[t]); 8 tokens per block
__global__ void __launch_bounds__(256) gather_rows_bf(
    const float* __restrict__ x1, const float* __restrict__ pmax,
    const int* __restrict__ dest, ushort_t* __restrict__ xsortb) {
  int c = threadIdx.x;
#pragma unroll
  for (int i = 0; i < 8; i++) {
    int t = blockIdx.x * 8 + i;
    int dt = dest[t];
    float p = pmax[t];
    float4 v = ((const float4*)x1)[(size_t)t * (Dn / 4) + c];
    ((uint2*)xsortb)[(size_t)dt * (Dn / 4) + c] =
        make_uint2(pk2(v.x * p, v.y * p), pk2(v.z * p, v.w * p));
  }
}

// =====================================================================================
extern "C" void kernel_launch(void* const* d_in, const int* in_sizes, int n_in,
                              void* d_out, int out_size) {
  const float* x = (const float*)d_in[0];
  const float* wq = (const float*)d_in[1];
  const float* bq = (const float*)d_in[2];
  const float* wk = (const float*)d_in[3];
  const float* bk = (const float*)d_in[4];
  const float* wv = (const float*)d_in[5];
  const float* bv = (const float*)d_in[6];
  const float* wo = (const float*)d_in[7];
  const float* bo = (const float*)d_in[8];
  const float* ln1g = (const float*)d_in[9];
  const float* ln1b = (const float*)d_in[10];
  const float* ln2g = (const float*)d_in[11];
  const float* ln2b = (const float*)d_in[12];
  const float* sw = (const float*)d_in[13];
  const float* sb = (const float*)d_in[14];
  const float* ew1 = (const float*)d_in[15];
  const float* eb1 = (const float*)d_in[16];
  const float* ew2 = (const float*)d_in[17];
  const float* eb2 = (const float*)d_in[18];
  const int* mask = (const int*)d_in[19];
  float* out = (float*)d_out;

  ushort_t *xb, *qb, *kb, *vb, *ctxb, *wqb, *wkb, *wvb, *wob;
  ushort_t *xsortb, *h1b, *w1b, *w2b;
  float *ao, *x1, *pmax, *moe;
  int *route, *dest, *off;
  cudaGetSymbolAddress((void**)&xb, g_xb);
  cudaGetSymbolAddress((void**)&qb, g_qb);
  cudaGetSymbolAddress((void**)&kb, g_kb);
  cudaGetSymbolAddress((void**)&vb, g_vb);
  cudaGetSymbolAddress((void**)&ctxb, g_ctxb);
  cudaGetSymbolAddress((void**)&wqb, g_wqb);
  cudaGetSymbolAddress((void**)&wkb, g_wkb);
  cudaGetSymbolAddress((void**)&wvb, g_wvb);
  cudaGetSymbolAddress((void**)&wob, g_wob);
  cudaGetSymbolAddress((void**)&ao, g_ao);
  cudaGetSymbolAddress((void**)&x1, g_x1);
  cudaGetSymbolAddress((void**)&pmax, g_pmax);
  cudaGetSymbolAddress((void**)&moe, g_moe);
  cudaGetSymbolAddress((void**)&xsortb, g_xsortb);
  cudaGetSymbolAddress((void**)&h1b, g_h1b);
  cudaGetSymbolAddress((void**)&w1b, g_w1b);
  cudaGetSymbolAddress((void**)&w2b, g_w2b);
  cudaGetSymbolAddress((void**)&route, g_route);
  cudaGetSymbolAddress((void**)&dest, g_dest);
  cudaGetSymbolAddress((void**)&off, g_off);

  cudaFuncSetAttribute(bgemm_qkv, cudaFuncAttributeMaxDynamicSharedMemorySize, BGEMM_SMEM);
  cudaFuncSetAttribute(bgemm_o, cudaFuncAttributeMaxDynamicSharedMemorySize, BGEMM_SMEM);
  cudaFuncSetAttribute(bgemm_moe<1, 1>, cudaFuncAttributeMaxDynamicSharedMemorySize, BGEMM_SMEM);
  cudaFuncSetAttribute(bgemm_moe<0, 0>, cudaFuncAttributeMaxDynamicSharedMemorySize, BGEMM_SMEM);

  dim3 blk(256);
  dim3 gblk(GEMM_THR);
  const int NCVT = 1184;  // 8 blocks/SM

  // side stream for expert-weight conversion (fork/join inside graph capture)
  cudaStream_t s2;
  cudaStreamCreateWithFlags(&s2, cudaStreamNonBlocking);
  cudaEvent_t ev_fork, ev_join;
  cudaEventCreateWithFlags(&ev_fork, cudaEventDisableTiming);
  cudaEventCreateWithFlags(&ev_join, cudaEventDisableTiming);

  const int XN4 = Tn * Dn / 4;
  const int WN4 = Dn * Dn / 4;
  const int W1N4 = En * Fn * Dn / 4;

  // fork: expert weight cvts run concurrently with the attention block
  cudaEventRecord(ev_fork, 0);
  cudaStreamWaitEvent(s2, ev_fork, 0);
  cvt_bf16_gs<<<NCVT, blk, 0, s2>>>(ew1, w1b, W1N4);
  cvt_bf16_gs<<<NCVT, blk, 0, s2>>>(ew2, w2b, W1N4);
  cudaEventRecord(ev_join, s2);

  // main stream: ONE launch converts x + all four dense weights
  cvt_bf16x5<<<dim3(NCVT / 5, 1, 5), blk>>>(
      x, wq, wk, wv, wo, xb, wqb, wkb, wvb, wob, XN4, WN4);

  // --- attention block ---
  bgemm_qkv<<<dim3(Dn / 128, Tn / 128, 3), gblk, BGEMM_SMEM>>>(
      xb, wqb, wkb, wvb, bq, bk, bv, qb, kb, vb);
  flash_bf<<<dim3(Sn / FQT, Bn * Hn), blk>>>(qb, kb, vb, mask, ctxb);
  bgemm_o<<<dim3(Dn / 128, Tn / 128, 1), gblk, BGEMM_SMEM>>>(ctxb, wob, bo, ao);

  // --- MoE block (add_ln1 fused with router) ---
  add_ln_router<<<Tn, 256>>>(x, ao, ln1g, ln1b, sw, sb, x1, pmax, route);
  sort_routes<<<1, 256>>>(route, dest, off);
  gather_rows_bf<<<Tn / 8, 256>>>(x1, pmax, dest, xsortb);

  // join: expert weights must be converted before the MoE GEMMs
  cudaStreamWaitEvent(0, ev_join, 0);
  bgemm_moe<1, 1><<<dim3(Fn / 128, Tn / 128, En), gblk, BGEMM_SMEM>>>(
      xsortb, w1b, eb1, h1b, Fn, Dn, off, (size_t)Fn * Dn);
  bgemm_moe<0, 0><<<dim3(Dn / 128, Tn / 128, En), gblk, BGEMM_SMEM>>>(
      h1b, w2b, eb2, moe, Dn, Fn, off, (size_t)Dn * Fn);
  add_ln<<<Tn, 256>>>(x1, moe, ln2g, ln2b, out);
}